// round 1
// baseline (speedup 1.0000x reference)
#include <cuda_runtime.h>
#include <math.h>

#define HW      65536
#define IMG     256
#define BATCH   2
#define CDIM    96
#define HEADS   8
#define CHEAD   12
#define HIDDEN  255

// ---------------------------------------------------------------------------
// Scratch (static device allocations; ~1.67 GB total)
// ---------------------------------------------------------------------------
__device__ float g_xn   [BATCH * CDIM * HW];
__device__ float g_yn   [BATCH * CDIM * HW];
__device__ float g_qkvA [BATCH * 3 * CDIM * HW];
__device__ float g_qkvAd[BATCH * 3 * CDIM * HW];
__device__ float g_qkvB [BATCH * 3 * CDIM * HW];
__device__ float g_qkvBd[BATCH * 3 * CDIM * HW];
__device__ float g_preA [BATCH * CDIM * HW];
__device__ float g_preB [BATCH * CDIM * HW];
__device__ float g_outAB[BATCH * 2 * CDIM * HW];
__device__ float g_x1   [BATCH * CDIM * HW];
__device__ float g_x1n  [BATCH * CDIM * HW];
__device__ float g_t    [BATCH * 2 * HIDDEN * HW];
__device__ float g_td   [BATCH * 2 * HIDDEN * HW];
__device__ float g_gate [BATCH * HIDDEN * HW];
__device__ float g_normsA[BATCH * 2 * CDIM];   // q,k row norms, branch A
__device__ float g_normsB[BATCH * 2 * CDIM];
__device__ float g_gpartA[BATCH * HEADS * 64 * 144];
__device__ float g_gpartB[BATCH * HEADS * 64 * 144];
__device__ float g_attnA [BATCH * HEADS * 144];
__device__ float g_attnB [BATCH * HEADS * 144];

// ---------------------------------------------------------------------------
// LayerNorm over channel dim (C=96) at each pixel.
// One thread per pixel; 96 channel values held in registers.
// ---------------------------------------------------------------------------
__global__ void ln_kernel(const float* __restrict__ in,
                          const float* __restrict__ w,
                          const float* __restrict__ bias,
                          float* __restrict__ out) {
    int p = blockIdx.x * blockDim.x + threadIdx.x;
    int b = blockIdx.y;
    const float* ip = in  + (size_t)b * CDIM * HW + p;
    float*       op = out + (size_t)b * CDIM * HW + p;

    float v[CDIM];
    float s = 0.f;
#pragma unroll
    for (int c = 0; c < CDIM; c++) { v[c] = ip[(size_t)c * HW]; s += v[c]; }
    float mu = s * (1.f / CDIM);
    float vs = 0.f;
#pragma unroll
    for (int c = 0; c < CDIM; c++) { float d = v[c] - mu; vs += d * d; }
    float inv = rsqrtf(vs * (1.f / CDIM) + 1e-5f);
#pragma unroll
    for (int c = 0; c < CDIM; c++)
        op[(size_t)c * HW] = (v[c] - mu) * inv * w[c] + bias[c];
}

// ---------------------------------------------------------------------------
// conv1x1 as GEMM: Y[M,N] = W[M,K] @ X[K,N] (+ residual), per batch (grid.z).
// N = HW (65536). BM=BN=64, BK=16, 256 threads, 4x4 microtile.
// grid.x = M tiles (fast-varying -> blocks sharing an X panel co-resident).
// ---------------------------------------------------------------------------
template <bool RES>
__global__ void conv1x1_kernel(const float* __restrict__ Wt,
                               const float* __restrict__ X,
                               const float* __restrict__ R,
                               float* __restrict__ Y,
                               int M, int K,
                               size_t xBatch, size_t yBatch, size_t rBatch) {
    const int N = HW;
    __shared__ float As[16][64];
    __shared__ float Bs[16][64];

    int b = blockIdx.z;
    const float* Xb = X + (size_t)b * xBatch;
    float*       Yb = Y + (size_t)b * yBatch;
    const float* Rb = RES ? (R + (size_t)b * rBatch) : nullptr;

    int m0 = blockIdx.x * 64;
    int n0 = blockIdx.y * 64;
    int tid = threadIdx.x;
    int tn = tid & 15;      // 0..15 -> 4 output columns each
    int tm = tid >> 4;      // 0..15 -> 4 output rows each

    float acc[4][4] = {};

    for (int kk = 0; kk < K; kk += 16) {
        // Load A tile (W): 64 x 16
#pragma unroll
        for (int i = 0; i < 4; i++) {
            int idx = tid + i * 256;
            int m = idx >> 4, k = idx & 15;
            float av = 0.f;
            if (m0 + m < M && kk + k < K) av = Wt[(size_t)(m0 + m) * K + kk + k];
            As[k][m] = av;
        }
        // Load B tile (X): 16 x 64, coalesced along n
#pragma unroll
        for (int i = 0; i < 4; i++) {
            int idx = tid + i * 256;
            int k = idx >> 6, n = idx & 63;
            float bv = 0.f;
            if (kk + k < K) bv = Xb[(size_t)(kk + k) * N + n0 + n];
            Bs[k][n] = bv;
        }
        __syncthreads();
#pragma unroll
        for (int k = 0; k < 16; k++) {
            float a[4], bb[4];
#pragma unroll
            for (int i = 0; i < 4; i++) a[i]  = As[k][tm * 4 + i];
#pragma unroll
            for (int j = 0; j < 4; j++) bb[j] = Bs[k][tn * 4 + j];
#pragma unroll
            for (int i = 0; i < 4; i++)
#pragma unroll
                for (int j = 0; j < 4; j++) acc[i][j] += a[i] * bb[j];
        }
        __syncthreads();
    }

#pragma unroll
    for (int i = 0; i < 4; i++) {
        int m = m0 + tm * 4 + i;
        if (m < M) {
#pragma unroll
            for (int j = 0; j < 4; j++) {
                int n = n0 + tn * 4 + j;
                float v = acc[i][j];
                if (RES) v += Rb[(size_t)m * N + n];
                Yb[(size_t)m * N + n] = v;
            }
        }
    }
}

// ---------------------------------------------------------------------------
// Depthwise 3x3, SAME (zero) padding, cross-correlation (XLA semantics).
// One thread per output pixel; grid.z = plane index (b*C + c).
// ---------------------------------------------------------------------------
__global__ void dw3_kernel(const float* __restrict__ in,
                           const float* __restrict__ w,
                           float* __restrict__ out, int C) {
    int pl = blockIdx.z;
    int c  = pl % C;
    int x  = blockIdx.x * 32 + threadIdx.x;
    int y  = blockIdx.y * 8  + threadIdx.y;
    const float* ip = in + (size_t)pl * HW;
    const float* wp = w + c * 9;
    float s = 0.f;
#pragma unroll
    for (int dy = -1; dy <= 1; dy++) {
        int yy = y + dy;
        if (yy < 0 || yy >= IMG) continue;
#pragma unroll
        for (int dx = -1; dx <= 1; dx++) {
            int xx = x + dx;
            if (xx < 0 || xx >= IMG) continue;
            s += wp[(dy + 1) * 3 + (dx + 1)] * ip[yy * IMG + xx];
        }
    }
    out[(size_t)pl * HW + y * IMG + x] = s;
}

// ---------------------------------------------------------------------------
// Row L2 norms for q,k (first 192 channels of a qkv buffer). One block/row.
// ---------------------------------------------------------------------------
__global__ void rownorm_kernel(const float* __restrict__ in,
                               float* __restrict__ norms) {
    int r  = blockIdx.x;              // b*192 + ch
    int b  = r / 192, ch = r % 192;
    const float* ip = in + ((size_t)b * 288 + ch) * HW;
    float s = 0.f;
    for (int i = threadIdx.x; i < HW; i += blockDim.x) {
        float v = ip[i];
        s += v * v;
    }
    __shared__ float red[256];
    red[threadIdx.x] = s;
    __syncthreads();
    for (int off = 128; off > 0; off >>= 1) {
        if (threadIdx.x < off) red[threadIdx.x] += red[threadIdx.x + off];
        __syncthreads();
    }
    if (threadIdx.x == 0) norms[r] = sqrtf(red[0]);
}

// ---------------------------------------------------------------------------
// Gram stage 1: partial G[c,d] = sum_n q[c,n]*k[d,n] over a 1024-pixel chunk.
// grid = (64 chunks, HEADS, BATCH), 256 threads, 144 register accumulators.
// ---------------------------------------------------------------------------
__global__ void __launch_bounds__(256) gram1_kernel(
        const float* __restrict__ Q, const float* __restrict__ Kp,
        float* __restrict__ part) {
    int chunk = blockIdx.x, h = blockIdx.y, b = blockIdx.z;
    const float* qb = Q  + ((size_t)b * 288 + h * CHEAD) * HW;
    const float* kb = Kp + ((size_t)b * 288 + h * CHEAD) * HW;

    float acc[144];
#pragma unroll
    for (int i = 0; i < 144; i++) acc[i] = 0.f;

    int p0 = chunk * 1024 + threadIdx.x;
    for (int it = 0; it < 4; it++) {
        int p = p0 + it * 256;
        float qv[CHEAD], kv[CHEAD];
#pragma unroll
        for (int c = 0; c < CHEAD; c++) qv[c] = qb[(size_t)c * HW + p];
#pragma unroll
        for (int d = 0; d < CHEAD; d++) kv[d] = kb[(size_t)d * HW + p];
#pragma unroll
        for (int c = 0; c < CHEAD; c++)
#pragma unroll
            for (int d = 0; d < CHEAD; d++) acc[c * CHEAD + d] += qv[c] * kv[d];
    }

    __shared__ float red[8];
    float* outp = part + (((size_t)(b * HEADS + h)) * 64 + chunk) * 144;
#pragma unroll
    for (int i = 0; i < 144; i++) {
        float v = acc[i];
#pragma unroll
        for (int off = 16; off > 0; off >>= 1)
            v += __shfl_down_sync(0xffffffffu, v, off);
        if ((threadIdx.x & 31) == 0) red[threadIdx.x >> 5] = v;
        __syncthreads();
        if (threadIdx.x == 0) {
            float s = 0.f;
            for (int w2 = 0; w2 < 8; w2++) s += red[w2];
            outp[i] = s;
        }
        __syncthreads();
    }
}

// ---------------------------------------------------------------------------
// Gram stage 2 + normalize + temperature + softmax (both branches).
// attnA logits = +G(q_B, k_A)/(|q_B||k_A|)*temp; attnB = -G(q_A, k_B)/... 
// grid = BATCH*HEADS, 160 threads.
// ---------------------------------------------------------------------------
__global__ void attn_kernel(const float* __restrict__ partA,
                            const float* __restrict__ partB,
                            const float* __restrict__ normsA,
                            const float* __restrict__ normsB,
                            const float* __restrict__ temp,
                            float* __restrict__ attnA,
                            float* __restrict__ attnB) {
    int bh = blockIdx.x;
    int b = bh / HEADS, h = bh % HEADS;
    __shared__ float GA[144], GB[144];
    int i = threadIdx.x;
    if (i < 144) {
        float sA = 0.f, sB = 0.f;
        const float* pA = partA + ((size_t)bh * 64) * 144 + i;
        const float* pB = partB + ((size_t)bh * 64) * 144 + i;
        for (int ch = 0; ch < 64; ch++) {
            sA += pA[(size_t)ch * 144];
            sB += pB[(size_t)ch * 144];
        }
        int c = i / CHEAD, d = i % CHEAD;
        float nqA = fmaxf(normsB[b * 192 +      h * CHEAD + c], 1e-12f);
        float nkA = fmaxf(normsA[b * 192 + 96 + h * CHEAD + d], 1e-12f);
        float nqB = fmaxf(normsA[b * 192 +      h * CHEAD + c], 1e-12f);
        float nkB = fmaxf(normsB[b * 192 + 96 + h * CHEAD + d], 1e-12f);
        float tp = temp[h];
        GA[i] =  sA / (nqA * nkA) * tp;
        GB[i] = -sB / (nqB * nkB) * tp;
    }
    __syncthreads();
    if (i < 24) {
        float* G = (i < CHEAD) ? GA : GB;
        float* O = (i < CHEAD) ? attnA : attnB;
        int c = i % CHEAD;
        float mx = -1e30f;
        for (int d = 0; d < CHEAD; d++) mx = fmaxf(mx, G[c * CHEAD + d]);
        float e[CHEAD];
        float s = 0.f;
        for (int d = 0; d < CHEAD; d++) {
            e[d] = expf(G[c * CHEAD + d] - mx);
            s += e[d];
        }
        float inv = 1.f / s;
        for (int d = 0; d < CHEAD; d++)
            O[(size_t)bh * 144 + c * CHEAD + d] = e[d] * inv;
    }
}

// ---------------------------------------------------------------------------
// out[c,p] = sum_d attn[c,d] * v[d,p] per (b,head). attn cached in smem.
// ---------------------------------------------------------------------------
__global__ void attnv_kernel(const float* __restrict__ attn,
                             const float* __restrict__ qkvd,
                             float* __restrict__ out) {
    int h = blockIdx.y, b = blockIdx.z;
    int p = blockIdx.x * 256 + threadIdx.x;
    __shared__ float a_s[144];
    if (threadIdx.x < 144)
        a_s[threadIdx.x] = attn[((size_t)(b * HEADS + h)) * 144 + threadIdx.x];
    __syncthreads();

    const float* vb = qkvd + ((size_t)b * 288 + 192 + h * CHEAD) * HW + p;
    float v[CHEAD];
#pragma unroll
    for (int d = 0; d < CHEAD; d++) v[d] = vb[(size_t)d * HW];

    float* ob = out + ((size_t)b * CDIM + h * CHEAD) * HW + p;
#pragma unroll
    for (int c = 0; c < CHEAD; c++) {
        float s = 0.f;
#pragma unroll
        for (int d = 0; d < CHEAD; d++) s += a_s[c * CHEAD + d] * v[d];
        ob[(size_t)c * HW] = s;
    }
}

// ---------------------------------------------------------------------------
// gate = gelu_exact(t[0:255]) * t[255:510]
// ---------------------------------------------------------------------------
__global__ void gate_kernel(const float* __restrict__ td,
                            float* __restrict__ gate) {
    size_t idx = (size_t)blockIdx.x * blockDim.x + threadIdx.x;
    const size_t per_b = (size_t)HIDDEN * HW;
    size_t b = idx / per_b;
    size_t r = idx - b * per_b;
    const float* tb = td + b * 2 * per_b;
    float g1 = tb[r];
    float g2 = tb[per_b + r];
    float gl = 0.5f * g1 * (1.f + erff(g1 * 0.7071067811865475f));
    gate[idx] = gl * g2;
}

// ---------------------------------------------------------------------------
// Launch
// ---------------------------------------------------------------------------
extern "C" void kernel_launch(void* const* d_in, const int* in_sizes, int n_in,
                              void* d_out, int out_size) {
    const float* x       = (const float*)d_in[0];
    const float* y       = (const float*)d_in[1];
    const float* ln1_w   = (const float*)d_in[2];
    const float* ln1_b   = (const float*)d_in[3];
    const float* ln2_w   = (const float*)d_in[4];
    const float* ln2_b   = (const float*)d_in[5];
    const float* qkvA_w  = (const float*)d_in[6];
    const float* dwA_w   = (const float*)d_in[7];
    const float* qkvB_w  = (const float*)d_in[8];
    const float* dwB_w   = (const float*)d_in[9];
    const float* projA_w = (const float*)d_in[10];
    const float* projB_w = (const float*)d_in[11];
    const float* concat_w= (const float*)d_in[12];
    const float* temp    = (const float*)d_in[13];
    const float* pin_w   = (const float*)d_in[14];
    const float* dwf_w   = (const float*)d_in[15];
    const float* pout_w  = (const float*)d_in[16];
    float* out = (float*)d_out;

    float *xn, *yn, *qkvA, *qkvAd, *qkvB, *qkvBd, *preA, *preB, *outAB;
    float *x1, *x1n, *t, *td, *gate, *normsA, *normsB, *gpA, *gpB, *atA, *atB;
    cudaGetSymbolAddress((void**)&xn,     g_xn);
    cudaGetSymbolAddress((void**)&yn,     g_yn);
    cudaGetSymbolAddress((void**)&qkvA,   g_qkvA);
    cudaGetSymbolAddress((void**)&qkvAd,  g_qkvAd);
    cudaGetSymbolAddress((void**)&qkvB,   g_qkvB);
    cudaGetSymbolAddress((void**)&qkvBd,  g_qkvBd);
    cudaGetSymbolAddress((void**)&preA,   g_preA);
    cudaGetSymbolAddress((void**)&preB,   g_preB);
    cudaGetSymbolAddress((void**)&outAB,  g_outAB);
    cudaGetSymbolAddress((void**)&x1,     g_x1);
    cudaGetSymbolAddress((void**)&x1n,    g_x1n);
    cudaGetSymbolAddress((void**)&t,      g_t);
    cudaGetSymbolAddress((void**)&td,     g_td);
    cudaGetSymbolAddress((void**)&gate,   g_gate);
    cudaGetSymbolAddress((void**)&normsA, g_normsA);
    cudaGetSymbolAddress((void**)&normsB, g_normsB);
    cudaGetSymbolAddress((void**)&gpA,    g_gpartA);
    cudaGetSymbolAddress((void**)&gpB,    g_gpartB);
    cudaGetSymbolAddress((void**)&atA,    g_attnA);
    cudaGetSymbolAddress((void**)&atB,    g_attnB);

    const size_t P96  = (size_t)CDIM * HW;          // 96*65536
    const size_t P192 = 2 * P96;
    const size_t P288 = 3 * P96;
    const size_t P510 = (size_t)2 * HIDDEN * HW;
    const size_t P255 = (size_t)HIDDEN * HW;

    dim3 lnGrid(HW / 256, BATCH);
    // 1) LayerNorm1 on x and y
    ln_kernel<<<lnGrid, 256>>>(x, ln1_w, ln1_b, xn);
    ln_kernel<<<lnGrid, 256>>>(y, ln1_w, ln1_b, yn);

    // 2) qkv conv1x1 (M=288, K=96)
    {
        dim3 g((288 + 63) / 64, HW / 64, BATCH);
        conv1x1_kernel<false><<<g, 256>>>(qkvA_w, xn, nullptr, qkvA, 288, 96, P96, P288, 0);
        conv1x1_kernel<false><<<g, 256>>>(qkvB_w, yn, nullptr, qkvB, 288, 96, P96, P288, 0);
    }

    // 3) depthwise 3x3 on both qkv stacks
    {
        dim3 blk(32, 8), g(IMG / 32, IMG / 8, BATCH * 288);
        dw3_kernel<<<g, blk>>>(qkvA, dwA_w, qkvAd, 288);
        dw3_kernel<<<g, blk>>>(qkvB, dwB_w, qkvBd, 288);
    }

    // 4) L2 norms of q,k rows (channels 0..191)
    rownorm_kernel<<<BATCH * 192, 256>>>(qkvAd, normsA);
    rownorm_kernel<<<BATCH * 192, 256>>>(qkvBd, normsB);

    // 5) Gram matrices: attnA uses (q of B, k of A); attnB uses (q of A, k of B)
    {
        dim3 g(64, HEADS, BATCH);
        gram1_kernel<<<g, 256>>>(qkvBd, qkvAd + 96 * (size_t)HW, gpA);
        gram1_kernel<<<g, 256>>>(qkvAd, qkvBd + 96 * (size_t)HW, gpB);
    }

    // 6) reduce + normalize + softmax
    attn_kernel<<<BATCH * HEADS, 160>>>(gpA, gpB, normsA, normsB, temp, atA, atB);

    // 7) attn @ v
    {
        dim3 g(HW / 256, HEADS, BATCH);
        attnv_kernel<<<g, 256>>>(atA, qkvAd, preA);
        attnv_kernel<<<g, 256>>>(atB, qkvBd, preB);
    }

    // 8) proj conv1x1 + residual (xn / yn), write into halves of outAB
    {
        dim3 g((96 + 63) / 64, HW / 64, BATCH);
        conv1x1_kernel<true><<<g, 256>>>(projA_w, preA, xn, outAB,            96, 96, P96, P192, P96);
        conv1x1_kernel<true><<<g, 256>>>(projB_w, preB, yn, outAB + 96 * (size_t)HW, 96, 96, P96, P192, P96);
    }

    // 9) concat conv1x1 + residual x -> x1
    {
        dim3 g((96 + 63) / 64, HW / 64, BATCH);
        conv1x1_kernel<true><<<g, 256>>>(concat_w, outAB, x, x1, 96, 192, P192, P96, P96);
    }

    // 10) LayerNorm2
    ln_kernel<<<lnGrid, 256>>>(x1, ln2_w, ln2_b, x1n);

    // 11) pin conv1x1 (M=510, K=96)
    {
        dim3 g((510 + 63) / 64, HW / 64, BATCH);
        conv1x1_kernel<false><<<g, 256>>>(pin_w, x1n, nullptr, t, 510, 96, P96, P510, 0);
    }

    // 12) depthwise 3x3 on t (510 channels)
    {
        dim3 blk(32, 8), g(IMG / 32, IMG / 8, BATCH * 510);
        dw3_kernel<<<g, blk>>>(t, dwf_w, td, 510);
    }

    // 13) gelu(g1)*g2
    {
        size_t total = (size_t)BATCH * HIDDEN * HW;
        gate_kernel<<<(unsigned)(total / 256), 256>>>(td, gate);
    }

    // 14) pout conv1x1 + residual x1 -> final output
    {
        dim3 g((96 + 63) / 64, HW / 64, BATCH);
        conv1x1_kernel<true><<<g, 256>>>(pout_w, gate, x1, out, 96, 255, P255, P96, P96);
    }
}

// round 2
// speedup vs baseline: 1.2154x; 1.2154x over previous
#include <cuda_runtime.h>
#include <math.h>

#define HW      65536
#define IMG     256
#define BATCH   2
#define CDIM    96
#define HEADS   8
#define CHEAD   12
#define HIDDEN  255

// ---------------------------------------------------------------------------
// Scratch (static device allocations)
// ---------------------------------------------------------------------------
__device__ float g_qkvA [BATCH * 3 * CDIM * HW];
__device__ float g_qkvAd[BATCH * 3 * CDIM * HW];
__device__ float g_qkvB [BATCH * 3 * CDIM * HW];
__device__ float g_qkvBd[BATCH * 3 * CDIM * HW];
__device__ float g_preA [BATCH * CDIM * HW];
__device__ float g_preB [BATCH * CDIM * HW];
__device__ float g_outAB[BATCH * 2 * CDIM * HW];
__device__ float g_x1   [BATCH * CDIM * HW];
__device__ float g_t    [BATCH * 2 * HIDDEN * HW];
__device__ float g_gate [BATCH * HIDDEN * HW];
__device__ float g_stsX [BATCH * HW * 2];
__device__ float g_stsY [BATCH * HW * 2];
__device__ float g_stsX1[BATCH * HW * 2];
__device__ float g_normsA[BATCH * 2 * CDIM];
__device__ float g_normsB[BATCH * 2 * CDIM];
__device__ float g_gpartA[BATCH * HEADS * 64 * 144];
__device__ float g_gpartB[BATCH * HEADS * 64 * 144];
__device__ float g_attnA [BATCH * HEADS * 144];
__device__ float g_attnB [BATCH * HEADS * 144];

// ---------------------------------------------------------------------------
// Per-pixel LayerNorm stats over C=96: writes (mu, inv_std) interleaved.
// ---------------------------------------------------------------------------
__global__ void stats_kernel(const float* __restrict__ in,
                             float2* __restrict__ st) {
    int p = blockIdx.x * blockDim.x + threadIdx.x;
    int b = blockIdx.y;
    const float* ip = in + (size_t)b * CDIM * HW + p;
    float v[CDIM];
    float s = 0.f;
#pragma unroll
    for (int c = 0; c < CDIM; c++) { v[c] = ip[(size_t)c * HW]; s += v[c]; }
    float mu = s * (1.f / CDIM);
    float vs = 0.f;
#pragma unroll
    for (int c = 0; c < CDIM; c++) { float d = v[c] - mu; vs += d * d; }
    float inv = rsqrtf(vs * (1.f / CDIM) + 1e-5f);
    st[(size_t)b * HW + p] = make_float2(mu, inv);
}

// ---------------------------------------------------------------------------
// GEMM: Y[M,N] = W[M,K] @ B[K,N] (+ residual), N = HW, per-batch grid.z.
// BM=96, BN=128, BK=16, 192 threads, 8x8 microtile, float4 everywhere.
// LNB:     B operand is LayerNorm((X - mu)*inv * lnw + lnb) computed on load.
// RESMODE: 0 none; 1 Y += Rsrc; 2 Y += LayerNorm(Rsrc) (stats + lnw/lnb).
// ---------------------------------------------------------------------------
template <bool LNB, int RESMODE>
__global__ void __launch_bounds__(192) gemm_kernel(
        const float* __restrict__ Wt,
        const float* __restrict__ X,
        const float* __restrict__ Rsrc,
        float* __restrict__ Y,
        const float* __restrict__ stats,
        const float* __restrict__ lnw,
        const float* __restrict__ lnb,
        int M, int K,
        size_t xBatch, size_t yBatch, size_t rBatch) {
    __shared__ __align__(16) float As[16][96];
    __shared__ __align__(16) float Bs[16][128];
    __shared__ float mu_s[128], inv_s[128];
    __shared__ float wln_s[96], bln_s[96];

    int b = blockIdx.z;
    const float* Xb = X + (size_t)b * xBatch;
    float*       Yb = Y + (size_t)b * yBatch;
    const float* Rb = (RESMODE != 0) ? (Rsrc + (size_t)b * rBatch) : nullptr;

    int m0 = blockIdx.x * 96;
    int n0 = blockIdx.y * 128;
    int tid = threadIdx.x;
    int tx = tid & 15;          // 0..15 -> 8 output columns each
    int ty = tid >> 4;          // 0..11 -> 8 output rows each

    if (LNB || RESMODE == 2) {
        if (tid < 128) {
            float2 s = reinterpret_cast<const float2*>(stats)[(size_t)b * HW + n0 + tid];
            mu_s[tid]  = s.x;
            inv_s[tid] = s.y;
        }
    }
    if (LNB) {               // LNB GEMMs always have K == 96
        if (tid < 96) { wln_s[tid] = lnw[tid]; bln_s[tid] = lnb[tid]; }
    }

    float acc[8][8] = {};

    for (int kk = 0; kk < K; kk += 16) {
        __syncthreads();     // also guards the preloads before the 1st iter
        // ---- A tile: 96 x 16 (scatter to As[k][m]) ----
#pragma unroll
        for (int i = 0; i < 8; i++) {
            int idx = tid + i * 192;
            int m = idx >> 4, k = idx & 15;
            float v = 0.f;
            if (m0 + m < M && kk + k < K) v = Wt[(size_t)(m0 + m) * K + kk + k];
            As[k][m] = v;
        }
        // ---- B tile: 16 x 128 via float4, optional fused LN ----
#pragma unroll
        for (int i = 0; i < 3; i++) {
            int q = tid + i * 192;
            if (q < 512) {
                int row = q >> 5, c4 = q & 31;
                int k = kk + row;
                float4 v = make_float4(0.f, 0.f, 0.f, 0.f);
                if (k < K) {
                    v = reinterpret_cast<const float4*>(Xb + (size_t)k * HW + n0)[c4];
                    if (LNB) {
                        int nb = c4 * 4;
                        float wk = wln_s[k], bk = bln_s[k];
                        v.x = (v.x - mu_s[nb + 0]) * inv_s[nb + 0] * wk + bk;
                        v.y = (v.y - mu_s[nb + 1]) * inv_s[nb + 1] * wk + bk;
                        v.z = (v.z - mu_s[nb + 2]) * inv_s[nb + 2] * wk + bk;
                        v.w = (v.w - mu_s[nb + 3]) * inv_s[nb + 3] * wk + bk;
                    }
                }
                reinterpret_cast<float4*>(&Bs[row][0])[c4] = v;
            }
        }
        __syncthreads();
        // ---- compute 8x8 ----
#pragma unroll
        for (int k = 0; k < 16; k++) {
            float a[8], bb[8];
#pragma unroll
            for (int i = 0; i < 8; i++) a[i]  = As[k][ty * 8 + i];
#pragma unroll
            for (int j = 0; j < 8; j++) bb[j] = Bs[k][tx * 8 + j];
#pragma unroll
            for (int i = 0; i < 8; i++)
#pragma unroll
                for (int j = 0; j < 8; j++) acc[i][j] += a[i] * bb[j];
        }
    }

    // ---- epilogue ----
#pragma unroll
    for (int i = 0; i < 8; i++) {
        int m = m0 + ty * 8 + i;
        if (m < M) {
            size_t off = (size_t)m * HW + n0 + tx * 8;
            float4 v0 = make_float4(acc[i][0], acc[i][1], acc[i][2], acc[i][3]);
            float4 v1 = make_float4(acc[i][4], acc[i][5], acc[i][6], acc[i][7]);
            if (RESMODE == 1) {
                float4 r0 = reinterpret_cast<const float4*>(Rb + off)[0];
                float4 r1 = reinterpret_cast<const float4*>(Rb + off)[1];
                v0.x += r0.x; v0.y += r0.y; v0.z += r0.z; v0.w += r0.w;
                v1.x += r1.x; v1.y += r1.y; v1.z += r1.z; v1.w += r1.w;
            } else if (RESMODE == 2) {
                float rw = lnw[m], rb2 = lnb[m];
                float4 r0 = reinterpret_cast<const float4*>(Rb + off)[0];
                float4 r1 = reinterpret_cast<const float4*>(Rb + off)[1];
                int nl = tx * 8;
                v0.x += (r0.x - mu_s[nl+0]) * inv_s[nl+0] * rw + rb2;
                v0.y += (r0.y - mu_s[nl+1]) * inv_s[nl+1] * rw + rb2;
                v0.z += (r0.z - mu_s[nl+2]) * inv_s[nl+2] * rw + rb2;
                v0.w += (r0.w - mu_s[nl+3]) * inv_s[nl+3] * rw + rb2;
                v1.x += (r1.x - mu_s[nl+4]) * inv_s[nl+4] * rw + rb2;
                v1.y += (r1.y - mu_s[nl+5]) * inv_s[nl+5] * rw + rb2;
                v1.z += (r1.z - mu_s[nl+6]) * inv_s[nl+6] * rw + rb2;
                v1.w += (r1.w - mu_s[nl+7]) * inv_s[nl+7] * rw + rb2;
            }
            reinterpret_cast<float4*>(Yb + off)[0] = v0;
            reinterpret_cast<float4*>(Yb + off)[1] = v1;
        }
    }
}

// ---------------------------------------------------------------------------
// Depthwise 3x3, SAME zero padding (XLA cross-correlation semantics).
// ---------------------------------------------------------------------------
__global__ void dw3_kernel(const float* __restrict__ in,
                           const float* __restrict__ w,
                           float* __restrict__ out, int C) {
    int pl = blockIdx.z;
    int c  = pl % C;
    int x  = blockIdx.x * 32 + threadIdx.x;
    int y  = blockIdx.y * 8  + threadIdx.y;
    const float* ip = in + (size_t)pl * HW;
    const float* wp = w + c * 9;
    float s = 0.f;
#pragma unroll
    for (int dy = -1; dy <= 1; dy++) {
        int yy = y + dy;
        if (yy < 0 || yy >= IMG) continue;
#pragma unroll
        for (int dx = -1; dx <= 1; dx++) {
            int xx = x + dx;
            if (xx < 0 || xx >= IMG) continue;
            s += wp[(dy + 1) * 3 + (dx + 1)] * ip[yy * IMG + xx];
        }
    }
    out[(size_t)pl * HW + y * IMG + x] = s;
}

// ---------------------------------------------------------------------------
// Fused FFN tail: depthwise-3x3 on both gate halves + exact gelu + multiply.
// gate[b,k,p] = gelu(dw(t[b,k])) * dw(t[b,255+k])
// ---------------------------------------------------------------------------
__global__ void dwgate_kernel(const float* __restrict__ t,
                              const float* __restrict__ dwf,
                              float* __restrict__ gate) {
    int pl = blockIdx.z;              // b*255 + k
    int b = pl / HIDDEN, k = pl % HIDDEN;
    int x = blockIdx.x * 32 + threadIdx.x;
    int y = blockIdx.y * 8  + threadIdx.y;
    const float* i1 = t + ((size_t)b * 2 * HIDDEN + k) * HW;
    const float* i2 = t + ((size_t)b * 2 * HIDDEN + HIDDEN + k) * HW;
    const float* w1 = dwf + k * 9;
    const float* w2 = dwf + (HIDDEN + k) * 9;
    float s1 = 0.f, s2 = 0.f;
#pragma unroll
    for (int dy = -1; dy <= 1; dy++) {
        int yy = y + dy;
        if (yy < 0 || yy >= IMG) continue;
#pragma unroll
        for (int dx = -1; dx <= 1; dx++) {
            int xx = x + dx;
            if (xx < 0 || xx >= IMG) continue;
            int o = yy * IMG + xx, wi = (dy + 1) * 3 + (dx + 1);
            s1 += w1[wi] * i1[o];
            s2 += w2[wi] * i2[o];
        }
    }
    float gl = 0.5f * s1 * (1.f + erff(s1 * 0.7071067811865475f));
    gate[((size_t)b * HIDDEN + k) * HW + y * IMG + x] = gl * s2;
}

// ---------------------------------------------------------------------------
// Row L2 norms for q,k (first 192 channels of a qkv buffer).
// ---------------------------------------------------------------------------
__global__ void rownorm_kernel(const float* __restrict__ in,
                               float* __restrict__ norms) {
    int r  = blockIdx.x;
    int b  = r / 192, ch = r % 192;
    const float* ip = in + ((size_t)b * 288 + ch) * HW;
    float s = 0.f;
    for (int i = threadIdx.x; i < HW; i += blockDim.x) {
        float v = ip[i];
        s += v * v;
    }
    __shared__ float red[256];
    red[threadIdx.x] = s;
    __syncthreads();
    for (int off = 128; off > 0; off >>= 1) {
        if (threadIdx.x < off) red[threadIdx.x] += red[threadIdx.x + off];
        __syncthreads();
    }
    if (threadIdx.x == 0) norms[r] = sqrtf(red[0]);
}

// ---------------------------------------------------------------------------
// Gram stage 1: partial G[c,d] over a 1024-pixel chunk.
// ---------------------------------------------------------------------------
__global__ void __launch_bounds__(256) gram1_kernel(
        const float* __restrict__ Q, const float* __restrict__ Kp,
        float* __restrict__ part) {
    int chunk = blockIdx.x, h = blockIdx.y, b = blockIdx.z;
    const float* qb = Q  + ((size_t)b * 288 + h * CHEAD) * HW;
    const float* kb = Kp + ((size_t)b * 288 + h * CHEAD) * HW;

    float acc[144];
#pragma unroll
    for (int i = 0; i < 144; i++) acc[i] = 0.f;

    int p0 = chunk * 1024 + threadIdx.x;
    for (int it = 0; it < 4; it++) {
        int p = p0 + it * 256;
        float qv[CHEAD], kv[CHEAD];
#pragma unroll
        for (int c = 0; c < CHEAD; c++) qv[c] = qb[(size_t)c * HW + p];
#pragma unroll
        for (int d = 0; d < CHEAD; d++) kv[d] = kb[(size_t)d * HW + p];
#pragma unroll
        for (int c = 0; c < CHEAD; c++)
#pragma unroll
            for (int d = 0; d < CHEAD; d++) acc[c * CHEAD + d] += qv[c] * kv[d];
    }

    __shared__ float red[8];
    float* outp = part + (((size_t)(b * HEADS + h)) * 64 + chunk) * 144;
#pragma unroll
    for (int i = 0; i < 144; i++) {
        float v = acc[i];
#pragma unroll
        for (int off = 16; off > 0; off >>= 1)
            v += __shfl_down_sync(0xffffffffu, v, off);
        if ((threadIdx.x & 31) == 0) red[threadIdx.x >> 5] = v;
        __syncthreads();
        if (threadIdx.x == 0) {
            float s = 0.f;
            for (int w2 = 0; w2 < 8; w2++) s += red[w2];
            outp[i] = s;
        }
        __syncthreads();
    }
}

// ---------------------------------------------------------------------------
// Gram stage 2 + normalize + temperature + softmax (both branches).
// ---------------------------------------------------------------------------
__global__ void attn_kernel(const float* __restrict__ partA,
                            const float* __restrict__ partB,
                            const float* __restrict__ normsA,
                            const float* __restrict__ normsB,
                            const float* __restrict__ temp,
                            float* __restrict__ attnA,
                            float* __restrict__ attnB) {
    int bh = blockIdx.x;
    int b = bh / HEADS, h = bh % HEADS;
    __shared__ float GA[144], GB[144];
    int i = threadIdx.x;
    if (i < 144) {
        float sA = 0.f, sB = 0.f;
        const float* pA = partA + ((size_t)bh * 64) * 144 + i;
        const float* pB = partB + ((size_t)bh * 64) * 144 + i;
        for (int ch = 0; ch < 64; ch++) {
            sA += pA[(size_t)ch * 144];
            sB += pB[(size_t)ch * 144];
        }
        int c = i / CHEAD, d = i % CHEAD;
        float nqA = fmaxf(normsB[b * 192 +      h * CHEAD + c], 1e-12f);
        float nkA = fmaxf(normsA[b * 192 + 96 + h * CHEAD + d], 1e-12f);
        float nqB = fmaxf(normsA[b * 192 +      h * CHEAD + c], 1e-12f);
        float nkB = fmaxf(normsB[b * 192 + 96 + h * CHEAD + d], 1e-12f);
        float tp = temp[h];
        GA[i] =  sA / (nqA * nkA) * tp;
        GB[i] = -sB / (nqB * nkB) * tp;
    }
    __syncthreads();
    if (i < 24) {
        float* G = (i < CHEAD) ? GA : GB;
        float* O = (i < CHEAD) ? attnA : attnB;
        int c = i % CHEAD;
        float mx = -1e30f;
        for (int d = 0; d < CHEAD; d++) mx = fmaxf(mx, G[c * CHEAD + d]);
        float e[CHEAD];
        float s = 0.f;
        for (int d = 0; d < CHEAD; d++) {
            e[d] = expf(G[c * CHEAD + d] - mx);
            s += e[d];
        }
        float inv = 1.f / s;
        for (int d = 0; d < CHEAD; d++)
            O[(size_t)bh * 144 + c * CHEAD + d] = e[d] * inv;
    }
}

// ---------------------------------------------------------------------------
// out[c,p] = sum_d attn[c,d] * v[d,p] per (b,head).
// ---------------------------------------------------------------------------
__global__ void attnv_kernel(const float* __restrict__ attn,
                             const float* __restrict__ qkvd,
                             float* __restrict__ out) {
    int h = blockIdx.y, b = blockIdx.z;
    int p = blockIdx.x * 256 + threadIdx.x;
    __shared__ float a_s[144];
    if (threadIdx.x < 144)
        a_s[threadIdx.x] = attn[((size_t)(b * HEADS + h)) * 144 + threadIdx.x];
    __syncthreads();

    const float* vb = qkvd + ((size_t)b * 288 + 192 + h * CHEAD) * HW + p;
    float v[CHEAD];
#pragma unroll
    for (int d = 0; d < CHEAD; d++) v[d] = vb[(size_t)d * HW];

    float* ob = out + ((size_t)b * CDIM + h * CHEAD) * HW + p;
#pragma unroll
    for (int c = 0; c < CHEAD; c++) {
        float s = 0.f;
#pragma unroll
        for (int d = 0; d < CHEAD; d++) s += a_s[c * CHEAD + d] * v[d];
        ob[(size_t)c * HW] = s;
    }
}

// ---------------------------------------------------------------------------
// Launch
// ---------------------------------------------------------------------------
extern "C" void kernel_launch(void* const* d_in, const int* in_sizes, int n_in,
                              void* d_out, int out_size) {
    const float* x       = (const float*)d_in[0];
    const float* y       = (const float*)d_in[1];
    const float* ln1_w   = (const float*)d_in[2];
    const float* ln1_b   = (const float*)d_in[3];
    const float* ln2_w   = (const float*)d_in[4];
    const float* ln2_b   = (const float*)d_in[5];
    const float* qkvA_w  = (const float*)d_in[6];
    const float* dwA_w   = (const float*)d_in[7];
    const float* qkvB_w  = (const float*)d_in[8];
    const float* dwB_w   = (const float*)d_in[9];
    const float* projA_w = (const float*)d_in[10];
    const float* projB_w = (const float*)d_in[11];
    const float* concat_w= (const float*)d_in[12];
    const float* temp    = (const float*)d_in[13];
    const float* pin_w   = (const float*)d_in[14];
    const float* dwf_w   = (const float*)d_in[15];
    const float* pout_w  = (const float*)d_in[16];
    float* out = (float*)d_out;

    float *qkvA, *qkvAd, *qkvB, *qkvBd, *preA, *preB, *outAB;
    float *x1, *t, *gate, *stsX, *stsY, *stsX1;
    float *normsA, *normsB, *gpA, *gpB, *atA, *atB;
    cudaGetSymbolAddress((void**)&qkvA,   g_qkvA);
    cudaGetSymbolAddress((void**)&qkvAd,  g_qkvAd);
    cudaGetSymbolAddress((void**)&qkvB,   g_qkvB);
    cudaGetSymbolAddress((void**)&qkvBd,  g_qkvBd);
    cudaGetSymbolAddress((void**)&preA,   g_preA);
    cudaGetSymbolAddress((void**)&preB,   g_preB);
    cudaGetSymbolAddress((void**)&outAB,  g_outAB);
    cudaGetSymbolAddress((void**)&x1,     g_x1);
    cudaGetSymbolAddress((void**)&t,      g_t);
    cudaGetSymbolAddress((void**)&gate,   g_gate);
    cudaGetSymbolAddress((void**)&stsX,   g_stsX);
    cudaGetSymbolAddress((void**)&stsY,   g_stsY);
    cudaGetSymbolAddress((void**)&stsX1,  g_stsX1);
    cudaGetSymbolAddress((void**)&normsA, g_normsA);
    cudaGetSymbolAddress((void**)&normsB, g_normsB);
    cudaGetSymbolAddress((void**)&gpA,    g_gpartA);
    cudaGetSymbolAddress((void**)&gpB,    g_gpartB);
    cudaGetSymbolAddress((void**)&atA,    g_attnA);
    cudaGetSymbolAddress((void**)&atB,    g_attnB);

    const size_t P96  = (size_t)CDIM * HW;
    const size_t P192 = 2 * P96;
    const size_t P288 = 3 * P96;
    const size_t P510 = (size_t)2 * HIDDEN * HW;
    const size_t P255 = (size_t)HIDDEN * HW;

    dim3 sGrid(HW / 256, BATCH);
    stats_kernel<<<sGrid, 256>>>(x, (float2*)stsX);
    stats_kernel<<<sGrid, 256>>>(y, (float2*)stsY);

    // qkv conv1x1 with fused LN1 (M=288, K=96)
    {
        dim3 g(3, HW / 128, BATCH);
        gemm_kernel<true, 0><<<g, 192>>>(qkvA_w, x, nullptr, qkvA, stsX,
                                         ln1_w, ln1_b, 288, 96, P96, P288, 0);
        gemm_kernel<true, 0><<<g, 192>>>(qkvB_w, y, nullptr, qkvB, stsY,
                                         ln1_w, ln1_b, 288, 96, P96, P288, 0);
    }

    // depthwise 3x3 on both qkv stacks
    {
        dim3 blk(32, 8), g(IMG / 32, IMG / 8, BATCH * 288);
        dw3_kernel<<<g, blk>>>(qkvA, dwA_w, qkvAd, 288);
        dw3_kernel<<<g, blk>>>(qkvB, dwB_w, qkvBd, 288);
    }

    rownorm_kernel<<<BATCH * 192, 256>>>(qkvAd, normsA);
    rownorm_kernel<<<BATCH * 192, 256>>>(qkvBd, normsB);

    {
        dim3 g(64, HEADS, BATCH);
        gram1_kernel<<<g, 256>>>(qkvBd, qkvAd + 96 * (size_t)HW, gpA);
        gram1_kernel<<<g, 256>>>(qkvAd, qkvBd + 96 * (size_t)HW, gpB);
    }

    attn_kernel<<<BATCH * HEADS, 160>>>(gpA, gpB, normsA, normsB, temp, atA, atB);

    {
        dim3 g(HW / 256, HEADS, BATCH);
        attnv_kernel<<<g, 256>>>(atA, qkvAd, preA);
        attnv_kernel<<<g, 256>>>(atB, qkvBd, preB);
    }

    // proj conv1x1 + fused LN residual, writes halves of outAB
    {
        dim3 g(1, HW / 128, BATCH);
        gemm_kernel<false, 2><<<g, 192>>>(projA_w, preA, x, outAB, stsX,
                                          ln1_w, ln1_b, 96, 96, P96, P192, P96);
        gemm_kernel<false, 2><<<g, 192>>>(projB_w, preB, y, outAB + 96 * (size_t)HW,
                                          stsY, ln1_w, ln1_b, 96, 96, P96, P192, P96);
    }

    // concat conv1x1 + residual x -> x1
    {
        dim3 g(1, HW / 128, BATCH);
        gemm_kernel<false, 1><<<g, 192>>>(concat_w, outAB, x, x1, nullptr,
                                          nullptr, nullptr, 96, 192, P192, P96, P96);
    }

    stats_kernel<<<sGrid, 256>>>(x1, (float2*)stsX1);

    // pin conv1x1 with fused LN2 (M=510, K=96)
    {
        dim3 g(6, HW / 128, BATCH);
        gemm_kernel<true, 0><<<g, 192>>>(pin_w, x1, nullptr, t, stsX1,
                                         ln2_w, ln2_b, 510, 96, P96, P510, 0);
    }

    // fused depthwise + gelu gate
    {
        dim3 blk(32, 8), g(IMG / 32, IMG / 8, BATCH * HIDDEN);
        dwgate_kernel<<<g, blk>>>(t, dwf_w, gate);
    }

    // pout conv1x1 + residual x1 -> final output
    {
        dim3 g(1, HW / 128, BATCH);
        gemm_kernel<false, 1><<<g, 192>>>(pout_w, gate, x1, out, nullptr,
                                          nullptr, nullptr, 96, 255, P255, P96, P96);
    }
}

// round 3
// speedup vs baseline: 1.6520x; 1.3593x over previous
#include <cuda_runtime.h>
#include <math.h>
#include <stdint.h>

#define HW      65536
#define IMG     256
#define BATCH   2
#define CDIM    96
#define HEADS   8
#define CHEAD   12
#define HIDDEN  255

// ---------------------------------------------------------------------------
// Scratch
// ---------------------------------------------------------------------------
__device__ float g_qkvA [BATCH * 3 * CDIM * HW];
__device__ float g_qkvAd[BATCH * 3 * CDIM * HW];
__device__ float g_qkvB [BATCH * 3 * CDIM * HW];
__device__ float g_qkvBd[BATCH * 3 * CDIM * HW];
__device__ float g_preA [BATCH * CDIM * HW];
__device__ float g_preB [BATCH * CDIM * HW];
__device__ float g_outAB[BATCH * 2 * CDIM * HW];
__device__ float g_x1   [BATCH * CDIM * HW];
__device__ float g_t    [BATCH * 2 * HIDDEN * HW];
__device__ float g_gate [BATCH * HIDDEN * HW];
__device__ float g_stsX [BATCH * HW * 2];
__device__ float g_stsY [BATCH * HW * 2];
__device__ float g_stsX1[BATCH * HW * 2];
__device__ float g_gpartA[BATCH * HEADS * 64 * 168];
__device__ float g_gpartB[BATCH * HEADS * 64 * 168];
__device__ float g_attnA [BATCH * HEADS * 144];
__device__ float g_attnB [BATCH * HEADS * 144];

// ---------------------------------------------------------------------------
// tf32 helpers
// ---------------------------------------------------------------------------
__device__ __forceinline__ uint32_t f2tf(float f) {
    uint32_t u;
    asm("cvt.rna.tf32.f32 %0, %1;" : "=r"(u) : "f"(f));
    return u;
}

__device__ __forceinline__ void mma_tf32(float* c, const uint32_t* a, const uint32_t* b) {
    asm volatile(
        "mma.sync.aligned.m16n8k8.row.col.f32.tf32.tf32.f32 "
        "{%0,%1,%2,%3}, {%4,%5,%6,%7}, {%8,%9}, {%0,%1,%2,%3};"
        : "+f"(c[0]), "+f"(c[1]), "+f"(c[2]), "+f"(c[3])
        : "r"(a[0]), "r"(a[1]), "r"(a[2]), "r"(a[3]), "r"(b[0]), "r"(b[1]));
}

// ---------------------------------------------------------------------------
// Per-pixel LayerNorm stats over C=96: (mu, inv_std).
// ---------------------------------------------------------------------------
__global__ void stats_kernel(const float* __restrict__ in,
                             float2* __restrict__ st) {
    int p = blockIdx.x * blockDim.x + threadIdx.x;
    int b = blockIdx.y;
    const float* ip = in + (size_t)b * CDIM * HW + p;
    float v[CDIM];
    float s = 0.f;
#pragma unroll
    for (int c = 0; c < CDIM; c++) { v[c] = ip[(size_t)c * HW]; s += v[c]; }
    float mu = s * (1.f / CDIM);
    float vs = 0.f;
#pragma unroll
    for (int c = 0; c < CDIM; c++) { float d = v[c] - mu; vs += d * d; }
    float inv = rsqrtf(vs * (1.f / CDIM) + 1e-5f);
    st[(size_t)b * HW + p] = make_float2(mu, inv);
}

// ---------------------------------------------------------------------------
// tf32 tensor-core GEMM: Y[M,N] = W[M,K] @ B[K,N] (+ residual), N = HW.
// BM=96, BN=128, stage BK=96, 256 threads = 8 warps (2m x 4n), warp tile 48x32.
// LNB:     B operand = LayerNorm(X) fused on load (K must be 96).
// RESMODE: 0 none; 1 Y += R; 2 Y += LayerNorm(R).
// Dynamic smem: As[96][104] tf32 | Bs[96][136] tf32 | mu[128] inv[128] w[96] b[96]
// ---------------------------------------------------------------------------
#define GEMM_SMEM_BYTES ((96*104 + 96*136 + 128 + 128 + 96 + 96) * 4)

template <bool LNB, int RESMODE>
__global__ void __launch_bounds__(256, 2) gemm_tc(
        const float* __restrict__ Wt,
        const float* __restrict__ X,
        const float* __restrict__ Rsrc,
        float* __restrict__ Y,
        const float* __restrict__ stats,
        const float* __restrict__ lnw,
        const float* __restrict__ lnb,
        int M, int K,
        size_t xBatch, size_t yBatch, size_t rBatch) {
    extern __shared__ uint32_t smem_u[];
    uint32_t* As  = smem_u;                    // [96][104]
    uint32_t* Bs  = As + 96 * 104;             // [96][136]
    float* mu_s   = (float*)(Bs + 96 * 136);   // [128]
    float* inv_s  = mu_s + 128;                // [128]
    float* wln_s  = inv_s + 128;               // [96]
    float* bln_s  = wln_s + 96;                // [96]

    int bz = blockIdx.z;
    const float* Xb = X + (size_t)bz * xBatch;
    float*       Yb = Y + (size_t)bz * yBatch;
    const float* Rb = (RESMODE != 0) ? (Rsrc + (size_t)bz * rBatch) : nullptr;

    int m0 = blockIdx.x * 96;
    int n0 = blockIdx.y * 128;
    int tid  = threadIdx.x;
    int warp = tid >> 5;
    int lane = tid & 31;
    int g = lane >> 2;          // groupID 0..7
    int t = lane & 3;           // threadID_in_group 0..3
    int wm = (warp >> 2) * 48;  // warp m offset (0 or 48)
    int wn = (warp & 3) * 32;   // warp n offset

    if (LNB || RESMODE == 2) {
        if (tid < 128) {
            float2 s = reinterpret_cast<const float2*>(stats)[(size_t)bz * HW + n0 + tid];
            mu_s[tid]  = s.x;
            inv_s[tid] = s.y;
        }
    }
    if (LNB) {
        if (tid < 96) { wln_s[tid] = lnw[tid]; bln_s[tid] = lnb[tid]; }
    }
    if (LNB || RESMODE == 2) __syncthreads();

    float acc[3][4][4];
#pragma unroll
    for (int mi = 0; mi < 3; mi++)
#pragma unroll
        for (int ni = 0; ni < 4; ni++)
#pragma unroll
            for (int r = 0; r < 4; r++) acc[mi][ni][r] = 0.f;

    const uint32_t* Asb = As + t * 104 + wm + g;
    const uint32_t* Bsb = Bs + t * 136 + wn + g;

    int nstages = (K + 95) / 96;
    for (int s = 0; s < nstages; s++) {
        int k0 = s * 96;
        // ---- A: 96m x 96k -> As[k][m] ----
#pragma unroll
        for (int i = 0; i < 36; i++) {
            int idx = tid + i * 256;
            int m = idx / 96;
            int k = idx - m * 96;
            float v = 0.f;
            if (m0 + m < M && k0 + k < K) v = Wt[(size_t)(m0 + m) * K + k0 + k];
            As[k * 104 + m] = f2tf(v);
        }
        // ---- B: 96k x 128n -> Bs[k][n], optional fused LN ----
#pragma unroll
        for (int i = 0; i < 12; i++) {
            int idx = tid + i * 256;     // 0..3071
            int k  = idx >> 5;
            int n4 = idx & 31;
            float4 v = make_float4(0.f, 0.f, 0.f, 0.f);
            if (k0 + k < K) {
                v = reinterpret_cast<const float4*>(Xb + (size_t)(k0 + k) * HW + n0)[n4];
                if (LNB) {
                    int nb = n4 * 4;
                    float wk = wln_s[k], bk = bln_s[k];
                    v.x = (v.x - mu_s[nb + 0]) * inv_s[nb + 0] * wk + bk;
                    v.y = (v.y - mu_s[nb + 1]) * inv_s[nb + 1] * wk + bk;
                    v.z = (v.z - mu_s[nb + 2]) * inv_s[nb + 2] * wk + bk;
                    v.w = (v.w - mu_s[nb + 3]) * inv_s[nb + 3] * wk + bk;
                }
            }
            uint4 u = make_uint4(f2tf(v.x), f2tf(v.y), f2tf(v.z), f2tf(v.w));
            *reinterpret_cast<uint4*>(Bs + k * 136 + n4 * 4) = u;
        }
        __syncthreads();
        // ---- 12 k-steps of m16n8k8 ----
#pragma unroll
        for (int ks = 0; ks < 96; ks += 8) {
            uint32_t af[3][4], bf[4][2];
#pragma unroll
            for (int mi = 0; mi < 3; mi++) {
                const uint32_t* p = Asb + ks * 104 + mi * 16;
                af[mi][0] = p[0];
                af[mi][1] = p[8];
                af[mi][2] = p[4 * 104];
                af[mi][3] = p[8 + 4 * 104];
            }
#pragma unroll
            for (int ni = 0; ni < 4; ni++) {
                const uint32_t* p = Bsb + ks * 136 + ni * 8;
                bf[ni][0] = p[0];
                bf[ni][1] = p[4 * 136];
            }
#pragma unroll
            for (int mi = 0; mi < 3; mi++)
#pragma unroll
                for (int ni = 0; ni < 4; ni++)
                    mma_tf32(acc[mi][ni], af[mi], bf[ni]);
        }
        __syncthreads();
    }

    // ---- epilogue: c0,c1 at (row, 2t..2t+1); c2,c3 at (row+8, ...) ----
#pragma unroll
    for (int mi = 0; mi < 3; mi++) {
        int r0 = m0 + wm + mi * 16 + g;
        int r1 = r0 + 8;
        float w0 = 0.f, b0v = 0.f, w1 = 0.f, b1v = 0.f;
        if (RESMODE == 2) {
            if (r0 < M) { w0 = lnw[r0]; b0v = lnb[r0]; }
            if (r1 < M) { w1 = lnw[r1]; b1v = lnb[r1]; }
        }
#pragma unroll
        for (int ni = 0; ni < 4; ni++) {
            int ln = wn + ni * 8 + 2 * t;
            int col = n0 + ln;
            float2 v01 = make_float2(acc[mi][ni][0], acc[mi][ni][1]);
            float2 v23 = make_float2(acc[mi][ni][2], acc[mi][ni][3]);
            if (RESMODE == 1) {
                if (r0 < M) {
                    float2 r = *reinterpret_cast<const float2*>(Rb + (size_t)r0 * HW + col);
                    v01.x += r.x; v01.y += r.y;
                }
                if (r1 < M) {
                    float2 r = *reinterpret_cast<const float2*>(Rb + (size_t)r1 * HW + col);
                    v23.x += r.x; v23.y += r.y;
                }
            } else if (RESMODE == 2) {
                if (r0 < M) {
                    float2 r = *reinterpret_cast<const float2*>(Rb + (size_t)r0 * HW + col);
                    v01.x += (r.x - mu_s[ln])     * inv_s[ln]     * w0 + b0v;
                    v01.y += (r.y - mu_s[ln + 1]) * inv_s[ln + 1] * w0 + b0v;
                }
                if (r1 < M) {
                    float2 r = *reinterpret_cast<const float2*>(Rb + (size_t)r1 * HW + col);
                    v23.x += (r.x - mu_s[ln])     * inv_s[ln]     * w1 + b1v;
                    v23.y += (r.y - mu_s[ln + 1]) * inv_s[ln + 1] * w1 + b1v;
                }
            }
            if (r0 < M)
                *reinterpret_cast<float2*>(Yb + (size_t)r0 * HW + col) = v01;
            if (r1 < M)
                *reinterpret_cast<float2*>(Yb + (size_t)r1 * HW + col) = v23;
        }
    }
}

// ---------------------------------------------------------------------------
// Depthwise 3x3, SAME zero padding.
// ---------------------------------------------------------------------------
__global__ void dw3_kernel(const float* __restrict__ in,
                           const float* __restrict__ w,
                           float* __restrict__ out, int C) {
    int pl = blockIdx.z;
    int c  = pl % C;
    int x  = blockIdx.x * 32 + threadIdx.x;
    int y  = blockIdx.y * 8  + threadIdx.y;
    const float* ip = in + (size_t)pl * HW;
    const float* wp = w + c * 9;
    float s = 0.f;
#pragma unroll
    for (int dy = -1; dy <= 1; dy++) {
        int yy = y + dy;
        if (yy < 0 || yy >= IMG) continue;
#pragma unroll
        for (int dx = -1; dx <= 1; dx++) {
            int xx = x + dx;
            if (xx < 0 || xx >= IMG) continue;
            s += wp[(dy + 1) * 3 + (dx + 1)] * ip[yy * IMG + xx];
        }
    }
    out[(size_t)pl * HW + y * IMG + x] = s;
}

// ---------------------------------------------------------------------------
// Fused FFN tail: dw3 on both halves + exact gelu + multiply.
// ---------------------------------------------------------------------------
__global__ void dwgate_kernel(const float* __restrict__ t,
                              const float* __restrict__ dwf,
                              float* __restrict__ gate) {
    int pl = blockIdx.z;
    int b = pl / HIDDEN, k = pl % HIDDEN;
    int x = blockIdx.x * 32 + threadIdx.x;
    int y = blockIdx.y * 8  + threadIdx.y;
    const float* i1 = t + ((size_t)b * 2 * HIDDEN + k) * HW;
    const float* i2 = t + ((size_t)b * 2 * HIDDEN + HIDDEN + k) * HW;
    const float* w1 = dwf + k * 9;
    const float* w2 = dwf + (HIDDEN + k) * 9;
    float s1 = 0.f, s2 = 0.f;
#pragma unroll
    for (int dy = -1; dy <= 1; dy++) {
        int yy = y + dy;
        if (yy < 0 || yy >= IMG) continue;
#pragma unroll
        for (int dx = -1; dx <= 1; dx++) {
            int xx = x + dx;
            if (xx < 0 || xx >= IMG) continue;
            int o = yy * IMG + xx, wi = (dy + 1) * 3 + (dx + 1);
            s1 += w1[wi] * i1[o];
            s2 += w2[wi] * i2[o];
        }
    }
    float gl = 0.5f * s1 * (1.f + erff(s1 * 0.7071067811865475f));
    gate[((size_t)b * HIDDEN + k) * HW + y * IMG + x] = gl * s2;
}

// ---------------------------------------------------------------------------
// Gram stage 1 + fused row-norm partials.
// Partial layout per (b,h,chunk): [0..143] sum q_c*k_d; [144..155] sum q_c^2;
// [156..167] sum k_d^2.
// ---------------------------------------------------------------------------
__global__ void __launch_bounds__(256) gram1_kernel(
        const float* __restrict__ Q, const float* __restrict__ Kp,
        float* __restrict__ part) {
    int chunk = blockIdx.x, h = blockIdx.y, b = blockIdx.z;
    const float* qb = Q  + ((size_t)b * 288 + h * CHEAD) * HW;
    const float* kb = Kp + ((size_t)b * 288 + h * CHEAD) * HW;

    float acc[168];
#pragma unroll
    for (int i = 0; i < 168; i++) acc[i] = 0.f;

    int p0 = chunk * 1024 + threadIdx.x;
    for (int it = 0; it < 4; it++) {
        int p = p0 + it * 256;
        float qv[CHEAD], kv[CHEAD];
#pragma unroll
        for (int c = 0; c < CHEAD; c++) qv[c] = qb[(size_t)c * HW + p];
#pragma unroll
        for (int d = 0; d < CHEAD; d++) kv[d] = kb[(size_t)d * HW + p];
#pragma unroll
        for (int c = 0; c < CHEAD; c++)
#pragma unroll
            for (int d = 0; d < CHEAD; d++) acc[c * CHEAD + d] += qv[c] * kv[d];
#pragma unroll
        for (int c = 0; c < CHEAD; c++) acc[144 + c] += qv[c] * qv[c];
#pragma unroll
        for (int d = 0; d < CHEAD; d++) acc[156 + d] += kv[d] * kv[d];
    }

    __shared__ float red[8];
    float* outp = part + (((size_t)(b * HEADS + h)) * 64 + chunk) * 168;
#pragma unroll
    for (int i = 0; i < 168; i++) {
        float v = acc[i];
#pragma unroll
        for (int off = 16; off > 0; off >>= 1)
            v += __shfl_down_sync(0xffffffffu, v, off);
        if ((threadIdx.x & 31) == 0) red[threadIdx.x >> 5] = v;
        __syncthreads();
        if (threadIdx.x == 0) {
            float s = 0.f;
            for (int w2 = 0; w2 < 8; w2++) s += red[w2];
            outp[i] = s;
        }
        __syncthreads();
    }
}

// ---------------------------------------------------------------------------
// Gram stage 2 + norms + temperature + softmax (both branches).
// ---------------------------------------------------------------------------
__global__ void attn_kernel(const float* __restrict__ partA,
                            const float* __restrict__ partB,
                            const float* __restrict__ temp,
                            float* __restrict__ attnA,
                            float* __restrict__ attnB) {
    int bh = blockIdx.x;
    int h = bh % HEADS;
    __shared__ float GA[144], GB[144];
    __shared__ float nqA[12], nkA[12], nqB[12], nkB[12];
    int i = threadIdx.x;
    float sA = 0.f, sB = 0.f;
    if (i < 168) {
        const float* pA = partA + ((size_t)bh * 64) * 168 + i;
        const float* pB = partB + ((size_t)bh * 64) * 168 + i;
        for (int ch = 0; ch < 64; ch++) {
            sA += pA[(size_t)ch * 168];
            sB += pB[(size_t)ch * 168];
        }
        if (i >= 156) {
            nkA[i - 156] = fmaxf(sqrtf(sA), 1e-12f);
            nkB[i - 156] = fmaxf(sqrtf(sB), 1e-12f);
        } else if (i >= 144) {
            nqA[i - 144] = fmaxf(sqrtf(sA), 1e-12f);
            nqB[i - 144] = fmaxf(sqrtf(sB), 1e-12f);
        }
    }
    __syncthreads();
    if (i < 144) {
        int c = i / CHEAD, d = i % CHEAD;
        float tp = temp[h];
        GA[i] =  sA / (nqA[c] * nkA[d]) * tp;
        GB[i] = -sB / (nqB[c] * nkB[d]) * tp;
    }
    __syncthreads();
    if (i < 24) {
        float* G = (i < CHEAD) ? GA : GB;
        float* O = (i < CHEAD) ? attnA : attnB;
        int c = i % CHEAD;
        float mx = -1e30f;
        for (int d = 0; d < CHEAD; d++) mx = fmaxf(mx, G[c * CHEAD + d]);
        float e[CHEAD];
        float s = 0.f;
        for (int d = 0; d < CHEAD; d++) {
            e[d] = expf(G[c * CHEAD + d] - mx);
            s += e[d];
        }
        float inv = 1.f / s;
        for (int d = 0; d < CHEAD; d++)
            O[(size_t)bh * 144 + c * CHEAD + d] = e[d] * inv;
    }
}

// ---------------------------------------------------------------------------
// out[c,p] = sum_d attn[c,d] * v[d,p] per (b,head).
// ---------------------------------------------------------------------------
__global__ void attnv_kernel(const float* __restrict__ attn,
                             const float* __restrict__ qkvd,
                             float* __restrict__ out) {
    int h = blockIdx.y, b = blockIdx.z;
    int p = blockIdx.x * 256 + threadIdx.x;
    __shared__ float a_s[144];
    if (threadIdx.x < 144)
        a_s[threadIdx.x] = attn[((size_t)(b * HEADS + h)) * 144 + threadIdx.x];
    __syncthreads();

    const float* vb = qkvd + ((size_t)b * 288 + 192 + h * CHEAD) * HW + p;
    float v[CHEAD];
#pragma unroll
    for (int d = 0; d < CHEAD; d++) v[d] = vb[(size_t)d * HW];

    float* ob = out + ((size_t)b * CDIM + h * CHEAD) * HW + p;
#pragma unroll
    for (int c = 0; c < CHEAD; c++) {
        float s = 0.f;
#pragma unroll
        for (int d = 0; d < CHEAD; d++) s += a_s[c * CHEAD + d] * v[d];
        ob[(size_t)c * HW] = s;
    }
}

// ---------------------------------------------------------------------------
// Launch
// ---------------------------------------------------------------------------
extern "C" void kernel_launch(void* const* d_in, const int* in_sizes, int n_in,
                              void* d_out, int out_size) {
    const float* x       = (const float*)d_in[0];
    const float* y       = (const float*)d_in[1];
    const float* ln1_w   = (const float*)d_in[2];
    const float* ln1_b   = (const float*)d_in[3];
    const float* ln2_w   = (const float*)d_in[4];
    const float* ln2_b   = (const float*)d_in[5];
    const float* qkvA_w  = (const float*)d_in[6];
    const float* dwA_w   = (const float*)d_in[7];
    const float* qkvB_w  = (const float*)d_in[8];
    const float* dwB_w   = (const float*)d_in[9];
    const float* projA_w = (const float*)d_in[10];
    const float* projB_w = (const float*)d_in[11];
    const float* concat_w= (const float*)d_in[12];
    const float* temp    = (const float*)d_in[13];
    const float* pin_w   = (const float*)d_in[14];
    const float* dwf_w   = (const float*)d_in[15];
    const float* pout_w  = (const float*)d_in[16];
    float* out = (float*)d_out;

    cudaFuncSetAttribute(gemm_tc<true, 0>,  cudaFuncAttributeMaxDynamicSharedMemorySize, GEMM_SMEM_BYTES);
    cudaFuncSetAttribute(gemm_tc<false, 1>, cudaFuncAttributeMaxDynamicSharedMemorySize, GEMM_SMEM_BYTES);
    cudaFuncSetAttribute(gemm_tc<false, 2>, cudaFuncAttributeMaxDynamicSharedMemorySize, GEMM_SMEM_BYTES);

    float *qkvA, *qkvAd, *qkvB, *qkvBd, *preA, *preB, *outAB;
    float *x1, *t, *gate, *stsX, *stsY, *stsX1;
    float *gpA, *gpB, *atA, *atB;
    cudaGetSymbolAddress((void**)&qkvA,   g_qkvA);
    cudaGetSymbolAddress((void**)&qkvAd,  g_qkvAd);
    cudaGetSymbolAddress((void**)&qkvB,   g_qkvB);
    cudaGetSymbolAddress((void**)&qkvBd,  g_qkvBd);
    cudaGetSymbolAddress((void**)&preA,   g_preA);
    cudaGetSymbolAddress((void**)&preB,   g_preB);
    cudaGetSymbolAddress((void**)&outAB,  g_outAB);
    cudaGetSymbolAddress((void**)&x1,     g_x1);
    cudaGetSymbolAddress((void**)&t,      g_t);
    cudaGetSymbolAddress((void**)&gate,   g_gate);
    cudaGetSymbolAddress((void**)&stsX,   g_stsX);
    cudaGetSymbolAddress((void**)&stsY,   g_stsY);
    cudaGetSymbolAddress((void**)&stsX1,  g_stsX1);
    cudaGetSymbolAddress((void**)&gpA,    g_gpartA);
    cudaGetSymbolAddress((void**)&gpB,    g_gpartB);
    cudaGetSymbolAddress((void**)&atA,    g_attnA);
    cudaGetSymbolAddress((void**)&atB,    g_attnB);

    const size_t P96  = (size_t)CDIM * HW;
    const size_t P192 = 2 * P96;
    const size_t P288 = 3 * P96;
    const size_t P510 = (size_t)2 * HIDDEN * HW;
    const size_t P255 = (size_t)HIDDEN * HW;

    dim3 sGrid(HW / 256, BATCH);
    stats_kernel<<<sGrid, 256>>>(x, (float2*)stsX);
    stats_kernel<<<sGrid, 256>>>(y, (float2*)stsY);

    // qkv conv1x1 with fused LN1 (M=288, K=96)
    {
        dim3 g(3, HW / 128, BATCH);
        gemm_tc<true, 0><<<g, 256, GEMM_SMEM_BYTES>>>(qkvA_w, x, nullptr, qkvA, stsX,
                                                      ln1_w, ln1_b, 288, 96, P96, P288, 0);
        gemm_tc<true, 0><<<g, 256, GEMM_SMEM_BYTES>>>(qkvB_w, y, nullptr, qkvB, stsY,
                                                      ln1_w, ln1_b, 288, 96, P96, P288, 0);
    }

    // depthwise 3x3
    {
        dim3 blk(32, 8), g(IMG / 32, IMG / 8, BATCH * 288);
        dw3_kernel<<<g, blk>>>(qkvA, dwA_w, qkvAd, 288);
        dw3_kernel<<<g, blk>>>(qkvB, dwB_w, qkvBd, 288);
    }

    // Gram + fused norms: attnA uses (q of B, k of A); attnB uses (q of A, k of B)
    {
        dim3 g(64, HEADS, BATCH);
        gram1_kernel<<<g, 256>>>(qkvBd, qkvAd + 96 * (size_t)HW, gpA);
        gram1_kernel<<<g, 256>>>(qkvAd, qkvBd + 96 * (size_t)HW, gpB);
    }

    attn_kernel<<<BATCH * HEADS, 192>>>(gpA, gpB, temp, atA, atB);

    {
        dim3 g(HW / 256, HEADS, BATCH);
        attnv_kernel<<<g, 256>>>(atA, qkvAd, preA);
        attnv_kernel<<<g, 256>>>(atB, qkvBd, preB);
    }

    // proj conv1x1 + fused LN residual
    {
        dim3 g(1, HW / 128, BATCH);
        gemm_tc<false, 2><<<g, 256, GEMM_SMEM_BYTES>>>(projA_w, preA, x, outAB, stsX,
                                                       ln1_w, ln1_b, 96, 96, P96, P192, P96);
        gemm_tc<false, 2><<<g, 256, GEMM_SMEM_BYTES>>>(projB_w, preB, y, outAB + 96 * (size_t)HW,
                                                       stsY, ln1_w, ln1_b, 96, 96, P96, P192, P96);
    }

    // concat conv1x1 + residual x -> x1
    {
        dim3 g(1, HW / 128, BATCH);
        gemm_tc<false, 1><<<g, 256, GEMM_SMEM_BYTES>>>(concat_w, outAB, x, x1, nullptr,
                                                       nullptr, nullptr, 96, 192, P192, P96, P96);
    }

    stats_kernel<<<sGrid, 256>>>(x1, (float2*)stsX1);

    // pin conv1x1 with fused LN2 (M=510, K=96)
    {
        dim3 g(6, HW / 128, BATCH);
        gemm_tc<true, 0><<<g, 256, GEMM_SMEM_BYTES>>>(pin_w, x1, nullptr, t, stsX1,
                                                      ln2_w, ln2_b, 510, 96, P96, P510, 0);
    }

    // fused depthwise + gelu gate
    {
        dim3 blk(32, 8), g(IMG / 32, IMG / 8, BATCH * HIDDEN);
        dwgate_kernel<<<g, blk>>>(t, dwf_w, gate);
    }

    // pout conv1x1 + residual x1 -> final output
    {
        dim3 g(1, HW / 128, BATCH);
        gemm_tc<false, 1><<<g, 256, GEMM_SMEM_BYTES>>>(pout_w, gate, x1, out, nullptr,
                                                       nullptr, nullptr, 96, 255, P255, P96, P96);
    }
}

// round 4
// speedup vs baseline: 2.0666x; 1.2509x over previous
#include <cuda_runtime.h>
#include <math.h>
#include <stdint.h>

#define HW      65536
#define IMG     256
#define BATCH   2
#define CDIM    96
#define HEADS   8
#define CHEAD   12
#define HIDDEN  255

// ---------------------------------------------------------------------------
// Scratch
// ---------------------------------------------------------------------------
__device__ float g_qkvA [BATCH * 3 * CDIM * HW];
__device__ float g_qkvAd[BATCH * 3 * CDIM * HW];
__device__ float g_qkvB [BATCH * 3 * CDIM * HW];
__device__ float g_qkvBd[BATCH * 3 * CDIM * HW];
__device__ float g_x1   [BATCH * CDIM * HW];
__device__ float g_t    [BATCH * 2 * HIDDEN * HW];
__device__ float g_gate [BATCH * HIDDEN * HW];
__device__ float g_stsX [BATCH * HW * 2];
__device__ float g_stsY [BATCH * HW * 2];
__device__ float g_stsX1[BATCH * HW * 2];
__device__ float g_gpartA[BATCH * HEADS * 256 * 168];
__device__ float g_gpartB[BATCH * HEADS * 256 * 168];
__device__ float g_attnA [BATCH * HEADS * 144];
__device__ float g_attnB [BATCH * HEADS * 144];
__device__ float g_P0  [CDIM * CDIM];
__device__ float g_P1  [CDIM * CDIM];
__device__ float g_cwA [BATCH * CDIM * CDIM];
__device__ float g_cwB [BATCH * CDIM * CDIM];

// ---------------------------------------------------------------------------
// tf32 helpers
// ---------------------------------------------------------------------------
__device__ __forceinline__ uint32_t f2tf(float f) {
    uint32_t u;
    asm("cvt.rna.tf32.f32 %0, %1;" : "=r"(u) : "f"(f));
    return u;
}

__device__ __forceinline__ void mma_tf32(float* c, const uint32_t* a, const uint32_t* b) {
    asm volatile(
        "mma.sync.aligned.m16n8k8.row.col.f32.tf32.tf32.f32 "
        "{%0,%1,%2,%3}, {%4,%5,%6,%7}, {%8,%9}, {%0,%1,%2,%3};"
        : "+f"(c[0]), "+f"(c[1]), "+f"(c[2]), "+f"(c[3])
        : "r"(a[0]), "r"(a[1]), "r"(a[2]), "r"(a[3]), "r"(b[0]), "r"(b[1]));
}

// A packed-fragment smem offset for element (m 0..95, k 0..95):
// [ks=k>>3][mblk=m>>4][g=m&7][t=k&3][w] with w = ((k>>2)&1)*2 + ((m>>3)&1)
__device__ __forceinline__ int a_pack_off(int m, int k) {
    return (k >> 3) * 768 + (m >> 4) * 128 + (m & 7) * 16 + (k & 3) * 4
         + ((k >> 2) & 1) * 2 + ((m >> 3) & 1);
}

#define GEMM_SMEM_WORDS (9216 + 96*136 + 128 + 128 + 96 + 96)
#define GEMM_SMEM_BYTES (GEMM_SMEM_WORDS * 4)

// ---------------------------------------------------------------------------
// Per-pixel LayerNorm stats over C=96: (mu, inv_std).
// ---------------------------------------------------------------------------
__global__ void stats_kernel(const float* __restrict__ in,
                             float2* __restrict__ st) {
    int p = blockIdx.x * blockDim.x + threadIdx.x;
    int b = blockIdx.y;
    const float* ip = in + (size_t)b * CDIM * HW + p;
    float v[CDIM];
    float s = 0.f;
#pragma unroll
    for (int c = 0; c < CDIM; c++) { v[c] = ip[(size_t)c * HW]; s += v[c]; }
    float mu = s * (1.f / CDIM);
    float vs = 0.f;
#pragma unroll
    for (int c = 0; c < CDIM; c++) { float d = v[c] - mu; vs += d * d; }
    float inv = rsqrtf(vs * (1.f / CDIM) + 1e-5f);
    st[(size_t)b * HW + p] = make_float2(mu, inv);
}

// ---------------------------------------------------------------------------
// tf32 GEMM: Y[M,N] = W[M,K] @ B[K,N] (+res). BM=96 BN=128, K staged by 96.
// A in packed-fragment layout (LDS.128), B rows [k][136] (raw fp32 bits,
// HW-truncated to tf32 by the MMA). LNB: B = LayerNorm(X) fused on load.
// RES: 0 none, 1 Y += R.
// ---------------------------------------------------------------------------
template <bool LNB, int RES>
__global__ void __launch_bounds__(256, 2) gemm_tc(
        const float* __restrict__ Wt,
        const float* __restrict__ X,
        const float* __restrict__ Rsrc,
        float* __restrict__ Y,
        const float* __restrict__ stats,
        const float* __restrict__ lnw,
        const float* __restrict__ lnb,
        int M, int K,
        size_t xBatch, size_t yBatch, size_t rBatch) {
    extern __shared__ uint32_t smem_u[];
    uint32_t* As  = smem_u;                  // 9216 packed words
    uint32_t* Bs  = As + 9216;               // [96][136]
    float* mu_s   = (float*)(Bs + 96 * 136); // [128]
    float* inv_s  = mu_s + 128;
    float* wln_s  = inv_s + 128;             // [96]
    float* bln_s  = wln_s + 96;

    int bz = blockIdx.z;
    const float* Xb = X + (size_t)bz * xBatch;
    float*       Yb = Y + (size_t)bz * yBatch;
    const float* Rb = RES ? (Rsrc + (size_t)bz * rBatch) : nullptr;

    int m0 = blockIdx.x * 96;
    int n0 = blockIdx.y * 128;
    int tid  = threadIdx.x;
    int warp = tid >> 5;
    int lane = tid & 31;
    int g = lane >> 2;
    int t = lane & 3;
    int wm  = (warp >> 2) * 48;
    int wmi = (warp >> 2) * 3;
    int wn  = (warp & 3) * 32;

    if (LNB) {
        if (tid < 128) {
            float2 s = reinterpret_cast<const float2*>(stats)[(size_t)bz * HW + n0 + tid];
            mu_s[tid]  = s.x;
            inv_s[tid] = s.y;
        }
        if (tid < 96) { wln_s[tid] = lnw[tid]; bln_s[tid] = lnb[tid]; }
        __syncthreads();
    }

    float acc[3][4][4];
#pragma unroll
    for (int mi = 0; mi < 3; mi++)
#pragma unroll
        for (int ni = 0; ni < 4; ni++)
#pragma unroll
            for (int r = 0; r < 4; r++) acc[mi][ni][r] = 0.f;

    int nstages = (K + 95) / 96;
    for (int s = 0; s < nstages; s++) {
        int k0 = s * 96;
        // ---- A: 96x96 -> packed fragments (rounded to tf32) ----
#pragma unroll
        for (int i = 0; i < 36; i++) {
            int idx = tid + i * 256;
            int m = idx / 96;
            int k = idx - m * 96;
            float v = 0.f;
            if (m0 + m < M && k0 + k < K) v = Wt[(size_t)(m0 + m) * K + k0 + k];
            As[a_pack_off(m, k)] = f2tf(v);
        }
        // ---- B: 96k x 128n, raw fp32 bits, optional fused LN ----
#pragma unroll
        for (int i = 0; i < 12; i++) {
            int idx = tid + i * 256;
            int k  = idx >> 5;
            int n4 = idx & 31;
            float4 v = make_float4(0.f, 0.f, 0.f, 0.f);
            if (k0 + k < K) {
                v = reinterpret_cast<const float4*>(Xb + (size_t)(k0 + k) * HW + n0)[n4];
                if (LNB) {
                    int nb = n4 * 4;
                    float wk = wln_s[k], bk = bln_s[k];
                    v.x = (v.x - mu_s[nb + 0]) * inv_s[nb + 0] * wk + bk;
                    v.y = (v.y - mu_s[nb + 1]) * inv_s[nb + 1] * wk + bk;
                    v.z = (v.z - mu_s[nb + 2]) * inv_s[nb + 2] * wk + bk;
                    v.w = (v.w - mu_s[nb + 3]) * inv_s[nb + 3] * wk + bk;
                }
            }
            uint4 u = make_uint4(__float_as_uint(v.x), __float_as_uint(v.y),
                                 __float_as_uint(v.z), __float_as_uint(v.w));
            *reinterpret_cast<uint4*>(Bs + k * 136 + n4 * 4) = u;
        }
        __syncthreads();
#pragma unroll
        for (int ks = 0; ks < 12; ks++) {
            const uint32_t* Ab = As + ks * 768 + g * 16 + t * 4;
            const uint32_t* Bb = Bs + (ks * 8 + t) * 136 + wn + g;
            uint4 a4[3];
            uint32_t bf[4][2];
#pragma unroll
            for (int mi = 0; mi < 3; mi++)
                a4[mi] = *reinterpret_cast<const uint4*>(Ab + (wmi + mi) * 128);
#pragma unroll
            for (int ni = 0; ni < 4; ni++) {
                bf[ni][0] = Bb[ni * 8];
                bf[ni][1] = Bb[4 * 136 + ni * 8];
            }
#pragma unroll
            for (int mi = 0; mi < 3; mi++) {
                uint32_t af[4] = {a4[mi].x, a4[mi].y, a4[mi].z, a4[mi].w};
#pragma unroll
                for (int ni = 0; ni < 4; ni++)
                    mma_tf32(acc[mi][ni], af, bf[ni]);
            }
        }
        __syncthreads();
    }

    // ---- epilogue ----
#pragma unroll
    for (int mi = 0; mi < 3; mi++) {
        int r0 = m0 + wm + mi * 16 + g;
        int r1 = r0 + 8;
#pragma unroll
        for (int ni = 0; ni < 4; ni++) {
            int col = n0 + wn + ni * 8 + 2 * t;
            float2 v01 = make_float2(acc[mi][ni][0], acc[mi][ni][1]);
            float2 v23 = make_float2(acc[mi][ni][2], acc[mi][ni][3]);
            if (RES) {
                if (r0 < M) {
                    float2 r = *reinterpret_cast<const float2*>(Rb + (size_t)r0 * HW + col);
                    v01.x += r.x; v01.y += r.y;
                }
                if (r1 < M) {
                    float2 r = *reinterpret_cast<const float2*>(Rb + (size_t)r1 * HW + col);
                    v23.x += r.x; v23.y += r.y;
                }
            }
            if (r0 < M)
                *reinterpret_cast<float2*>(Yb + (size_t)r0 * HW + col) = v01;
            if (r1 < M)
                *reinterpret_cast<float2*>(Yb + (size_t)r1 * HW + col) = v23;
        }
    }
}

// ---------------------------------------------------------------------------
// 4-source fused GEMM for x1:
//   x1 = x + sum_s W_s[96x96] @ X_s  (X_s optionally LayerNorm'd)
// Same tile geometry as gemm_tc; M=96, K=96 per source.
// ---------------------------------------------------------------------------
struct G4 {
    const float* W[4];
    int          wStride[4];
    size_t       wBatch[4];
    const float* X[4];
    size_t       xBatch[4];
    const float* stats[4];   // null -> no LN
};

__global__ void __launch_bounds__(256, 2) gemm4_tc(
        G4 p,
        const float* __restrict__ lnw,
        const float* __restrict__ lnb,
        const float* __restrict__ Rsrc,
        float* __restrict__ Y) {
    extern __shared__ uint32_t smem_u[];
    uint32_t* As  = smem_u;
    uint32_t* Bs  = As + 9216;
    float* mu_s   = (float*)(Bs + 96 * 136);
    float* inv_s  = mu_s + 128;
    float* wln_s  = inv_s + 128;
    float* bln_s  = wln_s + 96;

    int bz = blockIdx.z;
    int n0 = blockIdx.y * 128;
    float*       Yb = Y    + (size_t)bz * CDIM * HW;
    const float* Rb = Rsrc + (size_t)bz * CDIM * HW;

    int tid  = threadIdx.x;
    int warp = tid >> 5;
    int lane = tid & 31;
    int g = lane >> 2;
    int t = lane & 3;
    int wm  = (warp >> 2) * 48;
    int wmi = (warp >> 2) * 3;
    int wn  = (warp & 3) * 32;

    if (tid < 96) { wln_s[tid] = lnw[tid]; bln_s[tid] = lnb[tid]; }

    float acc[3][4][4];
#pragma unroll
    for (int mi = 0; mi < 3; mi++)
#pragma unroll
        for (int ni = 0; ni < 4; ni++)
#pragma unroll
            for (int r = 0; r < 4; r++) acc[mi][ni][r] = 0.f;

    for (int s = 0; s < 4; s++) {
        __syncthreads();   // guards smem reuse + initial wln/bln visibility
        const float* Wp = p.W[s] + (size_t)bz * p.wBatch[s];
        const float* Xb = p.X[s] + (size_t)bz * p.xBatch[s];
        int wstr = p.wStride[s];
        bool ln = (p.stats[s] != nullptr);
        if (ln && tid < 128) {
            float2 sv = reinterpret_cast<const float2*>(p.stats[s])[(size_t)bz * HW + n0 + tid];
            mu_s[tid]  = sv.x;
            inv_s[tid] = sv.y;
        }
#pragma unroll
        for (int i = 0; i < 36; i++) {
            int idx = tid + i * 256;
            int m = idx / 96;
            int k = idx - m * 96;
            As[a_pack_off(m, k)] = f2tf(Wp[(size_t)m * wstr + k]);
        }
        if (ln) __syncthreads();   // mu/inv ready before B staging uses them
#pragma unroll
        for (int i = 0; i < 12; i++) {
            int idx = tid + i * 256;
            int k  = idx >> 5;
            int n4 = idx & 31;
            float4 v = reinterpret_cast<const float4*>(Xb + (size_t)k * HW + n0)[n4];
            if (ln) {
                int nb = n4 * 4;
                float wk = wln_s[k], bk = bln_s[k];
                v.x = (v.x - mu_s[nb + 0]) * inv_s[nb + 0] * wk + bk;
                v.y = (v.y - mu_s[nb + 1]) * inv_s[nb + 1] * wk + bk;
                v.z = (v.z - mu_s[nb + 2]) * inv_s[nb + 2] * wk + bk;
                v.w = (v.w - mu_s[nb + 3]) * inv_s[nb + 3] * wk + bk;
            }
            uint4 u = make_uint4(__float_as_uint(v.x), __float_as_uint(v.y),
                                 __float_as_uint(v.z), __float_as_uint(v.w));
            *reinterpret_cast<uint4*>(Bs + k * 136 + n4 * 4) = u;
        }
        __syncthreads();
#pragma unroll
        for (int ks = 0; ks < 12; ks++) {
            const uint32_t* Ab = As + ks * 768 + g * 16 + t * 4;
            const uint32_t* Bb = Bs + (ks * 8 + t) * 136 + wn + g;
            uint4 a4[3];
            uint32_t bf[4][2];
#pragma unroll
            for (int mi = 0; mi < 3; mi++)
                a4[mi] = *reinterpret_cast<const uint4*>(Ab + (wmi + mi) * 128);
#pragma unroll
            for (int ni = 0; ni < 4; ni++) {
                bf[ni][0] = Bb[ni * 8];
                bf[ni][1] = Bb[4 * 136 + ni * 8];
            }
#pragma unroll
            for (int mi = 0; mi < 3; mi++) {
                uint32_t af[4] = {a4[mi].x, a4[mi].y, a4[mi].z, a4[mi].w};
#pragma unroll
                for (int ni = 0; ni < 4; ni++)
                    mma_tf32(acc[mi][ni], af, bf[ni]);
            }
        }
    }

#pragma unroll
    for (int mi = 0; mi < 3; mi++) {
        int r0 = wm + mi * 16 + g;
        int r1 = r0 + 8;
#pragma unroll
        for (int ni = 0; ni < 4; ni++) {
            int col = n0 + wn + ni * 8 + 2 * t;
            float2 ra = *reinterpret_cast<const float2*>(Rb + (size_t)r0 * HW + col);
            float2 rb = *reinterpret_cast<const float2*>(Rb + (size_t)r1 * HW + col);
            float2 v01 = make_float2(acc[mi][ni][0] + ra.x, acc[mi][ni][1] + ra.y);
            float2 v23 = make_float2(acc[mi][ni][2] + rb.x, acc[mi][ni][3] + rb.y);
            *reinterpret_cast<float2*>(Yb + (size_t)r0 * HW + col) = v01;
            *reinterpret_cast<float2*>(Yb + (size_t)r1 * HW + col) = v23;
        }
    }
}

// ---------------------------------------------------------------------------
// Depthwise 3x3, SAME zero padding.
// ---------------------------------------------------------------------------
__global__ void dw3_kernel(const float* __restrict__ in,
                           const float* __restrict__ w,
                           float* __restrict__ out, int C) {
    int pl = blockIdx.z;
    int c  = pl % C;
    int x  = blockIdx.x * 32 + threadIdx.x;
    int y  = blockIdx.y * 8  + threadIdx.y;
    const float* ip = in + (size_t)pl * HW;
    const float* wp = w + c * 9;
    float s = 0.f;
#pragma unroll
    for (int dy = -1; dy <= 1; dy++) {
        int yy = y + dy;
        if (yy < 0 || yy >= IMG) continue;
#pragma unroll
        for (int dx = -1; dx <= 1; dx++) {
            int xx = x + dx;
            if (xx < 0 || xx >= IMG) continue;
            s += wp[(dy + 1) * 3 + (dx + 1)] * ip[yy * IMG + xx];
        }
    }
    out[(size_t)pl * HW + y * IMG + x] = s;
}

// ---------------------------------------------------------------------------
// Fused FFN tail: dw3 on both halves + exact gelu + multiply.
// ---------------------------------------------------------------------------
__global__ void dwgate_kernel(const float* __restrict__ t,
                              const float* __restrict__ dwf,
                              float* __restrict__ gate) {
    int pl = blockIdx.z;
    int b = pl / HIDDEN, k = pl % HIDDEN;
    int x = blockIdx.x * 32 + threadIdx.x;
    int y = blockIdx.y * 8  + threadIdx.y;
    const float* i1 = t + ((size_t)b * 2 * HIDDEN + k) * HW;
    const float* i2 = t + ((size_t)b * 2 * HIDDEN + HIDDEN + k) * HW;
    const float* w1 = dwf + k * 9;
    const float* w2 = dwf + (HIDDEN + k) * 9;
    float s1 = 0.f, s2 = 0.f;
#pragma unroll
    for (int dy = -1; dy <= 1; dy++) {
        int yy = y + dy;
        if (yy < 0 || yy >= IMG) continue;
#pragma unroll
        for (int dx = -1; dx <= 1; dx++) {
            int xx = x + dx;
            if (xx < 0 || xx >= IMG) continue;
            int o = yy * IMG + xx, wi = (dy + 1) * 3 + (dx + 1);
            s1 += w1[wi] * i1[o];
            s2 += w2[wi] * i2[o];
        }
    }
    float gl = 0.5f * s1 * (1.f + erff(s1 * 0.7071067811865475f));
    gate[((size_t)b * HIDDEN + k) * HW + y * IMG + x] = gl * s2;
}

// ---------------------------------------------------------------------------
// Gram stage 1 + fused row-norm partials; warp-level reduce, 8 partials/block.
// Partial layout per (b,h): [chunk*8+warp][168].
// ---------------------------------------------------------------------------
__global__ void __launch_bounds__(256) gram1_kernel(
        const float* __restrict__ Q, const float* __restrict__ Kp,
        float* __restrict__ part) {
    int chunk = blockIdx.x, h = blockIdx.y, b = blockIdx.z;
    const float* qb = Q  + ((size_t)b * 288 + h * CHEAD) * HW;
    const float* kb = Kp + ((size_t)b * 288 + h * CHEAD) * HW;

    float acc[168];
#pragma unroll
    for (int i = 0; i < 168; i++) acc[i] = 0.f;

    int p0 = chunk * 2048 + threadIdx.x;
    for (int it = 0; it < 8; it++) {
        int p = p0 + it * 256;
        float qv[CHEAD], kv[CHEAD];
#pragma unroll
        for (int c = 0; c < CHEAD; c++) qv[c] = qb[(size_t)c * HW + p];
#pragma unroll
        for (int d = 0; d < CHEAD; d++) kv[d] = kb[(size_t)d * HW + p];
#pragma unroll
        for (int c = 0; c < CHEAD; c++)
#pragma unroll
            for (int d = 0; d < CHEAD; d++) acc[c * CHEAD + d] += qv[c] * kv[d];
#pragma unroll
        for (int c = 0; c < CHEAD; c++) acc[144 + c] += qv[c] * qv[c];
#pragma unroll
        for (int d = 0; d < CHEAD; d++) acc[156 + d] += kv[d] * kv[d];
    }

    int warp = threadIdx.x >> 5;
    int lane = threadIdx.x & 31;
    float* outp = part + ((((size_t)(b * HEADS + h)) * 32 + chunk) * 8 + warp) * 168;
#pragma unroll
    for (int i = 0; i < 168; i++) {
        float v = acc[i];
#pragma unroll
        for (int off = 16; off > 0; off >>= 1)
            v += __shfl_down_sync(0xffffffffu, v, off);
        if (lane == 0) outp[i] = v;
    }
}

// ---------------------------------------------------------------------------
// Gram stage 2 (sum 256 partials) + norms + temperature + softmax.
// ---------------------------------------------------------------------------
__global__ void attn_kernel(const float* __restrict__ partA,
                            const float* __restrict__ partB,
                            const float* __restrict__ temp,
                            float* __restrict__ attnA,
                            float* __restrict__ attnB) {
    int bh = blockIdx.x;
    int h = bh % HEADS;
    __shared__ float GA[144], GB[144];
    __shared__ float nqA[12], nkA[12], nqB[12], nkB[12];
    int i = threadIdx.x;
    float sA = 0.f, sB = 0.f;
    if (i < 168) {
        const float* pA = partA + (size_t)bh * 256 * 168 + i;
        const float* pB = partB + (size_t)bh * 256 * 168 + i;
        for (int ch = 0; ch < 256; ch++) {
            sA += pA[(size_t)ch * 168];
            sB += pB[(size_t)ch * 168];
        }
        if (i >= 156) {
            nkA[i - 156] = fmaxf(sqrtf(sA), 1e-12f);
            nkB[i - 156] = fmaxf(sqrtf(sB), 1e-12f);
        } else if (i >= 144) {
            nqA[i - 144] = fmaxf(sqrtf(sA), 1e-12f);
            nqB[i - 144] = fmaxf(sqrtf(sB), 1e-12f);
        }
    }
    __syncthreads();
    if (i < 144) {
        int c = i / CHEAD, d = i % CHEAD;
        float tp = temp[h];
        GA[i] =  sA / (nqA[c] * nkA[d]) * tp;
        GB[i] = -sB / (nqB[c] * nkB[d]) * tp;
    }
    __syncthreads();
    if (i < 24) {
        float* G = (i < CHEAD) ? GA : GB;
        float* O = (i < CHEAD) ? attnA : attnB;
        int c = i % CHEAD;
        float mx = -1e30f;
        for (int d = 0; d < CHEAD; d++) mx = fmaxf(mx, G[c * CHEAD + d]);
        float e[CHEAD];
        float s = 0.f;
        for (int d = 0; d < CHEAD; d++) {
            e[d] = expf(G[c * CHEAD + d] - mx);
            s += e[d];
        }
        float inv = 1.f / s;
        for (int d = 0; d < CHEAD; d++)
            O[(size_t)bh * 144 + c * CHEAD + d] = e[d] * inv;
    }
}

// ---------------------------------------------------------------------------
// P0 = concat_w[:, :96] @ projA_w; P1 = concat_w[:, 96:] @ projB_w  (fp32)
// ---------------------------------------------------------------------------
__global__ void wprod_kernel(const float* __restrict__ concat_w,
                             const float* __restrict__ projA,
                             const float* __restrict__ projB,
                             float* __restrict__ P0,
                             float* __restrict__ P1) {
    int br = blockIdx.x;               // 0 -> A, 1 -> B
    const float* proj = br ? projB : projA;
    const float* cw   = concat_w + (br ? 96 : 0);
    float* P = br ? P1 : P0;
    __shared__ float pj[96 * 96];
    for (int i = threadIdx.x; i < 96 * 96; i += blockDim.x) pj[i] = proj[i];
    __syncthreads();
    for (int o = threadIdx.x; o < 96 * 96; o += blockDim.x) {
        int m = o / 96, n = o % 96;
        float s = 0.f;
#pragma unroll 8
        for (int c = 0; c < 96; c++) s += cw[m * 192 + c] * pj[c * 96 + n];
        P[o] = s;
    }
}

// ---------------------------------------------------------------------------
// cw[b] = P @ blockdiag(attn[b])  (12-wide dots, fp32)
// ---------------------------------------------------------------------------
__global__ void cw_kernel(const float* __restrict__ P0,
                          const float* __restrict__ P1,
                          const float* __restrict__ atA,
                          const float* __restrict__ atB,
                          float* __restrict__ cwA,
                          float* __restrict__ cwB) {
    int b  = blockIdx.x >> 1;
    int br = blockIdx.x & 1;
    const float* P  = br ? P1 : P0;
    const float* at = (br ? atB : atA) + (size_t)b * HEADS * 144;
    float* out = (br ? cwB : cwA) + (size_t)b * 96 * 96;
    __shared__ float a_s[HEADS * 144];
    for (int i = threadIdx.x; i < HEADS * 144; i += blockDim.x) a_s[i] = at[i];
    __syncthreads();
    for (int o = threadIdx.x; o < 96 * 96; o += blockDim.x) {
        int m = o / 96, n = o % 96;
        int h = n / CHEAD, d = n % CHEAD;
        float s = 0.f;
#pragma unroll
        for (int c = 0; c < CHEAD; c++)
            s += P[m * 96 + h * CHEAD + c] * a_s[h * 144 + c * CHEAD + d];
        out[o] = s;
    }
}

// ---------------------------------------------------------------------------
// Launch
// ---------------------------------------------------------------------------
extern "C" void kernel_launch(void* const* d_in, const int* in_sizes, int n_in,
                              void* d_out, int out_size) {
    const float* x       = (const float*)d_in[0];
    const float* y       = (const float*)d_in[1];
    const float* ln1_w   = (const float*)d_in[2];
    const float* ln1_b   = (const float*)d_in[3];
    const float* ln2_w   = (const float*)d_in[4];
    const float* ln2_b   = (const float*)d_in[5];
    const float* qkvA_w  = (const float*)d_in[6];
    const float* dwA_w   = (const float*)d_in[7];
    const float* qkvB_w  = (const float*)d_in[8];
    const float* dwB_w   = (const float*)d_in[9];
    const float* projA_w = (const float*)d_in[10];
    const float* projB_w = (const float*)d_in[11];
    const float* concat_w= (const float*)d_in[12];
    const float* temp    = (const float*)d_in[13];
    const float* pin_w   = (const float*)d_in[14];
    const float* dwf_w   = (const float*)d_in[15];
    const float* pout_w  = (const float*)d_in[16];
    float* out = (float*)d_out;

    cudaFuncSetAttribute(gemm_tc<true, 0>,  cudaFuncAttributeMaxDynamicSharedMemorySize, GEMM_SMEM_BYTES);
    cudaFuncSetAttribute(gemm_tc<false, 1>, cudaFuncAttributeMaxDynamicSharedMemorySize, GEMM_SMEM_BYTES);
    cudaFuncSetAttribute(gemm4_tc,          cudaFuncAttributeMaxDynamicSharedMemorySize, GEMM_SMEM_BYTES);

    float *qkvA, *qkvAd, *qkvB, *qkvBd, *x1, *t, *gate;
    float *stsX, *stsY, *stsX1, *gpA, *gpB, *atA, *atB, *P0, *P1, *cwA, *cwB;
    cudaGetSymbolAddress((void**)&qkvA,   g_qkvA);
    cudaGetSymbolAddress((void**)&qkvAd,  g_qkvAd);
    cudaGetSymbolAddress((void**)&qkvB,   g_qkvB);
    cudaGetSymbolAddress((void**)&qkvBd,  g_qkvBd);
    cudaGetSymbolAddress((void**)&x1,     g_x1);
    cudaGetSymbolAddress((void**)&t,      g_t);
    cudaGetSymbolAddress((void**)&gate,   g_gate);
    cudaGetSymbolAddress((void**)&stsX,   g_stsX);
    cudaGetSymbolAddress((void**)&stsY,   g_stsY);
    cudaGetSymbolAddress((void**)&stsX1,  g_stsX1);
    cudaGetSymbolAddress((void**)&gpA,    g_gpartA);
    cudaGetSymbolAddress((void**)&gpB,    g_gpartB);
    cudaGetSymbolAddress((void**)&atA,    g_attnA);
    cudaGetSymbolAddress((void**)&atB,    g_attnB);
    cudaGetSymbolAddress((void**)&P0,     g_P0);
    cudaGetSymbolAddress((void**)&P1,     g_P1);
    cudaGetSymbolAddress((void**)&cwA,    g_cwA);
    cudaGetSymbolAddress((void**)&cwB,    g_cwB);

    const size_t P96  = (size_t)CDIM * HW;
    const size_t P288 = 3 * P96;
    const size_t P510 = (size_t)2 * HIDDEN * HW;
    const size_t P255 = (size_t)HIDDEN * HW;

    dim3 sGrid(HW / 256, BATCH);
    stats_kernel<<<sGrid, 256>>>(x, (float2*)stsX);
    stats_kernel<<<sGrid, 256>>>(y, (float2*)stsY);

    // weight product (independent of everything downstream of inputs)
    wprod_kernel<<<2, 256>>>(concat_w, projA_w, projB_w, P0, P1);

    // qkv conv1x1 with fused LN1 (M=288, K=96)
    {
        dim3 g(3, HW / 128, BATCH);
        gemm_tc<true, 0><<<g, 256, GEMM_SMEM_BYTES>>>(qkvA_w, x, nullptr, qkvA, stsX,
                                                      ln1_w, ln1_b, 288, 96, P96, P288, 0);
        gemm_tc<true, 0><<<g, 256, GEMM_SMEM_BYTES>>>(qkvB_w, y, nullptr, qkvB, stsY,
                                                      ln1_w, ln1_b, 288, 96, P96, P288, 0);
    }

    // depthwise 3x3
    {
        dim3 blk(32, 8), g(IMG / 32, IMG / 8, BATCH * 288);
        dw3_kernel<<<g, blk>>>(qkvA, dwA_w, qkvAd, 288);
        dw3_kernel<<<g, blk>>>(qkvB, dwB_w, qkvBd, 288);
    }

    // Gram + fused norms
    {
        dim3 g(32, HEADS, BATCH);
        gram1_kernel<<<g, 256>>>(qkvBd, qkvAd + 96 * (size_t)HW, gpA);
        gram1_kernel<<<g, 256>>>(qkvAd, qkvBd + 96 * (size_t)HW, gpB);
    }

    attn_kernel<<<BATCH * HEADS, 192>>>(gpA, gpB, temp, atA, atB);

    // fold attn into effective weights
    cw_kernel<<<4, 256>>>(P0, P1, atA, atB, cwA, cwB);

    // fused x1 = x + cwA@vA + cwB@vB + concat0@LN(x) + concat1@LN(y)
    {
        G4 p;
        p.W[0] = cwA;           p.wStride[0] = 96;  p.wBatch[0] = 96 * 96;
        p.W[1] = cwB;           p.wStride[1] = 96;  p.wBatch[1] = 96 * 96;
        p.W[2] = concat_w;      p.wStride[2] = 192; p.wBatch[2] = 0;
        p.W[3] = concat_w + 96; p.wStride[3] = 192; p.wBatch[3] = 0;
        p.X[0] = qkvAd + 192 * (size_t)HW; p.xBatch[0] = P288; p.stats[0] = nullptr;
        p.X[1] = qkvBd + 192 * (size_t)HW; p.xBatch[1] = P288; p.stats[1] = nullptr;
        p.X[2] = x;                        p.xBatch[2] = P96;  p.stats[2] = stsX;
        p.X[3] = y;                        p.xBatch[3] = P96;  p.stats[3] = stsY;
        dim3 g(1, HW / 128, BATCH);
        gemm4_tc<<<g, 256, GEMM_SMEM_BYTES>>>(p, ln1_w, ln1_b, x, x1);
    }

    stats_kernel<<<sGrid, 256>>>(x1, (float2*)stsX1);

    // pin conv1x1 with fused LN2 (M=510, K=96)
    {
        dim3 g(6, HW / 128, BATCH);
        gemm_tc<true, 0><<<g, 256, GEMM_SMEM_BYTES>>>(pin_w, x1, nullptr, t, stsX1,
                                                      ln2_w, ln2_b, 510, 96, P96, P510, 0);
    }

    // fused depthwise + gelu gate
    {
        dim3 blk(32, 8), g(IMG / 32, IMG / 8, BATCH * HIDDEN);
        dwgate_kernel<<<g, blk>>>(t, dwf_w, gate);
    }

    // pout conv1x1 + residual x1 -> final output
    {
        dim3 g(1, HW / 128, BATCH);
        gemm_tc<false, 1><<<g, 256, GEMM_SMEM_BYTES>>>(pout_w, gate, x1, out, nullptr,
                                                       nullptr, nullptr, 96, 255, P255, P96, P96);
    }
}

// round 5
// speedup vs baseline: 2.4622x; 1.1915x over previous
#include <cuda_runtime.h>
#include <math.h>
#include <stdint.h>

#define HW      65536
#define IMG     256
#define BATCH   2
#define CDIM    96
#define HEADS   8
#define CHEAD   12
#define HIDDEN  255

// ---------------------------------------------------------------------------
// Scratch
// ---------------------------------------------------------------------------
__device__ float g_qkvA [BATCH * 3 * CDIM * HW];
__device__ float g_qkvAd[BATCH * 3 * CDIM * HW];
__device__ float g_qkvB [BATCH * 3 * CDIM * HW];
__device__ float g_qkvBd[BATCH * 3 * CDIM * HW];
__device__ float g_x1   [BATCH * CDIM * HW];
__device__ float g_t    [BATCH * 2 * HIDDEN * HW];
__device__ float g_gate [BATCH * HIDDEN * HW];
__device__ float g_stsX [BATCH * HW * 2];
__device__ float g_stsY [BATCH * HW * 2];
__device__ float g_stsX1[BATCH * HW * 2];
__device__ float g_gpartA[BATCH * HEADS * 256 * 168];
__device__ float g_gpartB[BATCH * HEADS * 256 * 168];
__device__ float g_attnA [BATCH * HEADS * 144];
__device__ float g_attnB [BATCH * HEADS * 144];
__device__ float g_P0  [CDIM * CDIM];
__device__ float g_P1  [CDIM * CDIM];
__device__ float g_cwA [BATCH * CDIM * CDIM];
__device__ float g_cwB [BATCH * CDIM * CDIM];
// prepacked tf32 A tiles (W * diag(lnw)) + LN row sums
__device__ uint32_t g_prepQA [3 * 9216];
__device__ uint32_t g_prepQB [3 * 9216];
__device__ uint32_t g_prepPin[6 * 9216];
__device__ float g_sQA[288],  g_tQA[288];
__device__ float g_sQB[288],  g_tQB[288];
__device__ float g_sPin[576], g_tPin[576];

// ---------------------------------------------------------------------------
// tf32 / cp.async helpers
// ---------------------------------------------------------------------------
__device__ __forceinline__ uint32_t f2tf(float f) {
    uint32_t u;
    asm("cvt.rna.tf32.f32 %0, %1;" : "=r"(u) : "f"(f));
    return u;
}

__device__ __forceinline__ void mma_tf32(float* c, const uint32_t* a, const uint32_t* b) {
    asm volatile(
        "mma.sync.aligned.m16n8k8.row.col.f32.tf32.tf32.f32 "
        "{%0,%1,%2,%3}, {%4,%5,%6,%7}, {%8,%9}, {%0,%1,%2,%3};"
        : "+f"(c[0]), "+f"(c[1]), "+f"(c[2]), "+f"(c[3])
        : "r"(a[0]), "r"(a[1]), "r"(a[2]), "r"(a[3]), "r"(b[0]), "r"(b[1]));
}

__device__ __forceinline__ void cp16(void* smem, const void* gmem) {
    uint32_t a = (uint32_t)__cvta_generic_to_shared(smem);
    asm volatile("cp.async.cg.shared.global [%0], [%1], 16;\n" :: "r"(a), "l"(gmem));
}
#define CP_COMMIT()  asm volatile("cp.async.commit_group;\n")
#define CP_WAIT(n)   asm volatile("cp.async.wait_group %0;\n" :: "n"(n))

// A packed-fragment smem offset for element (m 0..95, k 0..95):
// [ks=k>>3][mblk=m>>4][g=m&7][t=k&3][w], w = ((k>>2)&1)*2 + ((m>>3)&1)
__device__ __forceinline__ int a_pack_off(int m, int k) {
    return (k >> 3) * 768 + (m >> 4) * 128 + (m & 7) * 16 + (k & 3) * 4
         + ((k >> 2) & 1) * 2 + ((m >> 3) & 1);
}

#define GEMM_SMEM_WORDS (9216 + 96*136 + 128 + 128 + 96 + 96)
#define GEMM_SMEM_BYTES (GEMM_SMEM_WORDS * 4)
#define G96_SMEM_WORDS  (9216 + 2*32*136 + 256)
#define G96_SMEM_BYTES  (G96_SMEM_WORDS * 4)

// ---------------------------------------------------------------------------
// Per-pixel LayerNorm stats over C=96: (mu, inv_std).
// ---------------------------------------------------------------------------
__global__ void stats_kernel(const float* __restrict__ in,
                             float2* __restrict__ st) {
    int p = blockIdx.x * blockDim.x + threadIdx.x;
    int b = blockIdx.y;
    const float* ip = in + (size_t)b * CDIM * HW + p;
    float v[CDIM];
    float s = 0.f;
#pragma unroll
    for (int c = 0; c < CDIM; c++) { v[c] = ip[(size_t)c * HW]; s += v[c]; }
    float mu = s * (1.f / CDIM);
    float vs = 0.f;
#pragma unroll
    for (int c = 0; c < CDIM; c++) { float d = v[c] - mu; vs += d * d; }
    float inv = rsqrtf(vs * (1.f / CDIM) + 1e-5f);
    st[(size_t)b * HW + p] = make_float2(mu, inv);
}

// ---------------------------------------------------------------------------
// Prep: Apk = pack_tf32(W * diag(wln)) per 96-row tile; s = W@wln, t = W@bln.
// One block per m-tile, 256 threads. K is always 96.
// ---------------------------------------------------------------------------
__global__ void prep_kernel(const float* __restrict__ W, int M,
                            const float* __restrict__ wln,
                            const float* __restrict__ bln,
                            uint32_t* __restrict__ Apk,
                            float* __restrict__ svec,
                            float* __restrict__ tvec) {
    int tile = blockIdx.x;
    int m0 = tile * 96;
    __shared__ float wls[96], bls[96];
    if (threadIdx.x < 96) { wls[threadIdx.x] = wln[threadIdx.x]; bls[threadIdx.x] = bln[threadIdx.x]; }
    __syncthreads();
#pragma unroll
    for (int i = 0; i < 36; i++) {
        int idx = threadIdx.x + i * 256;
        int m = idx / 96;
        int k = idx - m * 96;
        float v = 0.f;
        if (m0 + m < M) v = W[(size_t)(m0 + m) * 96 + k] * wls[k];
        Apk[tile * 9216 + a_pack_off(m, k)] = f2tf(v);
    }
    if (threadIdx.x < 96) {
        int gm = m0 + threadIdx.x;
        float s = 0.f, tt = 0.f;
        if (gm < M) {
            for (int k = 0; k < 96; k++) {
                float w = W[(size_t)gm * 96 + k];
                s  += w * wls[k];
                tt += w * bls[k];
            }
        }
        svec[tile * 96 + threadIdx.x] = s;
        tvec[tile * 96 + threadIdx.x] = tt;
    }
}

// ---------------------------------------------------------------------------
// K=96 pipelined tf32 GEMM with factored-LN epilogue:
//   Y[m,n] = inv[n]*acc[m,n] - mu[n]*inv[n]*s[m] + t[m],  acc = Apk @ X
// BM=96, BN=128. A prepacked (cp.async once). B raw fp32 (HW tf32 truncation),
// cp.async, BK=32 double-buffered ring. 256 thr, 8 warps, 48x32 warp tile.
// ---------------------------------------------------------------------------
__device__ __forceinline__ void g96_chunk(
        float acc[3][4][4], const uint32_t* __restrict__ As,
        const uint32_t* __restrict__ Bbuf,
        int kc, int g, int t, int wmi, int wn) {
#pragma unroll
    for (int ks2 = 0; ks2 < 4; ks2++) {
        const uint32_t* Ab = As + (kc * 4 + ks2) * 768 + g * 16 + t * 4;
        const uint32_t* Bb = Bbuf + (ks2 * 8 + t) * 136 + wn + g;
        uint4 a4[3];
        uint32_t bf[4][2];
#pragma unroll
        for (int mi = 0; mi < 3; mi++)
            a4[mi] = *reinterpret_cast<const uint4*>(Ab + (wmi + mi) * 128);
#pragma unroll
        for (int ni = 0; ni < 4; ni++) {
            bf[ni][0] = Bb[ni * 8];
            bf[ni][1] = Bb[4 * 136 + ni * 8];
        }
#pragma unroll
        for (int mi = 0; mi < 3; mi++) {
            uint32_t af[4] = {a4[mi].x, a4[mi].y, a4[mi].z, a4[mi].w};
#pragma unroll
            for (int ni = 0; ni < 4; ni++)
                mma_tf32(acc[mi][ni], af, bf[ni]);
        }
    }
}

__global__ void __launch_bounds__(256, 3) gemm96(
        const uint32_t* __restrict__ Apk,
        const float* __restrict__ svec,
        const float* __restrict__ tvec,
        const float* __restrict__ X,
        float* __restrict__ Y,
        const float2* __restrict__ stats,
        int M, size_t xBatch, size_t yBatch) {
    extern __shared__ uint32_t sm[];
    uint32_t* As = sm;                       // 9216 packed words
    uint32_t* Bs = sm + 9216;                // 2 * 32 * 136
    float* mu_s  = (float*)(sm + 9216 + 8704); // 128
    float* inv_s = mu_s + 128;

    int bz = blockIdx.z;
    const float* Xb = X + (size_t)bz * xBatch;
    float*       Yb = Y + (size_t)bz * yBatch;

    int mtile = blockIdx.x;
    int m0 = mtile * 96;
    int n0 = blockIdx.y * 128;
    int tid  = threadIdx.x;
    int warp = tid >> 5;
    int lane = tid & 31;
    int g = lane >> 2;
    int t = lane & 3;
    int wm  = (warp >> 2) * 48;
    int wmi = (warp >> 2) * 3;
    int wn  = (warp & 3) * 32;

    // stats -> smem (visible after the first barrier)
    if (tid < 128) {
        float2 s = stats[(size_t)bz * HW + n0 + tid];
        mu_s[tid]  = s.x;
        inv_s[tid] = s.y;
    }

    // ---- A (prepacked, 2304 uint4) + B chunk0 -> group0; B chunk1 -> group1
    {
        const uint4* Ag = reinterpret_cast<const uint4*>(Apk + (size_t)mtile * 9216);
#pragma unroll
        for (int i = 0; i < 9; i++) {
            int idx = tid + i * 256;
            cp16(As + idx * 4, Ag + idx);
        }
    }
#pragma unroll
    for (int j = 0; j < 4; j++) {                 // B chunk 0 -> buf0
        int idx = tid + j * 256;
        int k = idx >> 5, n4 = idx & 31;
        cp16(Bs + k * 136 + n4 * 4, Xb + (size_t)k * HW + n0 + n4 * 4);
    }
    CP_COMMIT();
#pragma unroll
    for (int j = 0; j < 4; j++) {                 // B chunk 1 -> buf1
        int idx = tid + j * 256;
        int k = idx >> 5, n4 = idx & 31;
        cp16(Bs + 4352 + k * 136 + n4 * 4, Xb + (size_t)(32 + k) * HW + n0 + n4 * 4);
    }
    CP_COMMIT();

    float acc[3][4][4];
#pragma unroll
    for (int mi = 0; mi < 3; mi++)
#pragma unroll
        for (int ni = 0; ni < 4; ni++)
#pragma unroll
            for (int r = 0; r < 4; r++) acc[mi][ni][r] = 0.f;

    // kc = 0
    CP_WAIT(1);
    __syncthreads();
    g96_chunk(acc, As, Bs, 0, g, t, wmi, wn);
    __syncthreads();
#pragma unroll
    for (int j = 0; j < 4; j++) {                 // B chunk 2 -> buf0
        int idx = tid + j * 256;
        int k = idx >> 5, n4 = idx & 31;
        cp16(Bs + k * 136 + n4 * 4, Xb + (size_t)(64 + k) * HW + n0 + n4 * 4);
    }
    CP_COMMIT();
    // kc = 1
    CP_WAIT(1);
    __syncthreads();
    g96_chunk(acc, As, Bs + 4352, 1, g, t, wmi, wn);
    // kc = 2
    CP_WAIT(0);
    __syncthreads();
    g96_chunk(acc, As, Bs, 2, g, t, wmi, wn);

    // ---- epilogue: factored LayerNorm ----
#pragma unroll
    for (int mi = 0; mi < 3; mi++) {
        int r0 = m0 + wm + mi * 16 + g;
        int r1 = r0 + 8;
        float s0 = 0.f, t0 = 0.f, s1 = 0.f, t1 = 0.f;
        if (r0 < M) { s0 = svec[r0]; t0 = tvec[r0]; }
        if (r1 < M) { s1 = svec[r1]; t1 = tvec[r1]; }
#pragma unroll
        for (int ni = 0; ni < 4; ni++) {
            int ln = wn + ni * 8 + 2 * t;
            int col = n0 + ln;
            float i0 = inv_s[ln],     m0v = mu_s[ln]     * i0;
            float i1 = inv_s[ln + 1], m1v = mu_s[ln + 1] * i1;
            if (r0 < M) {
                float2 v;
                v.x = acc[mi][ni][0] * i0 - m0v * s0 + t0;
                v.y = acc[mi][ni][1] * i1 - m1v * s0 + t0;
                *reinterpret_cast<float2*>(Yb + (size_t)r0 * HW + col) = v;
            }
            if (r1 < M) {
                float2 v;
                v.x = acc[mi][ni][2] * i0 - m0v * s1 + t1;
                v.y = acc[mi][ni][3] * i1 - m1v * s1 + t1;
                *reinterpret_cast<float2*>(Yb + (size_t)r1 * HW + col) = v;
            }
        }
    }
}

// ---------------------------------------------------------------------------
// Generic tf32 GEMM (used for pout, K=255): Y = W@X (+res). As in R4.
// ---------------------------------------------------------------------------
template <int RES>
__global__ void __launch_bounds__(256, 2) gemm_tc(
        const float* __restrict__ Wt,
        const float* __restrict__ X,
        const float* __restrict__ Rsrc,
        float* __restrict__ Y,
        int M, int K,
        size_t xBatch, size_t yBatch, size_t rBatch) {
    extern __shared__ uint32_t smem_u[];
    uint32_t* As  = smem_u;
    uint32_t* Bs  = As + 9216;

    int bz = blockIdx.z;
    const float* Xb = X + (size_t)bz * xBatch;
    float*       Yb = Y + (size_t)bz * yBatch;
    const float* Rb = RES ? (Rsrc + (size_t)bz * rBatch) : nullptr;

    int m0 = blockIdx.x * 96;
    int n0 = blockIdx.y * 128;
    int tid  = threadIdx.x;
    int warp = tid >> 5;
    int lane = tid & 31;
    int g = lane >> 2;
    int t = lane & 3;
    int wm  = (warp >> 2) * 48;
    int wmi = (warp >> 2) * 3;
    int wn  = (warp & 3) * 32;

    float acc[3][4][4];
#pragma unroll
    for (int mi = 0; mi < 3; mi++)
#pragma unroll
        for (int ni = 0; ni < 4; ni++)
#pragma unroll
            for (int r = 0; r < 4; r++) acc[mi][ni][r] = 0.f;

    int nstages = (K + 95) / 96;
    for (int s = 0; s < nstages; s++) {
        int k0 = s * 96;
#pragma unroll
        for (int i = 0; i < 36; i++) {
            int idx = tid + i * 256;
            int m = idx / 96;
            int k = idx - m * 96;
            float v = 0.f;
            if (m0 + m < M && k0 + k < K) v = Wt[(size_t)(m0 + m) * K + k0 + k];
            As[a_pack_off(m, k)] = f2tf(v);
        }
#pragma unroll
        for (int i = 0; i < 12; i++) {
            int idx = tid + i * 256;
            int k  = idx >> 5;
            int n4 = idx & 31;
            float4 v = make_float4(0.f, 0.f, 0.f, 0.f);
            if (k0 + k < K)
                v = reinterpret_cast<const float4*>(Xb + (size_t)(k0 + k) * HW + n0)[n4];
            uint4 u = make_uint4(__float_as_uint(v.x), __float_as_uint(v.y),
                                 __float_as_uint(v.z), __float_as_uint(v.w));
            *reinterpret_cast<uint4*>(Bs + k * 136 + n4 * 4) = u;
        }
        __syncthreads();
#pragma unroll
        for (int ks = 0; ks < 12; ks++) {
            const uint32_t* Ab = As + ks * 768 + g * 16 + t * 4;
            const uint32_t* Bb = Bs + (ks * 8 + t) * 136 + wn + g;
            uint4 a4[3];
            uint32_t bf[4][2];
#pragma unroll
            for (int mi = 0; mi < 3; mi++)
                a4[mi] = *reinterpret_cast<const uint4*>(Ab + (wmi + mi) * 128);
#pragma unroll
            for (int ni = 0; ni < 4; ni++) {
                bf[ni][0] = Bb[ni * 8];
                bf[ni][1] = Bb[4 * 136 + ni * 8];
            }
#pragma unroll
            for (int mi = 0; mi < 3; mi++) {
                uint32_t af[4] = {a4[mi].x, a4[mi].y, a4[mi].z, a4[mi].w};
#pragma unroll
                for (int ni = 0; ni < 4; ni++)
                    mma_tf32(acc[mi][ni], af, bf[ni]);
            }
        }
        __syncthreads();
    }

#pragma unroll
    for (int mi = 0; mi < 3; mi++) {
        int r0 = m0 + wm + mi * 16 + g;
        int r1 = r0 + 8;
#pragma unroll
        for (int ni = 0; ni < 4; ni++) {
            int col = n0 + wn + ni * 8 + 2 * t;
            float2 v01 = make_float2(acc[mi][ni][0], acc[mi][ni][1]);
            float2 v23 = make_float2(acc[mi][ni][2], acc[mi][ni][3]);
            if (RES) {
                if (r0 < M) {
                    float2 r = *reinterpret_cast<const float2*>(Rb + (size_t)r0 * HW + col);
                    v01.x += r.x; v01.y += r.y;
                }
                if (r1 < M) {
                    float2 r = *reinterpret_cast<const float2*>(Rb + (size_t)r1 * HW + col);
                    v23.x += r.x; v23.y += r.y;
                }
            }
            if (r0 < M)
                *reinterpret_cast<float2*>(Yb + (size_t)r0 * HW + col) = v01;
            if (r1 < M)
                *reinterpret_cast<float2*>(Yb + (size_t)r1 * HW + col) = v23;
        }
    }
}

// ---------------------------------------------------------------------------
// 4-source fused GEMM for x1 (unchanged from R4).
// ---------------------------------------------------------------------------
struct G4 {
    const float* W[4];
    int          wStride[4];
    size_t       wBatch[4];
    const float* X[4];
    size_t       xBatch[4];
    const float* stats[4];
};

__global__ void __launch_bounds__(256, 2) gemm4_tc(
        G4 p,
        const float* __restrict__ lnw,
        const float* __restrict__ lnb,
        const float* __restrict__ Rsrc,
        float* __restrict__ Y) {
    extern __shared__ uint32_t smem_u[];
    uint32_t* As  = smem_u;
    uint32_t* Bs  = As + 9216;
    float* mu_s   = (float*)(Bs + 96 * 136);
    float* inv_s  = mu_s + 128;
    float* wln_s  = inv_s + 128;
    float* bln_s  = wln_s + 96;

    int bz = blockIdx.z;
    int n0 = blockIdx.y * 128;
    float*       Yb = Y    + (size_t)bz * CDIM * HW;
    const float* Rb = Rsrc + (size_t)bz * CDIM * HW;

    int tid  = threadIdx.x;
    int warp = tid >> 5;
    int lane = tid & 31;
    int g = lane >> 2;
    int t = lane & 3;
    int wm  = (warp >> 2) * 48;
    int wmi = (warp >> 2) * 3;
    int wn  = (warp & 3) * 32;

    if (tid < 96) { wln_s[tid] = lnw[tid]; bln_s[tid] = lnb[tid]; }

    float acc[3][4][4];
#pragma unroll
    for (int mi = 0; mi < 3; mi++)
#pragma unroll
        for (int ni = 0; ni < 4; ni++)
#pragma unroll
            for (int r = 0; r < 4; r++) acc[mi][ni][r] = 0.f;

    for (int s = 0; s < 4; s++) {
        __syncthreads();
        const float* Wp = p.W[s] + (size_t)bz * p.wBatch[s];
        const float* Xb = p.X[s] + (size_t)bz * p.xBatch[s];
        int wstr = p.wStride[s];
        bool ln = (p.stats[s] != nullptr);
        if (ln && tid < 128) {
            float2 sv = reinterpret_cast<const float2*>(p.stats[s])[(size_t)bz * HW + n0 + tid];
            mu_s[tid]  = sv.x;
            inv_s[tid] = sv.y;
        }
#pragma unroll
        for (int i = 0; i < 36; i++) {
            int idx = tid + i * 256;
            int m = idx / 96;
            int k = idx - m * 96;
            As[a_pack_off(m, k)] = f2tf(Wp[(size_t)m * wstr + k]);
        }
        if (ln) __syncthreads();
#pragma unroll
        for (int i = 0; i < 12; i++) {
            int idx = tid + i * 256;
            int k  = idx >> 5;
            int n4 = idx & 31;
            float4 v = reinterpret_cast<const float4*>(Xb + (size_t)k * HW + n0)[n4];
            if (ln) {
                int nb = n4 * 4;
                float wk = wln_s[k], bk = bln_s[k];
                v.x = (v.x - mu_s[nb + 0]) * inv_s[nb + 0] * wk + bk;
                v.y = (v.y - mu_s[nb + 1]) * inv_s[nb + 1] * wk + bk;
                v.z = (v.z - mu_s[nb + 2]) * inv_s[nb + 2] * wk + bk;
                v.w = (v.w - mu_s[nb + 3]) * inv_s[nb + 3] * wk + bk;
            }
            uint4 u = make_uint4(__float_as_uint(v.x), __float_as_uint(v.y),
                                 __float_as_uint(v.z), __float_as_uint(v.w));
            *reinterpret_cast<uint4*>(Bs + k * 136 + n4 * 4) = u;
        }
        __syncthreads();
#pragma unroll
        for (int ks = 0; ks < 12; ks++) {
            const uint32_t* Ab = As + ks * 768 + g * 16 + t * 4;
            const uint32_t* Bb = Bs + (ks * 8 + t) * 136 + wn + g;
            uint4 a4[3];
            uint32_t bf[4][2];
#pragma unroll
            for (int mi = 0; mi < 3; mi++)
                a4[mi] = *reinterpret_cast<const uint4*>(Ab + (wmi + mi) * 128);
#pragma unroll
            for (int ni = 0; ni < 4; ni++) {
                bf[ni][0] = Bb[ni * 8];
                bf[ni][1] = Bb[4 * 136 + ni * 8];
            }
#pragma unroll
            for (int mi = 0; mi < 3; mi++) {
                uint32_t af[4] = {a4[mi].x, a4[mi].y, a4[mi].z, a4[mi].w};
#pragma unroll
                for (int ni = 0; ni < 4; ni++)
                    mma_tf32(acc[mi][ni], af, bf[ni]);
            }
        }
    }

#pragma unroll
    for (int mi = 0; mi < 3; mi++) {
        int r0 = wm + mi * 16 + g;
        int r1 = r0 + 8;
#pragma unroll
        for (int ni = 0; ni < 4; ni++) {
            int col = n0 + wn + ni * 8 + 2 * t;
            float2 ra = *reinterpret_cast<const float2*>(Rb + (size_t)r0 * HW + col);
            float2 rb = *reinterpret_cast<const float2*>(Rb + (size_t)r1 * HW + col);
            float2 v01 = make_float2(acc[mi][ni][0] + ra.x, acc[mi][ni][1] + ra.y);
            float2 v23 = make_float2(acc[mi][ni][2] + rb.x, acc[mi][ni][3] + rb.y);
            *reinterpret_cast<float2*>(Yb + (size_t)r0 * HW + col) = v01;
            *reinterpret_cast<float2*>(Yb + (size_t)r1 * HW + col) = v23;
        }
    }
}

// ---------------------------------------------------------------------------
// Depthwise 3x3, SAME zero padding.
// ---------------------------------------------------------------------------
__global__ void dw3_kernel(const float* __restrict__ in,
                           const float* __restrict__ w,
                           float* __restrict__ out, int C) {
    int pl = blockIdx.z;
    int c  = pl % C;
    int x  = blockIdx.x * 32 + threadIdx.x;
    int y  = blockIdx.y * 8  + threadIdx.y;
    const float* ip = in + (size_t)pl * HW;
    const float* wp = w + c * 9;
    float s = 0.f;
#pragma unroll
    for (int dy = -1; dy <= 1; dy++) {
        int yy = y + dy;
        if (yy < 0 || yy >= IMG) continue;
#pragma unroll
        for (int dx = -1; dx <= 1; dx++) {
            int xx = x + dx;
            if (xx < 0 || xx >= IMG) continue;
            s += wp[(dy + 1) * 3 + (dx + 1)] * ip[yy * IMG + xx];
        }
    }
    out[(size_t)pl * HW + y * IMG + x] = s;
}

// ---------------------------------------------------------------------------
// Fused FFN tail: dw3 on both halves + exact gelu + multiply.
// ---------------------------------------------------------------------------
__global__ void dwgate_kernel(const float* __restrict__ t,
                              const float* __restrict__ dwf,
                              float* __restrict__ gate) {
    int pl = blockIdx.z;
    int b = pl / HIDDEN, k = pl % HIDDEN;
    int x = blockIdx.x * 32 + threadIdx.x;
    int y = blockIdx.y * 8  + threadIdx.y;
    const float* i1 = t + ((size_t)b * 2 * HIDDEN + k) * HW;
    const float* i2 = t + ((size_t)b * 2 * HIDDEN + HIDDEN + k) * HW;
    const float* w1 = dwf + k * 9;
    const float* w2 = dwf + (HIDDEN + k) * 9;
    float s1 = 0.f, s2 = 0.f;
#pragma unroll
    for (int dy = -1; dy <= 1; dy++) {
        int yy = y + dy;
        if (yy < 0 || yy >= IMG) continue;
#pragma unroll
        for (int dx = -1; dx <= 1; dx++) {
            int xx = x + dx;
            if (xx < 0 || xx >= IMG) continue;
            int o = yy * IMG + xx, wi = (dy + 1) * 3 + (dx + 1);
            s1 += w1[wi] * i1[o];
            s2 += w2[wi] * i2[o];
        }
    }
    float gl = 0.5f * s1 * (1.f + erff(s1 * 0.7071067811865475f));
    gate[((size_t)b * HIDDEN + k) * HW + y * IMG + x] = gl * s2;
}

// ---------------------------------------------------------------------------
// Gram stage 1 + fused row-norm partials; warp-level reduce.
// ---------------------------------------------------------------------------
__global__ void __launch_bounds__(256) gram1_kernel(
        const float* __restrict__ Q, const float* __restrict__ Kp,
        float* __restrict__ part) {
    int chunk = blockIdx.x, h = blockIdx.y, b = blockIdx.z;
    const float* qb = Q  + ((size_t)b * 288 + h * CHEAD) * HW;
    const float* kb = Kp + ((size_t)b * 288 + h * CHEAD) * HW;

    float acc[168];
#pragma unroll
    for (int i = 0; i < 168; i++) acc[i] = 0.f;

    int p0 = chunk * 2048 + threadIdx.x;
    for (int it = 0; it < 8; it++) {
        int p = p0 + it * 256;
        float qv[CHEAD], kv[CHEAD];
#pragma unroll
        for (int c = 0; c < CHEAD; c++) qv[c] = qb[(size_t)c * HW + p];
#pragma unroll
        for (int d = 0; d < CHEAD; d++) kv[d] = kb[(size_t)d * HW + p];
#pragma unroll
        for (int c = 0; c < CHEAD; c++)
#pragma unroll
            for (int d = 0; d < CHEAD; d++) acc[c * CHEAD + d] += qv[c] * kv[d];
#pragma unroll
        for (int c = 0; c < CHEAD; c++) acc[144 + c] += qv[c] * qv[c];
#pragma unroll
        for (int d = 0; d < CHEAD; d++) acc[156 + d] += kv[d] * kv[d];
    }

    int warp = threadIdx.x >> 5;
    int lane = threadIdx.x & 31;
    float* outp = part + ((((size_t)(b * HEADS + h)) * 32 + chunk) * 8 + warp) * 168;
#pragma unroll
    for (int i = 0; i < 168; i++) {
        float v = acc[i];
#pragma unroll
        for (int off = 16; off > 0; off >>= 1)
            v += __shfl_down_sync(0xffffffffu, v, off);
        if (lane == 0) outp[i] = v;
    }
}

// ---------------------------------------------------------------------------
// Gram stage 2 + norms + temperature + softmax.
// ---------------------------------------------------------------------------
__global__ void attn_kernel(const float* __restrict__ partA,
                            const float* __restrict__ partB,
                            const float* __restrict__ temp,
                            float* __restrict__ attnA,
                            float* __restrict__ attnB) {
    int bh = blockIdx.x;
    int h = bh % HEADS;
    __shared__ float GA[144], GB[144];
    __shared__ float nqA[12], nkA[12], nqB[12], nkB[12];
    int i = threadIdx.x;
    float sA = 0.f, sB = 0.f;
    if (i < 168) {
        const float* pA = partA + (size_t)bh * 256 * 168 + i;
        const float* pB = partB + (size_t)bh * 256 * 168 + i;
        for (int ch = 0; ch < 256; ch++) {
            sA += pA[(size_t)ch * 168];
            sB += pB[(size_t)ch * 168];
        }
        if (i >= 156) {
            nkA[i - 156] = fmaxf(sqrtf(sA), 1e-12f);
            nkB[i - 156] = fmaxf(sqrtf(sB), 1e-12f);
        } else if (i >= 144) {
            nqA[i - 144] = fmaxf(sqrtf(sA), 1e-12f);
            nqB[i - 144] = fmaxf(sqrtf(sB), 1e-12f);
        }
    }
    __syncthreads();
    if (i < 144) {
        int c = i / CHEAD, d = i % CHEAD;
        float tp = temp[h];
        GA[i] =  sA / (nqA[c] * nkA[d]) * tp;
        GB[i] = -sB / (nqB[c] * nkB[d]) * tp;
    }
    __syncthreads();
    if (i < 24) {
        float* G = (i < CHEAD) ? GA : GB;
        float* O = (i < CHEAD) ? attnA : attnB;
        int c = i % CHEAD;
        float mx = -1e30f;
        for (int d = 0; d < CHEAD; d++) mx = fmaxf(mx, G[c * CHEAD + d]);
        float e[CHEAD];
        float s = 0.f;
        for (int d = 0; d < CHEAD; d++) {
            e[d] = expf(G[c * CHEAD + d] - mx);
            s += e[d];
        }
        float inv = 1.f / s;
        for (int d = 0; d < CHEAD; d++)
            O[(size_t)bh * 144 + c * CHEAD + d] = e[d] * inv;
    }
}

// ---------------------------------------------------------------------------
// P0 = concat_w[:, :96] @ projA_w; P1 = concat_w[:, 96:] @ projB_w
// ---------------------------------------------------------------------------
__global__ void wprod_kernel(const float* __restrict__ concat_w,
                             const float* __restrict__ projA,
                             const float* __restrict__ projB,
                             float* __restrict__ P0,
                             float* __restrict__ P1) {
    int br = blockIdx.x;
    const float* proj = br ? projB : projA;
    const float* cw   = concat_w + (br ? 96 : 0);
    float* P = br ? P1 : P0;
    __shared__ float pj[96 * 96];
    for (int i = threadIdx.x; i < 96 * 96; i += blockDim.x) pj[i] = proj[i];
    __syncthreads();
    for (int o = threadIdx.x; o < 96 * 96; o += blockDim.x) {
        int m = o / 96, n = o % 96;
        float s = 0.f;
#pragma unroll 8
        for (int c = 0; c < 96; c++) s += cw[m * 192 + c] * pj[c * 96 + n];
        P[o] = s;
    }
}

// ---------------------------------------------------------------------------
// cw[b] = P @ blockdiag(attn[b])
// ---------------------------------------------------------------------------
__global__ void cw_kernel(const float* __restrict__ P0,
                          const float* __restrict__ P1,
                          const float* __restrict__ atA,
                          const float* __restrict__ atB,
                          float* __restrict__ cwA,
                          float* __restrict__ cwB) {
    int b  = blockIdx.x >> 1;
    int br = blockIdx.x & 1;
    const float* P  = br ? P1 : P0;
    const float* at = (br ? atB : atA) + (size_t)b * HEADS * 144;
    float* out = (br ? cwB : cwA) + (size_t)b * 96 * 96;
    __shared__ float a_s[HEADS * 144];
    for (int i = threadIdx.x; i < HEADS * 144; i += blockDim.x) a_s[i] = at[i];
    __syncthreads();
    for (int o = threadIdx.x; o < 96 * 96; o += blockDim.x) {
        int m = o / 96, n = o % 96;
        int h = n / CHEAD, d = n % CHEAD;
        float s = 0.f;
#pragma unroll
        for (int c = 0; c < CHEAD; c++)
            s += P[m * 96 + h * CHEAD + c] * a_s[h * 144 + c * CHEAD + d];
        out[o] = s;
    }
}

// ---------------------------------------------------------------------------
// Launch
// ---------------------------------------------------------------------------
extern "C" void kernel_launch(void* const* d_in, const int* in_sizes, int n_in,
                              void* d_out, int out_size) {
    const float* x       = (const float*)d_in[0];
    const float* y       = (const float*)d_in[1];
    const float* ln1_w   = (const float*)d_in[2];
    const float* ln1_b   = (const float*)d_in[3];
    const float* ln2_w   = (const float*)d_in[4];
    const float* ln2_b   = (const float*)d_in[5];
    const float* qkvA_w  = (const float*)d_in[6];
    const float* dwA_w   = (const float*)d_in[7];
    const float* qkvB_w  = (const float*)d_in[8];
    const float* dwB_w   = (const float*)d_in[9];
    const float* projA_w = (const float*)d_in[10];
    const float* projB_w = (const float*)d_in[11];
    const float* concat_w= (const float*)d_in[12];
    const float* temp    = (const float*)d_in[13];
    const float* pin_w   = (const float*)d_in[14];
    const float* dwf_w   = (const float*)d_in[15];
    const float* pout_w  = (const float*)d_in[16];
    float* out = (float*)d_out;

    cudaFuncSetAttribute(gemm96,      cudaFuncAttributeMaxDynamicSharedMemorySize, G96_SMEM_BYTES);
    cudaFuncSetAttribute(gemm_tc<1>,  cudaFuncAttributeMaxDynamicSharedMemorySize, GEMM_SMEM_BYTES);
    cudaFuncSetAttribute(gemm4_tc,    cudaFuncAttributeMaxDynamicSharedMemorySize, GEMM_SMEM_BYTES);

    float *qkvA, *qkvAd, *qkvB, *qkvBd, *x1, *t, *gate;
    float *stsX, *stsY, *stsX1, *gpA, *gpB, *atA, *atB, *P0, *P1, *cwA, *cwB;
    uint32_t *prepQA, *prepQB, *prepPin;
    float *sQA, *tQA, *sQB, *tQB, *sPin, *tPin;
    cudaGetSymbolAddress((void**)&qkvA,   g_qkvA);
    cudaGetSymbolAddress((void**)&qkvAd,  g_qkvAd);
    cudaGetSymbolAddress((void**)&qkvB,   g_qkvB);
    cudaGetSymbolAddress((void**)&qkvBd,  g_qkvBd);
    cudaGetSymbolAddress((void**)&x1,     g_x1);
    cudaGetSymbolAddress((void**)&t,      g_t);
    cudaGetSymbolAddress((void**)&gate,   g_gate);
    cudaGetSymbolAddress((void**)&stsX,   g_stsX);
    cudaGetSymbolAddress((void**)&stsY,   g_stsY);
    cudaGetSymbolAddress((void**)&stsX1,  g_stsX1);
    cudaGetSymbolAddress((void**)&gpA,    g_gpartA);
    cudaGetSymbolAddress((void**)&gpB,    g_gpartB);
    cudaGetSymbolAddress((void**)&atA,    g_attnA);
    cudaGetSymbolAddress((void**)&atB,    g_attnB);
    cudaGetSymbolAddress((void**)&P0,     g_P0);
    cudaGetSymbolAddress((void**)&P1,     g_P1);
    cudaGetSymbolAddress((void**)&cwA,    g_cwA);
    cudaGetSymbolAddress((void**)&cwB,    g_cwB);
    cudaGetSymbolAddress((void**)&prepQA, g_prepQA);
    cudaGetSymbolAddress((void**)&prepQB, g_prepQB);
    cudaGetSymbolAddress((void**)&prepPin,g_prepPin);
    cudaGetSymbolAddress((void**)&sQA,    g_sQA);
    cudaGetSymbolAddress((void**)&tQA,    g_tQA);
    cudaGetSymbolAddress((void**)&sQB,    g_sQB);
    cudaGetSymbolAddress((void**)&tQB,    g_tQB);
    cudaGetSymbolAddress((void**)&sPin,   g_sPin);
    cudaGetSymbolAddress((void**)&tPin,   g_tPin);

    const size_t P96  = (size_t)CDIM * HW;
    const size_t P288 = 3 * P96;
    const size_t P510 = (size_t)2 * HIDDEN * HW;
    const size_t P255 = (size_t)HIDDEN * HW;

    // weight prep (tiny)
    prep_kernel<<<3, 256>>>(qkvA_w, 288, ln1_w, ln1_b, prepQA, sQA, tQA);
    prep_kernel<<<3, 256>>>(qkvB_w, 288, ln1_w, ln1_b, prepQB, sQB, tQB);
    prep_kernel<<<6, 256>>>(pin_w,  510, ln2_w, ln2_b, prepPin, sPin, tPin);
    wprod_kernel<<<2, 256>>>(concat_w, projA_w, projB_w, P0, P1);

    dim3 sGrid(HW / 256, BATCH);
    stats_kernel<<<sGrid, 256>>>(x, (float2*)stsX);
    stats_kernel<<<sGrid, 256>>>(y, (float2*)stsY);

    // qkv = W@LN(x) via factored-LN pipelined GEMM
    {
        dim3 g(3, HW / 128, BATCH);
        gemm96<<<g, 256, G96_SMEM_BYTES>>>(prepQA, sQA, tQA, x, qkvA,
                                           (const float2*)stsX, 288, P96, P288);
        gemm96<<<g, 256, G96_SMEM_BYTES>>>(prepQB, sQB, tQB, y, qkvB,
                                           (const float2*)stsY, 288, P96, P288);
    }

    // depthwise 3x3
    {
        dim3 blk(32, 8), g(IMG / 32, IMG / 8, BATCH * 288);
        dw3_kernel<<<g, blk>>>(qkvA, dwA_w, qkvAd, 288);
        dw3_kernel<<<g, blk>>>(qkvB, dwB_w, qkvBd, 288);
    }

    // Gram + fused norms
    {
        dim3 g(32, HEADS, BATCH);
        gram1_kernel<<<g, 256>>>(qkvBd, qkvAd + 96 * (size_t)HW, gpA);
        gram1_kernel<<<g, 256>>>(qkvAd, qkvBd + 96 * (size_t)HW, gpB);
    }

    attn_kernel<<<BATCH * HEADS, 192>>>(gpA, gpB, temp, atA, atB);
    cw_kernel<<<4, 256>>>(P0, P1, atA, atB, cwA, cwB);

    // fused x1 = x + cwA@vA + cwB@vB + concat0@LN(x) + concat1@LN(y)
    {
        G4 p;
        p.W[0] = cwA;           p.wStride[0] = 96;  p.wBatch[0] = 96 * 96;
        p.W[1] = cwB;           p.wStride[1] = 96;  p.wBatch[1] = 96 * 96;
        p.W[2] = concat_w;      p.wStride[2] = 192; p.wBatch[2] = 0;
        p.W[3] = concat_w + 96; p.wStride[3] = 192; p.wBatch[3] = 0;
        p.X[0] = qkvAd + 192 * (size_t)HW; p.xBatch[0] = P288; p.stats[0] = nullptr;
        p.X[1] = qkvBd + 192 * (size_t)HW; p.xBatch[1] = P288; p.stats[1] = nullptr;
        p.X[2] = x;                        p.xBatch[2] = P96;  p.stats[2] = stsX;
        p.X[3] = y;                        p.xBatch[3] = P96;  p.stats[3] = stsY;
        dim3 g(1, HW / 128, BATCH);
        gemm4_tc<<<g, 256, GEMM_SMEM_BYTES>>>(p, ln1_w, ln1_b, x, x1);
    }

    stats_kernel<<<sGrid, 256>>>(x1, (float2*)stsX1);

    // pin = W@LN2(x1) via factored-LN pipelined GEMM (M=510)
    {
        dim3 g(6, HW / 128, BATCH);
        gemm96<<<g, 256, G96_SMEM_BYTES>>>(prepPin, sPin, tPin, x1, t,
                                           (const float2*)stsX1, 510, P96, P510);
    }

    // fused depthwise + gelu gate
    {
        dim3 blk(32, 8), g(IMG / 32, IMG / 8, BATCH * HIDDEN);
        dwgate_kernel<<<g, blk>>>(t, dwf_w, gate);
    }

    // pout conv1x1 + residual x1 -> final output
    {
        dim3 g(1, HW / 128, BATCH);
        gemm_tc<1><<<g, 256, GEMM_SMEM_BYTES>>>(pout_w, gate, x1, out,
                                                96, 255, P255, P96, P96);
    }
}

// round 6
// speedup vs baseline: 2.7812x; 1.1295x over previous
#include <cuda_runtime.h>
#include <math.h>
#include <stdint.h>

#define HW      65536
#define IMG     256
#define BATCH   2
#define CDIM    96
#define HEADS   8
#define CHEAD   12
#define HIDDEN  255

// ---------------------------------------------------------------------------
// Scratch
// ---------------------------------------------------------------------------
__device__ float g_qkvA [BATCH * 3 * CDIM * HW];
__device__ float g_qkvAd[BATCH * 3 * CDIM * HW];
__device__ float g_qkvB [BATCH * 3 * CDIM * HW];
__device__ float g_qkvBd[BATCH * 3 * CDIM * HW];
__device__ float g_x1   [BATCH * CDIM * HW];
__device__ float g_t    [BATCH * 2 * HIDDEN * HW];
__device__ float g_gate [BATCH * 288 * HW];      // 288-row pitch; rows 255..287 stay zero
__device__ float g_stsX [BATCH * HW * 2];
__device__ float g_stsY [BATCH * HW * 2];
__device__ float g_stsX1[BATCH * HW * 2];
__device__ float g_gpartA[BATCH * HEADS * 256 * 168];
__device__ float g_gpartB[BATCH * HEADS * 256 * 168];
__device__ float g_attnA [BATCH * HEADS * 144];
__device__ float g_attnB [BATCH * HEADS * 144];
__device__ float g_P0  [CDIM * CDIM];
__device__ float g_P1  [CDIM * CDIM];
// prepacked tf32 fragment tiles
__device__ uint32_t g_prepQA  [3 * 9216];
__device__ uint32_t g_prepQB  [3 * 9216];
__device__ uint32_t g_prepPin [6 * 9216];
__device__ uint32_t g_prepPout[3 * 9216];
__device__ uint32_t g_prepC0  [9216];
__device__ uint32_t g_prepC1  [9216];
__device__ uint32_t g_cwApk   [BATCH * 9216];
__device__ uint32_t g_cwBpk   [BATCH * 9216];
__device__ float g_sQA[288],  g_tQA[288];
__device__ float g_sQB[288],  g_tQB[288];
__device__ float g_sPin[576], g_tPin[576];

// ---------------------------------------------------------------------------
// tf32 / cp.async helpers
// ---------------------------------------------------------------------------
__device__ __forceinline__ uint32_t f2tf(float f) {
    uint32_t u;
    asm("cvt.rna.tf32.f32 %0, %1;" : "=r"(u) : "f"(f));
    return u;
}

__device__ __forceinline__ void mma_tf32(float* c, const uint32_t* a, const uint32_t* b) {
    asm volatile(
        "mma.sync.aligned.m16n8k8.row.col.f32.tf32.tf32.f32 "
        "{%0,%1,%2,%3}, {%4,%5,%6,%7}, {%8,%9}, {%0,%1,%2,%3};"
        : "+f"(c[0]), "+f"(c[1]), "+f"(c[2]), "+f"(c[3])
        : "r"(a[0]), "r"(a[1]), "r"(a[2]), "r"(a[3]), "r"(b[0]), "r"(b[1]));
}

__device__ __forceinline__ void cp16(void* smem, const void* gmem) {
    uint32_t a = (uint32_t)__cvta_generic_to_shared(smem);
    asm volatile("cp.async.cg.shared.global [%0], [%1], 16;\n" :: "r"(a), "l"(gmem));
}
#define CP_COMMIT()  asm volatile("cp.async.commit_group;\n")
#define CP_WAIT(n)   asm volatile("cp.async.wait_group %0;\n" :: "n"(n))

// A packed-fragment smem offset for element (m 0..95, k 0..95)
__device__ __forceinline__ int a_pack_off(int m, int k) {
    return (k >> 3) * 768 + (m >> 4) * 128 + (m & 7) * 16 + (k & 3) * 4
         + ((k >> 2) & 1) * 2 + ((m >> 3) & 1);
}

#define GEMM_SMEM_WORDS (9216 + 96*136 + 128 + 128 + 96 + 96)
#define GEMM_SMEM_BYTES (GEMM_SMEM_WORDS * 4)
#define G96_SMEM_WORDS  (9216 + 2*32*136 + 256)
#define G96_SMEM_BYTES  (G96_SMEM_WORDS * 4)

// ---------------------------------------------------------------------------
// Per-pixel LayerNorm stats over C=96: (mu, inv_std).
// ---------------------------------------------------------------------------
__global__ void stats_kernel(const float* __restrict__ in,
                             float2* __restrict__ st) {
    int p = blockIdx.x * blockDim.x + threadIdx.x;
    int b = blockIdx.y;
    const float* ip = in + (size_t)b * CDIM * HW + p;
    float v[CDIM];
    float s = 0.f;
#pragma unroll
    for (int c = 0; c < CDIM; c++) { v[c] = ip[(size_t)c * HW]; s += v[c]; }
    float mu = s * (1.f / CDIM);
    float vs = 0.f;
#pragma unroll
    for (int c = 0; c < CDIM; c++) { float d = v[c] - mu; vs += d * d; }
    float inv = rsqrtf(vs * (1.f / CDIM) + 1e-5f);
    st[(size_t)b * HW + p] = make_float2(mu, inv);
}

// ---------------------------------------------------------------------------
// Prep: Apk = pack_tf32(W * diag(wln)); s = W@wln; t = W@bln.  K=96.
// ---------------------------------------------------------------------------
__global__ void prep_kernel(const float* __restrict__ W, int M,
                            const float* __restrict__ wln,
                            const float* __restrict__ bln,
                            uint32_t* __restrict__ Apk,
                            float* __restrict__ svec,
                            float* __restrict__ tvec) {
    int tile = blockIdx.x;
    int m0 = tile * 96;
    __shared__ float wls[96], bls[96];
    if (threadIdx.x < 96) { wls[threadIdx.x] = wln[threadIdx.x]; bls[threadIdx.x] = bln[threadIdx.x]; }
    __syncthreads();
#pragma unroll
    for (int i = 0; i < 36; i++) {
        int idx = threadIdx.x + i * 256;
        int m = idx / 96;
        int k = idx - m * 96;
        float v = 0.f;
        if (m0 + m < M) v = W[(size_t)(m0 + m) * 96 + k] * wls[k];
        Apk[tile * 9216 + a_pack_off(m, k)] = f2tf(v);
    }
    if (threadIdx.x < 96) {
        int gm = m0 + threadIdx.x;
        float s = 0.f, tt = 0.f;
        if (gm < M) {
            for (int k = 0; k < 96; k++) {
                float w = W[(size_t)gm * 96 + k];
                s  += w * wls[k];
                tt += w * bls[k];
            }
        }
        svec[tile * 96 + threadIdx.x] = s;
        tvec[tile * 96 + threadIdx.x] = tt;
    }
}

// ---------------------------------------------------------------------------
// Pack a 96x96 weight block (row stride ld) into tf32 packed fragments.
// ---------------------------------------------------------------------------
__global__ void pack96_kernel(const float* __restrict__ W, int ld,
                              uint32_t* __restrict__ out) {
#pragma unroll
    for (int i = 0; i < 36; i++) {
        int idx = threadIdx.x + i * 256;
        int m = idx / 96;
        int k = idx - m * 96;
        out[a_pack_off(m, k)] = f2tf(W[(size_t)m * ld + k]);
    }
}

// ---------------------------------------------------------------------------
// Pack pout_w [96 x 255] into 3 zero-padded 96x96 stages.
// ---------------------------------------------------------------------------
__global__ void prep_pout(const float* __restrict__ W,
                          uint32_t* __restrict__ Apk) {
    int s = blockIdx.x;
#pragma unroll
    for (int i = 0; i < 36; i++) {
        int idx = threadIdx.x + i * 256;
        int m = idx / 96;
        int k = idx - m * 96;
        int kg = s * 96 + k;
        float v = (kg < HIDDEN) ? W[(size_t)m * HIDDEN + kg] : 0.f;
        Apk[s * 9216 + a_pack_off(m, k)] = f2tf(v);
    }
}

// ---------------------------------------------------------------------------
// MMA chunk helper: 4 k-steps (one 32-k chunk) of m16n8k8 on the 96x128 tile.
// ---------------------------------------------------------------------------
__device__ __forceinline__ void g96_chunk(
        float acc[3][4][4], const uint32_t* __restrict__ As,
        const uint32_t* __restrict__ Bbuf,
        int kc, int g, int t, int wmi, int wn) {
#pragma unroll
    for (int ks2 = 0; ks2 < 4; ks2++) {
        const uint32_t* Ab = As + (kc * 4 + ks2) * 768 + g * 16 + t * 4;
        const uint32_t* Bb = Bbuf + (ks2 * 8 + t) * 136 + wn + g;
        uint4 a4[3];
        uint32_t bf[4][2];
#pragma unroll
        for (int mi = 0; mi < 3; mi++)
            a4[mi] = *reinterpret_cast<const uint4*>(Ab + (wmi + mi) * 128);
#pragma unroll
        for (int ni = 0; ni < 4; ni++) {
            bf[ni][0] = Bb[ni * 8];
            bf[ni][1] = Bb[4 * 136 + ni * 8];
        }
#pragma unroll
        for (int mi = 0; mi < 3; mi++) {
            uint32_t af[4] = {a4[mi].x, a4[mi].y, a4[mi].z, a4[mi].w};
#pragma unroll
            for (int ni = 0; ni < 4; ni++)
                mma_tf32(acc[mi][ni], af, bf[ni]);
        }
    }
}

// ---------------------------------------------------------------------------
// K=96 pipelined tf32 GEMM with factored-LN epilogue (qkv, pin).
// ---------------------------------------------------------------------------
__global__ void __launch_bounds__(256, 3) gemm96(
        const uint32_t* __restrict__ Apk,
        const float* __restrict__ svec,
        const float* __restrict__ tvec,
        const float* __restrict__ X,
        float* __restrict__ Y,
        const float2* __restrict__ stats,
        int M, size_t xBatch, size_t yBatch) {
    extern __shared__ uint32_t sm[];
    uint32_t* As = sm;
    uint32_t* Bs = sm + 9216;
    float* mu_s  = (float*)(sm + 9216 + 8704);
    float* inv_s = mu_s + 128;

    int bz = blockIdx.z;
    const float* Xb = X + (size_t)bz * xBatch;
    float*       Yb = Y + (size_t)bz * yBatch;

    int mtile = blockIdx.x;
    int m0 = mtile * 96;
    int n0 = blockIdx.y * 128;
    int tid  = threadIdx.x;
    int warp = tid >> 5;
    int lane = tid & 31;
    int g = lane >> 2;
    int t = lane & 3;
    int wm  = (warp >> 2) * 48;
    int wmi = (warp >> 2) * 3;
    int wn  = (warp & 3) * 32;

    if (tid < 128) {
        float2 s = stats[(size_t)bz * HW + n0 + tid];
        mu_s[tid]  = s.x;
        inv_s[tid] = s.y;
    }

    {
        const uint4* Ag = reinterpret_cast<const uint4*>(Apk + (size_t)mtile * 9216);
#pragma unroll
        for (int i = 0; i < 9; i++) {
            int idx = tid + i * 256;
            cp16(As + idx * 4, Ag + idx);
        }
    }
#pragma unroll
    for (int j = 0; j < 4; j++) {
        int idx = tid + j * 256;
        int k = idx >> 5, n4 = idx & 31;
        cp16(Bs + k * 136 + n4 * 4, Xb + (size_t)k * HW + n0 + n4 * 4);
    }
    CP_COMMIT();
#pragma unroll
    for (int j = 0; j < 4; j++) {
        int idx = tid + j * 256;
        int k = idx >> 5, n4 = idx & 31;
        cp16(Bs + 4352 + k * 136 + n4 * 4, Xb + (size_t)(32 + k) * HW + n0 + n4 * 4);
    }
    CP_COMMIT();

    float acc[3][4][4];
#pragma unroll
    for (int mi = 0; mi < 3; mi++)
#pragma unroll
        for (int ni = 0; ni < 4; ni++)
#pragma unroll
            for (int r = 0; r < 4; r++) acc[mi][ni][r] = 0.f;

    CP_WAIT(1);
    __syncthreads();
    g96_chunk(acc, As, Bs, 0, g, t, wmi, wn);
    __syncthreads();
#pragma unroll
    for (int j = 0; j < 4; j++) {
        int idx = tid + j * 256;
        int k = idx >> 5, n4 = idx & 31;
        cp16(Bs + k * 136 + n4 * 4, Xb + (size_t)(64 + k) * HW + n0 + n4 * 4);
    }
    CP_COMMIT();
    CP_WAIT(1);
    __syncthreads();
    g96_chunk(acc, As, Bs + 4352, 1, g, t, wmi, wn);
    CP_WAIT(0);
    __syncthreads();
    g96_chunk(acc, As, Bs, 2, g, t, wmi, wn);

#pragma unroll
    for (int mi = 0; mi < 3; mi++) {
        int r0 = m0 + wm + mi * 16 + g;
        int r1 = r0 + 8;
        float s0 = 0.f, t0 = 0.f, s1 = 0.f, t1 = 0.f;
        if (r0 < M) { s0 = svec[r0]; t0 = tvec[r0]; }
        if (r1 < M) { s1 = svec[r1]; t1 = tvec[r1]; }
#pragma unroll
        for (int ni = 0; ni < 4; ni++) {
            int ln = wn + ni * 8 + 2 * t;
            int col = n0 + ln;
            float i0 = inv_s[ln],     m0v = mu_s[ln]     * i0;
            float i1 = inv_s[ln + 1], m1v = mu_s[ln + 1] * i1;
            if (r0 < M) {
                float2 v;
                v.x = acc[mi][ni][0] * i0 - m0v * s0 + t0;
                v.y = acc[mi][ni][1] * i1 - m1v * s0 + t0;
                *reinterpret_cast<float2*>(Yb + (size_t)r0 * HW + col) = v;
            }
            if (r1 < M) {
                float2 v;
                v.x = acc[mi][ni][2] * i0 - m0v * s1 + t1;
                v.y = acc[mi][ni][3] * i1 - m1v * s1 + t1;
                *reinterpret_cast<float2*>(Yb + (size_t)r1 * HW + col) = v;
            }
        }
    }
}

// ---------------------------------------------------------------------------
// pout: K=288 (zero-padded), 3 prepacked A stages, BK=32 double-buffered
// cp.async pipeline, plain +residual epilogue. M=96.
// ---------------------------------------------------------------------------
__global__ void __launch_bounds__(256, 3) gemmPout(
        const uint32_t* __restrict__ Apk,
        const float* __restrict__ X,
        const float* __restrict__ Rsrc,
        float* __restrict__ Y,
        size_t xBatch, size_t yBatch, size_t rBatch) {
    extern __shared__ uint32_t sm[];
    uint32_t* As = sm;
    uint32_t* Bs = sm + 9216;

    int bz = blockIdx.z;
    const float* Xb = X    + (size_t)bz * xBatch;
    float*       Yb = Y    + (size_t)bz * yBatch;
    const float* Rb = Rsrc + (size_t)bz * rBatch;

    int n0 = blockIdx.y * 128;
    int tid  = threadIdx.x;
    int warp = tid >> 5;
    int lane = tid & 31;
    int g = lane >> 2;
    int t = lane & 3;
    int wm  = (warp >> 2) * 48;
    int wmi = (warp >> 2) * 3;
    int wn  = (warp & 3) * 32;

    // B-chunk loader: chunk c covers k = 32c..32c+31, buffer c&1
#define LOADB(c)                                                            \
    {                                                                       \
        uint32_t* buf = Bs + ((c) & 1) * 4352;                              \
        _Pragma("unroll")                                                   \
        for (int j = 0; j < 4; j++) {                                       \
            int idx = tid + j * 256;                                        \
            int k = idx >> 5, n4 = idx & 31;                                \
            cp16(buf + k * 136 + n4 * 4,                                    \
                 Xb + (size_t)((c) * 32 + k) * HW + n0 + n4 * 4);           \
        }                                                                   \
    }
#define LOADA(s)                                                            \
    {                                                                       \
        const uint4* Ag = reinterpret_cast<const uint4*>(Apk + (s) * 9216); \
        _Pragma("unroll")                                                   \
        for (int i = 0; i < 9; i++) {                                       \
            int idx = tid + i * 256;                                        \
            cp16(As + idx * 4, Ag + idx);                                   \
        }                                                                   \
    }

    LOADA(0);
    LOADB(0);
    CP_COMMIT();
    LOADB(1);
    CP_COMMIT();

    float acc[3][4][4];
#pragma unroll
    for (int mi = 0; mi < 3; mi++)
#pragma unroll
        for (int ni = 0; ni < 4; ni++)
#pragma unroll
            for (int r = 0; r < 4; r++) acc[mi][ni][r] = 0.f;

#pragma unroll
    for (int c = 0; c < 9; c++) {
        if ((c > 0 && c % 3 == 0) || c == 8) { CP_WAIT(0); } else { CP_WAIT(1); }
        __syncthreads();
        g96_chunk(acc, As, Bs + (c & 1) * 4352, c % 3, g, t, wmi, wn);
        if (c + 2 <= 8) {
            __syncthreads();
            if (c % 3 == 2) LOADA(c / 3 + 1);   // safe: stage c/3 fully consumed
            LOADB(c + 2);
            CP_COMMIT();
        }
    }
#undef LOADA
#undef LOADB

#pragma unroll
    for (int mi = 0; mi < 3; mi++) {
        int r0 = wm + mi * 16 + g;
        int r1 = r0 + 8;
#pragma unroll
        for (int ni = 0; ni < 4; ni++) {
            int col = n0 + wn + ni * 8 + 2 * t;
            float2 ra = *reinterpret_cast<const float2*>(Rb + (size_t)r0 * HW + col);
            float2 rb = *reinterpret_cast<const float2*>(Rb + (size_t)r1 * HW + col);
            float2 v01 = make_float2(acc[mi][ni][0] + ra.x, acc[mi][ni][1] + ra.y);
            float2 v23 = make_float2(acc[mi][ni][2] + rb.x, acc[mi][ni][3] + rb.y);
            *reinterpret_cast<float2*>(Yb + (size_t)r0 * HW + col) = v01;
            *reinterpret_cast<float2*>(Yb + (size_t)r1 * HW + col) = v23;
        }
    }
}

// ---------------------------------------------------------------------------
// 4-source fused GEMM for x1; A prepacked (cp.async), B LN-on-load.
// ---------------------------------------------------------------------------
struct G4 {
    const uint32_t* Apk[4];
    size_t          aBatch[4];
    const float*    X[4];
    size_t          xBatch[4];
    const float*    stats[4];
};

__global__ void __launch_bounds__(256, 2) gemm4_tc(
        G4 p,
        const float* __restrict__ lnw,
        const float* __restrict__ lnb,
        const float* __restrict__ Rsrc,
        float* __restrict__ Y) {
    extern __shared__ uint32_t smem_u[];
    uint32_t* As  = smem_u;
    uint32_t* Bs  = As + 9216;
    float* mu_s   = (float*)(Bs + 96 * 136);
    float* inv_s  = mu_s + 128;
    float* wln_s  = inv_s + 128;
    float* bln_s  = wln_s + 96;

    int bz = blockIdx.z;
    int n0 = blockIdx.y * 128;
    float*       Yb = Y    + (size_t)bz * CDIM * HW;
    const float* Rb = Rsrc + (size_t)bz * CDIM * HW;

    int tid  = threadIdx.x;
    int warp = tid >> 5;
    int lane = tid & 31;
    int g = lane >> 2;
    int t = lane & 3;
    int wm  = (warp >> 2) * 48;
    int wmi = (warp >> 2) * 3;
    int wn  = (warp & 3) * 32;

    if (tid < 96) { wln_s[tid] = lnw[tid]; bln_s[tid] = lnb[tid]; }

    float acc[3][4][4];
#pragma unroll
    for (int mi = 0; mi < 3; mi++)
#pragma unroll
        for (int ni = 0; ni < 4; ni++)
#pragma unroll
            for (int r = 0; r < 4; r++) acc[mi][ni][r] = 0.f;

    for (int s = 0; s < 4; s++) {
        __syncthreads();
        // A: 9 cp.async.128 from prepacked fragments
        {
            const uint4* Ag = reinterpret_cast<const uint4*>(p.Apk[s] + (size_t)bz * p.aBatch[s]);
#pragma unroll
            for (int i = 0; i < 9; i++) {
                int idx = tid + i * 256;
                cp16(As + idx * 4, Ag + idx);
            }
            CP_COMMIT();
        }
        const float* Xb = p.X[s] + (size_t)bz * p.xBatch[s];
        bool ln = (p.stats[s] != nullptr);
        if (ln && tid < 128) {
            float2 sv = reinterpret_cast<const float2*>(p.stats[s])[(size_t)bz * HW + n0 + tid];
            mu_s[tid]  = sv.x;
            inv_s[tid] = sv.y;
        }
        if (ln) __syncthreads();
#pragma unroll
        for (int i = 0; i < 12; i++) {
            int idx = tid + i * 256;
            int k  = idx >> 5;
            int n4 = idx & 31;
            float4 v = reinterpret_cast<const float4*>(Xb + (size_t)k * HW + n0)[n4];
            if (ln) {
                int nb = n4 * 4;
                float wk = wln_s[k], bk = bln_s[k];
                v.x = (v.x - mu_s[nb + 0]) * inv_s[nb + 0] * wk + bk;
                v.y = (v.y - mu_s[nb + 1]) * inv_s[nb + 1] * wk + bk;
                v.z = (v.z - mu_s[nb + 2]) * inv_s[nb + 2] * wk + bk;
                v.w = (v.w - mu_s[nb + 3]) * inv_s[nb + 3] * wk + bk;
            }
            uint4 u = make_uint4(__float_as_uint(v.x), __float_as_uint(v.y),
                                 __float_as_uint(v.z), __float_as_uint(v.w));
            *reinterpret_cast<uint4*>(Bs + k * 136 + n4 * 4) = u;
        }
        CP_WAIT(0);
        __syncthreads();
#pragma unroll
        for (int ks = 0; ks < 12; ks++) {
            const uint32_t* Ab = As + ks * 768 + g * 16 + t * 4;
            const uint32_t* Bb = Bs + (ks * 8 + t) * 136 + wn + g;
            uint4 a4[3];
            uint32_t bf[4][2];
#pragma unroll
            for (int mi = 0; mi < 3; mi++)
                a4[mi] = *reinterpret_cast<const uint4*>(Ab + (wmi + mi) * 128);
#pragma unroll
            for (int ni = 0; ni < 4; ni++) {
                bf[ni][0] = Bb[ni * 8];
                bf[ni][1] = Bb[4 * 136 + ni * 8];
            }
#pragma unroll
            for (int mi = 0; mi < 3; mi++) {
                uint32_t af[4] = {a4[mi].x, a4[mi].y, a4[mi].z, a4[mi].w};
#pragma unroll
                for (int ni = 0; ni < 4; ni++)
                    mma_tf32(acc[mi][ni], af, bf[ni]);
            }
        }
    }

#pragma unroll
    for (int mi = 0; mi < 3; mi++) {
        int r0 = wm + mi * 16 + g;
        int r1 = r0 + 8;
#pragma unroll
        for (int ni = 0; ni < 4; ni++) {
            int col = n0 + wn + ni * 8 + 2 * t;
            float2 ra = *reinterpret_cast<const float2*>(Rb + (size_t)r0 * HW + col);
            float2 rb = *reinterpret_cast<const float2*>(Rb + (size_t)r1 * HW + col);
            float2 v01 = make_float2(acc[mi][ni][0] + ra.x, acc[mi][ni][1] + ra.y);
            float2 v23 = make_float2(acc[mi][ni][2] + rb.x, acc[mi][ni][3] + rb.y);
            *reinterpret_cast<float2*>(Yb + (size_t)r0 * HW + col) = v01;
            *reinterpret_cast<float2*>(Yb + (size_t)r1 * HW + col) = v23;
        }
    }
}

// ---------------------------------------------------------------------------
// Depthwise 3x3, SAME zero padding.
// ---------------------------------------------------------------------------
__global__ void dw3_kernel(const float* __restrict__ in,
                           const float* __restrict__ w,
                           float* __restrict__ out, int C) {
    int pl = blockIdx.z;
    int c  = pl % C;
    int x  = blockIdx.x * 32 + threadIdx.x;
    int y  = blockIdx.y * 8  + threadIdx.y;
    const float* ip = in + (size_t)pl * HW;
    const float* wp = w + c * 9;
    float s = 0.f;
#pragma unroll
    for (int dy = -1; dy <= 1; dy++) {
        int yy = y + dy;
        if (yy < 0 || yy >= IMG) continue;
#pragma unroll
        for (int dx = -1; dx <= 1; dx++) {
            int xx = x + dx;
            if (xx < 0 || xx >= IMG) continue;
            s += wp[(dy + 1) * 3 + (dx + 1)] * ip[yy * IMG + xx];
        }
    }
    out[(size_t)pl * HW + y * IMG + x] = s;
}

// ---------------------------------------------------------------------------
// Fused FFN tail: dw3 on both halves + exact gelu + multiply.
// gate buffer pitch: 288 rows/batch (rows 255..287 untouched = zero).
// ---------------------------------------------------------------------------
__global__ void dwgate_kernel(const float* __restrict__ t,
                              const float* __restrict__ dwf,
                              float* __restrict__ gate) {
    int pl = blockIdx.z;
    int b = pl / HIDDEN, k = pl % HIDDEN;
    int x = blockIdx.x * 32 + threadIdx.x;
    int y = blockIdx.y * 8  + threadIdx.y;
    const float* i1 = t + ((size_t)b * 2 * HIDDEN + k) * HW;
    const float* i2 = t + ((size_t)b * 2 * HIDDEN + HIDDEN + k) * HW;
    const float* w1 = dwf + k * 9;
    const float* w2 = dwf + (HIDDEN + k) * 9;
    float s1 = 0.f, s2 = 0.f;
#pragma unroll
    for (int dy = -1; dy <= 1; dy++) {
        int yy = y + dy;
        if (yy < 0 || yy >= IMG) continue;
#pragma unroll
        for (int dx = -1; dx <= 1; dx++) {
            int xx = x + dx;
            if (xx < 0 || xx >= IMG) continue;
            int o = yy * IMG + xx, wi = (dy + 1) * 3 + (dx + 1);
            s1 += w1[wi] * i1[o];
            s2 += w2[wi] * i2[o];
        }
    }
    float gl = 0.5f * s1 * (1.f + erff(s1 * 0.7071067811865475f));
    gate[((size_t)b * 288 + k) * HW + y * IMG + x] = gl * s2;
}

// ---------------------------------------------------------------------------
// Gram stage 1 + fused row-norm partials; warp-level reduce.
// ---------------------------------------------------------------------------
__global__ void __launch_bounds__(256) gram1_kernel(
        const float* __restrict__ Q, const float* __restrict__ Kp,
        float* __restrict__ part) {
    int chunk = blockIdx.x, h = blockIdx.y, b = blockIdx.z;
    const float* qb = Q  + ((size_t)b * 288 + h * CHEAD) * HW;
    const float* kb = Kp + ((size_t)b * 288 + h * CHEAD) * HW;

    float acc[168];
#pragma unroll
    for (int i = 0; i < 168; i++) acc[i] = 0.f;

    int p0 = chunk * 2048 + threadIdx.x;
    for (int it = 0; it < 8; it++) {
        int p = p0 + it * 256;
        float qv[CHEAD], kv[CHEAD];
#pragma unroll
        for (int c = 0; c < CHEAD; c++) qv[c] = qb[(size_t)c * HW + p];
#pragma unroll
        for (int d = 0; d < CHEAD; d++) kv[d] = kb[(size_t)d * HW + p];
#pragma unroll
        for (int c = 0; c < CHEAD; c++)
#pragma unroll
            for (int d = 0; d < CHEAD; d++) acc[c * CHEAD + d] += qv[c] * kv[d];
#pragma unroll
        for (int c = 0; c < CHEAD; c++) acc[144 + c] += qv[c] * qv[c];
#pragma unroll
        for (int d = 0; d < CHEAD; d++) acc[156 + d] += kv[d] * kv[d];
    }

    int warp = threadIdx.x >> 5;
    int lane = threadIdx.x & 31;
    float* outp = part + ((((size_t)(b * HEADS + h)) * 32 + chunk) * 8 + warp) * 168;
#pragma unroll
    for (int i = 0; i < 168; i++) {
        float v = acc[i];
#pragma unroll
        for (int off = 16; off > 0; off >>= 1)
            v += __shfl_down_sync(0xffffffffu, v, off);
        if (lane == 0) outp[i] = v;
    }
}

// ---------------------------------------------------------------------------
// Gram stage 2 + norms + temperature + softmax.
// ---------------------------------------------------------------------------
__global__ void attn_kernel(const float* __restrict__ partA,
                            const float* __restrict__ partB,
                            const float* __restrict__ temp,
                            float* __restrict__ attnA,
                            float* __restrict__ attnB) {
    int bh = blockIdx.x;
    int h = bh % HEADS;
    __shared__ float GA[144], GB[144];
    __shared__ float nqA[12], nkA[12], nqB[12], nkB[12];
    int i = threadIdx.x;
    float sA = 0.f, sB = 0.f;
    if (i < 168) {
        const float* pA = partA + (size_t)bh * 256 * 168 + i;
        const float* pB = partB + (size_t)bh * 256 * 168 + i;
        for (int ch = 0; ch < 256; ch++) {
            sA += pA[(size_t)ch * 168];
            sB += pB[(size_t)ch * 168];
        }
        if (i >= 156) {
            nkA[i - 156] = fmaxf(sqrtf(sA), 1e-12f);
            nkB[i - 156] = fmaxf(sqrtf(sB), 1e-12f);
        } else if (i >= 144) {
            nqA[i - 144] = fmaxf(sqrtf(sA), 1e-12f);
            nqB[i - 144] = fmaxf(sqrtf(sB), 1e-12f);
        }
    }
    __syncthreads();
    if (i < 144) {
        int c = i / CHEAD, d = i % CHEAD;
        float tp = temp[h];
        GA[i] =  sA / (nqA[c] * nkA[d]) * tp;
        GB[i] = -sB / (nqB[c] * nkB[d]) * tp;
    }
    __syncthreads();
    if (i < 24) {
        float* G = (i < CHEAD) ? GA : GB;
        float* O = (i < CHEAD) ? attnA : attnB;
        int c = i % CHEAD;
        float mx = -1e30f;
        for (int d = 0; d < CHEAD; d++) mx = fmaxf(mx, G[c * CHEAD + d]);
        float e[CHEAD];
        float s = 0.f;
        for (int d = 0; d < CHEAD; d++) {
            e[d] = expf(G[c * CHEAD + d] - mx);
            s += e[d];
        }
        float inv = 1.f / s;
        for (int d = 0; d < CHEAD; d++)
            O[(size_t)bh * 144 + c * CHEAD + d] = e[d] * inv;
    }
}

// ---------------------------------------------------------------------------
// P0 = concat_w[:, :96] @ projA_w; P1 = concat_w[:, 96:] @ projB_w
// grid (2, 18): 512 outputs per block.
// ---------------------------------------------------------------------------
__global__ void wprod_kernel(const float* __restrict__ concat_w,
                             const float* __restrict__ projA,
                             const float* __restrict__ projB,
                             float* __restrict__ P0,
                             float* __restrict__ P1) {
    int br = blockIdx.x;
    const float* proj = br ? projB : projA;
    const float* cw   = concat_w + (br ? 96 : 0);
    float* P = br ? P1 : P0;
    __shared__ float pj[96 * 96];
    for (int i = threadIdx.x; i < 96 * 96; i += blockDim.x) pj[i] = proj[i];
    __syncthreads();
    int base = blockIdx.y * 512;
#pragma unroll
    for (int r = 0; r < 2; r++) {
        int o = base + r * 256 + threadIdx.x;
        int m = o / 96, n = o % 96;
        float s = 0.f;
#pragma unroll 8
        for (int c = 0; c < 96; c++) s += cw[m * 192 + c] * pj[c * 96 + n];
        P[o] = s;
    }
}

// ---------------------------------------------------------------------------
// cw_pk[b] = pack_tf32(P @ blockdiag(attn[b])); grid (4, 6).
// ---------------------------------------------------------------------------
__global__ void cw_kernel(const float* __restrict__ P0,
                          const float* __restrict__ P1,
                          const float* __restrict__ atA,
                          const float* __restrict__ atB,
                          uint32_t* __restrict__ cwApk,
                          uint32_t* __restrict__ cwBpk) {
    int b  = blockIdx.x >> 1;
    int br = blockIdx.x & 1;
    const float* P  = br ? P1 : P0;
    const float* at = (br ? atB : atA) + (size_t)b * HEADS * 144;
    uint32_t* out = (br ? cwBpk : cwApk) + (size_t)b * 9216;
    __shared__ float a_s[HEADS * 144];
    for (int i = threadIdx.x; i < HEADS * 144; i += blockDim.x) a_s[i] = at[i];
    __syncthreads();
    int base = blockIdx.y * 1536;
#pragma unroll
    for (int r = 0; r < 6; r++) {
        int o = base + r * 256 + threadIdx.x;
        int m = o / 96, n = o % 96;
        int h = n / CHEAD, d = n % CHEAD;
        float s = 0.f;
#pragma unroll
        for (int c = 0; c < CHEAD; c++)
            s += P[m * 96 + h * CHEAD + c] * a_s[h * 144 + c * CHEAD + d];
        out[a_pack_off(m, n)] = f2tf(s);
    }
}

// ---------------------------------------------------------------------------
// Launch
// ---------------------------------------------------------------------------
extern "C" void kernel_launch(void* const* d_in, const int* in_sizes, int n_in,
                              void* d_out, int out_size) {
    const float* x       = (const float*)d_in[0];
    const float* y       = (const float*)d_in[1];
    const float* ln1_w   = (const float*)d_in[2];
    const float* ln1_b   = (const float*)d_in[3];
    const float* ln2_w   = (const float*)d_in[4];
    const float* ln2_b   = (const float*)d_in[5];
    const float* qkvA_w  = (const float*)d_in[6];
    const float* dwA_w   = (const float*)d_in[7];
    const float* qkvB_w  = (const float*)d_in[8];
    const float* dwB_w   = (const float*)d_in[9];
    const float* projA_w = (const float*)d_in[10];
    const float* projB_w = (const float*)d_in[11];
    const float* concat_w= (const float*)d_in[12];
    const float* temp    = (const float*)d_in[13];
    const float* pin_w   = (const float*)d_in[14];
    const float* dwf_w   = (const float*)d_in[15];
    const float* pout_w  = (const float*)d_in[16];
    float* out = (float*)d_out;

    cudaFuncSetAttribute(gemm96,   cudaFuncAttributeMaxDynamicSharedMemorySize, G96_SMEM_BYTES);
    cudaFuncSetAttribute(gemmPout, cudaFuncAttributeMaxDynamicSharedMemorySize, G96_SMEM_BYTES);
    cudaFuncSetAttribute(gemm4_tc, cudaFuncAttributeMaxDynamicSharedMemorySize, GEMM_SMEM_BYTES);

    float *qkvA, *qkvAd, *qkvB, *qkvBd, *x1, *t, *gate;
    float *stsX, *stsY, *stsX1, *gpA, *gpB, *atA, *atB, *P0, *P1;
    uint32_t *prepQA, *prepQB, *prepPin, *prepPout_p, *prepC0, *prepC1, *cwApk, *cwBpk;
    float *sQA, *tQA, *sQB, *tQB, *sPin, *tPin;
    cudaGetSymbolAddress((void**)&qkvA,   g_qkvA);
    cudaGetSymbolAddress((void**)&qkvAd,  g_qkvAd);
    cudaGetSymbolAddress((void**)&qkvB,   g_qkvB);
    cudaGetSymbolAddress((void**)&qkvBd,  g_qkvBd);
    cudaGetSymbolAddress((void**)&x1,     g_x1);
    cudaGetSymbolAddress((void**)&t,      g_t);
    cudaGetSymbolAddress((void**)&gate,   g_gate);
    cudaGetSymbolAddress((void**)&stsX,   g_stsX);
    cudaGetSymbolAddress((void**)&stsY,   g_stsY);
    cudaGetSymbolAddress((void**)&stsX1,  g_stsX1);
    cudaGetSymbolAddress((void**)&gpA,    g_gpartA);
    cudaGetSymbolAddress((void**)&gpB,    g_gpartB);
    cudaGetSymbolAddress((void**)&atA,    g_attnA);
    cudaGetSymbolAddress((void**)&atB,    g_attnB);
    cudaGetSymbolAddress((void**)&P0,     g_P0);
    cudaGetSymbolAddress((void**)&P1,     g_P1);
    cudaGetSymbolAddress((void**)&prepQA,   g_prepQA);
    cudaGetSymbolAddress((void**)&prepQB,   g_prepQB);
    cudaGetSymbolAddress((void**)&prepPin,  g_prepPin);
    cudaGetSymbolAddress((void**)&prepPout_p, g_prepPout);
    cudaGetSymbolAddress((void**)&prepC0,   g_prepC0);
    cudaGetSymbolAddress((void**)&prepC1,   g_prepC1);
    cudaGetSymbolAddress((void**)&cwApk,    g_cwApk);
    cudaGetSymbolAddress((void**)&cwBpk,    g_cwBpk);
    cudaGetSymbolAddress((void**)&sQA,    g_sQA);
    cudaGetSymbolAddress((void**)&tQA,    g_tQA);
    cudaGetSymbolAddress((void**)&sQB,    g_sQB);
    cudaGetSymbolAddress((void**)&tQB,    g_tQB);
    cudaGetSymbolAddress((void**)&sPin,   g_sPin);
    cudaGetSymbolAddress((void**)&tPin,   g_tPin);

    const size_t P96  = (size_t)CDIM * HW;
    const size_t P288 = 3 * P96;
    const size_t P510 = (size_t)2 * HIDDEN * HW;
    const size_t PGATE = (size_t)288 * HW;

    // weight prep (wide, cheap)
    prep_kernel<<<3, 256>>>(qkvA_w, 288, ln1_w, ln1_b, prepQA, sQA, tQA);
    prep_kernel<<<3, 256>>>(qkvB_w, 288, ln1_w, ln1_b, prepQB, sQB, tQB);
    prep_kernel<<<6, 256>>>(pin_w,  510, ln2_w, ln2_b, prepPin, sPin, tPin);
    prep_pout<<<3, 256>>>(pout_w, prepPout_p);
    pack96_kernel<<<1, 256>>>(concat_w,      192, prepC0);
    pack96_kernel<<<1, 256>>>(concat_w + 96, 192, prepC1);
    {
        dim3 g(2, 18);
        wprod_kernel<<<g, 256>>>(concat_w, projA_w, projB_w, P0, P1);
    }

    dim3 sGrid(HW / 256, BATCH);
    stats_kernel<<<sGrid, 256>>>(x, (float2*)stsX);
    stats_kernel<<<sGrid, 256>>>(y, (float2*)stsY);

    // qkv = W@LN(x)
    {
        dim3 g(3, HW / 128, BATCH);
        gemm96<<<g, 256, G96_SMEM_BYTES>>>(prepQA, sQA, tQA, x, qkvA,
                                           (const float2*)stsX, 288, P96, P288);
        gemm96<<<g, 256, G96_SMEM_BYTES>>>(prepQB, sQB, tQB, y, qkvB,
                                           (const float2*)stsY, 288, P96, P288);
    }

    // depthwise 3x3
    {
        dim3 blk(32, 8), g(IMG / 32, IMG / 8, BATCH * 288);
        dw3_kernel<<<g, blk>>>(qkvA, dwA_w, qkvAd, 288);
        dw3_kernel<<<g, blk>>>(qkvB, dwB_w, qkvBd, 288);
    }

    // Gram + fused norms
    {
        dim3 g(32, HEADS, BATCH);
        gram1_kernel<<<g, 256>>>(qkvBd, qkvAd + 96 * (size_t)HW, gpA);
        gram1_kernel<<<g, 256>>>(qkvAd, qkvBd + 96 * (size_t)HW, gpB);
    }

    attn_kernel<<<BATCH * HEADS, 192>>>(gpA, gpB, temp, atA, atB);
    {
        dim3 g(4, 6);
        cw_kernel<<<g, 256>>>(P0, P1, atA, atB, cwApk, cwBpk);
    }

    // fused x1 = x + cwA@vA + cwB@vB + concat0@LN(x) + concat1@LN(y)
    {
        G4 p;
        p.Apk[0] = cwApk;  p.aBatch[0] = 9216;
        p.Apk[1] = cwBpk;  p.aBatch[1] = 9216;
        p.Apk[2] = prepC0; p.aBatch[2] = 0;
        p.Apk[3] = prepC1; p.aBatch[3] = 0;
        p.X[0] = qkvAd + 192 * (size_t)HW; p.xBatch[0] = P288; p.stats[0] = nullptr;
        p.X[1] = qkvBd + 192 * (size_t)HW; p.xBatch[1] = P288; p.stats[1] = nullptr;
        p.X[2] = x;                        p.xBatch[2] = P96;  p.stats[2] = stsX;
        p.X[3] = y;                        p.xBatch[3] = P96;  p.stats[3] = stsY;
        dim3 g(1, HW / 128, BATCH);
        gemm4_tc<<<g, 256, GEMM_SMEM_BYTES>>>(p, ln1_w, ln1_b, x, x1);
    }

    stats_kernel<<<sGrid, 256>>>(x1, (float2*)stsX1);

    // pin = W@LN2(x1)
    {
        dim3 g(6, HW / 128, BATCH);
        gemm96<<<g, 256, G96_SMEM_BYTES>>>(prepPin, sPin, tPin, x1, t,
                                           (const float2*)stsX1, 510, P96, P510);
    }

    // fused depthwise + gelu gate (288-pitch output)
    {
        dim3 blk(32, 8), g(IMG / 32, IMG / 8, BATCH * HIDDEN);
        dwgate_kernel<<<g, blk>>>(t, dwf_w, gate);
    }

    // pout pipelined (K padded to 288) + residual x1 -> final output
    {
        dim3 g(1, HW / 128, BATCH);
        gemmPout<<<g, 256, G96_SMEM_BYTES>>>(prepPout_p, gate, x1, out,
                                             PGATE, P96, P96);
    }
}

// round 8
// speedup vs baseline: 3.7815x; 1.3597x over previous
#include <cuda_runtime.h>
#include <cuda_bf16.h>
#include <math.h>
#include <stdint.h>

#define HW      65536
#define IMG     256
#define BATCH   2
#define CDIM    96
#define HEADS   8
#define CHEAD   12
#define HIDDEN  255

// ---------------------------------------------------------------------------
// Scratch
// ---------------------------------------------------------------------------
__device__ __nv_bfloat16 g_qkvA [BATCH * 3 * CDIM * HW];
__device__ __nv_bfloat16 g_qkvAd[BATCH * 3 * CDIM * HW];
__device__ __nv_bfloat16 g_qkvB [BATCH * 3 * CDIM * HW];
__device__ __nv_bfloat16 g_qkvBd[BATCH * 3 * CDIM * HW];
__device__ __nv_bfloat16 g_t    [BATCH * 2 * HIDDEN * HW];
__device__ float g_x1   [BATCH * CDIM * HW];
__device__ float g_gate [BATCH * 288 * HW];      // 288-pitch; rows 255..287 stay zero
__device__ float g_stsX [BATCH * HW * 2];
__device__ float g_stsY [BATCH * HW * 2];
__device__ float g_stsX1[BATCH * HW * 2];
__device__ float g_gpartA[BATCH * HEADS * 256 * 168];
__device__ float g_gpartB[BATCH * HEADS * 256 * 168];
__device__ float g_attnA [BATCH * HEADS * 144];
__device__ float g_attnB [BATCH * HEADS * 144];
__device__ float g_P0  [CDIM * CDIM];
__device__ float g_P1  [CDIM * CDIM];
// prepacked tf32 fragment tiles
__device__ uint32_t g_prepQA  [3 * 9216];
__device__ uint32_t g_prepQB  [3 * 9216];
__device__ uint32_t g_prepPin [6 * 9216];
__device__ uint32_t g_prepPout[3 * 9216];
__device__ uint32_t g_prepC0  [9216];
__device__ uint32_t g_prepC1  [9216];
__device__ uint32_t g_cwApk   [BATCH * 9216];
__device__ uint32_t g_cwBpk   [BATCH * 9216];
__device__ float g_sQA[288],  g_tQA[288];
__device__ float g_sQB[288],  g_tQB[288];
__device__ float g_sPin[576], g_tPin[576];

// ---------------------------------------------------------------------------
// tf32 / cp.async helpers
// ---------------------------------------------------------------------------
__device__ __forceinline__ uint32_t f2tf(float f) {
    uint32_t u;
    asm("cvt.rna.tf32.f32 %0, %1;" : "=r"(u) : "f"(f));
    return u;
}

__device__ __forceinline__ void mma_tf32(float* c, const uint32_t* a, const uint32_t* b) {
    asm volatile(
        "mma.sync.aligned.m16n8k8.row.col.f32.tf32.tf32.f32 "
        "{%0,%1,%2,%3}, {%4,%5,%6,%7}, {%8,%9}, {%0,%1,%2,%3};"
        : "+f"(c[0]), "+f"(c[1]), "+f"(c[2]), "+f"(c[3])
        : "r"(a[0]), "r"(a[1]), "r"(a[2]), "r"(a[3]), "r"(b[0]), "r"(b[1]));
}

__device__ __forceinline__ void cp16(void* smem, const void* gmem) {
    uint32_t a = (uint32_t)__cvta_generic_to_shared(smem);
    asm volatile("cp.async.cg.shared.global [%0], [%1], 16;\n" :: "r"(a), "l"(gmem));
}
#define CP_COMMIT()  asm volatile("cp.async.commit_group;\n")
#define CP_WAIT(n)   asm volatile("cp.async.wait_group %0;\n" :: "n"(n))

__device__ __forceinline__ int a_pack_off(int m, int k) {
    return (k >> 3) * 768 + (m >> 4) * 128 + (m & 7) * 16 + (k & 3) * 4
         + ((k >> 2) & 1) * 2 + ((m >> 3) & 1);
}

#define GEMM_SMEM_WORDS (9216 + 96*136 + 128 + 128 + 96 + 96)
#define GEMM_SMEM_BYTES (GEMM_SMEM_WORDS * 4)
#define G96_SMEM_WORDS  (9216 + 2*32*136 + 256)
#define G96_SMEM_BYTES  (G96_SMEM_WORDS * 4)

// ---------------------------------------------------------------------------
// LayerNorm stats (mu, inv_std) for x and y in one launch (grid.z picks).
// ---------------------------------------------------------------------------
__global__ void stats2_kernel(const float* __restrict__ x,
                              const float* __restrict__ y,
                              float2* __restrict__ sx,
                              float2* __restrict__ sy) {
    const float* in = blockIdx.z ? y : x;
    float2*      st = blockIdx.z ? sy : sx;
    int p = blockIdx.x * blockDim.x + threadIdx.x;
    int b = blockIdx.y;
    const float* ip = in + (size_t)b * CDIM * HW + p;
    float v[CDIM];
    float s = 0.f;
#pragma unroll
    for (int c = 0; c < CDIM; c++) { v[c] = ip[(size_t)c * HW]; s += v[c]; }
    float mu = s * (1.f / CDIM);
    float vs = 0.f;
#pragma unroll
    for (int c = 0; c < CDIM; c++) { float d = v[c] - mu; vs += d * d; }
    float inv = rsqrtf(vs * (1.f / CDIM) + 1e-5f);
    st[(size_t)b * HW + p] = make_float2(mu, inv);
}

__global__ void stats_kernel(const float* __restrict__ in,
                             float2* __restrict__ st) {
    int p = blockIdx.x * blockDim.x + threadIdx.x;
    int b = blockIdx.y;
    const float* ip = in + (size_t)b * CDIM * HW + p;
    float v[CDIM];
    float s = 0.f;
#pragma unroll
    for (int c = 0; c < CDIM; c++) { v[c] = ip[(size_t)c * HW]; s += v[c]; }
    float mu = s * (1.f / CDIM);
    float vs = 0.f;
#pragma unroll
    for (int c = 0; c < CDIM; c++) { float d = v[c] - mu; vs += d * d; }
    float inv = rsqrtf(vs * (1.f / CDIM) + 1e-5f);
    st[(size_t)b * HW + p] = make_float2(mu, inv);
}

// ---------------------------------------------------------------------------
// Prep: Apk = pack_tf32(W * diag(wln)); s = W@wln; t = W@bln.  K=96.
// ---------------------------------------------------------------------------
__global__ void prep_kernel(const float* __restrict__ W, int M,
                            const float* __restrict__ wln,
                            const float* __restrict__ bln,
                            uint32_t* __restrict__ Apk,
                            float* __restrict__ svec,
                            float* __restrict__ tvec) {
    int tile = blockIdx.x;
    int m0 = tile * 96;
    __shared__ float wls[96], bls[96];
    if (threadIdx.x < 96) { wls[threadIdx.x] = wln[threadIdx.x]; bls[threadIdx.x] = bln[threadIdx.x]; }
    __syncthreads();
#pragma unroll
    for (int i = 0; i < 36; i++) {
        int idx = threadIdx.x + i * 256;
        int m = idx / 96;
        int k = idx - m * 96;
        float v = 0.f;
        if (m0 + m < M) v = W[(size_t)(m0 + m) * 96 + k] * wls[k];
        Apk[tile * 9216 + a_pack_off(m, k)] = f2tf(v);
    }
    if (threadIdx.x < 96) {
        int gm = m0 + threadIdx.x;
        float s = 0.f, tt = 0.f;
        if (gm < M) {
            for (int k = 0; k < 96; k++) {
                float w = W[(size_t)gm * 96 + k];
                s  += w * wls[k];
                tt += w * bls[k];
            }
        }
        svec[tile * 96 + threadIdx.x] = s;
        tvec[tile * 96 + threadIdx.x] = tt;
    }
}

__global__ void pack96_kernel(const float* __restrict__ W, int ld,
                              uint32_t* __restrict__ out) {
#pragma unroll
    for (int i = 0; i < 36; i++) {
        int idx = threadIdx.x + i * 256;
        int m = idx / 96;
        int k = idx - m * 96;
        out[a_pack_off(m, k)] = f2tf(W[(size_t)m * ld + k]);
    }
}

__global__ void prep_pout(const float* __restrict__ W,
                          uint32_t* __restrict__ Apk) {
    int s = blockIdx.x;
#pragma unroll
    for (int i = 0; i < 36; i++) {
        int idx = threadIdx.x + i * 256;
        int m = idx / 96;
        int k = idx - m * 96;
        int kg = s * 96 + k;
        float v = (kg < HIDDEN) ? W[(size_t)m * HIDDEN + kg] : 0.f;
        Apk[s * 9216 + a_pack_off(m, k)] = f2tf(v);
    }
}

// ---------------------------------------------------------------------------
// 32-k MMA chunk on the 96x128 tile.
// ---------------------------------------------------------------------------
__device__ __forceinline__ void g96_chunk(
        float acc[3][4][4], const uint32_t* __restrict__ As,
        const uint32_t* __restrict__ Bbuf,
        int kc, int g, int t, int wmi, int wn) {
#pragma unroll
    for (int ks2 = 0; ks2 < 4; ks2++) {
        const uint32_t* Ab = As + (kc * 4 + ks2) * 768 + g * 16 + t * 4;
        const uint32_t* Bb = Bbuf + (ks2 * 8 + t) * 136 + wn + g;
        uint4 a4[3];
        uint32_t bf[4][2];
#pragma unroll
        for (int mi = 0; mi < 3; mi++)
            a4[mi] = *reinterpret_cast<const uint4*>(Ab + (wmi + mi) * 128);
#pragma unroll
        for (int ni = 0; ni < 4; ni++) {
            bf[ni][0] = Bb[ni * 8];
            bf[ni][1] = Bb[4 * 136 + ni * 8];
        }
#pragma unroll
        for (int mi = 0; mi < 3; mi++) {
            uint32_t af[4] = {a4[mi].x, a4[mi].y, a4[mi].z, a4[mi].w};
#pragma unroll
            for (int ni = 0; ni < 4; ni++)
                mma_tf32(acc[mi][ni], af, bf[ni]);
        }
    }
}

// ---------------------------------------------------------------------------
// K=96 pipelined tf32 GEMM, factored-LN epilogue, bf16 output.
// ---------------------------------------------------------------------------
struct G96P {
    const uint32_t* Apk[2];
    const float*    sv[2];
    const float*    tv[2];
    const float*    X[2];
    const float2*   sts[2];
    __nv_bfloat16*  Y[2];
};

__global__ void __launch_bounds__(256, 3) gemm96(
        G96P p, int M, int NB, size_t xBatch, size_t yBatch) {
    extern __shared__ uint32_t sm[];
    uint32_t* As = sm;
    uint32_t* Bs = sm + 9216;
    float* mu_s  = (float*)(sm + 9216 + 8704);
    float* inv_s = mu_s + 128;

    int z  = blockIdx.z;
    int br = z % NB;
    int bz = z / NB;
    const float* Xb = p.X[br] + (size_t)bz * xBatch;
    __nv_bfloat16* Yb = p.Y[br] + (size_t)bz * yBatch;
    const float* svec = p.sv[br];
    const float* tvec = p.tv[br];

    int mtile = blockIdx.x;
    int m0 = mtile * 96;
    int n0 = blockIdx.y * 128;
    int tid  = threadIdx.x;
    int warp = tid >> 5;
    int lane = tid & 31;
    int g = lane >> 2;
    int t = lane & 3;
    int wm  = (warp >> 2) * 48;
    int wmi = (warp >> 2) * 3;
    int wn  = (warp & 3) * 32;

    if (tid < 128) {
        float2 s = p.sts[br][(size_t)bz * HW + n0 + tid];
        mu_s[tid]  = s.x;
        inv_s[tid] = s.y;
    }

    {
        const uint4* Ag = reinterpret_cast<const uint4*>(p.Apk[br] + (size_t)mtile * 9216);
#pragma unroll
        for (int i = 0; i < 9; i++) {
            int idx = tid + i * 256;
            cp16(As + idx * 4, Ag + idx);
        }
    }
#pragma unroll
    for (int j = 0; j < 4; j++) {
        int idx = tid + j * 256;
        int k = idx >> 5, n4 = idx & 31;
        cp16(Bs + k * 136 + n4 * 4, Xb + (size_t)k * HW + n0 + n4 * 4);
    }
    CP_COMMIT();
#pragma unroll
    for (int j = 0; j < 4; j++) {
        int idx = tid + j * 256;
        int k = idx >> 5, n4 = idx & 31;
        cp16(Bs + 4352 + k * 136 + n4 * 4, Xb + (size_t)(32 + k) * HW + n0 + n4 * 4);
    }
    CP_COMMIT();

    float acc[3][4][4];
#pragma unroll
    for (int mi = 0; mi < 3; mi++)
#pragma unroll
        for (int ni = 0; ni < 4; ni++)
#pragma unroll
            for (int r = 0; r < 4; r++) acc[mi][ni][r] = 0.f;

    CP_WAIT(1);
    __syncthreads();
    g96_chunk(acc, As, Bs, 0, g, t, wmi, wn);
    __syncthreads();
#pragma unroll
    for (int j = 0; j < 4; j++) {
        int idx = tid + j * 256;
        int k = idx >> 5, n4 = idx & 31;
        cp16(Bs + k * 136 + n4 * 4, Xb + (size_t)(64 + k) * HW + n0 + n4 * 4);
    }
    CP_COMMIT();
    CP_WAIT(1);
    __syncthreads();
    g96_chunk(acc, As, Bs + 4352, 1, g, t, wmi, wn);
    CP_WAIT(0);
    __syncthreads();
    g96_chunk(acc, As, Bs, 2, g, t, wmi, wn);

#pragma unroll
    for (int mi = 0; mi < 3; mi++) {
        int r0 = m0 + wm + mi * 16 + g;
        int r1 = r0 + 8;
        float s0 = 0.f, t0 = 0.f, s1 = 0.f, t1 = 0.f;
        if (r0 < M) { s0 = svec[r0]; t0 = tvec[r0]; }
        if (r1 < M) { s1 = svec[r1]; t1 = tvec[r1]; }
#pragma unroll
        for (int ni = 0; ni < 4; ni++) {
            int ln = wn + ni * 8 + 2 * t;
            int col = n0 + ln;
            float i0 = inv_s[ln],     m0v = mu_s[ln]     * i0;
            float i1 = inv_s[ln + 1], m1v = mu_s[ln + 1] * i1;
            if (r0 < M) {
                float vx = acc[mi][ni][0] * i0 - m0v * s0 + t0;
                float vy = acc[mi][ni][1] * i1 - m1v * s0 + t0;
                *reinterpret_cast<__nv_bfloat162*>(Yb + (size_t)r0 * HW + col) =
                    __floats2bfloat162_rn(vx, vy);
            }
            if (r1 < M) {
                float vx = acc[mi][ni][2] * i0 - m0v * s1 + t1;
                float vy = acc[mi][ni][3] * i1 - m1v * s1 + t1;
                *reinterpret_cast<__nv_bfloat162*>(Yb + (size_t)r1 * HW + col) =
                    __floats2bfloat162_rn(vx, vy);
            }
        }
    }
}

// ---------------------------------------------------------------------------
// pout: K=288 (zero-padded), pipelined, fp32 in/out.
// ---------------------------------------------------------------------------
__global__ void __launch_bounds__(256, 3) gemmPout(
        const uint32_t* __restrict__ Apk,
        const float* __restrict__ X,
        const float* __restrict__ Rsrc,
        float* __restrict__ Y,
        size_t xBatch, size_t yBatch, size_t rBatch) {
    extern __shared__ uint32_t sm[];
    uint32_t* As = sm;
    uint32_t* Bs = sm + 9216;

    int bz = blockIdx.z;
    const float* Xb = X    + (size_t)bz * xBatch;
    float*       Yb = Y    + (size_t)bz * yBatch;
    const float* Rb = Rsrc + (size_t)bz * rBatch;

    int n0 = blockIdx.y * 128;
    int tid  = threadIdx.x;
    int warp = tid >> 5;
    int lane = tid & 31;
    int g = lane >> 2;
    int t = lane & 3;
    int wm  = (warp >> 2) * 48;
    int wmi = (warp >> 2) * 3;
    int wn  = (warp & 3) * 32;

#define LOADB(c)                                                            \
    {                                                                       \
        uint32_t* buf = Bs + ((c) & 1) * 4352;                              \
        _Pragma("unroll")                                                   \
        for (int j = 0; j < 4; j++) {                                       \
            int idx = tid + j * 256;                                        \
            int k = idx >> 5, n4 = idx & 31;                                \
            cp16(buf + k * 136 + n4 * 4,                                    \
                 Xb + (size_t)((c) * 32 + k) * HW + n0 + n4 * 4);           \
        }                                                                   \
    }
#define LOADA(s)                                                            \
    {                                                                       \
        const uint4* Ag = reinterpret_cast<const uint4*>(Apk + (s) * 9216); \
        _Pragma("unroll")                                                   \
        for (int i = 0; i < 9; i++) {                                       \
            int idx = tid + i * 256;                                        \
            cp16(As + idx * 4, Ag + idx);                                   \
        }                                                                   \
    }

    LOADA(0);
    LOADB(0);
    CP_COMMIT();
    LOADB(1);
    CP_COMMIT();

    float acc[3][4][4];
#pragma unroll
    for (int mi = 0; mi < 3; mi++)
#pragma unroll
        for (int ni = 0; ni < 4; ni++)
#pragma unroll
            for (int r = 0; r < 4; r++) acc[mi][ni][r] = 0.f;

#pragma unroll
    for (int c = 0; c < 9; c++) {
        if ((c > 0 && c % 3 == 0) || c == 8) { CP_WAIT(0); } else { CP_WAIT(1); }
        __syncthreads();
        g96_chunk(acc, As, Bs + (c & 1) * 4352, c % 3, g, t, wmi, wn);
        if (c + 2 <= 8) {
            __syncthreads();
            if (c % 3 == 2) LOADA(c / 3 + 1);
            LOADB(c + 2);
            CP_COMMIT();
        }
    }
#undef LOADA
#undef LOADB

#pragma unroll
    for (int mi = 0; mi < 3; mi++) {
        int r0 = wm + mi * 16 + g;
        int r1 = r0 + 8;
#pragma unroll
        for (int ni = 0; ni < 4; ni++) {
            int col = n0 + wn + ni * 8 + 2 * t;
            float2 ra = *reinterpret_cast<const float2*>(Rb + (size_t)r0 * HW + col);
            float2 rb = *reinterpret_cast<const float2*>(Rb + (size_t)r1 * HW + col);
            float2 v01 = make_float2(acc[mi][ni][0] + ra.x, acc[mi][ni][1] + ra.y);
            float2 v23 = make_float2(acc[mi][ni][2] + rb.x, acc[mi][ni][3] + rb.y);
            *reinterpret_cast<float2*>(Yb + (size_t)r0 * HW + col) = v01;
            *reinterpret_cast<float2*>(Yb + (size_t)r1 * HW + col) = v23;
        }
    }
}

// ---------------------------------------------------------------------------
// 4-source fused GEMM for x1; v sources bf16, LN sources fp32.
// ---------------------------------------------------------------------------
struct G4 {
    const uint32_t* Apk[4];
    size_t          aBatch[4];
    const void*     X[4];
    size_t          xBatch[4];   // elements of the source dtype
    const float*    stats[4];
    int             isbf16[4];
};

__global__ void __launch_bounds__(256, 2) gemm4_tc(
        G4 p,
        const float* __restrict__ lnw,
        const float* __restrict__ lnb,
        const float* __restrict__ Rsrc,
        float* __restrict__ Y) {
    extern __shared__ uint32_t smem_u[];
    uint32_t* As  = smem_u;
    uint32_t* Bs  = As + 9216;
    float* mu_s   = (float*)(Bs + 96 * 136);
    float* inv_s  = mu_s + 128;
    float* wln_s  = inv_s + 128;
    float* bln_s  = wln_s + 96;

    int bz = blockIdx.z;
    int n0 = blockIdx.y * 128;
    float*       Yb = Y    + (size_t)bz * CDIM * HW;
    const float* Rb = Rsrc + (size_t)bz * CDIM * HW;

    int tid  = threadIdx.x;
    int warp = tid >> 5;
    int lane = tid & 31;
    int g = lane >> 2;
    int t = lane & 3;
    int wm  = (warp >> 2) * 48;
    int wmi = (warp >> 2) * 3;
    int wn  = (warp & 3) * 32;

    if (tid < 96) { wln_s[tid] = lnw[tid]; bln_s[tid] = lnb[tid]; }

    float acc[3][4][4];
#pragma unroll
    for (int mi = 0; mi < 3; mi++)
#pragma unroll
        for (int ni = 0; ni < 4; ni++)
#pragma unroll
            for (int r = 0; r < 4; r++) acc[mi][ni][r] = 0.f;

    for (int s = 0; s < 4; s++) {
        __syncthreads();
        {
            const uint4* Ag = reinterpret_cast<const uint4*>(p.Apk[s] + (size_t)bz * p.aBatch[s]);
#pragma unroll
            for (int i = 0; i < 9; i++) {
                int idx = tid + i * 256;
                cp16(As + idx * 4, Ag + idx);
            }
            CP_COMMIT();
        }
        if (p.isbf16[s]) {
            const __nv_bfloat16* Xh = (const __nv_bfloat16*)p.X[s] + (size_t)bz * p.xBatch[s];
#pragma unroll
            for (int i = 0; i < 6; i++) {           // FIX: 1536 idx * 8 vals = 96x128
                int idx = tid + i * 256;
                int k = idx >> 4, n8 = idx & 15;
                const __nv_bfloat162* src =
                    reinterpret_cast<const __nv_bfloat162*>(Xh + (size_t)k * HW + n0 + n8 * 8);
                uint32_t* dst = Bs + k * 136 + n8 * 8;
#pragma unroll
                for (int j = 0; j < 4; j++) {
                    float2 f = __bfloat1622float2(src[j]);
                    dst[2 * j]     = __float_as_uint(f.x);
                    dst[2 * j + 1] = __float_as_uint(f.y);
                }
            }
        } else {
            const float* Xb = (const float*)p.X[s] + (size_t)bz * p.xBatch[s];
            bool ln = (p.stats[s] != nullptr);
            if (ln && tid < 128) {
                float2 sv = reinterpret_cast<const float2*>(p.stats[s])[(size_t)bz * HW + n0 + tid];
                mu_s[tid]  = sv.x;
                inv_s[tid] = sv.y;
            }
            if (ln) __syncthreads();
#pragma unroll
            for (int i = 0; i < 12; i++) {
                int idx = tid + i * 256;
                int k  = idx >> 5;
                int n4 = idx & 31;
                float4 v = reinterpret_cast<const float4*>(Xb + (size_t)k * HW + n0)[n4];
                if (ln) {
                    int nb = n4 * 4;
                    float wk = wln_s[k], bk = bln_s[k];
                    v.x = (v.x - mu_s[nb + 0]) * inv_s[nb + 0] * wk + bk;
                    v.y = (v.y - mu_s[nb + 1]) * inv_s[nb + 1] * wk + bk;
                    v.z = (v.z - mu_s[nb + 2]) * inv_s[nb + 2] * wk + bk;
                    v.w = (v.w - mu_s[nb + 3]) * inv_s[nb + 3] * wk + bk;
                }
                uint4 u = make_uint4(__float_as_uint(v.x), __float_as_uint(v.y),
                                     __float_as_uint(v.z), __float_as_uint(v.w));
                *reinterpret_cast<uint4*>(Bs + k * 136 + n4 * 4) = u;
            }
        }
        CP_WAIT(0);
        __syncthreads();
#pragma unroll
        for (int ks = 0; ks < 12; ks++) {
            const uint32_t* Ab = As + ks * 768 + g * 16 + t * 4;
            const uint32_t* Bb = Bs + (ks * 8 + t) * 136 + wn + g;
            uint4 a4[3];
            uint32_t bf[4][2];
#pragma unroll
            for (int mi = 0; mi < 3; mi++)
                a4[mi] = *reinterpret_cast<const uint4*>(Ab + (wmi + mi) * 128);
#pragma unroll
            for (int ni = 0; ni < 4; ni++) {
                bf[ni][0] = Bb[ni * 8];
                bf[ni][1] = Bb[4 * 136 + ni * 8];
            }
#pragma unroll
            for (int mi = 0; mi < 3; mi++) {
                uint32_t af[4] = {a4[mi].x, a4[mi].y, a4[mi].z, a4[mi].w};
#pragma unroll
                for (int ni = 0; ni < 4; ni++)
                    mma_tf32(acc[mi][ni], af, bf[ni]);
            }
        }
    }

#pragma unroll
    for (int mi = 0; mi < 3; mi++) {
        int r0 = wm + mi * 16 + g;
        int r1 = r0 + 8;
#pragma unroll
        for (int ni = 0; ni < 4; ni++) {
            int col = n0 + wn + ni * 8 + 2 * t;
            float2 ra = *reinterpret_cast<const float2*>(Rb + (size_t)r0 * HW + col);
            float2 rb = *reinterpret_cast<const float2*>(Rb + (size_t)r1 * HW + col);
            float2 v01 = make_float2(acc[mi][ni][0] + ra.x, acc[mi][ni][1] + ra.y);
            float2 v23 = make_float2(acc[mi][ni][2] + rb.x, acc[mi][ni][3] + rb.y);
            *reinterpret_cast<float2*>(Yb + (size_t)r0 * HW + col) = v01;
            *reinterpret_cast<float2*>(Yb + (size_t)r1 * HW + col) = v23;
        }
    }
}

// ---------------------------------------------------------------------------
// Depthwise 3x3, bf16 in/out, 4 px per thread, both branches in one launch.
// ---------------------------------------------------------------------------
__global__ void dw3_kernel(const __nv_bfloat16* __restrict__ qA,
                           const __nv_bfloat16* __restrict__ qB,
                           const float* __restrict__ wA,
                           const float* __restrict__ wB,
                           __nv_bfloat16* __restrict__ oA,
                           __nv_bfloat16* __restrict__ oB) {
    int pl = blockIdx.z;
    int br = pl >= BATCH * 288;
    int rem = pl - br * BATCH * 288;
    int c = rem % 288;
    const __nv_bfloat16* ip = (br ? qB : qA) + (size_t)rem * HW;
    const float* wp = (br ? wB : wA) + c * 9;
    __nv_bfloat16* op = (br ? oB : oA) + (size_t)rem * HW;

    int x0 = (blockIdx.x * 32 + threadIdx.x) * 4;
    int y  = blockIdx.y * 8 + threadIdx.y;

    float w[9];
#pragma unroll
    for (int i = 0; i < 9; i++) w[i] = wp[i];

    float acc[4] = {0.f, 0.f, 0.f, 0.f};
#pragma unroll
    for (int dy = -1; dy <= 1; dy++) {
        int yy = y + dy;
        if (yy < 0 || yy >= IMG) continue;
        const __nv_bfloat16* row = ip + yy * IMG;
        float v[6];
        v[0] = (x0 > 0) ? __bfloat162float(row[x0 - 1]) : 0.f;
        {
            const __nv_bfloat162* r2 = reinterpret_cast<const __nv_bfloat162*>(row + x0);
            float2 a = __bfloat1622float2(r2[0]);
            float2 b = __bfloat1622float2(r2[1]);
            v[1] = a.x; v[2] = a.y; v[3] = b.x; v[4] = b.y;
        }
        v[5] = (x0 + 4 < IMG) ? __bfloat162float(row[x0 + 4]) : 0.f;
        const float* wr = w + (dy + 1) * 3;
#pragma unroll
        for (int j = 0; j < 4; j++)
            acc[j] += wr[0] * v[j] + wr[1] * v[j + 1] + wr[2] * v[j + 2];
    }

    __nv_bfloat162 o0 = __floats2bfloat162_rn(acc[0], acc[1]);
    __nv_bfloat162 o1 = __floats2bfloat162_rn(acc[2], acc[3]);
    *reinterpret_cast<__nv_bfloat162*>(op + y * IMG + x0)     = o0;
    *reinterpret_cast<__nv_bfloat162*>(op + y * IMG + x0 + 2) = o1;
}

// ---------------------------------------------------------------------------
// Fused FFN tail: dw3 on both t halves (bf16) + exact gelu + multiply.
// ---------------------------------------------------------------------------
__global__ void dwgate_kernel(const __nv_bfloat16* __restrict__ t,
                              const float* __restrict__ dwf,
                              float* __restrict__ gate) {
    int pl = blockIdx.z;
    int b = pl / HIDDEN, k = pl % HIDDEN;
    int x0 = (blockIdx.x * 32 + threadIdx.x) * 4;
    int y  = blockIdx.y * 8 + threadIdx.y;
    const __nv_bfloat16* i1 = t + ((size_t)b * 2 * HIDDEN + k) * HW;
    const __nv_bfloat16* i2 = t + ((size_t)b * 2 * HIDDEN + HIDDEN + k) * HW;
    const float* w1 = dwf + k * 9;
    const float* w2 = dwf + (HIDDEN + k) * 9;

    float wa[9], wb[9];
#pragma unroll
    for (int i = 0; i < 9; i++) { wa[i] = w1[i]; wb[i] = w2[i]; }

    float s1[4] = {0.f, 0.f, 0.f, 0.f};
    float s2[4] = {0.f, 0.f, 0.f, 0.f};
#pragma unroll
    for (int dy = -1; dy <= 1; dy++) {
        int yy = y + dy;
        if (yy < 0 || yy >= IMG) continue;
        const __nv_bfloat16* r1 = i1 + yy * IMG;
        const __nv_bfloat16* r2 = i2 + yy * IMG;
        float v1[6], v2[6];
        v1[0] = (x0 > 0) ? __bfloat162float(r1[x0 - 1]) : 0.f;
        v2[0] = (x0 > 0) ? __bfloat162float(r2[x0 - 1]) : 0.f;
        {
            const __nv_bfloat162* p1 = reinterpret_cast<const __nv_bfloat162*>(r1 + x0);
            const __nv_bfloat162* p2 = reinterpret_cast<const __nv_bfloat162*>(r2 + x0);
            float2 a1 = __bfloat1622float2(p1[0]), b1 = __bfloat1622float2(p1[1]);
            float2 a2 = __bfloat1622float2(p2[0]), b2 = __bfloat1622float2(p2[1]);
            v1[1] = a1.x; v1[2] = a1.y; v1[3] = b1.x; v1[4] = b1.y;
            v2[1] = a2.x; v2[2] = a2.y; v2[3] = b2.x; v2[4] = b2.y;
        }
        v1[5] = (x0 + 4 < IMG) ? __bfloat162float(r1[x0 + 4]) : 0.f;
        v2[5] = (x0 + 4 < IMG) ? __bfloat162float(r2[x0 + 4]) : 0.f;
        const float* wra = wa + (dy + 1) * 3;
        const float* wrb = wb + (dy + 1) * 3;
#pragma unroll
        for (int j = 0; j < 4; j++) {
            s1[j] += wra[0] * v1[j] + wra[1] * v1[j + 1] + wra[2] * v1[j + 2];
            s2[j] += wrb[0] * v2[j] + wrb[1] * v2[j + 1] + wrb[2] * v2[j + 2];
        }
    }

    float4 o;
    float* op = &o.x;
#pragma unroll
    for (int j = 0; j < 4; j++) {
        float gl = 0.5f * s1[j] * (1.f + erff(s1[j] * 0.7071067811865475f));
        op[j] = gl * s2[j];
    }
    *reinterpret_cast<float4*>(gate + ((size_t)b * 288 + k) * HW + y * IMG + x0) = o;
}

// ---------------------------------------------------------------------------
// Gram stage 1 (bf16 inputs) + fused norms; both branches in one launch.
// ---------------------------------------------------------------------------
__global__ void __launch_bounds__(256) gram1_kernel(
        const __nv_bfloat16* __restrict__ qkvAd,
        const __nv_bfloat16* __restrict__ qkvBd,
        float* __restrict__ gpA, float* __restrict__ gpB) {
    int chunk = blockIdx.x, h = blockIdx.y;
    int b  = blockIdx.z >> 1;
    int br = blockIdx.z & 1;
    const __nv_bfloat16* qb = (br ? qkvAd : qkvBd) + ((size_t)b * 288 + h * CHEAD) * HW;
    const __nv_bfloat16* kb = (br ? qkvBd : qkvAd) + ((size_t)b * 288 + 96 + h * CHEAD) * HW;
    float* part = br ? gpB : gpA;

    float acc[168];
#pragma unroll
    for (int i = 0; i < 168; i++) acc[i] = 0.f;

    int p0 = chunk * 2048 + threadIdx.x;
    for (int it = 0; it < 8; it++) {
        int p = p0 + it * 256;
        float qv[CHEAD], kv[CHEAD];
#pragma unroll
        for (int c = 0; c < CHEAD; c++) qv[c] = __bfloat162float(qb[(size_t)c * HW + p]);
#pragma unroll
        for (int d = 0; d < CHEAD; d++) kv[d] = __bfloat162float(kb[(size_t)d * HW + p]);
#pragma unroll
        for (int c = 0; c < CHEAD; c++)
#pragma unroll
            for (int d = 0; d < CHEAD; d++) acc[c * CHEAD + d] += qv[c] * kv[d];
#pragma unroll
        for (int c = 0; c < CHEAD; c++) acc[144 + c] += qv[c] * qv[c];
#pragma unroll
        for (int d = 0; d < CHEAD; d++) acc[156 + d] += kv[d] * kv[d];
    }

    int warp = threadIdx.x >> 5;
    int lane = threadIdx.x & 31;
    float* outp = part + ((((size_t)(b * HEADS + h)) * 32 + chunk) * 8 + warp) * 168;
#pragma unroll
    for (int i = 0; i < 168; i++) {
        float v = acc[i];
#pragma unroll
        for (int off = 16; off > 0; off >>= 1)
            v += __shfl_down_sync(0xffffffffu, v, off);
        if (lane == 0) outp[i] = v;
    }
}

// ---------------------------------------------------------------------------
// Gram stage 2 + norms + temperature + softmax.
// ---------------------------------------------------------------------------
__global__ void attn_kernel(const float* __restrict__ partA,
                            const float* __restrict__ partB,
                            const float* __restrict__ temp,
                            float* __restrict__ attnA,
                            float* __restrict__ attnB) {
    int bh = blockIdx.x;
    int h = bh % HEADS;
    __shared__ float GA[144], GB[144];
    __shared__ float nqA[12], nkA[12], nqB[12], nkB[12];
    int i = threadIdx.x;
    float sA = 0.f, sB = 0.f;
    if (i < 168) {
        const float* pA = partA + (size_t)bh * 256 * 168 + i;
        const float* pB = partB + (size_t)bh * 256 * 168 + i;
        for (int ch = 0; ch < 256; ch++) {
            sA += pA[(size_t)ch * 168];
            sB += pB[(size_t)ch * 168];
        }
        if (i >= 156) {
            nkA[i - 156] = fmaxf(sqrtf(sA), 1e-12f);
            nkB[i - 156] = fmaxf(sqrtf(sB), 1e-12f);
        } else if (i >= 144) {
            nqA[i - 144] = fmaxf(sqrtf(sA), 1e-12f);
            nqB[i - 144] = fmaxf(sqrtf(sB), 1e-12f);
        }
    }
    __syncthreads();
    if (i < 144) {
        int c = i / CHEAD, d = i % CHEAD;
        float tp = temp[h];
        GA[i] =  sA / (nqA[c] * nkA[d]) * tp;
        GB[i] = -sB / (nqB[c] * nkB[d]) * tp;
    }
    __syncthreads();
    if (i < 24) {
        float* G = (i < CHEAD) ? GA : GB;
        float* O = (i < CHEAD) ? attnA : attnB;
        int c = i % CHEAD;
        float mx = -1e30f;
        for (int d = 0; d < CHEAD; d++) mx = fmaxf(mx, G[c * CHEAD + d]);
        float e[CHEAD];
        float s = 0.f;
        for (int d = 0; d < CHEAD; d++) {
            e[d] = expf(G[c * CHEAD + d] - mx);
            s += e[d];
        }
        float inv = 1.f / s;
        for (int d = 0; d < CHEAD; d++)
            O[(size_t)bh * 144 + c * CHEAD + d] = e[d] * inv;
    }
}

// ---------------------------------------------------------------------------
// P0 = concat_w[:, :96] @ projA_w; P1 = concat_w[:, 96:] @ projB_w
// ---------------------------------------------------------------------------
__global__ void wprod_kernel(const float* __restrict__ concat_w,
                             const float* __restrict__ projA,
                             const float* __restrict__ projB,
                             float* __restrict__ P0,
                             float* __restrict__ P1) {
    int br = blockIdx.x;
    const float* proj = br ? projB : projA;
    const float* cw   = concat_w + (br ? 96 : 0);
    float* P = br ? P1 : P0;
    __shared__ float pj[96 * 96];
    for (int i = threadIdx.x; i < 96 * 96; i += blockDim.x) pj[i] = proj[i];
    __syncthreads();
    int base = blockIdx.y * 512;
#pragma unroll
    for (int r = 0; r < 2; r++) {
        int o = base + r * 256 + threadIdx.x;
        int m = o / 96, n = o % 96;
        float s = 0.f;
#pragma unroll 8
        for (int c = 0; c < 96; c++) s += cw[m * 192 + c] * pj[c * 96 + n];
        P[o] = s;
    }
}

// ---------------------------------------------------------------------------
// cw_pk[b] = pack_tf32(P @ blockdiag(attn[b])); grid (4, 6).
// ---------------------------------------------------------------------------
__global__ void cw_kernel(const float* __restrict__ P0,
                          const float* __restrict__ P1,
                          const float* __restrict__ atA,
                          const float* __restrict__ atB,
                          uint32_t* __restrict__ cwApk,
                          uint32_t* __restrict__ cwBpk) {
    int b  = blockIdx.x >> 1;
    int br = blockIdx.x & 1;
    const float* P  = br ? P1 : P0;
    const float* at = (br ? atB : atA) + (size_t)b * HEADS * 144;
    uint32_t* out = (br ? cwBpk : cwApk) + (size_t)b * 9216;
    __shared__ float a_s[HEADS * 144];
    for (int i = threadIdx.x; i < HEADS * 144; i += blockDim.x) a_s[i] = at[i];
    __syncthreads();
    int base = blockIdx.y * 1536;
#pragma unroll
    for (int r = 0; r < 6; r++) {
        int o = base + r * 256 + threadIdx.x;
        int m = o / 96, n = o % 96;
        int h = n / CHEAD, d = n % CHEAD;
        float s = 0.f;
#pragma unroll
        for (int c = 0; c < CHEAD; c++)
            s += P[m * 96 + h * CHEAD + c] * a_s[h * 144 + c * CHEAD + d];
        out[a_pack_off(m, n)] = f2tf(s);
    }
}

// ---------------------------------------------------------------------------
// Launch
// ---------------------------------------------------------------------------
extern "C" void kernel_launch(void* const* d_in, const int* in_sizes, int n_in,
                              void* d_out, int out_size) {
    const float* x       = (const float*)d_in[0];
    const float* y       = (const float*)d_in[1];
    const float* ln1_w   = (const float*)d_in[2];
    const float* ln1_b   = (const float*)d_in[3];
    const float* ln2_w   = (const float*)d_in[4];
    const float* ln2_b   = (const float*)d_in[5];
    const float* qkvA_w  = (const float*)d_in[6];
    const float* dwA_w   = (const float*)d_in[7];
    const float* qkvB_w  = (const float*)d_in[8];
    const float* dwB_w   = (const float*)d_in[9];
    const float* projA_w = (const float*)d_in[10];
    const float* projB_w = (const float*)d_in[11];
    const float* concat_w= (const float*)d_in[12];
    const float* temp    = (const float*)d_in[13];
    const float* pin_w   = (const float*)d_in[14];
    const float* dwf_w   = (const float*)d_in[15];
    const float* pout_w  = (const float*)d_in[16];
    float* out = (float*)d_out;

    cudaFuncSetAttribute(gemm96,   cudaFuncAttributeMaxDynamicSharedMemorySize, G96_SMEM_BYTES);
    cudaFuncSetAttribute(gemmPout, cudaFuncAttributeMaxDynamicSharedMemorySize, G96_SMEM_BYTES);
    cudaFuncSetAttribute(gemm4_tc, cudaFuncAttributeMaxDynamicSharedMemorySize, GEMM_SMEM_BYTES);

    __nv_bfloat16 *qkvA, *qkvAd, *qkvB, *qkvBd, *t;
    float *x1, *gate, *stsX, *stsY, *stsX1, *gpA, *gpB, *atA, *atB, *P0, *P1;
    uint32_t *prepQA, *prepQB, *prepPin, *prepPout_p, *prepC0, *prepC1, *cwApk, *cwBpk;
    float *sQA, *tQA, *sQB, *tQB, *sPin, *tPin;
    cudaGetSymbolAddress((void**)&qkvA,   g_qkvA);
    cudaGetSymbolAddress((void**)&qkvAd,  g_qkvAd);
    cudaGetSymbolAddress((void**)&qkvB,   g_qkvB);
    cudaGetSymbolAddress((void**)&qkvBd,  g_qkvBd);
    cudaGetSymbolAddress((void**)&t,      g_t);
    cudaGetSymbolAddress((void**)&x1,     g_x1);
    cudaGetSymbolAddress((void**)&gate,   g_gate);
    cudaGetSymbolAddress((void**)&stsX,   g_stsX);
    cudaGetSymbolAddress((void**)&stsY,   g_stsY);
    cudaGetSymbolAddress((void**)&stsX1,  g_stsX1);
    cudaGetSymbolAddress((void**)&gpA,    g_gpartA);
    cudaGetSymbolAddress((void**)&gpB,    g_gpartB);
    cudaGetSymbolAddress((void**)&atA,    g_attnA);
    cudaGetSymbolAddress((void**)&atB,    g_attnB);
    cudaGetSymbolAddress((void**)&P0,     g_P0);
    cudaGetSymbolAddress((void**)&P1,     g_P1);
    cudaGetSymbolAddress((void**)&prepQA,   g_prepQA);
    cudaGetSymbolAddress((void**)&prepQB,   g_prepQB);
    cudaGetSymbolAddress((void**)&prepPin,  g_prepPin);
    cudaGetSymbolAddress((void**)&prepPout_p, g_prepPout);
    cudaGetSymbolAddress((void**)&prepC0,   g_prepC0);
    cudaGetSymbolAddress((void**)&prepC1,   g_prepC1);
    cudaGetSymbolAddress((void**)&cwApk,    g_cwApk);
    cudaGetSymbolAddress((void**)&cwBpk,    g_cwBpk);
    cudaGetSymbolAddress((void**)&sQA,    g_sQA);
    cudaGetSymbolAddress((void**)&tQA,    g_tQA);
    cudaGetSymbolAddress((void**)&sQB,    g_sQB);
    cudaGetSymbolAddress((void**)&tQB,    g_tQB);
    cudaGetSymbolAddress((void**)&sPin,   g_sPin);
    cudaGetSymbolAddress((void**)&tPin,   g_tPin);

    const size_t P96   = (size_t)CDIM * HW;       // fp32 input batch stride
    const size_t P288E = (size_t)3 * CDIM * HW;   // bf16 qkv batch stride (elements)
    const size_t P510E = (size_t)2 * HIDDEN * HW; // bf16 t batch stride
    const size_t PGATE = (size_t)288 * HW;

    // weight prep
    prep_kernel<<<3, 256>>>(qkvA_w, 288, ln1_w, ln1_b, prepQA, sQA, tQA);
    prep_kernel<<<3, 256>>>(qkvB_w, 288, ln1_w, ln1_b, prepQB, sQB, tQB);
    prep_kernel<<<6, 256>>>(pin_w,  510, ln2_w, ln2_b, prepPin, sPin, tPin);
    prep_pout<<<3, 256>>>(pout_w, prepPout_p);
    pack96_kernel<<<1, 256>>>(concat_w,      192, prepC0);
    pack96_kernel<<<1, 256>>>(concat_w + 96, 192, prepC1);
    {
        dim3 g(2, 18);
        wprod_kernel<<<g, 256>>>(concat_w, projA_w, projB_w, P0, P1);
    }

    // stats for x and y in one launch
    {
        dim3 g(HW / 256, BATCH, 2);
        stats2_kernel<<<g, 256>>>(x, y, (float2*)stsX, (float2*)stsY);
    }

    // qkv for both branches in one launch (bf16 out)
    {
        G96P p;
        p.Apk[0] = prepQA; p.Apk[1] = prepQB;
        p.sv[0] = sQA; p.sv[1] = sQB;
        p.tv[0] = tQA; p.tv[1] = tQB;
        p.X[0] = x; p.X[1] = y;
        p.sts[0] = (const float2*)stsX; p.sts[1] = (const float2*)stsY;
        p.Y[0] = qkvA; p.Y[1] = qkvB;
        dim3 g(3, HW / 128, BATCH * 2);
        gemm96<<<g, 256, G96_SMEM_BYTES>>>(p, 288, 2, P96, P288E);
    }

    // depthwise 3x3, both branches, 4px/thread, bf16
    {
        dim3 blk(32, 8), g(IMG / 128, IMG / 8, 2 * BATCH * 288);
        dw3_kernel<<<g, blk>>>(qkvA, qkvB, dwA_w, dwB_w, qkvAd, qkvBd);
    }

    // Gram + fused norms, both branches
    {
        dim3 g(32, HEADS, 2 * BATCH);
        gram1_kernel<<<g, 256>>>(qkvAd, qkvBd, gpA, gpB);
    }

    attn_kernel<<<BATCH * HEADS, 192>>>(gpA, gpB, temp, atA, atB);
    {
        dim3 g(4, 6);
        cw_kernel<<<g, 256>>>(P0, P1, atA, atB, cwApk, cwBpk);
    }

    // fused x1 = x + cwA@vA + cwB@vB + concat0@LN(x) + concat1@LN(y)
    {
        G4 p;
        p.Apk[0] = cwApk;  p.aBatch[0] = 9216;
        p.Apk[1] = cwBpk;  p.aBatch[1] = 9216;
        p.Apk[2] = prepC0; p.aBatch[2] = 0;
        p.Apk[3] = prepC1; p.aBatch[3] = 0;
        p.X[0] = qkvAd + 192 * (size_t)HW; p.xBatch[0] = P288E; p.stats[0] = nullptr; p.isbf16[0] = 1;
        p.X[1] = qkvBd + 192 * (size_t)HW; p.xBatch[1] = P288E; p.stats[1] = nullptr; p.isbf16[1] = 1;
        p.X[2] = x;                        p.xBatch[2] = P96;   p.stats[2] = stsX;    p.isbf16[2] = 0;
        p.X[3] = y;                        p.xBatch[3] = P96;   p.stats[3] = stsY;    p.isbf16[3] = 0;
        dim3 g(1, HW / 128, BATCH);
        gemm4_tc<<<g, 256, GEMM_SMEM_BYTES>>>(p, ln1_w, ln1_b, x, x1);
    }

    {
        dim3 g(HW / 256, BATCH);
        stats_kernel<<<g, 256>>>(x1, (float2*)stsX1);
    }

    // pin = W@LN2(x1) -> t (bf16)
    {
        G96P p;
        p.Apk[0] = prepPin; p.Apk[1] = prepPin;
        p.sv[0] = sPin; p.sv[1] = sPin;
        p.tv[0] = tPin; p.tv[1] = tPin;
        p.X[0] = x1; p.X[1] = x1;
        p.sts[0] = (const float2*)stsX1; p.sts[1] = (const float2*)stsX1;
        p.Y[0] = t; p.Y[1] = t;
        dim3 g(6, HW / 128, BATCH);
        gemm96<<<g, 256, G96_SMEM_BYTES>>>(p, 510, 1, P96, P510E);
    }

    // fused depthwise + gelu gate, 4px/thread (bf16 in, fp32 288-pitch out)
    {
        dim3 blk(32, 8), g(IMG / 128, IMG / 8, BATCH * HIDDEN);
        dwgate_kernel<<<g, blk>>>(t, dwf_w, gate);
    }

    // pout pipelined (K padded to 288) + residual x1 -> final output
    {
        dim3 g(1, HW / 128, BATCH);
        gemmPout<<<g, 256, G96_SMEM_BYTES>>>(prepPout_p, gate, x1, out,
                                             PGATE, P96, P96);
    }
}

// round 9
// speedup vs baseline: 3.8050x; 1.0062x over previous
#include <cuda_runtime.h>
#include <cuda_bf16.h>
#include <math.h>
#include <stdint.h>

#define HW      65536
#define IMG     256
#define BATCH   2
#define CDIM    96
#define HEADS   8
#define CHEAD   12
#define HIDDEN  255

// ---------------------------------------------------------------------------
// Scratch
// ---------------------------------------------------------------------------
__device__ __nv_bfloat16 g_qkvA [BATCH * 3 * CDIM * HW];
__device__ __nv_bfloat16 g_qkvAd[BATCH * 3 * CDIM * HW];
__device__ __nv_bfloat16 g_qkvB [BATCH * 3 * CDIM * HW];
__device__ __nv_bfloat16 g_qkvBd[BATCH * 3 * CDIM * HW];
__device__ __nv_bfloat16 g_t    [BATCH * 2 * HIDDEN * HW];
__device__ __nv_bfloat16 g_gate [BATCH * 288 * HW];   // 288-pitch; rows 255..287 stay zero
__device__ float g_x1   [BATCH * CDIM * HW];
__device__ float g_stsX [BATCH * HW * 2];
__device__ float g_stsY [BATCH * HW * 2];
__device__ float g_gpartA[BATCH * HEADS * 256 * 168];
__device__ float g_gpartB[BATCH * HEADS * 256 * 168];
__device__ float g_attnA [BATCH * HEADS * 144];
__device__ float g_attnB [BATCH * HEADS * 144];
__device__ float g_P0  [CDIM * CDIM];
__device__ float g_P1  [CDIM * CDIM];
// prepacked tf32 fragment tiles
__device__ uint32_t g_prepQA  [3 * 9216];
__device__ uint32_t g_prepQB  [3 * 9216];
__device__ uint32_t g_prepPin [6 * 9216];
__device__ uint32_t g_prepPout[3 * 9216];
__device__ uint32_t g_prepC0  [9216];
__device__ uint32_t g_prepC1  [9216];
__device__ uint32_t g_cwApk   [BATCH * 9216];
__device__ uint32_t g_cwBpk   [BATCH * 9216];
__device__ float g_sQA[288],  g_tQA[288];
__device__ float g_sQB[288],  g_tQB[288];
__device__ float g_sPin[576], g_tPin[576];

// ---------------------------------------------------------------------------
// tf32 / cp.async helpers
// ---------------------------------------------------------------------------
__device__ __forceinline__ uint32_t f2tf(float f) {
    uint32_t u;
    asm("cvt.rna.tf32.f32 %0, %1;" : "=r"(u) : "f"(f));
    return u;
}

__device__ __forceinline__ void mma_tf32(float* c, const uint32_t* a, const uint32_t* b) {
    asm volatile(
        "mma.sync.aligned.m16n8k8.row.col.f32.tf32.tf32.f32 "
        "{%0,%1,%2,%3}, {%4,%5,%6,%7}, {%8,%9}, {%0,%1,%2,%3};"
        : "+f"(c[0]), "+f"(c[1]), "+f"(c[2]), "+f"(c[3])
        : "r"(a[0]), "r"(a[1]), "r"(a[2]), "r"(a[3]), "r"(b[0]), "r"(b[1]));
}

__device__ __forceinline__ void cp16(void* smem, const void* gmem) {
    uint32_t a = (uint32_t)__cvta_generic_to_shared(smem);
    asm volatile("cp.async.cg.shared.global [%0], [%1], 16;\n" :: "r"(a), "l"(gmem));
}
#define CP_COMMIT()  asm volatile("cp.async.commit_group;\n")
#define CP_WAIT(n)   asm volatile("cp.async.wait_group %0;\n" :: "n"(n))

__device__ __forceinline__ int a_pack_off(int m, int k) {
    return (k >> 3) * 768 + (m >> 4) * 128 + (m & 7) * 16 + (k & 3) * 4
         + ((k >> 2) & 1) * 2 + ((m >> 3) & 1);
}

#define GEMM_SMEM_WORDS (9216 + 96*136 + 128 + 128 + 96 + 96)
#define GEMM_SMEM_BYTES (GEMM_SMEM_WORDS * 4)
#define G96_SMEM_WORDS  (9216 + 2*32*136 + 256)
#define G96_SMEM_BYTES  (G96_SMEM_WORDS * 4)

// ---------------------------------------------------------------------------
// Mega-prep: all weight preprocessing in ONE launch (53 blocks).
//   bid 0..2   prep qkvA (LN1 fold) ; 3..5 prep qkvB ; 6..11 prep pin (LN2)
//   bid 12..14 pack pout stage      ; 15/16 pack concat halves
//   bid 17..52 wprod (P0/P1)
// ---------------------------------------------------------------------------
__device__ void prep_tile(const float* __restrict__ W, int M, int tile,
                          const float* __restrict__ wln,
                          const float* __restrict__ bln,
                          uint32_t* __restrict__ Apk,
                          float* __restrict__ svec, float* __restrict__ tvec,
                          float* wls, float* bls) {
    int m0 = tile * 96;
    if (threadIdx.x < 96) { wls[threadIdx.x] = wln[threadIdx.x]; bls[threadIdx.x] = bln[threadIdx.x]; }
    __syncthreads();
#pragma unroll
    for (int i = 0; i < 36; i++) {
        int idx = threadIdx.x + i * 256;
        int m = idx / 96;
        int k = idx - m * 96;
        float v = 0.f;
        if (m0 + m < M) v = W[(size_t)(m0 + m) * 96 + k] * wls[k];
        Apk[tile * 9216 + a_pack_off(m, k)] = f2tf(v);
    }
    if (threadIdx.x < 96) {
        int gm = m0 + threadIdx.x;
        float s = 0.f, tt = 0.f;
        if (gm < M) {
            for (int k = 0; k < 96; k++) {
                float w = W[(size_t)gm * 96 + k];
                s  += w * wls[k];
                tt += w * bls[k];
            }
        }
        svec[tile * 96 + threadIdx.x] = s;
        tvec[tile * 96 + threadIdx.x] = tt;
    }
}

__global__ void megaprep(
        const float* __restrict__ qkvA_w, const float* __restrict__ qkvB_w,
        const float* __restrict__ pin_w,  const float* __restrict__ pout_w,
        const float* __restrict__ concat_w,
        const float* __restrict__ projA_w, const float* __restrict__ projB_w,
        const float* __restrict__ ln1_w, const float* __restrict__ ln1_b,
        const float* __restrict__ ln2_w, const float* __restrict__ ln2_b,
        uint32_t* __restrict__ prepQA, uint32_t* __restrict__ prepQB,
        uint32_t* __restrict__ prepPin, uint32_t* __restrict__ prepPout,
        uint32_t* __restrict__ prepC0, uint32_t* __restrict__ prepC1,
        float* __restrict__ sQA, float* __restrict__ tQA,
        float* __restrict__ sQB, float* __restrict__ tQB,
        float* __restrict__ sPin, float* __restrict__ tPin,
        float* __restrict__ P0, float* __restrict__ P1) {
    __shared__ float sbuf[96 * 96];
    int bid = blockIdx.x;
    if (bid < 3) {
        prep_tile(qkvA_w, 288, bid, ln1_w, ln1_b, prepQA, sQA, tQA, sbuf, sbuf + 96);
    } else if (bid < 6) {
        prep_tile(qkvB_w, 288, bid - 3, ln1_w, ln1_b, prepQB, sQB, tQB, sbuf, sbuf + 96);
    } else if (bid < 12) {
        prep_tile(pin_w, 510, bid - 6, ln2_w, ln2_b, prepPin, sPin, tPin, sbuf, sbuf + 96);
    } else if (bid < 15) {
        int s = bid - 12;
#pragma unroll
        for (int i = 0; i < 36; i++) {
            int idx = threadIdx.x + i * 256;
            int m = idx / 96;
            int k = idx - m * 96;
            int kg = s * 96 + k;
            float v = (kg < HIDDEN) ? pout_w[(size_t)m * HIDDEN + kg] : 0.f;
            prepPout[s * 9216 + a_pack_off(m, k)] = f2tf(v);
        }
    } else if (bid < 17) {
        const float* W = concat_w + (bid == 16 ? 96 : 0);
        uint32_t* out = (bid == 16) ? prepC1 : prepC0;
#pragma unroll
        for (int i = 0; i < 36; i++) {
            int idx = threadIdx.x + i * 256;
            int m = idx / 96;
            int k = idx - m * 96;
            out[a_pack_off(m, k)] = f2tf(W[(size_t)m * 192 + k]);
        }
    } else {
        int w = bid - 17;
        int br = w & 1;
        int yt = w >> 1;
        const float* proj = br ? projB_w : projA_w;
        const float* cw   = concat_w + (br ? 96 : 0);
        float* P = br ? P1 : P0;
        for (int i = threadIdx.x; i < 96 * 96; i += 256) sbuf[i] = proj[i];
        __syncthreads();
        int base = yt * 512;
#pragma unroll
        for (int r = 0; r < 2; r++) {
            int o = base + r * 256 + threadIdx.x;
            int m = o / 96, n = o % 96;
            float s = 0.f;
#pragma unroll 8
            for (int c = 0; c < 96; c++) s += cw[m * 192 + c] * sbuf[c * 96 + n];
            P[o] = s;
        }
    }
}

// ---------------------------------------------------------------------------
// 32-k MMA chunk on the 96x128 tile.
// ---------------------------------------------------------------------------
__device__ __forceinline__ void g96_chunk(
        float acc[3][4][4], const uint32_t* __restrict__ As,
        const uint32_t* __restrict__ Bbuf,
        int kc, int g, int t, int wmi, int wn) {
#pragma unroll
    for (int ks2 = 0; ks2 < 4; ks2++) {
        const uint32_t* Ab = As + (kc * 4 + ks2) * 768 + g * 16 + t * 4;
        const uint32_t* Bb = Bbuf + (ks2 * 8 + t) * 136 + wn + g;
        uint4 a4[3];
        uint32_t bf[4][2];
#pragma unroll
        for (int mi = 0; mi < 3; mi++)
            a4[mi] = *reinterpret_cast<const uint4*>(Ab + (wmi + mi) * 128);
#pragma unroll
        for (int ni = 0; ni < 4; ni++) {
            bf[ni][0] = Bb[ni * 8];
            bf[ni][1] = Bb[4 * 136 + ni * 8];
        }
#pragma unroll
        for (int mi = 0; mi < 3; mi++) {
            uint32_t af[4] = {a4[mi].x, a4[mi].y, a4[mi].z, a4[mi].w};
#pragma unroll
            for (int ni = 0; ni < 4; ni++)
                mma_tf32(acc[mi][ni], af, bf[ni]);
        }
    }
}

// ---------------------------------------------------------------------------
// K=96 pipelined tf32 GEMM with SELF-COMPUTED LayerNorm stats.
// Thread<128 owns column tid: accumulates sum/sumsq from the staged raw B
// chunks, finalizes (mu, inv) before the factored-LN epilogue. mtile==0
// optionally persists stats for downstream consumers (gemm4).
// ---------------------------------------------------------------------------
struct G96P {
    const uint32_t* Apk[2];
    const float*    sv[2];
    const float*    tv[2];
    const float*    X[2];
    float2*         stsOut[2];   // may be null
    __nv_bfloat16*  Y[2];
};

__global__ void __launch_bounds__(256, 3) gemm96(
        G96P p, int M, int NB, size_t xBatch, size_t yBatch) {
    extern __shared__ uint32_t sm[];
    uint32_t* As = sm;
    uint32_t* Bs = sm + 9216;
    float* mu_s  = (float*)(sm + 9216 + 8704);
    float* inv_s = mu_s + 128;

    int z  = blockIdx.z;
    int br = z % NB;
    int bz = z / NB;
    const float* Xb = p.X[br] + (size_t)bz * xBatch;
    __nv_bfloat16* Yb = p.Y[br] + (size_t)bz * yBatch;
    const float* svec = p.sv[br];
    const float* tvec = p.tv[br];

    int mtile = blockIdx.x;
    int m0 = mtile * 96;
    int n0 = blockIdx.y * 128;
    int tid  = threadIdx.x;
    int warp = tid >> 5;
    int lane = tid & 31;
    int g = lane >> 2;
    int t = lane & 3;
    int wm  = (warp >> 2) * 48;
    int wmi = (warp >> 2) * 3;
    int wn  = (warp & 3) * 32;

    {
        const uint4* Ag = reinterpret_cast<const uint4*>(p.Apk[br] + (size_t)mtile * 9216);
#pragma unroll
        for (int i = 0; i < 9; i++) {
            int idx = tid + i * 256;
            cp16(As + idx * 4, Ag + idx);
        }
    }
#pragma unroll
    for (int j = 0; j < 4; j++) {
        int idx = tid + j * 256;
        int k = idx >> 5, n4 = idx & 31;
        cp16(Bs + k * 136 + n4 * 4, Xb + (size_t)k * HW + n0 + n4 * 4);
    }
    CP_COMMIT();
#pragma unroll
    for (int j = 0; j < 4; j++) {
        int idx = tid + j * 256;
        int k = idx >> 5, n4 = idx & 31;
        cp16(Bs + 4352 + k * 136 + n4 * 4, Xb + (size_t)(32 + k) * HW + n0 + n4 * 4);
    }
    CP_COMMIT();

    float acc[3][4][4];
#pragma unroll
    for (int mi = 0; mi < 3; mi++)
#pragma unroll
        for (int ni = 0; ni < 4; ni++)
#pragma unroll
            for (int r = 0; r < 4; r++) acc[mi][ni][r] = 0.f;

    float csum = 0.f, csq = 0.f;
#define STATS_ACC(BUF)                                                      \
    if (tid < 128) {                                                        \
        _Pragma("unroll 8")                                                 \
        for (int k = 0; k < 32; k++) {                                      \
            float v = __uint_as_float((BUF)[k * 136 + tid]);                \
            csum += v; csq += v * v;                                        \
        }                                                                   \
    }

    CP_WAIT(1);
    __syncthreads();
    STATS_ACC(Bs);
    g96_chunk(acc, As, Bs, 0, g, t, wmi, wn);
    __syncthreads();
#pragma unroll
    for (int j = 0; j < 4; j++) {
        int idx = tid + j * 256;
        int k = idx >> 5, n4 = idx & 31;
        cp16(Bs + k * 136 + n4 * 4, Xb + (size_t)(64 + k) * HW + n0 + n4 * 4);
    }
    CP_COMMIT();
    CP_WAIT(1);
    __syncthreads();
    STATS_ACC(Bs + 4352);
    g96_chunk(acc, As, Bs + 4352, 1, g, t, wmi, wn);
    CP_WAIT(0);
    __syncthreads();
    STATS_ACC(Bs);
    g96_chunk(acc, As, Bs, 2, g, t, wmi, wn);
#undef STATS_ACC

    if (tid < 128) {
        float mu  = csum * (1.f / 96.f);
        float var = csq * (1.f / 96.f) - mu * mu;
        float inv = rsqrtf(var + 1e-5f);
        mu_s[tid]  = mu;
        inv_s[tid] = inv;
        if (mtile == 0 && p.stsOut[br] != nullptr)
            p.stsOut[br][(size_t)bz * HW + n0 + tid] = make_float2(mu, inv);
    }
    __syncthreads();

#pragma unroll
    for (int mi = 0; mi < 3; mi++) {
        int r0 = m0 + wm + mi * 16 + g;
        int r1 = r0 + 8;
        float s0 = 0.f, t0 = 0.f, s1 = 0.f, t1 = 0.f;
        if (r0 < M) { s0 = svec[r0]; t0 = tvec[r0]; }
        if (r1 < M) { s1 = svec[r1]; t1 = tvec[r1]; }
#pragma unroll
        for (int ni = 0; ni < 4; ni++) {
            int ln = wn + ni * 8 + 2 * t;
            int col = n0 + ln;
            float i0 = inv_s[ln],     m0v = mu_s[ln]     * i0;
            float i1 = inv_s[ln + 1], m1v = mu_s[ln + 1] * i1;
            if (r0 < M) {
                float vx = acc[mi][ni][0] * i0 - m0v * s0 + t0;
                float vy = acc[mi][ni][1] * i1 - m1v * s0 + t0;
                *reinterpret_cast<__nv_bfloat162*>(Yb + (size_t)r0 * HW + col) =
                    __floats2bfloat162_rn(vx, vy);
            }
            if (r1 < M) {
                float vx = acc[mi][ni][2] * i0 - m0v * s1 + t1;
                float vy = acc[mi][ni][3] * i1 - m1v * s1 + t1;
                *reinterpret_cast<__nv_bfloat162*>(Yb + (size_t)r1 * HW + col) =
                    __floats2bfloat162_rn(vx, vy);
            }
        }
    }
}

// ---------------------------------------------------------------------------
// pout: K=288 zero-padded, bf16 B with register-prefetch double buffering,
// prepacked A via cp.async. bf16->fp32 by bit shift (tf32 truncates anyway).
// ---------------------------------------------------------------------------
__global__ void __launch_bounds__(256, 3) gemmPout(
        const uint32_t* __restrict__ Apk,
        const __nv_bfloat16* __restrict__ X,
        const float* __restrict__ Rsrc,
        float* __restrict__ Y,
        size_t xBatch, size_t yBatch, size_t rBatch) {
    extern __shared__ uint32_t sm[];
    uint32_t* As = sm;
    uint32_t* Bs = sm + 9216;

    int bz = blockIdx.z;
    const __nv_bfloat16* Xb = X + (size_t)bz * xBatch;
    float*       Yb = Y    + (size_t)bz * yBatch;
    const float* Rb = Rsrc + (size_t)bz * rBatch;

    int n0 = blockIdx.y * 128;
    int tid  = threadIdx.x;
    int warp = tid >> 5;
    int lane = tid & 31;
    int g = lane >> 2;
    int t = lane & 3;
    int wm  = (warp >> 2) * 48;
    int wmi = (warp >> 2) * 3;
    int wn  = (warp & 3) * 32;

    // per-thread B slot: 16 bf16 at (row kk, cols nb..nb+15)
    int kk = tid >> 3;
    int nb = (tid & 7) * 16;

    uint4 rA, rB;
#define LDGB(c)                                                             \
    {                                                                       \
        const uint4* src = reinterpret_cast<const uint4*>(                  \
            Xb + (size_t)((c) * 32 + kk) * HW + n0 + nb);                   \
        rA = src[0]; rB = src[1];                                           \
    }
#define STSB(c)                                                             \
    {                                                                       \
        uint32_t* dst = Bs + ((c) & 1) * 4352 + kk * 136 + nb;              \
        uint32_t u;                                                         \
        u = rA.x; dst[0]  = u << 16; dst[1]  = u & 0xFFFF0000u;             \
        u = rA.y; dst[2]  = u << 16; dst[3]  = u & 0xFFFF0000u;             \
        u = rA.z; dst[4]  = u << 16; dst[5]  = u & 0xFFFF0000u;             \
        u = rA.w; dst[6]  = u << 16; dst[7]  = u & 0xFFFF0000u;             \
        u = rB.x; dst[8]  = u << 16; dst[9]  = u & 0xFFFF0000u;             \
        u = rB.y; dst[10] = u << 16; dst[11] = u & 0xFFFF0000u;             \
        u = rB.z; dst[12] = u << 16; dst[13] = u & 0xFFFF0000u;             \
        u = rB.w; dst[14] = u << 16; dst[15] = u & 0xFFFF0000u;             \
    }
#define LOADA(s)                                                            \
    {                                                                       \
        const uint4* Ag = reinterpret_cast<const uint4*>(Apk + (s) * 9216); \
        _Pragma("unroll")                                                   \
        for (int i = 0; i < 9; i++) {                                       \
            int idx = tid + i * 256;                                        \
            cp16(As + idx * 4, Ag + idx);                                   \
        }                                                                   \
        CP_COMMIT();                                                        \
    }

    LOADA(0);
    LDGB(0);
    STSB(0);
    LDGB(1);
    CP_WAIT(0);
    __syncthreads();

    float acc[3][4][4];
#pragma unroll
    for (int mi = 0; mi < 3; mi++)
#pragma unroll
        for (int ni = 0; ni < 4; ni++)
#pragma unroll
            for (int r = 0; r < 4; r++) acc[mi][ni][r] = 0.f;

#pragma unroll
    for (int c = 0; c < 9; c++) {
        g96_chunk(acc, As, Bs + (c & 1) * 4352, c % 3, g, t, wmi, wn);
        if (c < 8) {
            __syncthreads();
            bool newA = (c % 3 == 2);
            if (newA) LOADA(c / 3 + 1);
            STSB(c + 1);
            if (c + 2 <= 8) LDGB(c + 2);
            if (newA) CP_WAIT(0);
            __syncthreads();
        }
    }
#undef LOADA
#undef LDGB
#undef STSB

#pragma unroll
    for (int mi = 0; mi < 3; mi++) {
        int r0 = wm + mi * 16 + g;
        int r1 = r0 + 8;
#pragma unroll
        for (int ni = 0; ni < 4; ni++) {
            int col = n0 + wn + ni * 8 + 2 * t;
            float2 ra = *reinterpret_cast<const float2*>(Rb + (size_t)r0 * HW + col);
            float2 rb = *reinterpret_cast<const float2*>(Rb + (size_t)r1 * HW + col);
            float2 v01 = make_float2(acc[mi][ni][0] + ra.x, acc[mi][ni][1] + ra.y);
            float2 v23 = make_float2(acc[mi][ni][2] + rb.x, acc[mi][ni][3] + rb.y);
            *reinterpret_cast<float2*>(Yb + (size_t)r0 * HW + col) = v01;
            *reinterpret_cast<float2*>(Yb + (size_t)r1 * HW + col) = v23;
        }
    }
}

// ---------------------------------------------------------------------------
// 4-source fused GEMM for x1; v sources bf16, LN sources fp32.
// ---------------------------------------------------------------------------
struct G4 {
    const uint32_t* Apk[4];
    size_t          aBatch[4];
    const void*     X[4];
    size_t          xBatch[4];
    const float*    stats[4];
    int             isbf16[4];
};

__global__ void __launch_bounds__(256, 2) gemm4_tc(
        G4 p,
        const float* __restrict__ lnw,
        const float* __restrict__ lnb,
        const float* __restrict__ Rsrc,
        float* __restrict__ Y) {
    extern __shared__ uint32_t smem_u[];
    uint32_t* As  = smem_u;
    uint32_t* Bs  = As + 9216;
    float* mu_s   = (float*)(Bs + 96 * 136);
    float* inv_s  = mu_s + 128;
    float* wln_s  = inv_s + 128;
    float* bln_s  = wln_s + 96;

    int bz = blockIdx.z;
    int n0 = blockIdx.y * 128;
    float*       Yb = Y    + (size_t)bz * CDIM * HW;
    const float* Rb = Rsrc + (size_t)bz * CDIM * HW;

    int tid  = threadIdx.x;
    int warp = tid >> 5;
    int lane = tid & 31;
    int g = lane >> 2;
    int t = lane & 3;
    int wm  = (warp >> 2) * 48;
    int wmi = (warp >> 2) * 3;
    int wn  = (warp & 3) * 32;

    if (tid < 96) { wln_s[tid] = lnw[tid]; bln_s[tid] = lnb[tid]; }

    float acc[3][4][4];
#pragma unroll
    for (int mi = 0; mi < 3; mi++)
#pragma unroll
        for (int ni = 0; ni < 4; ni++)
#pragma unroll
            for (int r = 0; r < 4; r++) acc[mi][ni][r] = 0.f;

    for (int s = 0; s < 4; s++) {
        __syncthreads();
        {
            const uint4* Ag = reinterpret_cast<const uint4*>(p.Apk[s] + (size_t)bz * p.aBatch[s]);
#pragma unroll
            for (int i = 0; i < 9; i++) {
                int idx = tid + i * 256;
                cp16(As + idx * 4, Ag + idx);
            }
            CP_COMMIT();
        }
        if (p.isbf16[s]) {
            const __nv_bfloat16* Xh = (const __nv_bfloat16*)p.X[s] + (size_t)bz * p.xBatch[s];
#pragma unroll
            for (int i = 0; i < 6; i++) {
                int idx = tid + i * 256;
                int k = idx >> 4, n8 = idx & 15;
                const uint32_t* src =
                    reinterpret_cast<const uint32_t*>(Xh + (size_t)k * HW + n0 + n8 * 8);
                uint32_t* dst = Bs + k * 136 + n8 * 8;
#pragma unroll
                for (int j = 0; j < 4; j++) {
                    uint32_t u = src[j];
                    dst[2 * j]     = u << 16;
                    dst[2 * j + 1] = u & 0xFFFF0000u;
                }
            }
        } else {
            const float* Xb = (const float*)p.X[s] + (size_t)bz * p.xBatch[s];
            bool ln = (p.stats[s] != nullptr);
            if (ln && tid < 128) {
                float2 sv = reinterpret_cast<const float2*>(p.stats[s])[(size_t)bz * HW + n0 + tid];
                mu_s[tid]  = sv.x;
                inv_s[tid] = sv.y;
            }
            if (ln) __syncthreads();
#pragma unroll
            for (int i = 0; i < 12; i++) {
                int idx = tid + i * 256;
                int k  = idx >> 5;
                int n4 = idx & 31;
                float4 v = reinterpret_cast<const float4*>(Xb + (size_t)k * HW + n0)[n4];
                if (ln) {
                    int nbq = n4 * 4;
                    float wk = wln_s[k], bk = bln_s[k];
                    v.x = (v.x - mu_s[nbq + 0]) * inv_s[nbq + 0] * wk + bk;
                    v.y = (v.y - mu_s[nbq + 1]) * inv_s[nbq + 1] * wk + bk;
                    v.z = (v.z - mu_s[nbq + 2]) * inv_s[nbq + 2] * wk + bk;
                    v.w = (v.w - mu_s[nbq + 3]) * inv_s[nbq + 3] * wk + bk;
                }
                uint4 u = make_uint4(__float_as_uint(v.x), __float_as_uint(v.y),
                                     __float_as_uint(v.z), __float_as_uint(v.w));
                *reinterpret_cast<uint4*>(Bs + k * 136 + n4 * 4) = u;
            }
        }
        CP_WAIT(0);
        __syncthreads();
#pragma unroll
        for (int ks = 0; ks < 12; ks++) {
            const uint32_t* Ab = As + ks * 768 + g * 16 + t * 4;
            const uint32_t* Bb = Bs + (ks * 8 + t) * 136 + wn + g;
            uint4 a4[3];
            uint32_t bf[4][2];
#pragma unroll
            for (int mi = 0; mi < 3; mi++)
                a4[mi] = *reinterpret_cast<const uint4*>(Ab + (wmi + mi) * 128);
#pragma unroll
            for (int ni = 0; ni < 4; ni++) {
                bf[ni][0] = Bb[ni * 8];
                bf[ni][1] = Bb[4 * 136 + ni * 8];
            }
#pragma unroll
            for (int mi = 0; mi < 3; mi++) {
                uint32_t af[4] = {a4[mi].x, a4[mi].y, a4[mi].z, a4[mi].w};
#pragma unroll
                for (int ni = 0; ni < 4; ni++)
                    mma_tf32(acc[mi][ni], af, bf[ni]);
            }
        }
    }

#pragma unroll
    for (int mi = 0; mi < 3; mi++) {
        int r0 = wm + mi * 16 + g;
        int r1 = r0 + 8;
#pragma unroll
        for (int ni = 0; ni < 4; ni++) {
            int col = n0 + wn + ni * 8 + 2 * t;
            float2 ra = *reinterpret_cast<const float2*>(Rb + (size_t)r0 * HW + col);
            float2 rb = *reinterpret_cast<const float2*>(Rb + (size_t)r1 * HW + col);
            float2 v01 = make_float2(acc[mi][ni][0] + ra.x, acc[mi][ni][1] + ra.y);
            float2 v23 = make_float2(acc[mi][ni][2] + rb.x, acc[mi][ni][3] + rb.y);
            *reinterpret_cast<float2*>(Yb + (size_t)r0 * HW + col) = v01;
            *reinterpret_cast<float2*>(Yb + (size_t)r1 * HW + col) = v23;
        }
    }
}

// ---------------------------------------------------------------------------
// Depthwise 3x3, bf16 in/out, 4 px per thread, both branches in one launch.
// ---------------------------------------------------------------------------
__global__ void dw3_kernel(const __nv_bfloat16* __restrict__ qA,
                           const __nv_bfloat16* __restrict__ qB,
                           const float* __restrict__ wA,
                           const float* __restrict__ wB,
                           __nv_bfloat16* __restrict__ oA,
                           __nv_bfloat16* __restrict__ oB) {
    int pl = blockIdx.z;
    int br = pl >= BATCH * 288;
    int rem = pl - br * BATCH * 288;
    int c = rem % 288;
    const __nv_bfloat16* ip = (br ? qB : qA) + (size_t)rem * HW;
    const float* wp = (br ? wB : wA) + c * 9;
    __nv_bfloat16* op = (br ? oB : oA) + (size_t)rem * HW;

    int x0 = (blockIdx.x * 32 + threadIdx.x) * 4;
    int y  = blockIdx.y * 8 + threadIdx.y;

    float w[9];
#pragma unroll
    for (int i = 0; i < 9; i++) w[i] = wp[i];

    float acc[4] = {0.f, 0.f, 0.f, 0.f};
#pragma unroll
    for (int dy = -1; dy <= 1; dy++) {
        int yy = y + dy;
        if (yy < 0 || yy >= IMG) continue;
        const __nv_bfloat16* row = ip + yy * IMG;
        float v[6];
        v[0] = (x0 > 0) ? __bfloat162float(row[x0 - 1]) : 0.f;
        {
            const __nv_bfloat162* r2 = reinterpret_cast<const __nv_bfloat162*>(row + x0);
            float2 a = __bfloat1622float2(r2[0]);
            float2 b = __bfloat1622float2(r2[1]);
            v[1] = a.x; v[2] = a.y; v[3] = b.x; v[4] = b.y;
        }
        v[5] = (x0 + 4 < IMG) ? __bfloat162float(row[x0 + 4]) : 0.f;
        const float* wr = w + (dy + 1) * 3;
#pragma unroll
        for (int j = 0; j < 4; j++)
            acc[j] += wr[0] * v[j] + wr[1] * v[j + 1] + wr[2] * v[j + 2];
    }

    *reinterpret_cast<__nv_bfloat162*>(op + y * IMG + x0)     = __floats2bfloat162_rn(acc[0], acc[1]);
    *reinterpret_cast<__nv_bfloat162*>(op + y * IMG + x0 + 2) = __floats2bfloat162_rn(acc[2], acc[3]);
}

// ---------------------------------------------------------------------------
// Fused FFN tail: dw3 on both t halves + gelu + multiply; bf16 out, 288-pitch.
// ---------------------------------------------------------------------------
__global__ void dwgate_kernel(const __nv_bfloat16* __restrict__ t,
                              const float* __restrict__ dwf,
                              __nv_bfloat16* __restrict__ gate) {
    int pl = blockIdx.z;
    int b = pl / HIDDEN, k = pl % HIDDEN;
    int x0 = (blockIdx.x * 32 + threadIdx.x) * 4;
    int y  = blockIdx.y * 8 + threadIdx.y;
    const __nv_bfloat16* i1 = t + ((size_t)b * 2 * HIDDEN + k) * HW;
    const __nv_bfloat16* i2 = t + ((size_t)b * 2 * HIDDEN + HIDDEN + k) * HW;
    const float* w1 = dwf + k * 9;
    const float* w2 = dwf + (HIDDEN + k) * 9;

    float wa[9], wb[9];
#pragma unroll
    for (int i = 0; i < 9; i++) { wa[i] = w1[i]; wb[i] = w2[i]; }

    float s1[4] = {0.f, 0.f, 0.f, 0.f};
    float s2[4] = {0.f, 0.f, 0.f, 0.f};
#pragma unroll
    for (int dy = -1; dy <= 1; dy++) {
        int yy = y + dy;
        if (yy < 0 || yy >= IMG) continue;
        const __nv_bfloat16* r1 = i1 + yy * IMG;
        const __nv_bfloat16* r2 = i2 + yy * IMG;
        float v1[6], v2[6];
        v1[0] = (x0 > 0) ? __bfloat162float(r1[x0 - 1]) : 0.f;
        v2[0] = (x0 > 0) ? __bfloat162float(r2[x0 - 1]) : 0.f;
        {
            const __nv_bfloat162* p1 = reinterpret_cast<const __nv_bfloat162*>(r1 + x0);
            const __nv_bfloat162* p2 = reinterpret_cast<const __nv_bfloat162*>(r2 + x0);
            float2 a1 = __bfloat1622float2(p1[0]), b1 = __bfloat1622float2(p1[1]);
            float2 a2 = __bfloat1622float2(p2[0]), b2 = __bfloat1622float2(p2[1]);
            v1[1] = a1.x; v1[2] = a1.y; v1[3] = b1.x; v1[4] = b1.y;
            v2[1] = a2.x; v2[2] = a2.y; v2[3] = b2.x; v2[4] = b2.y;
        }
        v1[5] = (x0 + 4 < IMG) ? __bfloat162float(r1[x0 + 4]) : 0.f;
        v2[5] = (x0 + 4 < IMG) ? __bfloat162float(r2[x0 + 4]) : 0.f;
        const float* wra = wa + (dy + 1) * 3;
        const float* wrb = wb + (dy + 1) * 3;
#pragma unroll
        for (int j = 0; j < 4; j++) {
            s1[j] += wra[0] * v1[j] + wra[1] * v1[j + 1] + wra[2] * v1[j + 2];
            s2[j] += wrb[0] * v2[j] + wrb[1] * v2[j + 1] + wrb[2] * v2[j + 2];
        }
    }

    float o[4];
#pragma unroll
    for (int j = 0; j < 4; j++) {
        float gl = 0.5f * s1[j] * (1.f + erff(s1[j] * 0.7071067811865475f));
        o[j] = gl * s2[j];
    }
    __nv_bfloat16* gp = gate + ((size_t)b * 288 + k) * HW + y * IMG + x0;
    *reinterpret_cast<__nv_bfloat162*>(gp)     = __floats2bfloat162_rn(o[0], o[1]);
    *reinterpret_cast<__nv_bfloat162*>(gp + 2) = __floats2bfloat162_rn(o[2], o[3]);
}

// ---------------------------------------------------------------------------
// Gram stage 1 (bf16 inputs) + fused norms; both branches in one launch.
// ---------------------------------------------------------------------------
__global__ void __launch_bounds__(256) gram1_kernel(
        const __nv_bfloat16* __restrict__ qkvAd,
        const __nv_bfloat16* __restrict__ qkvBd,
        float* __restrict__ gpA, float* __restrict__ gpB) {
    int chunk = blockIdx.x, h = blockIdx.y;
    int b  = blockIdx.z >> 1;
    int br = blockIdx.z & 1;
    const __nv_bfloat16* qb = (br ? qkvAd : qkvBd) + ((size_t)b * 288 + h * CHEAD) * HW;
    const __nv_bfloat16* kb = (br ? qkvBd : qkvAd) + ((size_t)b * 288 + 96 + h * CHEAD) * HW;
    float* part = br ? gpB : gpA;

    float acc[168];
#pragma unroll
    for (int i = 0; i < 168; i++) acc[i] = 0.f;

    int p0 = chunk * 2048 + threadIdx.x;
    for (int it = 0; it < 8; it++) {
        int p = p0 + it * 256;
        float qv[CHEAD], kv[CHEAD];
#pragma unroll
        for (int c = 0; c < CHEAD; c++) qv[c] = __bfloat162float(qb[(size_t)c * HW + p]);
#pragma unroll
        for (int d = 0; d < CHEAD; d++) kv[d] = __bfloat162float(kb[(size_t)d * HW + p]);
#pragma unroll
        for (int c = 0; c < CHEAD; c++)
#pragma unroll
            for (int d = 0; d < CHEAD; d++) acc[c * CHEAD + d] += qv[c] * kv[d];
#pragma unroll
        for (int c = 0; c < CHEAD; c++) acc[144 + c] += qv[c] * qv[c];
#pragma unroll
        for (int d = 0; d < CHEAD; d++) acc[156 + d] += kv[d] * kv[d];
    }

    int warp = threadIdx.x >> 5;
    int lane = threadIdx.x & 31;
    float* outp = part + ((((size_t)(b * HEADS + h)) * 32 + chunk) * 8 + warp) * 168;
#pragma unroll
    for (int i = 0; i < 168; i++) {
        float v = acc[i];
#pragma unroll
        for (int off = 16; off > 0; off >>= 1)
            v += __shfl_down_sync(0xffffffffu, v, off);
        if (lane == 0) outp[i] = v;
    }
}

// ---------------------------------------------------------------------------
// Gram stage 2 + norms + temperature + softmax.
// ---------------------------------------------------------------------------
__global__ void attn_kernel(const float* __restrict__ partA,
                            const float* __restrict__ partB,
                            const float* __restrict__ temp,
                            float* __restrict__ attnA,
                            float* __restrict__ attnB) {
    int bh = blockIdx.x;
    int h = bh % HEADS;
    __shared__ float GA[144], GB[144];
    __shared__ float nqA[12], nkA[12], nqB[12], nkB[12];
    int i = threadIdx.x;
    float sA = 0.f, sB = 0.f;
    if (i < 168) {
        const float* pA = partA + (size_t)bh * 256 * 168 + i;
        const float* pB = partB + (size_t)bh * 256 * 168 + i;
        for (int ch = 0; ch < 256; ch++) {
            sA += pA[(size_t)ch * 168];
            sB += pB[(size_t)ch * 168];
        }
        if (i >= 156) {
            nkA[i - 156] = fmaxf(sqrtf(sA), 1e-12f);
            nkB[i - 156] = fmaxf(sqrtf(sB), 1e-12f);
        } else if (i >= 144) {
            nqA[i - 144] = fmaxf(sqrtf(sA), 1e-12f);
            nqB[i - 144] = fmaxf(sqrtf(sB), 1e-12f);
        }
    }
    __syncthreads();
    if (i < 144) {
        int c = i / CHEAD, d = i % CHEAD;
        float tp = temp[h];
        GA[i] =  sA / (nqA[c] * nkA[d]) * tp;
        GB[i] = -sB / (nqB[c] * nkB[d]) * tp;
    }
    __syncthreads();
    if (i < 24) {
        float* G = (i < CHEAD) ? GA : GB;
        float* O = (i < CHEAD) ? attnA : attnB;
        int c = i % CHEAD;
        float mx = -1e30f;
        for (int d = 0; d < CHEAD; d++) mx = fmaxf(mx, G[c * CHEAD + d]);
        float e[CHEAD];
        float s = 0.f;
        for (int d = 0; d < CHEAD; d++) {
            e[d] = expf(G[c * CHEAD + d] - mx);
            s += e[d];
        }
        float inv = 1.f / s;
        for (int d = 0; d < CHEAD; d++)
            O[(size_t)bh * 144 + c * CHEAD + d] = e[d] * inv;
    }
}

// ---------------------------------------------------------------------------
// cw_pk[b] = pack_tf32(P @ blockdiag(attn[b])); grid (4, 6).
// ---------------------------------------------------------------------------
__global__ void cw_kernel(const float* __restrict__ P0,
                          const float* __restrict__ P1,
                          const float* __restrict__ atA,
                          const float* __restrict__ atB,
                          uint32_t* __restrict__ cwApk,
                          uint32_t* __restrict__ cwBpk) {
    int b  = blockIdx.x >> 1;
    int br = blockIdx.x & 1;
    const float* P  = br ? P1 : P0;
    const float* at = (br ? atB : atA) + (size_t)b * HEADS * 144;
    uint32_t* out = (br ? cwBpk : cwApk) + (size_t)b * 9216;
    __shared__ float a_s[HEADS * 144];
    for (int i = threadIdx.x; i < HEADS * 144; i += blockDim.x) a_s[i] = at[i];
    __syncthreads();
    int base = blockIdx.y * 1536;
#pragma unroll
    for (int r = 0; r < 6; r++) {
        int o = base + r * 256 + threadIdx.x;
        int m = o / 96, n = o % 96;
        int h = n / CHEAD, d = n % CHEAD;
        float s = 0.f;
#pragma unroll
        for (int c = 0; c < CHEAD; c++)
            s += P[m * 96 + h * CHEAD + c] * a_s[h * 144 + c * CHEAD + d];
        out[a_pack_off(m, n)] = f2tf(s);
    }
}

// ---------------------------------------------------------------------------
// Launch
// ---------------------------------------------------------------------------
extern "C" void kernel_launch(void* const* d_in, const int* in_sizes, int n_in,
                              void* d_out, int out_size) {
    const float* x       = (const float*)d_in[0];
    const float* y       = (const float*)d_in[1];
    const float* ln1_w   = (const float*)d_in[2];
    const float* ln1_b   = (const float*)d_in[3];
    const float* ln2_w   = (const float*)d_in[4];
    const float* ln2_b   = (const float*)d_in[5];
    const float* qkvA_w  = (const float*)d_in[6];
    const float* dwA_w   = (const float*)d_in[7];
    const float* qkvB_w  = (const float*)d_in[8];
    const float* dwB_w   = (const float*)d_in[9];
    const float* projA_w = (const float*)d_in[10];
    const float* projB_w = (const float*)d_in[11];
    const float* concat_w= (const float*)d_in[12];
    const float* temp    = (const float*)d_in[13];
    const float* pin_w   = (const float*)d_in[14];
    const float* dwf_w   = (const float*)d_in[15];
    const float* pout_w  = (const float*)d_in[16];
    float* out = (float*)d_out;

    cudaFuncSetAttribute(gemm96,   cudaFuncAttributeMaxDynamicSharedMemorySize, G96_SMEM_BYTES);
    cudaFuncSetAttribute(gemmPout, cudaFuncAttributeMaxDynamicSharedMemorySize, G96_SMEM_BYTES);
    cudaFuncSetAttribute(gemm4_tc, cudaFuncAttributeMaxDynamicSharedMemorySize, GEMM_SMEM_BYTES);

    __nv_bfloat16 *qkvA, *qkvAd, *qkvB, *qkvBd, *t, *gate;
    float *x1, *stsX, *stsY, *gpA, *gpB, *atA, *atB, *P0, *P1;
    uint32_t *prepQA, *prepQB, *prepPin, *prepPout_p, *prepC0, *prepC1, *cwApk, *cwBpk;
    float *sQA, *tQA, *sQB, *tQB, *sPin, *tPin;
    cudaGetSymbolAddress((void**)&qkvA,   g_qkvA);
    cudaGetSymbolAddress((void**)&qkvAd,  g_qkvAd);
    cudaGetSymbolAddress((void**)&qkvB,   g_qkvB);
    cudaGetSymbolAddress((void**)&qkvBd,  g_qkvBd);
    cudaGetSymbolAddress((void**)&t,      g_t);
    cudaGetSymbolAddress((void**)&gate,   g_gate);
    cudaGetSymbolAddress((void**)&x1,     g_x1);
    cudaGetSymbolAddress((void**)&stsX,   g_stsX);
    cudaGetSymbolAddress((void**)&stsY,   g_stsY);
    cudaGetSymbolAddress((void**)&gpA,    g_gpartA);
    cudaGetSymbolAddress((void**)&gpB,    g_gpartB);
    cudaGetSymbolAddress((void**)&atA,    g_attnA);
    cudaGetSymbolAddress((void**)&atB,    g_attnB);
    cudaGetSymbolAddress((void**)&P0,     g_P0);
    cudaGetSymbolAddress((void**)&P1,     g_P1);
    cudaGetSymbolAddress((void**)&prepQA,   g_prepQA);
    cudaGetSymbolAddress((void**)&prepQB,   g_prepQB);
    cudaGetSymbolAddress((void**)&prepPin,  g_prepPin);
    cudaGetSymbolAddress((void**)&prepPout_p, g_prepPout);
    cudaGetSymbolAddress((void**)&prepC0,   g_prepC0);
    cudaGetSymbolAddress((void**)&prepC1,   g_prepC1);
    cudaGetSymbolAddress((void**)&cwApk,    g_cwApk);
    cudaGetSymbolAddress((void**)&cwBpk,    g_cwBpk);
    cudaGetSymbolAddress((void**)&sQA,    g_sQA);
    cudaGetSymbolAddress((void**)&tQA,    g_tQA);
    cudaGetSymbolAddress((void**)&sQB,    g_sQB);
    cudaGetSymbolAddress((void**)&tQB,    g_tQB);
    cudaGetSymbolAddress((void**)&sPin,   g_sPin);
    cudaGetSymbolAddress((void**)&tPin,   g_tPin);

    const size_t P96   = (size_t)CDIM * HW;
    const size_t P288E = (size_t)3 * CDIM * HW;
    const size_t P510E = (size_t)2 * HIDDEN * HW;
    const size_t PGATE = (size_t)288 * HW;

    // one mega-prep launch
    megaprep<<<53, 256>>>(qkvA_w, qkvB_w, pin_w, pout_w, concat_w,
                          projA_w, projB_w, ln1_w, ln1_b, ln2_w, ln2_b,
                          prepQA, prepQB, prepPin, prepPout_p, prepC0, prepC1,
                          sQA, tQA, sQB, tQB, sPin, tPin, P0, P1);

    // qkv for both branches; stats self-computed, persisted for gemm4
    {
        G96P p;
        p.Apk[0] = prepQA; p.Apk[1] = prepQB;
        p.sv[0] = sQA; p.sv[1] = sQB;
        p.tv[0] = tQA; p.tv[1] = tQB;
        p.X[0] = x; p.X[1] = y;
        p.stsOut[0] = (float2*)stsX; p.stsOut[1] = (float2*)stsY;
        p.Y[0] = qkvA; p.Y[1] = qkvB;
        dim3 g(3, HW / 128, BATCH * 2);
        gemm96<<<g, 256, G96_SMEM_BYTES>>>(p, 288, 2, P96, P288E);
    }

    // depthwise 3x3, both branches
    {
        dim3 blk(32, 8), g(IMG / 128, IMG / 8, 2 * BATCH * 288);
        dw3_kernel<<<g, blk>>>(qkvA, qkvB, dwA_w, dwB_w, qkvAd, qkvBd);
    }

    // Gram + fused norms, both branches
    {
        dim3 g(32, HEADS, 2 * BATCH);
        gram1_kernel<<<g, 256>>>(qkvAd, qkvBd, gpA, gpB);
    }

    attn_kernel<<<BATCH * HEADS, 192>>>(gpA, gpB, temp, atA, atB);
    {
        dim3 g(4, 6);
        cw_kernel<<<g, 256>>>(P0, P1, atA, atB, cwApk, cwBpk);
    }

    // fused x1 = x + cwA@vA + cwB@vB + concat0@LN(x) + concat1@LN(y)
    {
        G4 p;
        p.Apk[0] = cwApk;  p.aBatch[0] = 9216;
        p.Apk[1] = cwBpk;  p.aBatch[1] = 9216;
        p.Apk[2] = prepC0; p.aBatch[2] = 0;
        p.Apk[3] = prepC1; p.aBatch[3] = 0;
        p.X[0] = qkvAd + 192 * (size_t)HW; p.xBatch[0] = P288E; p.stats[0] = nullptr; p.isbf16[0] = 1;
        p.X[1] = qkvBd + 192 * (size_t)HW; p.xBatch[1] = P288E; p.stats[1] = nullptr; p.isbf16[1] = 1;
        p.X[2] = x;                        p.xBatch[2] = P96;   p.stats[2] = stsX;    p.isbf16[2] = 0;
        p.X[3] = y;                        p.xBatch[3] = P96;   p.stats[3] = stsY;    p.isbf16[3] = 0;
        dim3 g(1, HW / 128, BATCH);
        gemm4_tc<<<g, 256, GEMM_SMEM_BYTES>>>(p, ln1_w, ln1_b, x, x1);
    }

    // pin = W@LN2(x1): stats self-computed, no persistence needed
    {
        G96P p;
        p.Apk[0] = prepPin; p.Apk[1] = prepPin;
        p.sv[0] = sPin; p.sv[1] = sPin;
        p.tv[0] = tPin; p.tv[1] = tPin;
        p.X[0] = x1; p.X[1] = x1;
        p.stsOut[0] = nullptr; p.stsOut[1] = nullptr;
        p.Y[0] = t; p.Y[1] = t;
        dim3 g(6, HW / 128, BATCH);
        gemm96<<<g, 256, G96_SMEM_BYTES>>>(p, 510, 1, P96, P510E);
    }

    // fused depthwise + gelu gate (bf16 out, 288-pitch)
    {
        dim3 blk(32, 8), g(IMG / 128, IMG / 8, BATCH * HIDDEN);
        dwgate_kernel<<<g, blk>>>(t, dwf_w, gate);
    }

    // pout pipelined (K padded to 288, bf16 B) + residual x1 -> output
    {
        dim3 g(1, HW / 128, BATCH);
        gemmPout<<<g, 256, G96_SMEM_BYTES>>>(prepPout_p, gate, x1, out,
                                             PGATE, P96, P96);
    }
}

// round 10
// speedup vs baseline: 4.0451x; 1.0631x over previous
#include <cuda_runtime.h>
#include <cuda_bf16.h>
#include <math.h>
#include <stdint.h>

#define HW      65536
#define IMG     256
#define BATCH   2
#define CDIM    96
#define HEADS   8
#define CHEAD   12
#define HIDDEN  255

// ---------------------------------------------------------------------------
// Scratch
// ---------------------------------------------------------------------------
__device__ __nv_bfloat16 g_qkvA [BATCH * 3 * CDIM * HW];
__device__ __nv_bfloat16 g_qkvAd[BATCH * 3 * CDIM * HW];
__device__ __nv_bfloat16 g_qkvB [BATCH * 3 * CDIM * HW];
__device__ __nv_bfloat16 g_qkvBd[BATCH * 3 * CDIM * HW];
__device__ __nv_bfloat16 g_t    [BATCH * 2 * HIDDEN * HW];
__device__ __nv_bfloat16 g_gate [BATCH * 288 * HW];   // 288-pitch; rows 255..287 stay zero
__device__ float g_x1   [BATCH * CDIM * HW];
__device__ float g_stsX [BATCH * HW * 2];
__device__ float g_stsY [BATCH * HW * 2];
// Gram partials: [bh][chunk*4+quad][warp][48]  (48 = acc36 + qsq6 + ksq6)
__device__ float g_gpartA[BATCH * HEADS * 128 * 8 * 48];
__device__ float g_gpartB[BATCH * HEADS * 128 * 8 * 48];
__device__ float g_attnA [BATCH * HEADS * 144];
__device__ float g_attnB [BATCH * HEADS * 144];
__device__ float g_P0  [CDIM * CDIM];
__device__ float g_P1  [CDIM * CDIM];
// prepacked tf32 fragment tiles
__device__ uint32_t g_prepQA  [3 * 9216];
__device__ uint32_t g_prepQB  [3 * 9216];
__device__ uint32_t g_prepPin [6 * 9216];
__device__ uint32_t g_prepPout[3 * 9216];
__device__ uint32_t g_prepC0  [9216];
__device__ uint32_t g_prepC1  [9216];
__device__ uint32_t g_cwApk   [BATCH * 9216];
__device__ uint32_t g_cwBpk   [BATCH * 9216];
__device__ float g_sQA[288],  g_tQA[288];
__device__ float g_sQB[288],  g_tQB[288];
__device__ float g_sPin[576], g_tPin[576];

// ---------------------------------------------------------------------------
// tf32 / cp.async helpers
// ---------------------------------------------------------------------------
__device__ __forceinline__ uint32_t f2tf(float f) {
    uint32_t u;
    asm("cvt.rna.tf32.f32 %0, %1;" : "=r"(u) : "f"(f));
    return u;
}

__device__ __forceinline__ void mma_tf32(float* c, const uint32_t* a, const uint32_t* b) {
    asm volatile(
        "mma.sync.aligned.m16n8k8.row.col.f32.tf32.tf32.f32 "
        "{%0,%1,%2,%3}, {%4,%5,%6,%7}, {%8,%9}, {%0,%1,%2,%3};"
        : "+f"(c[0]), "+f"(c[1]), "+f"(c[2]), "+f"(c[3])
        : "r"(a[0]), "r"(a[1]), "r"(a[2]), "r"(a[3]), "r"(b[0]), "r"(b[1]));
}

__device__ __forceinline__ void cp16(void* smem, const void* gmem) {
    uint32_t a = (uint32_t)__cvta_generic_to_shared(smem);
    asm volatile("cp.async.cg.shared.global [%0], [%1], 16;\n" :: "r"(a), "l"(gmem));
}
#define CP_COMMIT()  asm volatile("cp.async.commit_group;\n")
#define CP_WAIT(n)   asm volatile("cp.async.wait_group %0;\n" :: "n"(n))

__device__ __forceinline__ int a_pack_off(int m, int k) {
    return (k >> 3) * 768 + (m >> 4) * 128 + (m & 7) * 16 + (k & 3) * 4
         + ((k >> 2) & 1) * 2 + ((m >> 3) & 1);
}

#define GEMM_SMEM_WORDS (9216 + 96*136 + 128 + 128 + 96 + 96)
#define GEMM_SMEM_BYTES (GEMM_SMEM_WORDS * 4)
#define G96_SMEM_WORDS  (9216 + 2*32*136 + 256)
#define G96_SMEM_BYTES  (G96_SMEM_WORDS * 4)

// ---------------------------------------------------------------------------
// Mega-prep (unchanged from R9).
// ---------------------------------------------------------------------------
__device__ void prep_tile(const float* __restrict__ W, int M, int tile,
                          const float* __restrict__ wln,
                          const float* __restrict__ bln,
                          uint32_t* __restrict__ Apk,
                          float* __restrict__ svec, float* __restrict__ tvec,
                          float* wls, float* bls) {
    int m0 = tile * 96;
    if (threadIdx.x < 96) { wls[threadIdx.x] = wln[threadIdx.x]; bls[threadIdx.x] = bln[threadIdx.x]; }
    __syncthreads();
#pragma unroll
    for (int i = 0; i < 36; i++) {
        int idx = threadIdx.x + i * 256;
        int m = idx / 96;
        int k = idx - m * 96;
        float v = 0.f;
        if (m0 + m < M) v = W[(size_t)(m0 + m) * 96 + k] * wls[k];
        Apk[tile * 9216 + a_pack_off(m, k)] = f2tf(v);
    }
    if (threadIdx.x < 96) {
        int gm = m0 + threadIdx.x;
        float s = 0.f, tt = 0.f;
        if (gm < M) {
            for (int k = 0; k < 96; k++) {
                float w = W[(size_t)gm * 96 + k];
                s  += w * wls[k];
                tt += w * bls[k];
            }
        }
        svec[tile * 96 + threadIdx.x] = s;
        tvec[tile * 96 + threadIdx.x] = tt;
    }
}

__global__ void megaprep(
        const float* __restrict__ qkvA_w, const float* __restrict__ qkvB_w,
        const float* __restrict__ pin_w,  const float* __restrict__ pout_w,
        const float* __restrict__ concat_w,
        const float* __restrict__ projA_w, const float* __restrict__ projB_w,
        const float* __restrict__ ln1_w, const float* __restrict__ ln1_b,
        const float* __restrict__ ln2_w, const float* __restrict__ ln2_b,
        uint32_t* __restrict__ prepQA, uint32_t* __restrict__ prepQB,
        uint32_t* __restrict__ prepPin, uint32_t* __restrict__ prepPout,
        uint32_t* __restrict__ prepC0, uint32_t* __restrict__ prepC1,
        float* __restrict__ sQA, float* __restrict__ tQA,
        float* __restrict__ sQB, float* __restrict__ tQB,
        float* __restrict__ sPin, float* __restrict__ tPin,
        float* __restrict__ P0, float* __restrict__ P1) {
    __shared__ float sbuf[96 * 96];
    int bid = blockIdx.x;
    if (bid < 3) {
        prep_tile(qkvA_w, 288, bid, ln1_w, ln1_b, prepQA, sQA, tQA, sbuf, sbuf + 96);
    } else if (bid < 6) {
        prep_tile(qkvB_w, 288, bid - 3, ln1_w, ln1_b, prepQB, sQB, tQB, sbuf, sbuf + 96);
    } else if (bid < 12) {
        prep_tile(pin_w, 510, bid - 6, ln2_w, ln2_b, prepPin, sPin, tPin, sbuf, sbuf + 96);
    } else if (bid < 15) {
        int s = bid - 12;
#pragma unroll
        for (int i = 0; i < 36; i++) {
            int idx = threadIdx.x + i * 256;
            int m = idx / 96;
            int k = idx - m * 96;
            int kg = s * 96 + k;
            float v = (kg < HIDDEN) ? pout_w[(size_t)m * HIDDEN + kg] : 0.f;
            prepPout[s * 9216 + a_pack_off(m, k)] = f2tf(v);
        }
    } else if (bid < 17) {
        const float* W = concat_w + (bid == 16 ? 96 : 0);
        uint32_t* out = (bid == 16) ? prepC1 : prepC0;
#pragma unroll
        for (int i = 0; i < 36; i++) {
            int idx = threadIdx.x + i * 256;
            int m = idx / 96;
            int k = idx - m * 96;
            out[a_pack_off(m, k)] = f2tf(W[(size_t)m * 192 + k]);
        }
    } else {
        int w = bid - 17;
        int br = w & 1;
        int yt = w >> 1;
        const float* proj = br ? projB_w : projA_w;
        const float* cw   = concat_w + (br ? 96 : 0);
        float* P = br ? P1 : P0;
        for (int i = threadIdx.x; i < 96 * 96; i += 256) sbuf[i] = proj[i];
        __syncthreads();
        int base = yt * 512;
#pragma unroll
        for (int r = 0; r < 2; r++) {
            int o = base + r * 256 + threadIdx.x;
            int m = o / 96, n = o % 96;
            float s = 0.f;
#pragma unroll 8
            for (int c = 0; c < 96; c++) s += cw[m * 192 + c] * sbuf[c * 96 + n];
            P[o] = s;
        }
    }
}

// ---------------------------------------------------------------------------
// 32-k MMA chunk on the 96x128 tile.
// ---------------------------------------------------------------------------
__device__ __forceinline__ void g96_chunk(
        float acc[3][4][4], const uint32_t* __restrict__ As,
        const uint32_t* __restrict__ Bbuf,
        int kc, int g, int t, int wmi, int wn) {
#pragma unroll
    for (int ks2 = 0; ks2 < 4; ks2++) {
        const uint32_t* Ab = As + (kc * 4 + ks2) * 768 + g * 16 + t * 4;
        const uint32_t* Bb = Bbuf + (ks2 * 8 + t) * 136 + wn + g;
        uint4 a4[3];
        uint32_t bf[4][2];
#pragma unroll
        for (int mi = 0; mi < 3; mi++)
            a4[mi] = *reinterpret_cast<const uint4*>(Ab + (wmi + mi) * 128);
#pragma unroll
        for (int ni = 0; ni < 4; ni++) {
            bf[ni][0] = Bb[ni * 8];
            bf[ni][1] = Bb[4 * 136 + ni * 8];
        }
#pragma unroll
        for (int mi = 0; mi < 3; mi++) {
            uint32_t af[4] = {a4[mi].x, a4[mi].y, a4[mi].z, a4[mi].w};
#pragma unroll
            for (int ni = 0; ni < 4; ni++)
                mma_tf32(acc[mi][ni], af, bf[ni]);
        }
    }
}

// ---------------------------------------------------------------------------
// K=96 pipelined tf32 GEMM with self-computed LayerNorm stats (unchanged).
// ---------------------------------------------------------------------------
struct G96P {
    const uint32_t* Apk[2];
    const float*    sv[2];
    const float*    tv[2];
    const float*    X[2];
    float2*         stsOut[2];
    __nv_bfloat16*  Y[2];
};

__global__ void __launch_bounds__(256, 3) gemm96(
        G96P p, int M, int NB, size_t xBatch, size_t yBatch) {
    extern __shared__ uint32_t sm[];
    uint32_t* As = sm;
    uint32_t* Bs = sm + 9216;
    float* mu_s  = (float*)(sm + 9216 + 8704);
    float* inv_s = mu_s + 128;

    int z  = blockIdx.z;
    int br = z % NB;
    int bz = z / NB;
    const float* Xb = p.X[br] + (size_t)bz * xBatch;
    __nv_bfloat16* Yb = p.Y[br] + (size_t)bz * yBatch;
    const float* svec = p.sv[br];
    const float* tvec = p.tv[br];

    int mtile = blockIdx.x;
    int m0 = mtile * 96;
    int n0 = blockIdx.y * 128;
    int tid  = threadIdx.x;
    int warp = tid >> 5;
    int lane = tid & 31;
    int g = lane >> 2;
    int t = lane & 3;
    int wm  = (warp >> 2) * 48;
    int wmi = (warp >> 2) * 3;
    int wn  = (warp & 3) * 32;

    {
        const uint4* Ag = reinterpret_cast<const uint4*>(p.Apk[br] + (size_t)mtile * 9216);
#pragma unroll
        for (int i = 0; i < 9; i++) {
            int idx = tid + i * 256;
            cp16(As + idx * 4, Ag + idx);
        }
    }
#pragma unroll
    for (int j = 0; j < 4; j++) {
        int idx = tid + j * 256;
        int k = idx >> 5, n4 = idx & 31;
        cp16(Bs + k * 136 + n4 * 4, Xb + (size_t)k * HW + n0 + n4 * 4);
    }
    CP_COMMIT();
#pragma unroll
    for (int j = 0; j < 4; j++) {
        int idx = tid + j * 256;
        int k = idx >> 5, n4 = idx & 31;
        cp16(Bs + 4352 + k * 136 + n4 * 4, Xb + (size_t)(32 + k) * HW + n0 + n4 * 4);
    }
    CP_COMMIT();

    float acc[3][4][4];
#pragma unroll
    for (int mi = 0; mi < 3; mi++)
#pragma unroll
        for (int ni = 0; ni < 4; ni++)
#pragma unroll
            for (int r = 0; r < 4; r++) acc[mi][ni][r] = 0.f;

    float csum = 0.f, csq = 0.f;
#define STATS_ACC(BUF)                                                      \
    if (tid < 128) {                                                        \
        _Pragma("unroll 8")                                                 \
        for (int k = 0; k < 32; k++) {                                      \
            float v = __uint_as_float((BUF)[k * 136 + tid]);                \
            csum += v; csq += v * v;                                        \
        }                                                                   \
    }

    CP_WAIT(1);
    __syncthreads();
    STATS_ACC(Bs);
    g96_chunk(acc, As, Bs, 0, g, t, wmi, wn);
    __syncthreads();
#pragma unroll
    for (int j = 0; j < 4; j++) {
        int idx = tid + j * 256;
        int k = idx >> 5, n4 = idx & 31;
        cp16(Bs + k * 136 + n4 * 4, Xb + (size_t)(64 + k) * HW + n0 + n4 * 4);
    }
    CP_COMMIT();
    CP_WAIT(1);
    __syncthreads();
    STATS_ACC(Bs + 4352);
    g96_chunk(acc, As, Bs + 4352, 1, g, t, wmi, wn);
    CP_WAIT(0);
    __syncthreads();
    STATS_ACC(Bs);
    g96_chunk(acc, As, Bs, 2, g, t, wmi, wn);
#undef STATS_ACC

    if (tid < 128) {
        float mu  = csum * (1.f / 96.f);
        float var = csq * (1.f / 96.f) - mu * mu;
        float inv = rsqrtf(var + 1e-5f);
        mu_s[tid]  = mu;
        inv_s[tid] = inv;
        if (mtile == 0 && p.stsOut[br] != nullptr)
            p.stsOut[br][(size_t)bz * HW + n0 + tid] = make_float2(mu, inv);
    }
    __syncthreads();

#pragma unroll
    for (int mi = 0; mi < 3; mi++) {
        int r0 = m0 + wm + mi * 16 + g;
        int r1 = r0 + 8;
        float s0 = 0.f, t0 = 0.f, s1 = 0.f, t1 = 0.f;
        if (r0 < M) { s0 = svec[r0]; t0 = tvec[r0]; }
        if (r1 < M) { s1 = svec[r1]; t1 = tvec[r1]; }
#pragma unroll
        for (int ni = 0; ni < 4; ni++) {
            int ln = wn + ni * 8 + 2 * t;
            int col = n0 + ln;
            float i0 = inv_s[ln],     m0v = mu_s[ln]     * i0;
            float i1 = inv_s[ln + 1], m1v = mu_s[ln + 1] * i1;
            if (r0 < M) {
                float vx = acc[mi][ni][0] * i0 - m0v * s0 + t0;
                float vy = acc[mi][ni][1] * i1 - m1v * s0 + t0;
                *reinterpret_cast<__nv_bfloat162*>(Yb + (size_t)r0 * HW + col) =
                    __floats2bfloat162_rn(vx, vy);
            }
            if (r1 < M) {
                float vx = acc[mi][ni][2] * i0 - m0v * s1 + t1;
                float vy = acc[mi][ni][3] * i1 - m1v * s1 + t1;
                *reinterpret_cast<__nv_bfloat162*>(Yb + (size_t)r1 * HW + col) =
                    __floats2bfloat162_rn(vx, vy);
            }
        }
    }
}

// ---------------------------------------------------------------------------
// pout (unchanged from R9).
// ---------------------------------------------------------------------------
__global__ void __launch_bounds__(256, 3) gemmPout(
        const uint32_t* __restrict__ Apk,
        const __nv_bfloat16* __restrict__ X,
        const float* __restrict__ Rsrc,
        float* __restrict__ Y,
        size_t xBatch, size_t yBatch, size_t rBatch) {
    extern __shared__ uint32_t sm[];
    uint32_t* As = sm;
    uint32_t* Bs = sm + 9216;

    int bz = blockIdx.z;
    const __nv_bfloat16* Xb = X + (size_t)bz * xBatch;
    float*       Yb = Y    + (size_t)bz * yBatch;
    const float* Rb = Rsrc + (size_t)bz * rBatch;

    int n0 = blockIdx.y * 128;
    int tid  = threadIdx.x;
    int warp = tid >> 5;
    int lane = tid & 31;
    int g = lane >> 2;
    int t = lane & 3;
    int wm  = (warp >> 2) * 48;
    int wmi = (warp >> 2) * 3;
    int wn  = (warp & 3) * 32;

    int kk = tid >> 3;
    int nb = (tid & 7) * 16;

    uint4 rA, rB;
#define LDGB(c)                                                             \
    {                                                                       \
        const uint4* src = reinterpret_cast<const uint4*>(                  \
            Xb + (size_t)((c) * 32 + kk) * HW + n0 + nb);                   \
        rA = src[0]; rB = src[1];                                           \
    }
#define STSB(c)                                                             \
    {                                                                       \
        uint32_t* dst = Bs + ((c) & 1) * 4352 + kk * 136 + nb;              \
        uint32_t u;                                                         \
        u = rA.x; dst[0]  = u << 16; dst[1]  = u & 0xFFFF0000u;             \
        u = rA.y; dst[2]  = u << 16; dst[3]  = u & 0xFFFF0000u;             \
        u = rA.z; dst[4]  = u << 16; dst[5]  = u & 0xFFFF0000u;             \
        u = rA.w; dst[6]  = u << 16; dst[7]  = u & 0xFFFF0000u;             \
        u = rB.x; dst[8]  = u << 16; dst[9]  = u & 0xFFFF0000u;             \
        u = rB.y; dst[10] = u << 16; dst[11] = u & 0xFFFF0000u;             \
        u = rB.z; dst[12] = u << 16; dst[13] = u & 0xFFFF0000u;             \
        u = rB.w; dst[14] = u << 16; dst[15] = u & 0xFFFF0000u;             \
    }
#define LOADA(s)                                                            \
    {                                                                       \
        const uint4* Ag = reinterpret_cast<const uint4*>(Apk + (s) * 9216); \
        _Pragma("unroll")                                                   \
        for (int i = 0; i < 9; i++) {                                       \
            int idx = tid + i * 256;                                        \
            cp16(As + idx * 4, Ag + idx);                                   \
        }                                                                   \
        CP_COMMIT();                                                        \
    }

    LOADA(0);
    LDGB(0);
    STSB(0);
    LDGB(1);
    CP_WAIT(0);
    __syncthreads();

    float acc[3][4][4];
#pragma unroll
    for (int mi = 0; mi < 3; mi++)
#pragma unroll
        for (int ni = 0; ni < 4; ni++)
#pragma unroll
            for (int r = 0; r < 4; r++) acc[mi][ni][r] = 0.f;

#pragma unroll
    for (int c = 0; c < 9; c++) {
        g96_chunk(acc, As, Bs + (c & 1) * 4352, c % 3, g, t, wmi, wn);
        if (c < 8) {
            __syncthreads();
            bool newA = (c % 3 == 2);
            if (newA) LOADA(c / 3 + 1);
            STSB(c + 1);
            if (c + 2 <= 8) LDGB(c + 2);
            if (newA) CP_WAIT(0);
            __syncthreads();
        }
    }
#undef LOADA
#undef LDGB
#undef STSB

#pragma unroll
    for (int mi = 0; mi < 3; mi++) {
        int r0 = wm + mi * 16 + g;
        int r1 = r0 + 8;
#pragma unroll
        for (int ni = 0; ni < 4; ni++) {
            int col = n0 + wn + ni * 8 + 2 * t;
            float2 ra = *reinterpret_cast<const float2*>(Rb + (size_t)r0 * HW + col);
            float2 rb = *reinterpret_cast<const float2*>(Rb + (size_t)r1 * HW + col);
            float2 v01 = make_float2(acc[mi][ni][0] + ra.x, acc[mi][ni][1] + ra.y);
            float2 v23 = make_float2(acc[mi][ni][2] + rb.x, acc[mi][ni][3] + rb.y);
            *reinterpret_cast<float2*>(Yb + (size_t)r0 * HW + col) = v01;
            *reinterpret_cast<float2*>(Yb + (size_t)r1 * HW + col) = v23;
        }
    }
}

// ---------------------------------------------------------------------------
// 4-source fused GEMM for x1 (unchanged from R9).
// ---------------------------------------------------------------------------
struct G4 {
    const uint32_t* Apk[4];
    size_t          aBatch[4];
    const void*     X[4];
    size_t          xBatch[4];
    const float*    stats[4];
    int             isbf16[4];
};

__global__ void __launch_bounds__(256, 2) gemm4_tc(
        G4 p,
        const float* __restrict__ lnw,
        const float* __restrict__ lnb,
        const float* __restrict__ Rsrc,
        float* __restrict__ Y) {
    extern __shared__ uint32_t smem_u[];
    uint32_t* As  = smem_u;
    uint32_t* Bs  = As + 9216;
    float* mu_s   = (float*)(Bs + 96 * 136);
    float* inv_s  = mu_s + 128;
    float* wln_s  = inv_s + 128;
    float* bln_s  = wln_s + 96;

    int bz = blockIdx.z;
    int n0 = blockIdx.y * 128;
    float*       Yb = Y    + (size_t)bz * CDIM * HW;
    const float* Rb = Rsrc + (size_t)bz * CDIM * HW;

    int tid  = threadIdx.x;
    int warp = tid >> 5;
    int lane = tid & 31;
    int g = lane >> 2;
    int t = lane & 3;
    int wm  = (warp >> 2) * 48;
    int wmi = (warp >> 2) * 3;
    int wn  = (warp & 3) * 32;

    if (tid < 96) { wln_s[tid] = lnw[tid]; bln_s[tid] = lnb[tid]; }

    float acc[3][4][4];
#pragma unroll
    for (int mi = 0; mi < 3; mi++)
#pragma unroll
        for (int ni = 0; ni < 4; ni++)
#pragma unroll
            for (int r = 0; r < 4; r++) acc[mi][ni][r] = 0.f;

    for (int s = 0; s < 4; s++) {
        __syncthreads();
        {
            const uint4* Ag = reinterpret_cast<const uint4*>(p.Apk[s] + (size_t)bz * p.aBatch[s]);
#pragma unroll
            for (int i = 0; i < 9; i++) {
                int idx = tid + i * 256;
                cp16(As + idx * 4, Ag + idx);
            }
            CP_COMMIT();
        }
        if (p.isbf16[s]) {
            const __nv_bfloat16* Xh = (const __nv_bfloat16*)p.X[s] + (size_t)bz * p.xBatch[s];
#pragma unroll
            for (int i = 0; i < 6; i++) {
                int idx = tid + i * 256;
                int k = idx >> 4, n8 = idx & 15;
                const uint32_t* src =
                    reinterpret_cast<const uint32_t*>(Xh + (size_t)k * HW + n0 + n8 * 8);
                uint32_t* dst = Bs + k * 136 + n8 * 8;
#pragma unroll
                for (int j = 0; j < 4; j++) {
                    uint32_t u = src[j];
                    dst[2 * j]     = u << 16;
                    dst[2 * j + 1] = u & 0xFFFF0000u;
                }
            }
        } else {
            const float* Xb = (const float*)p.X[s] + (size_t)bz * p.xBatch[s];
            bool ln = (p.stats[s] != nullptr);
            if (ln && tid < 128) {
                float2 sv = reinterpret_cast<const float2*>(p.stats[s])[(size_t)bz * HW + n0 + tid];
                mu_s[tid]  = sv.x;
                inv_s[tid] = sv.y;
            }
            if (ln) __syncthreads();
#pragma unroll
            for (int i = 0; i < 12; i++) {
                int idx = tid + i * 256;
                int k  = idx >> 5;
                int n4 = idx & 31;
                float4 v = reinterpret_cast<const float4*>(Xb + (size_t)k * HW + n0)[n4];
                if (ln) {
                    int nbq = n4 * 4;
                    float wk = wln_s[k], bk = bln_s[k];
                    v.x = (v.x - mu_s[nbq + 0]) * inv_s[nbq + 0] * wk + bk;
                    v.y = (v.y - mu_s[nbq + 1]) * inv_s[nbq + 1] * wk + bk;
                    v.z = (v.z - mu_s[nbq + 2]) * inv_s[nbq + 2] * wk + bk;
                    v.w = (v.w - mu_s[nbq + 3]) * inv_s[nbq + 3] * wk + bk;
                }
                uint4 u = make_uint4(__float_as_uint(v.x), __float_as_uint(v.y),
                                     __float_as_uint(v.z), __float_as_uint(v.w));
                *reinterpret_cast<uint4*>(Bs + k * 136 + n4 * 4) = u;
            }
        }
        CP_WAIT(0);
        __syncthreads();
#pragma unroll
        for (int ks = 0; ks < 12; ks++) {
            const uint32_t* Ab = As + ks * 768 + g * 16 + t * 4;
            const uint32_t* Bb = Bs + (ks * 8 + t) * 136 + wn + g;
            uint4 a4[3];
            uint32_t bf[4][2];
#pragma unroll
            for (int mi = 0; mi < 3; mi++)
                a4[mi] = *reinterpret_cast<const uint4*>(Ab + (wmi + mi) * 128);
#pragma unroll
            for (int ni = 0; ni < 4; ni++) {
                bf[ni][0] = Bb[ni * 8];
                bf[ni][1] = Bb[4 * 136 + ni * 8];
            }
#pragma unroll
            for (int mi = 0; mi < 3; mi++) {
                uint32_t af[4] = {a4[mi].x, a4[mi].y, a4[mi].z, a4[mi].w};
#pragma unroll
                for (int ni = 0; ni < 4; ni++)
                    mma_tf32(acc[mi][ni], af, bf[ni]);
            }
        }
    }

#pragma unroll
    for (int mi = 0; mi < 3; mi++) {
        int r0 = wm + mi * 16 + g;
        int r1 = r0 + 8;
#pragma unroll
        for (int ni = 0; ni < 4; ni++) {
            int col = n0 + wn + ni * 8 + 2 * t;
            float2 ra = *reinterpret_cast<const float2*>(Rb + (size_t)r0 * HW + col);
            float2 rb = *reinterpret_cast<const float2*>(Rb + (size_t)r1 * HW + col);
            float2 v01 = make_float2(acc[mi][ni][0] + ra.x, acc[mi][ni][1] + ra.y);
            float2 v23 = make_float2(acc[mi][ni][2] + rb.x, acc[mi][ni][3] + rb.y);
            *reinterpret_cast<float2*>(Yb + (size_t)r0 * HW + col) = v01;
            *reinterpret_cast<float2*>(Yb + (size_t)r1 * HW + col) = v23;
        }
    }
}

// ---------------------------------------------------------------------------
// Depthwise 3x3 (unchanged).
// ---------------------------------------------------------------------------
__global__ void dw3_kernel(const __nv_bfloat16* __restrict__ qA,
                           const __nv_bfloat16* __restrict__ qB,
                           const float* __restrict__ wA,
                           const float* __restrict__ wB,
                           __nv_bfloat16* __restrict__ oA,
                           __nv_bfloat16* __restrict__ oB) {
    int pl = blockIdx.z;
    int br = pl >= BATCH * 288;
    int rem = pl - br * BATCH * 288;
    int c = rem % 288;
    const __nv_bfloat16* ip = (br ? qB : qA) + (size_t)rem * HW;
    const float* wp = (br ? wB : wA) + c * 9;
    __nv_bfloat16* op = (br ? oB : oA) + (size_t)rem * HW;

    int x0 = (blockIdx.x * 32 + threadIdx.x) * 4;
    int y  = blockIdx.y * 8 + threadIdx.y;

    float w[9];
#pragma unroll
    for (int i = 0; i < 9; i++) w[i] = wp[i];

    float acc[4] = {0.f, 0.f, 0.f, 0.f};
#pragma unroll
    for (int dy = -1; dy <= 1; dy++) {
        int yy = y + dy;
        if (yy < 0 || yy >= IMG) continue;
        const __nv_bfloat16* row = ip + yy * IMG;
        float v[6];
        v[0] = (x0 > 0) ? __bfloat162float(row[x0 - 1]) : 0.f;
        {
            const __nv_bfloat162* r2 = reinterpret_cast<const __nv_bfloat162*>(row + x0);
            float2 a = __bfloat1622float2(r2[0]);
            float2 b = __bfloat1622float2(r2[1]);
            v[1] = a.x; v[2] = a.y; v[3] = b.x; v[4] = b.y;
        }
        v[5] = (x0 + 4 < IMG) ? __bfloat162float(row[x0 + 4]) : 0.f;
        const float* wr = w + (dy + 1) * 3;
#pragma unroll
        for (int j = 0; j < 4; j++)
            acc[j] += wr[0] * v[j] + wr[1] * v[j + 1] + wr[2] * v[j + 2];
    }

    *reinterpret_cast<__nv_bfloat162*>(op + y * IMG + x0)     = __floats2bfloat162_rn(acc[0], acc[1]);
    *reinterpret_cast<__nv_bfloat162*>(op + y * IMG + x0 + 2) = __floats2bfloat162_rn(acc[2], acc[3]);
}

// ---------------------------------------------------------------------------
// Fused FFN tail (unchanged).
// ---------------------------------------------------------------------------
__global__ void dwgate_kernel(const __nv_bfloat16* __restrict__ t,
                              const float* __restrict__ dwf,
                              __nv_bfloat16* __restrict__ gate) {
    int pl = blockIdx.z;
    int b = pl / HIDDEN, k = pl % HIDDEN;
    int x0 = (blockIdx.x * 32 + threadIdx.x) * 4;
    int y  = blockIdx.y * 8 + threadIdx.y;
    const __nv_bfloat16* i1 = t + ((size_t)b * 2 * HIDDEN + k) * HW;
    const __nv_bfloat16* i2 = t + ((size_t)b * 2 * HIDDEN + HIDDEN + k) * HW;
    const float* w1 = dwf + k * 9;
    const float* w2 = dwf + (HIDDEN + k) * 9;

    float wa[9], wb[9];
#pragma unroll
    for (int i = 0; i < 9; i++) { wa[i] = w1[i]; wb[i] = w2[i]; }

    float s1[4] = {0.f, 0.f, 0.f, 0.f};
    float s2[4] = {0.f, 0.f, 0.f, 0.f};
#pragma unroll
    for (int dy = -1; dy <= 1; dy++) {
        int yy = y + dy;
        if (yy < 0 || yy >= IMG) continue;
        const __nv_bfloat16* r1 = i1 + yy * IMG;
        const __nv_bfloat16* r2 = i2 + yy * IMG;
        float v1[6], v2[6];
        v1[0] = (x0 > 0) ? __bfloat162float(r1[x0 - 1]) : 0.f;
        v2[0] = (x0 > 0) ? __bfloat162float(r2[x0 - 1]) : 0.f;
        {
            const __nv_bfloat162* p1 = reinterpret_cast<const __nv_bfloat162*>(r1 + x0);
            const __nv_bfloat162* p2 = reinterpret_cast<const __nv_bfloat162*>(r2 + x0);
            float2 a1 = __bfloat1622float2(p1[0]), b1 = __bfloat1622float2(p1[1]);
            float2 a2 = __bfloat1622float2(p2[0]), b2 = __bfloat1622float2(p2[1]);
            v1[1] = a1.x; v1[2] = a1.y; v1[3] = b1.x; v1[4] = b1.y;
            v2[1] = a2.x; v2[2] = a2.y; v2[3] = b2.x; v2[4] = b2.y;
        }
        v1[5] = (x0 + 4 < IMG) ? __bfloat162float(r1[x0 + 4]) : 0.f;
        v2[5] = (x0 + 4 < IMG) ? __bfloat162float(r2[x0 + 4]) : 0.f;
        const float* wra = wa + (dy + 1) * 3;
        const float* wrb = wb + (dy + 1) * 3;
#pragma unroll
        for (int j = 0; j < 4; j++) {
            s1[j] += wra[0] * v1[j] + wra[1] * v1[j + 1] + wra[2] * v1[j + 2];
            s2[j] += wrb[0] * v2[j] + wrb[1] * v2[j + 1] + wrb[2] * v2[j + 2];
        }
    }

    float o[4];
#pragma unroll
    for (int j = 0; j < 4; j++) {
        float gl = 0.5f * s1[j] * (1.f + erff(s1[j] * 0.7071067811865475f));
        o[j] = gl * s2[j];
    }
    __nv_bfloat16* gp = gate + ((size_t)b * 288 + k) * HW + y * IMG + x0;
    *reinterpret_cast<__nv_bfloat162*>(gp)     = __floats2bfloat162_rn(o[0], o[1]);
    *reinterpret_cast<__nv_bfloat162*>(gp + 2) = __floats2bfloat162_rn(o[2], o[3]);
}

// ---------------------------------------------------------------------------
// Gram stage 1, QUADRANT SPLIT: each block computes a 6x6 sub-Gram.
// grid (128, HEADS, 2*BATCH): bid.x = chunk*4 + quad, quad = qh*2+kh.
// Partial slot (48 floats): [0..35] acc(c%6, d%6); [36..41] qsq; [42..47] ksq.
// bf162 loads, 2 px/thread/iter, 4 iters over 2048-px chunks.
// ---------------------------------------------------------------------------
__global__ void __launch_bounds__(256) gram1_kernel(
        const __nv_bfloat16* __restrict__ qkvAd,
        const __nv_bfloat16* __restrict__ qkvBd,
        float* __restrict__ gpA, float* __restrict__ gpB) {
    int bx = blockIdx.x;
    int chunk = bx >> 2;
    int quad  = bx & 3;
    int qh = quad >> 1;
    int kh = quad & 1;
    int h = blockIdx.y;
    int b  = blockIdx.z >> 1;
    int br = blockIdx.z & 1;
    const __nv_bfloat16* qb = (br ? qkvAd : qkvBd) + ((size_t)b * 288 + h * CHEAD + qh * 6) * HW;
    const __nv_bfloat16* kb = (br ? qkvBd : qkvAd) + ((size_t)b * 288 + 96 + h * CHEAD + kh * 6) * HW;
    float* part = br ? gpB : gpA;

    float acc[36];
#pragma unroll
    for (int i = 0; i < 36; i++) acc[i] = 0.f;
    float qsq[6] = {0.f, 0.f, 0.f, 0.f, 0.f, 0.f};
    float ksq[6] = {0.f, 0.f, 0.f, 0.f, 0.f, 0.f};

    int p0 = chunk * 2048 + threadIdx.x * 2;
#pragma unroll
    for (int it = 0; it < 4; it++) {
        int p = p0 + it * 512;
        float2 qv[6], kv[6];
#pragma unroll
        for (int c = 0; c < 6; c++)
            qv[c] = __bfloat1622float2(
                *reinterpret_cast<const __nv_bfloat162*>(qb + (size_t)c * HW + p));
#pragma unroll
        for (int d = 0; d < 6; d++)
            kv[d] = __bfloat1622float2(
                *reinterpret_cast<const __nv_bfloat162*>(kb + (size_t)d * HW + p));
#pragma unroll
        for (int c = 0; c < 6; c++)
#pragma unroll
            for (int d = 0; d < 6; d++)
                acc[c * 6 + d] += qv[c].x * kv[d].x + qv[c].y * kv[d].y;
#pragma unroll
        for (int c = 0; c < 6; c++) qsq[c] += qv[c].x * qv[c].x + qv[c].y * qv[c].y;
#pragma unroll
        for (int d = 0; d < 6; d++) ksq[d] += kv[d].x * kv[d].x + kv[d].y * kv[d].y;
    }

    int warp = threadIdx.x >> 5;
    int lane = threadIdx.x & 31;
    float* outp = part + ((((size_t)(b * HEADS + h)) * 128 + bx) * 8 + warp) * 48;
#pragma unroll
    for (int i = 0; i < 48; i++) {
        float v = (i < 36) ? acc[i] : (i < 42 ? qsq[i - 36] : ksq[i - 42]);
#pragma unroll
        for (int off = 16; off > 0; off >>= 1)
            v += __shfl_down_sync(0xffffffffu, v, off);
        if (lane == 0) outp[i] = v;
    }
}

// ---------------------------------------------------------------------------
// Gram stage 2 with quadrant-layout partials + norms + temp + softmax.
// Partial addressing: slot(bh, chunk, quad, warp)[off].
// ---------------------------------------------------------------------------
__global__ void attn_kernel(const float* __restrict__ partA,
                            const float* __restrict__ partB,
                            const float* __restrict__ temp,
                            float* __restrict__ attnA,
                            float* __restrict__ attnB) {
    int bh = blockIdx.x;
    int h = bh % HEADS;
    __shared__ float GA[144], GB[144];
    __shared__ float nqA[12], nkA[12], nqB[12], nkB[12];
    int i = threadIdx.x;
    float sA = 0.f, sB = 0.f;
    if (i < 168) {
        int quad, off;
        if (i < 144) {
            int c = i / CHEAD, d = i % CHEAD;
            quad = (c / 6) * 2 + (d / 6);
            off  = (c % 6) * 6 + (d % 6);
        } else if (i < 156) {
            int c = i - 144;
            quad = (c / 6) * 2;          // kh = 0 owns qsq
            off  = 36 + (c % 6);
        } else {
            int d = i - 156;
            quad = (d / 6);              // qh = 0 owns ksq
            off  = 42 + (d % 6);
        }
        const float* pA = partA + (((size_t)bh * 128 + quad) * 8) * 48 + off;
        const float* pB = partB + (((size_t)bh * 128 + quad) * 8) * 48 + off;
        for (int ch = 0; ch < 32; ch++) {
#pragma unroll
            for (int w = 0; w < 8; w++) {
                size_t o = (size_t)ch * (4 * 8 * 48) + (size_t)w * 48;
                sA += pA[o];
                sB += pB[o];
            }
        }
        if (i >= 156) {
            nkA[i - 156] = fmaxf(sqrtf(sA), 1e-12f);
            nkB[i - 156] = fmaxf(sqrtf(sB), 1e-12f);
        } else if (i >= 144) {
            nqA[i - 144] = fmaxf(sqrtf(sA), 1e-12f);
            nqB[i - 144] = fmaxf(sqrtf(sB), 1e-12f);
        }
    }
    __syncthreads();
    if (i < 144) {
        int c = i / CHEAD, d = i % CHEAD;
        float tp = temp[h];
        GA[i] =  sA / (nqA[c] * nkA[d]) * tp;
        GB[i] = -sB / (nqB[c] * nkB[d]) * tp;
    }
    __syncthreads();
    if (i < 24) {
        float* G = (i < CHEAD) ? GA : GB;
        float* O = (i < CHEAD) ? attnA : attnB;
        int c = i % CHEAD;
        float mx = -1e30f;
        for (int d = 0; d < CHEAD; d++) mx = fmaxf(mx, G[c * CHEAD + d]);
        float e[CHEAD];
        float s = 0.f;
        for (int d = 0; d < CHEAD; d++) {
            e[d] = expf(G[c * CHEAD + d] - mx);
            s += e[d];
        }
        float inv = 1.f / s;
        for (int d = 0; d < CHEAD; d++)
            O[(size_t)bh * 144 + c * CHEAD + d] = e[d] * inv;
    }
}

// ---------------------------------------------------------------------------
// cw_pk[b] = pack_tf32(P @ blockdiag(attn[b])); grid (4, 6). (unchanged)
// ---------------------------------------------------------------------------
__global__ void cw_kernel(const float* __restrict__ P0,
                          const float* __restrict__ P1,
                          const float* __restrict__ atA,
                          const float* __restrict__ atB,
                          uint32_t* __restrict__ cwApk,
                          uint32_t* __restrict__ cwBpk) {
    int b  = blockIdx.x >> 1;
    int br = blockIdx.x & 1;
    const float* P  = br ? P1 : P0;
    const float* at = (br ? atB : atA) + (size_t)b * HEADS * 144;
    uint32_t* out = (br ? cwBpk : cwApk) + (size_t)b * 9216;
    __shared__ float a_s[HEADS * 144];
    for (int i = threadIdx.x; i < HEADS * 144; i += blockDim.x) a_s[i] = at[i];
    __syncthreads();
    int base = blockIdx.y * 1536;
#pragma unroll
    for (int r = 0; r < 6; r++) {
        int o = base + r * 256 + threadIdx.x;
        int m = o / 96, n = o % 96;
        int h = n / CHEAD, d = n % CHEAD;
        float s = 0.f;
#pragma unroll
        for (int c = 0; c < CHEAD; c++)
            s += P[m * 96 + h * CHEAD + c] * a_s[h * 144 + c * CHEAD + d];
        out[a_pack_off(m, n)] = f2tf(s);
    }
}

// ---------------------------------------------------------------------------
// Launch
// ---------------------------------------------------------------------------
extern "C" void kernel_launch(void* const* d_in, const int* in_sizes, int n_in,
                              void* d_out, int out_size) {
    const float* x       = (const float*)d_in[0];
    const float* y       = (const float*)d_in[1];
    const float* ln1_w   = (const float*)d_in[2];
    const float* ln1_b   = (const float*)d_in[3];
    const float* ln2_w   = (const float*)d_in[4];
    const float* ln2_b   = (const float*)d_in[5];
    const float* qkvA_w  = (const float*)d_in[6];
    const float* dwA_w   = (const float*)d_in[7];
    const float* qkvB_w  = (const float*)d_in[8];
    const float* dwB_w   = (const float*)d_in[9];
    const float* projA_w = (const float*)d_in[10];
    const float* projB_w = (const float*)d_in[11];
    const float* concat_w= (const float*)d_in[12];
    const float* temp    = (const float*)d_in[13];
    const float* pin_w   = (const float*)d_in[14];
    const float* dwf_w   = (const float*)d_in[15];
    const float* pout_w  = (const float*)d_in[16];
    float* out = (float*)d_out;

    cudaFuncSetAttribute(gemm96,   cudaFuncAttributeMaxDynamicSharedMemorySize, G96_SMEM_BYTES);
    cudaFuncSetAttribute(gemmPout, cudaFuncAttributeMaxDynamicSharedMemorySize, G96_SMEM_BYTES);
    cudaFuncSetAttribute(gemm4_tc, cudaFuncAttributeMaxDynamicSharedMemorySize, GEMM_SMEM_BYTES);

    __nv_bfloat16 *qkvA, *qkvAd, *qkvB, *qkvBd, *t, *gate;
    float *x1, *stsX, *stsY, *gpA, *gpB, *atA, *atB, *P0, *P1;
    uint32_t *prepQA, *prepQB, *prepPin, *prepPout_p, *prepC0, *prepC1, *cwApk, *cwBpk;
    float *sQA, *tQA, *sQB, *tQB, *sPin, *tPin;
    cudaGetSymbolAddress((void**)&qkvA,   g_qkvA);
    cudaGetSymbolAddress((void**)&qkvAd,  g_qkvAd);
    cudaGetSymbolAddress((void**)&qkvB,   g_qkvB);
    cudaGetSymbolAddress((void**)&qkvBd,  g_qkvBd);
    cudaGetSymbolAddress((void**)&t,      g_t);
    cudaGetSymbolAddress((void**)&gate,   g_gate);
    cudaGetSymbolAddress((void**)&x1,     g_x1);
    cudaGetSymbolAddress((void**)&stsX,   g_stsX);
    cudaGetSymbolAddress((void**)&stsY,   g_stsY);
    cudaGetSymbolAddress((void**)&gpA,    g_gpartA);
    cudaGetSymbolAddress((void**)&gpB,    g_gpartB);
    cudaGetSymbolAddress((void**)&atA,    g_attnA);
    cudaGetSymbolAddress((void**)&atB,    g_attnB);
    cudaGetSymbolAddress((void**)&P0,     g_P0);
    cudaGetSymbolAddress((void**)&P1,     g_P1);
    cudaGetSymbolAddress((void**)&prepQA,   g_prepQA);
    cudaGetSymbolAddress((void**)&prepQB,   g_prepQB);
    cudaGetSymbolAddress((void**)&prepPin,  g_prepPin);
    cudaGetSymbolAddress((void**)&prepPout_p, g_prepPout);
    cudaGetSymbolAddress((void**)&prepC0,   g_prepC0);
    cudaGetSymbolAddress((void**)&prepC1,   g_prepC1);
    cudaGetSymbolAddress((void**)&cwApk,    g_cwApk);
    cudaGetSymbolAddress((void**)&cwBpk,    g_cwBpk);
    cudaGetSymbolAddress((void**)&sQA,    g_sQA);
    cudaGetSymbolAddress((void**)&tQA,    g_tQA);
    cudaGetSymbolAddress((void**)&sQB,    g_sQB);
    cudaGetSymbolAddress((void**)&tQB,    g_tQB);
    cudaGetSymbolAddress((void**)&sPin,   g_sPin);
    cudaGetSymbolAddress((void**)&tPin,   g_tPin);

    const size_t P96   = (size_t)CDIM * HW;
    const size_t P288E = (size_t)3 * CDIM * HW;
    const size_t P510E = (size_t)2 * HIDDEN * HW;
    const size_t PGATE = (size_t)288 * HW;

    megaprep<<<53, 256>>>(qkvA_w, qkvB_w, pin_w, pout_w, concat_w,
                          projA_w, projB_w, ln1_w, ln1_b, ln2_w, ln2_b,
                          prepQA, prepQB, prepPin, prepPout_p, prepC0, prepC1,
                          sQA, tQA, sQB, tQB, sPin, tPin, P0, P1);

    // qkv for both branches; stats self-computed, persisted for gemm4
    {
        G96P p;
        p.Apk[0] = prepQA; p.Apk[1] = prepQB;
        p.sv[0] = sQA; p.sv[1] = sQB;
        p.tv[0] = tQA; p.tv[1] = tQB;
        p.X[0] = x; p.X[1] = y;
        p.stsOut[0] = (float2*)stsX; p.stsOut[1] = (float2*)stsY;
        p.Y[0] = qkvA; p.Y[1] = qkvB;
        dim3 g(3, HW / 128, BATCH * 2);
        gemm96<<<g, 256, G96_SMEM_BYTES>>>(p, 288, 2, P96, P288E);
    }

    // depthwise 3x3, both branches
    {
        dim3 blk(32, 8), g(IMG / 128, IMG / 8, 2 * BATCH * 288);
        dw3_kernel<<<g, blk>>>(qkvA, qkvB, dwA_w, dwB_w, qkvAd, qkvBd);
    }

    // Gram quadrants + fused norms, both branches
    {
        dim3 g(128, HEADS, 2 * BATCH);
        gram1_kernel<<<g, 256>>>(qkvAd, qkvBd, gpA, gpB);
    }

    attn_kernel<<<BATCH * HEADS, 192>>>(gpA, gpB, temp, atA, atB);
    {
        dim3 g(4, 6);
        cw_kernel<<<g, 256>>>(P0, P1, atA, atB, cwApk, cwBpk);
    }

    // fused x1 = x + cwA@vA + cwB@vB + concat0@LN(x) + concat1@LN(y)
    {
        G4 p;
        p.Apk[0] = cwApk;  p.aBatch[0] = 9216;
        p.Apk[1] = cwBpk;  p.aBatch[1] = 9216;
        p.Apk[2] = prepC0; p.aBatch[2] = 0;
        p.Apk[3] = prepC1; p.aBatch[3] = 0;
        p.X[0] = qkvAd + 192 * (size_t)HW; p.xBatch[0] = P288E; p.stats[0] = nullptr; p.isbf16[0] = 1;
        p.X[1] = qkvBd + 192 * (size_t)HW; p.xBatch[1] = P288E; p.stats[1] = nullptr; p.isbf16[1] = 1;
        p.X[2] = x;                        p.xBatch[2] = P96;   p.stats[2] = stsX;    p.isbf16[2] = 0;
        p.X[3] = y;                        p.xBatch[3] = P96;   p.stats[3] = stsY;    p.isbf16[3] = 0;
        dim3 g(1, HW / 128, BATCH);
        gemm4_tc<<<g, 256, GEMM_SMEM_BYTES>>>(p, ln1_w, ln1_b, x, x1);
    }

    // pin = W@LN2(x1): stats self-computed
    {
        G96P p;
        p.Apk[0] = prepPin; p.Apk[1] = prepPin;
        p.sv[0] = sPin; p.sv[1] = sPin;
        p.tv[0] = tPin; p.tv[1] = tPin;
        p.X[0] = x1; p.X[1] = x1;
        p.stsOut[0] = nullptr; p.stsOut[1] = nullptr;
        p.Y[0] = t; p.Y[1] = t;
        dim3 g(6, HW / 128, BATCH);
        gemm96<<<g, 256, G96_SMEM_BYTES>>>(p, 510, 1, P96, P510E);
    }

    // fused depthwise + gelu gate
    {
        dim3 blk(32, 8), g(IMG / 128, IMG / 8, BATCH * HIDDEN);
        dwgate_kernel<<<g, blk>>>(t, dwf_w, gate);
    }

    // pout + residual x1 -> output
    {
        dim3 g(1, HW / 128, BATCH);
        gemmPout<<<g, 256, G96_SMEM_BYTES>>>(prepPout_p, gate, x1, out,
                                             PGATE, P96, P96);
    }
}

// round 11
// speedup vs baseline: 4.3478x; 1.0748x over previous
#include <cuda_runtime.h>
#include <cuda_bf16.h>
#include <math.h>
#include <stdint.h>

#define HW      65536
#define IMG     256
#define BATCH   2
#define CDIM    96
#define HEADS   8
#define CHEAD   12
#define HIDDEN  255

// ---------------------------------------------------------------------------
// Scratch
// ---------------------------------------------------------------------------
__device__ __nv_bfloat16 g_qkvA [BATCH * 3 * CDIM * HW];
__device__ __nv_bfloat16 g_qkvAd[BATCH * 3 * CDIM * HW];
__device__ __nv_bfloat16 g_qkvB [BATCH * 3 * CDIM * HW];
__device__ __nv_bfloat16 g_qkvBd[BATCH * 3 * CDIM * HW];
__device__ __nv_bfloat16 g_t    [BATCH * 2 * HIDDEN * HW];
__device__ __nv_bfloat16 g_gate [BATCH * 288 * HW];   // 288-pitch; rows 255..287 stay zero
__device__ float g_x1   [BATCH * CDIM * HW];
__device__ float g_stsX [BATCH * HW * 2];
__device__ float g_stsY [BATCH * HW * 2];
// Gram partials: [bh][chunk*4+quad][warp][48]  (48 = acc36 + qsq6 + ksq6)
__device__ float g_gpartA[BATCH * HEADS * 128 * 8 * 48];
__device__ float g_gpartB[BATCH * HEADS * 128 * 8 * 48];
__device__ float g_attnA [BATCH * HEADS * 144];
__device__ float g_attnB [BATCH * HEADS * 144];
__device__ float g_P0  [CDIM * CDIM];
__device__ float g_P1  [CDIM * CDIM];
// prepacked tf32 fragment tiles
__device__ uint32_t g_prepQA  [3 * 9216];
__device__ uint32_t g_prepQB  [3 * 9216];
__device__ uint32_t g_prepPin [6 * 9216];
__device__ uint32_t g_prepPout[3 * 9216];
__device__ uint32_t g_prepC0  [9216];
__device__ uint32_t g_prepC1  [9216];
__device__ uint32_t g_cwApk   [BATCH * 9216];
__device__ uint32_t g_cwBpk   [BATCH * 9216];
__device__ float g_sQA[288],  g_tQA[288];
__device__ float g_sQB[288],  g_tQB[288];
__device__ float g_sPin[576], g_tPin[576];

// ---------------------------------------------------------------------------
// tf32 / cp.async helpers
// ---------------------------------------------------------------------------
__device__ __forceinline__ uint32_t f2tf(float f) {
    uint32_t u;
    asm("cvt.rna.tf32.f32 %0, %1;" : "=r"(u) : "f"(f));
    return u;
}

__device__ __forceinline__ void mma_tf32(float* c, const uint32_t* a, const uint32_t* b) {
    asm volatile(
        "mma.sync.aligned.m16n8k8.row.col.f32.tf32.tf32.f32 "
        "{%0,%1,%2,%3}, {%4,%5,%6,%7}, {%8,%9}, {%0,%1,%2,%3};"
        : "+f"(c[0]), "+f"(c[1]), "+f"(c[2]), "+f"(c[3])
        : "r"(a[0]), "r"(a[1]), "r"(a[2]), "r"(a[3]), "r"(b[0]), "r"(b[1]));
}

__device__ __forceinline__ void cp16(void* smem, const void* gmem) {
    uint32_t a = (uint32_t)__cvta_generic_to_shared(smem);
    asm volatile("cp.async.cg.shared.global [%0], [%1], 16;\n" :: "r"(a), "l"(gmem));
}
#define CP_COMMIT()  asm volatile("cp.async.commit_group;\n")
#define CP_WAIT(n)   asm volatile("cp.async.wait_group %0;\n" :: "n"(n))

__device__ __forceinline__ int a_pack_off(int m, int k) {
    return (k >> 3) * 768 + (m >> 4) * 128 + (m & 7) * 16 + (k & 3) * 4
         + ((k >> 2) & 1) * 2 + ((m >> 3) & 1);
}

#define GEMM_SMEM_WORDS (9216 + 96*136 + 128 + 128 + 96 + 96)
#define GEMM_SMEM_BYTES (GEMM_SMEM_WORDS * 4)
#define G96_SMEM_WORDS  (9216 + 2*32*136 + 256)
#define G96_SMEM_BYTES  (G96_SMEM_WORDS * 4)

// ---------------------------------------------------------------------------
// Mega-prep (unchanged).
// ---------------------------------------------------------------------------
__device__ void prep_tile(const float* __restrict__ W, int M, int tile,
                          const float* __restrict__ wln,
                          const float* __restrict__ bln,
                          uint32_t* __restrict__ Apk,
                          float* __restrict__ svec, float* __restrict__ tvec,
                          float* wls, float* bls) {
    int m0 = tile * 96;
    if (threadIdx.x < 96) { wls[threadIdx.x] = wln[threadIdx.x]; bls[threadIdx.x] = bln[threadIdx.x]; }
    __syncthreads();
#pragma unroll
    for (int i = 0; i < 36; i++) {
        int idx = threadIdx.x + i * 256;
        int m = idx / 96;
        int k = idx - m * 96;
        float v = 0.f;
        if (m0 + m < M) v = W[(size_t)(m0 + m) * 96 + k] * wls[k];
        Apk[tile * 9216 + a_pack_off(m, k)] = f2tf(v);
    }
    if (threadIdx.x < 96) {
        int gm = m0 + threadIdx.x;
        float s = 0.f, tt = 0.f;
        if (gm < M) {
            for (int k = 0; k < 96; k++) {
                float w = W[(size_t)gm * 96 + k];
                s  += w * wls[k];
                tt += w * bls[k];
            }
        }
        svec[tile * 96 + threadIdx.x] = s;
        tvec[tile * 96 + threadIdx.x] = tt;
    }
}

__global__ void megaprep(
        const float* __restrict__ qkvA_w, const float* __restrict__ qkvB_w,
        const float* __restrict__ pin_w,  const float* __restrict__ pout_w,
        const float* __restrict__ concat_w,
        const float* __restrict__ projA_w, const float* __restrict__ projB_w,
        const float* __restrict__ ln1_w, const float* __restrict__ ln1_b,
        const float* __restrict__ ln2_w, const float* __restrict__ ln2_b,
        uint32_t* __restrict__ prepQA, uint32_t* __restrict__ prepQB,
        uint32_t* __restrict__ prepPin, uint32_t* __restrict__ prepPout,
        uint32_t* __restrict__ prepC0, uint32_t* __restrict__ prepC1,
        float* __restrict__ sQA, float* __restrict__ tQA,
        float* __restrict__ sQB, float* __restrict__ tQB,
        float* __restrict__ sPin, float* __restrict__ tPin,
        float* __restrict__ P0, float* __restrict__ P1) {
    __shared__ float sbuf[96 * 96];
    int bid = blockIdx.x;
    if (bid < 3) {
        prep_tile(qkvA_w, 288, bid, ln1_w, ln1_b, prepQA, sQA, tQA, sbuf, sbuf + 96);
    } else if (bid < 6) {
        prep_tile(qkvB_w, 288, bid - 3, ln1_w, ln1_b, prepQB, sQB, tQB, sbuf, sbuf + 96);
    } else if (bid < 12) {
        prep_tile(pin_w, 510, bid - 6, ln2_w, ln2_b, prepPin, sPin, tPin, sbuf, sbuf + 96);
    } else if (bid < 15) {
        int s = bid - 12;
#pragma unroll
        for (int i = 0; i < 36; i++) {
            int idx = threadIdx.x + i * 256;
            int m = idx / 96;
            int k = idx - m * 96;
            int kg = s * 96 + k;
            float v = (kg < HIDDEN) ? pout_w[(size_t)m * HIDDEN + kg] : 0.f;
            prepPout[s * 9216 + a_pack_off(m, k)] = f2tf(v);
        }
    } else if (bid < 17) {
        const float* W = concat_w + (bid == 16 ? 96 : 0);
        uint32_t* out = (bid == 16) ? prepC1 : prepC0;
#pragma unroll
        for (int i = 0; i < 36; i++) {
            int idx = threadIdx.x + i * 256;
            int m = idx / 96;
            int k = idx - m * 96;
            out[a_pack_off(m, k)] = f2tf(W[(size_t)m * 192 + k]);
        }
    } else {
        int w = bid - 17;
        int br = w & 1;
        int yt = w >> 1;
        const float* proj = br ? projB_w : projA_w;
        const float* cw   = concat_w + (br ? 96 : 0);
        float* P = br ? P1 : P0;
        for (int i = threadIdx.x; i < 96 * 96; i += 256) sbuf[i] = proj[i];
        __syncthreads();
        int base = yt * 512;
#pragma unroll
        for (int r = 0; r < 2; r++) {
            int o = base + r * 256 + threadIdx.x;
            int m = o / 96, n = o % 96;
            float s = 0.f;
#pragma unroll 8
            for (int c = 0; c < 96; c++) s += cw[m * 192 + c] * sbuf[c * 96 + n];
            P[o] = s;
        }
    }
}

// ---------------------------------------------------------------------------
// 32-k MMA chunk on the 96x128 tile.
// ---------------------------------------------------------------------------
__device__ __forceinline__ void g96_chunk(
        float acc[3][4][4], const uint32_t* __restrict__ As,
        const uint32_t* __restrict__ Bbuf,
        int kc, int g, int t, int wmi, int wn) {
#pragma unroll
    for (int ks2 = 0; ks2 < 4; ks2++) {
        const uint32_t* Ab = As + (kc * 4 + ks2) * 768 + g * 16 + t * 4;
        const uint32_t* Bb = Bbuf + (ks2 * 8 + t) * 136 + wn + g;
        uint4 a4[3];
        uint32_t bf[4][2];
#pragma unroll
        for (int mi = 0; mi < 3; mi++)
            a4[mi] = *reinterpret_cast<const uint4*>(Ab + (wmi + mi) * 128);
#pragma unroll
        for (int ni = 0; ni < 4; ni++) {
            bf[ni][0] = Bb[ni * 8];
            bf[ni][1] = Bb[4 * 136 + ni * 8];
        }
#pragma unroll
        for (int mi = 0; mi < 3; mi++) {
            uint32_t af[4] = {a4[mi].x, a4[mi].y, a4[mi].z, a4[mi].w};
#pragma unroll
            for (int ni = 0; ni < 4; ni++)
                mma_tf32(acc[mi][ni], af, bf[ni]);
        }
    }
}

// ---------------------------------------------------------------------------
// K=96 pipelined tf32 GEMM with self-computed LayerNorm stats (unchanged).
// ---------------------------------------------------------------------------
struct G96P {
    const uint32_t* Apk[2];
    const float*    sv[2];
    const float*    tv[2];
    const float*    X[2];
    float2*         stsOut[2];
    __nv_bfloat16*  Y[2];
};

__global__ void __launch_bounds__(256, 3) gemm96(
        G96P p, int M, int NB, size_t xBatch, size_t yBatch) {
    extern __shared__ uint32_t sm[];
    uint32_t* As = sm;
    uint32_t* Bs = sm + 9216;
    float* mu_s  = (float*)(sm + 9216 + 8704);
    float* inv_s = mu_s + 128;

    int z  = blockIdx.z;
    int br = z % NB;
    int bz = z / NB;
    const float* Xb = p.X[br] + (size_t)bz * xBatch;
    __nv_bfloat16* Yb = p.Y[br] + (size_t)bz * yBatch;
    const float* svec = p.sv[br];
    const float* tvec = p.tv[br];

    int mtile = blockIdx.x;
    int m0 = mtile * 96;
    int n0 = blockIdx.y * 128;
    int tid  = threadIdx.x;
    int warp = tid >> 5;
    int lane = tid & 31;
    int g = lane >> 2;
    int t = lane & 3;
    int wm  = (warp >> 2) * 48;
    int wmi = (warp >> 2) * 3;
    int wn  = (warp & 3) * 32;

    {
        const uint4* Ag = reinterpret_cast<const uint4*>(p.Apk[br] + (size_t)mtile * 9216);
#pragma unroll
        for (int i = 0; i < 9; i++) {
            int idx = tid + i * 256;
            cp16(As + idx * 4, Ag + idx);
        }
    }
#pragma unroll
    for (int j = 0; j < 4; j++) {
        int idx = tid + j * 256;
        int k = idx >> 5, n4 = idx & 31;
        cp16(Bs + k * 136 + n4 * 4, Xb + (size_t)k * HW + n0 + n4 * 4);
    }
    CP_COMMIT();
#pragma unroll
    for (int j = 0; j < 4; j++) {
        int idx = tid + j * 256;
        int k = idx >> 5, n4 = idx & 31;
        cp16(Bs + 4352 + k * 136 + n4 * 4, Xb + (size_t)(32 + k) * HW + n0 + n4 * 4);
    }
    CP_COMMIT();

    float acc[3][4][4];
#pragma unroll
    for (int mi = 0; mi < 3; mi++)
#pragma unroll
        for (int ni = 0; ni < 4; ni++)
#pragma unroll
            for (int r = 0; r < 4; r++) acc[mi][ni][r] = 0.f;

    float csum = 0.f, csq = 0.f;
#define STATS_ACC(BUF)                                                      \
    if (tid < 128) {                                                        \
        _Pragma("unroll 8")                                                 \
        for (int k = 0; k < 32; k++) {                                      \
            float v = __uint_as_float((BUF)[k * 136 + tid]);                \
            csum += v; csq += v * v;                                        \
        }                                                                   \
    }

    CP_WAIT(1);
    __syncthreads();
    STATS_ACC(Bs);
    g96_chunk(acc, As, Bs, 0, g, t, wmi, wn);
    __syncthreads();
#pragma unroll
    for (int j = 0; j < 4; j++) {
        int idx = tid + j * 256;
        int k = idx >> 5, n4 = idx & 31;
        cp16(Bs + k * 136 + n4 * 4, Xb + (size_t)(64 + k) * HW + n0 + n4 * 4);
    }
    CP_COMMIT();
    CP_WAIT(1);
    __syncthreads();
    STATS_ACC(Bs + 4352);
    g96_chunk(acc, As, Bs + 4352, 1, g, t, wmi, wn);
    CP_WAIT(0);
    __syncthreads();
    STATS_ACC(Bs);
    g96_chunk(acc, As, Bs, 2, g, t, wmi, wn);
#undef STATS_ACC

    if (tid < 128) {
        float mu  = csum * (1.f / 96.f);
        float var = csq * (1.f / 96.f) - mu * mu;
        float inv = rsqrtf(var + 1e-5f);
        mu_s[tid]  = mu;
        inv_s[tid] = inv;
        if (mtile == 0 && p.stsOut[br] != nullptr)
            p.stsOut[br][(size_t)bz * HW + n0 + tid] = make_float2(mu, inv);
    }
    __syncthreads();

#pragma unroll
    for (int mi = 0; mi < 3; mi++) {
        int r0 = m0 + wm + mi * 16 + g;
        int r1 = r0 + 8;
        float s0 = 0.f, t0 = 0.f, s1 = 0.f, t1 = 0.f;
        if (r0 < M) { s0 = svec[r0]; t0 = tvec[r0]; }
        if (r1 < M) { s1 = svec[r1]; t1 = tvec[r1]; }
#pragma unroll
        for (int ni = 0; ni < 4; ni++) {
            int ln = wn + ni * 8 + 2 * t;
            int col = n0 + ln;
            float i0 = inv_s[ln],     m0v = mu_s[ln]     * i0;
            float i1 = inv_s[ln + 1], m1v = mu_s[ln + 1] * i1;
            if (r0 < M) {
                float vx = acc[mi][ni][0] * i0 - m0v * s0 + t0;
                float vy = acc[mi][ni][1] * i1 - m1v * s0 + t0;
                *reinterpret_cast<__nv_bfloat162*>(Yb + (size_t)r0 * HW + col) =
                    __floats2bfloat162_rn(vx, vy);
            }
            if (r1 < M) {
                float vx = acc[mi][ni][2] * i0 - m0v * s1 + t1;
                float vy = acc[mi][ni][3] * i1 - m1v * s1 + t1;
                *reinterpret_cast<__nv_bfloat162*>(Yb + (size_t)r1 * HW + col) =
                    __floats2bfloat162_rn(vx, vy);
            }
        }
    }
}

// ---------------------------------------------------------------------------
// pout (unchanged).
// ---------------------------------------------------------------------------
__global__ void __launch_bounds__(256, 3) gemmPout(
        const uint32_t* __restrict__ Apk,
        const __nv_bfloat16* __restrict__ X,
        const float* __restrict__ Rsrc,
        float* __restrict__ Y,
        size_t xBatch, size_t yBatch, size_t rBatch) {
    extern __shared__ uint32_t sm[];
    uint32_t* As = sm;
    uint32_t* Bs = sm + 9216;

    int bz = blockIdx.z;
    const __nv_bfloat16* Xb = X + (size_t)bz * xBatch;
    float*       Yb = Y    + (size_t)bz * yBatch;
    const float* Rb = Rsrc + (size_t)bz * rBatch;

    int n0 = blockIdx.y * 128;
    int tid  = threadIdx.x;
    int warp = tid >> 5;
    int lane = tid & 31;
    int g = lane >> 2;
    int t = lane & 3;
    int wm  = (warp >> 2) * 48;
    int wmi = (warp >> 2) * 3;
    int wn  = (warp & 3) * 32;

    int kk = tid >> 3;
    int nb = (tid & 7) * 16;

    uint4 rA, rB;
#define LDGB(c)                                                             \
    {                                                                       \
        const uint4* src = reinterpret_cast<const uint4*>(                  \
            Xb + (size_t)((c) * 32 + kk) * HW + n0 + nb);                   \
        rA = src[0]; rB = src[1];                                           \
    }
#define STSB(c)                                                             \
    {                                                                       \
        uint32_t* dst = Bs + ((c) & 1) * 4352 + kk * 136 + nb;              \
        uint32_t u;                                                         \
        u = rA.x; dst[0]  = u << 16; dst[1]  = u & 0xFFFF0000u;             \
        u = rA.y; dst[2]  = u << 16; dst[3]  = u & 0xFFFF0000u;             \
        u = rA.z; dst[4]  = u << 16; dst[5]  = u & 0xFFFF0000u;             \
        u = rA.w; dst[6]  = u << 16; dst[7]  = u & 0xFFFF0000u;             \
        u = rB.x; dst[8]  = u << 16; dst[9]  = u & 0xFFFF0000u;             \
        u = rB.y; dst[10] = u << 16; dst[11] = u & 0xFFFF0000u;             \
        u = rB.z; dst[12] = u << 16; dst[13] = u & 0xFFFF0000u;             \
        u = rB.w; dst[14] = u << 16; dst[15] = u & 0xFFFF0000u;             \
    }
#define LOADA(s)                                                            \
    {                                                                       \
        const uint4* Ag = reinterpret_cast<const uint4*>(Apk + (s) * 9216); \
        _Pragma("unroll")                                                   \
        for (int i = 0; i < 9; i++) {                                       \
            int idx = tid + i * 256;                                        \
            cp16(As + idx * 4, Ag + idx);                                   \
        }                                                                   \
        CP_COMMIT();                                                        \
    }

    LOADA(0);
    LDGB(0);
    STSB(0);
    LDGB(1);
    CP_WAIT(0);
    __syncthreads();

    float acc[3][4][4];
#pragma unroll
    for (int mi = 0; mi < 3; mi++)
#pragma unroll
        for (int ni = 0; ni < 4; ni++)
#pragma unroll
            for (int r = 0; r < 4; r++) acc[mi][ni][r] = 0.f;

#pragma unroll
    for (int c = 0; c < 9; c++) {
        g96_chunk(acc, As, Bs + (c & 1) * 4352, c % 3, g, t, wmi, wn);
        if (c < 8) {
            __syncthreads();
            bool newA = (c % 3 == 2);
            if (newA) LOADA(c / 3 + 1);
            STSB(c + 1);
            if (c + 2 <= 8) LDGB(c + 2);
            if (newA) CP_WAIT(0);
            __syncthreads();
        }
    }
#undef LOADA
#undef LDGB
#undef STSB

#pragma unroll
    for (int mi = 0; mi < 3; mi++) {
        int r0 = wm + mi * 16 + g;
        int r1 = r0 + 8;
#pragma unroll
        for (int ni = 0; ni < 4; ni++) {
            int col = n0 + wn + ni * 8 + 2 * t;
            float2 ra = *reinterpret_cast<const float2*>(Rb + (size_t)r0 * HW + col);
            float2 rb = *reinterpret_cast<const float2*>(Rb + (size_t)r1 * HW + col);
            float2 v01 = make_float2(acc[mi][ni][0] + ra.x, acc[mi][ni][1] + ra.y);
            float2 v23 = make_float2(acc[mi][ni][2] + rb.x, acc[mi][ni][3] + rb.y);
            *reinterpret_cast<float2*>(Yb + (size_t)r0 * HW + col) = v01;
            *reinterpret_cast<float2*>(Yb + (size_t)r1 * HW + col) = v23;
        }
    }
}

// ---------------------------------------------------------------------------
// 4-source fused GEMM for x1 (unchanged).
// ---------------------------------------------------------------------------
struct G4 {
    const uint32_t* Apk[4];
    size_t          aBatch[4];
    const void*     X[4];
    size_t          xBatch[4];
    const float*    stats[4];
    int             isbf16[4];
};

__global__ void __launch_bounds__(256, 2) gemm4_tc(
        G4 p,
        const float* __restrict__ lnw,
        const float* __restrict__ lnb,
        const float* __restrict__ Rsrc,
        float* __restrict__ Y) {
    extern __shared__ uint32_t smem_u[];
    uint32_t* As  = smem_u;
    uint32_t* Bs  = As + 9216;
    float* mu_s   = (float*)(Bs + 96 * 136);
    float* inv_s  = mu_s + 128;
    float* wln_s  = inv_s + 128;
    float* bln_s  = wln_s + 96;

    int bz = blockIdx.z;
    int n0 = blockIdx.y * 128;
    float*       Yb = Y    + (size_t)bz * CDIM * HW;
    const float* Rb = Rsrc + (size_t)bz * CDIM * HW;

    int tid  = threadIdx.x;
    int warp = tid >> 5;
    int lane = tid & 31;
    int g = lane >> 2;
    int t = lane & 3;
    int wm  = (warp >> 2) * 48;
    int wmi = (warp >> 2) * 3;
    int wn  = (warp & 3) * 32;

    if (tid < 96) { wln_s[tid] = lnw[tid]; bln_s[tid] = lnb[tid]; }

    float acc[3][4][4];
#pragma unroll
    for (int mi = 0; mi < 3; mi++)
#pragma unroll
        for (int ni = 0; ni < 4; ni++)
#pragma unroll
            for (int r = 0; r < 4; r++) acc[mi][ni][r] = 0.f;

    for (int s = 0; s < 4; s++) {
        __syncthreads();
        {
            const uint4* Ag = reinterpret_cast<const uint4*>(p.Apk[s] + (size_t)bz * p.aBatch[s]);
#pragma unroll
            for (int i = 0; i < 9; i++) {
                int idx = tid + i * 256;
                cp16(As + idx * 4, Ag + idx);
            }
            CP_COMMIT();
        }
        if (p.isbf16[s]) {
            const __nv_bfloat16* Xh = (const __nv_bfloat16*)p.X[s] + (size_t)bz * p.xBatch[s];
#pragma unroll
            for (int i = 0; i < 6; i++) {
                int idx = tid + i * 256;
                int k = idx >> 4, n8 = idx & 15;
                const uint32_t* src =
                    reinterpret_cast<const uint32_t*>(Xh + (size_t)k * HW + n0 + n8 * 8);
                uint32_t* dst = Bs + k * 136 + n8 * 8;
#pragma unroll
                for (int j = 0; j < 4; j++) {
                    uint32_t u = src[j];
                    dst[2 * j]     = u << 16;
                    dst[2 * j + 1] = u & 0xFFFF0000u;
                }
            }
        } else {
            const float* Xb = (const float*)p.X[s] + (size_t)bz * p.xBatch[s];
            bool ln = (p.stats[s] != nullptr);
            if (ln && tid < 128) {
                float2 sv = reinterpret_cast<const float2*>(p.stats[s])[(size_t)bz * HW + n0 + tid];
                mu_s[tid]  = sv.x;
                inv_s[tid] = sv.y;
            }
            if (ln) __syncthreads();
#pragma unroll
            for (int i = 0; i < 12; i++) {
                int idx = tid + i * 256;
                int k  = idx >> 5;
                int n4 = idx & 31;
                float4 v = reinterpret_cast<const float4*>(Xb + (size_t)k * HW + n0)[n4];
                if (ln) {
                    int nbq = n4 * 4;
                    float wk = wln_s[k], bk = bln_s[k];
                    v.x = (v.x - mu_s[nbq + 0]) * inv_s[nbq + 0] * wk + bk;
                    v.y = (v.y - mu_s[nbq + 1]) * inv_s[nbq + 1] * wk + bk;
                    v.z = (v.z - mu_s[nbq + 2]) * inv_s[nbq + 2] * wk + bk;
                    v.w = (v.w - mu_s[nbq + 3]) * inv_s[nbq + 3] * wk + bk;
                }
                uint4 u = make_uint4(__float_as_uint(v.x), __float_as_uint(v.y),
                                     __float_as_uint(v.z), __float_as_uint(v.w));
                *reinterpret_cast<uint4*>(Bs + k * 136 + n4 * 4) = u;
            }
        }
        CP_WAIT(0);
        __syncthreads();
#pragma unroll
        for (int ks = 0; ks < 12; ks++) {
            const uint32_t* Ab = As + ks * 768 + g * 16 + t * 4;
            const uint32_t* Bb = Bs + (ks * 8 + t) * 136 + wn + g;
            uint4 a4[3];
            uint32_t bf[4][2];
#pragma unroll
            for (int mi = 0; mi < 3; mi++)
                a4[mi] = *reinterpret_cast<const uint4*>(Ab + (wmi + mi) * 128);
#pragma unroll
            for (int ni = 0; ni < 4; ni++) {
                bf[ni][0] = Bb[ni * 8];
                bf[ni][1] = Bb[4 * 136 + ni * 8];
            }
#pragma unroll
            for (int mi = 0; mi < 3; mi++) {
                uint32_t af[4] = {a4[mi].x, a4[mi].y, a4[mi].z, a4[mi].w};
#pragma unroll
                for (int ni = 0; ni < 4; ni++)
                    mma_tf32(acc[mi][ni], af, bf[ni]);
            }
        }
    }

#pragma unroll
    for (int mi = 0; mi < 3; mi++) {
        int r0 = wm + mi * 16 + g;
        int r1 = r0 + 8;
#pragma unroll
        for (int ni = 0; ni < 4; ni++) {
            int col = n0 + wn + ni * 8 + 2 * t;
            float2 ra = *reinterpret_cast<const float2*>(Rb + (size_t)r0 * HW + col);
            float2 rb = *reinterpret_cast<const float2*>(Rb + (size_t)r1 * HW + col);
            float2 v01 = make_float2(acc[mi][ni][0] + ra.x, acc[mi][ni][1] + ra.y);
            float2 v23 = make_float2(acc[mi][ni][2] + rb.x, acc[mi][ni][3] + rb.y);
            *reinterpret_cast<float2*>(Yb + (size_t)r0 * HW + col) = v01;
            *reinterpret_cast<float2*>(Yb + (size_t)r1 * HW + col) = v23;
        }
    }
}

// ---------------------------------------------------------------------------
// Depthwise 3x3, 2 output rows per thread (4 input rows shared in regs).
// grid: (IMG/128, IMG/16, 2*BATCH*288), block (32, 8).
// ---------------------------------------------------------------------------
__global__ void dw3_kernel(const __nv_bfloat16* __restrict__ qA,
                           const __nv_bfloat16* __restrict__ qB,
                           const float* __restrict__ wA,
                           const float* __restrict__ wB,
                           __nv_bfloat16* __restrict__ oA,
                           __nv_bfloat16* __restrict__ oB) {
    int pl = blockIdx.z;
    int br = pl >= BATCH * 288;
    int rem = pl - br * BATCH * 288;
    int c = rem % 288;
    const __nv_bfloat16* ip = (br ? qB : qA) + (size_t)rem * HW;
    const float* wp = (br ? wB : wA) + c * 9;
    __nv_bfloat16* op = (br ? oB : oA) + (size_t)rem * HW;

    int x0 = (blockIdx.x * 32 + threadIdx.x) * 4;
    int y0 = (blockIdx.y * 8 + threadIdx.y) * 2;

    float w[9];
#pragma unroll
    for (int i = 0; i < 9; i++) w[i] = wp[i];

    float a0[4] = {0.f, 0.f, 0.f, 0.f};
    float a1[4] = {0.f, 0.f, 0.f, 0.f};
#pragma unroll
    for (int dy = -1; dy <= 2; dy++) {
        int yy = y0 + dy;
        if (yy < 0 || yy >= IMG) continue;
        const __nv_bfloat16* row = ip + yy * IMG;
        float v[6];
        v[0] = (x0 > 0) ? __bfloat162float(row[x0 - 1]) : 0.f;
        {
            const __nv_bfloat162* r2 = reinterpret_cast<const __nv_bfloat162*>(row + x0);
            float2 a = __bfloat1622float2(r2[0]);
            float2 b = __bfloat1622float2(r2[1]);
            v[1] = a.x; v[2] = a.y; v[3] = b.x; v[4] = b.y;
        }
        v[5] = (x0 + 4 < IMG) ? __bfloat162float(row[x0 + 4]) : 0.f;
        if (dy <= 1) {
            const float* wr = w + (dy + 1) * 3;
#pragma unroll
            for (int j = 0; j < 4; j++)
                a0[j] += wr[0] * v[j] + wr[1] * v[j + 1] + wr[2] * v[j + 2];
        }
        if (dy >= 0) {
            const float* wr = w + dy * 3;
#pragma unroll
            for (int j = 0; j < 4; j++)
                a1[j] += wr[0] * v[j] + wr[1] * v[j + 1] + wr[2] * v[j + 2];
        }
    }

    *reinterpret_cast<__nv_bfloat162*>(op + y0 * IMG + x0)     = __floats2bfloat162_rn(a0[0], a0[1]);
    *reinterpret_cast<__nv_bfloat162*>(op + y0 * IMG + x0 + 2) = __floats2bfloat162_rn(a0[2], a0[3]);
    *reinterpret_cast<__nv_bfloat162*>(op + (y0 + 1) * IMG + x0)     = __floats2bfloat162_rn(a1[0], a1[1]);
    *reinterpret_cast<__nv_bfloat162*>(op + (y0 + 1) * IMG + x0 + 2) = __floats2bfloat162_rn(a1[2], a1[3]);
}

// ---------------------------------------------------------------------------
// Fused FFN tail: dw3 on both t halves + gelu + multiply, 2 rows per thread.
// grid: (IMG/128, IMG/16, BATCH*HIDDEN).
// ---------------------------------------------------------------------------
__global__ void dwgate_kernel(const __nv_bfloat16* __restrict__ t,
                              const float* __restrict__ dwf,
                              __nv_bfloat16* __restrict__ gate) {
    int pl = blockIdx.z;
    int b = pl / HIDDEN, k = pl % HIDDEN;
    int x0 = (blockIdx.x * 32 + threadIdx.x) * 4;
    int y0 = (blockIdx.y * 8 + threadIdx.y) * 2;
    const __nv_bfloat16* i1 = t + ((size_t)b * 2 * HIDDEN + k) * HW;
    const __nv_bfloat16* i2 = t + ((size_t)b * 2 * HIDDEN + HIDDEN + k) * HW;
    const float* w1 = dwf + k * 9;
    const float* w2 = dwf + (HIDDEN + k) * 9;

    float wa[9], wb[9];
#pragma unroll
    for (int i = 0; i < 9; i++) { wa[i] = w1[i]; wb[i] = w2[i]; }

    float s1r0[4] = {0.f, 0.f, 0.f, 0.f}, s2r0[4] = {0.f, 0.f, 0.f, 0.f};
    float s1r1[4] = {0.f, 0.f, 0.f, 0.f}, s2r1[4] = {0.f, 0.f, 0.f, 0.f};
#pragma unroll
    for (int dy = -1; dy <= 2; dy++) {
        int yy = y0 + dy;
        if (yy < 0 || yy >= IMG) continue;
        const __nv_bfloat16* r1 = i1 + yy * IMG;
        const __nv_bfloat16* r2 = i2 + yy * IMG;
        float v1[6], v2[6];
        v1[0] = (x0 > 0) ? __bfloat162float(r1[x0 - 1]) : 0.f;
        v2[0] = (x0 > 0) ? __bfloat162float(r2[x0 - 1]) : 0.f;
        {
            const __nv_bfloat162* p1 = reinterpret_cast<const __nv_bfloat162*>(r1 + x0);
            const __nv_bfloat162* p2 = reinterpret_cast<const __nv_bfloat162*>(r2 + x0);
            float2 a1 = __bfloat1622float2(p1[0]), b1 = __bfloat1622float2(p1[1]);
            float2 a2 = __bfloat1622float2(p2[0]), b2 = __bfloat1622float2(p2[1]);
            v1[1] = a1.x; v1[2] = a1.y; v1[3] = b1.x; v1[4] = b1.y;
            v2[1] = a2.x; v2[2] = a2.y; v2[3] = b2.x; v2[4] = b2.y;
        }
        v1[5] = (x0 + 4 < IMG) ? __bfloat162float(r1[x0 + 4]) : 0.f;
        v2[5] = (x0 + 4 < IMG) ? __bfloat162float(r2[x0 + 4]) : 0.f;
        if (dy <= 1) {
            const float* wra = wa + (dy + 1) * 3;
            const float* wrb = wb + (dy + 1) * 3;
#pragma unroll
            for (int j = 0; j < 4; j++) {
                s1r0[j] += wra[0] * v1[j] + wra[1] * v1[j + 1] + wra[2] * v1[j + 2];
                s2r0[j] += wrb[0] * v2[j] + wrb[1] * v2[j + 1] + wrb[2] * v2[j + 2];
            }
        }
        if (dy >= 0) {
            const float* wra = wa + dy * 3;
            const float* wrb = wb + dy * 3;
#pragma unroll
            for (int j = 0; j < 4; j++) {
                s1r1[j] += wra[0] * v1[j] + wra[1] * v1[j + 1] + wra[2] * v1[j + 2];
                s2r1[j] += wrb[0] * v2[j] + wrb[1] * v2[j + 1] + wrb[2] * v2[j + 2];
            }
        }
    }

    float o0[4], o1[4];
#pragma unroll
    for (int j = 0; j < 4; j++) {
        float gl0 = 0.5f * s1r0[j] * (1.f + erff(s1r0[j] * 0.7071067811865475f));
        o0[j] = gl0 * s2r0[j];
        float gl1 = 0.5f * s1r1[j] * (1.f + erff(s1r1[j] * 0.7071067811865475f));
        o1[j] = gl1 * s2r1[j];
    }
    __nv_bfloat16* gp0 = gate + ((size_t)b * 288 + k) * HW + y0 * IMG + x0;
    __nv_bfloat16* gp1 = gp0 + IMG;
    *reinterpret_cast<__nv_bfloat162*>(gp0)     = __floats2bfloat162_rn(o0[0], o0[1]);
    *reinterpret_cast<__nv_bfloat162*>(gp0 + 2) = __floats2bfloat162_rn(o0[2], o0[3]);
    *reinterpret_cast<__nv_bfloat162*>(gp1)     = __floats2bfloat162_rn(o1[0], o1[1]);
    *reinterpret_cast<__nv_bfloat162*>(gp1 + 2) = __floats2bfloat162_rn(o1[2], o1[3]);
}

// ---------------------------------------------------------------------------
// Gram stage 1, quadrant split, 4 px/thread via uint2 (2x bf162) loads.
// grid (128, HEADS, 2*BATCH): bid.x = chunk*4 + quad, quad = qh*2+kh.
// Partial slot (48 floats): [0..35] acc; [36..41] qsq; [42..47] ksq.
// ---------------------------------------------------------------------------
__global__ void __launch_bounds__(256, 2) gram1_kernel(
        const __nv_bfloat16* __restrict__ qkvAd,
        const __nv_bfloat16* __restrict__ qkvBd,
        float* __restrict__ gpA, float* __restrict__ gpB) {
    int bx = blockIdx.x;
    int chunk = bx >> 2;
    int quad  = bx & 3;
    int qh = quad >> 1;
    int kh = quad & 1;
    int h = blockIdx.y;
    int b  = blockIdx.z >> 1;
    int br = blockIdx.z & 1;
    const __nv_bfloat16* qb = (br ? qkvAd : qkvBd) + ((size_t)b * 288 + h * CHEAD + qh * 6) * HW;
    const __nv_bfloat16* kb = (br ? qkvBd : qkvAd) + ((size_t)b * 288 + 96 + h * CHEAD + kh * 6) * HW;
    float* part = br ? gpB : gpA;

    float acc[36];
#pragma unroll
    for (int i = 0; i < 36; i++) acc[i] = 0.f;
    float qsq[6] = {0.f, 0.f, 0.f, 0.f, 0.f, 0.f};
    float ksq[6] = {0.f, 0.f, 0.f, 0.f, 0.f, 0.f};

    int p0 = chunk * 2048 + threadIdx.x * 4;
#pragma unroll
    for (int it = 0; it < 2; it++) {
        int p = p0 + it * 1024;
        float2 qv[6][2], kv[6][2];
#pragma unroll
        for (int c = 0; c < 6; c++) {
            uint2 u = *reinterpret_cast<const uint2*>(qb + (size_t)c * HW + p);
            qv[c][0] = __bfloat1622float2(*reinterpret_cast<__nv_bfloat162*>(&u.x));
            qv[c][1] = __bfloat1622float2(*reinterpret_cast<__nv_bfloat162*>(&u.y));
        }
#pragma unroll
        for (int d = 0; d < 6; d++) {
            uint2 u = *reinterpret_cast<const uint2*>(kb + (size_t)d * HW + p);
            kv[d][0] = __bfloat1622float2(*reinterpret_cast<__nv_bfloat162*>(&u.x));
            kv[d][1] = __bfloat1622float2(*reinterpret_cast<__nv_bfloat162*>(&u.y));
        }
#pragma unroll
        for (int c = 0; c < 6; c++)
#pragma unroll
            for (int d = 0; d < 6; d++)
                acc[c * 6 + d] += qv[c][0].x * kv[d][0].x + qv[c][0].y * kv[d][0].y
                                + qv[c][1].x * kv[d][1].x + qv[c][1].y * kv[d][1].y;
#pragma unroll
        for (int c = 0; c < 6; c++)
            qsq[c] += qv[c][0].x * qv[c][0].x + qv[c][0].y * qv[c][0].y
                    + qv[c][1].x * qv[c][1].x + qv[c][1].y * qv[c][1].y;
#pragma unroll
        for (int d = 0; d < 6; d++)
            ksq[d] += kv[d][0].x * kv[d][0].x + kv[d][0].y * kv[d][0].y
                    + kv[d][1].x * kv[d][1].x + kv[d][1].y * kv[d][1].y;
    }

    int warp = threadIdx.x >> 5;
    int lane = threadIdx.x & 31;
    float* outp = part + ((((size_t)(b * HEADS + h)) * 128 + bx) * 8 + warp) * 48;
#pragma unroll
    for (int i = 0; i < 48; i++) {
        float v = (i < 36) ? acc[i] : (i < 42 ? qsq[i - 36] : ksq[i - 42]);
#pragma unroll
        for (int off = 16; off > 0; off >>= 1)
            v += __shfl_down_sync(0xffffffffu, v, off);
        if (lane == 0) outp[i] = v;
    }
}

// ---------------------------------------------------------------------------
// Gram stage 2 with quadrant-layout partials + norms + temp + softmax.
// ---------------------------------------------------------------------------
__global__ void attn_kernel(const float* __restrict__ partA,
                            const float* __restrict__ partB,
                            const float* __restrict__ temp,
                            float* __restrict__ attnA,
                            float* __restrict__ attnB) {
    int bh = blockIdx.x;
    int h = bh % HEADS;
    __shared__ float GA[144], GB[144];
    __shared__ float nqA[12], nkA[12], nqB[12], nkB[12];
    int i = threadIdx.x;
    float sA = 0.f, sB = 0.f;
    if (i < 168) {
        int quad, off;
        if (i < 144) {
            int c = i / CHEAD, d = i % CHEAD;
            quad = (c / 6) * 2 + (d / 6);
            off  = (c % 6) * 6 + (d % 6);
        } else if (i < 156) {
            int c = i - 144;
            quad = (c / 6) * 2;
            off  = 36 + (c % 6);
        } else {
            int d = i - 156;
            quad = (d / 6);
            off  = 42 + (d % 6);
        }
        const float* pA = partA + (((size_t)bh * 128 + quad) * 8) * 48 + off;
        const float* pB = partB + (((size_t)bh * 128 + quad) * 8) * 48 + off;
        for (int ch = 0; ch < 32; ch++) {
#pragma unroll
            for (int w = 0; w < 8; w++) {
                size_t o = (size_t)ch * (4 * 8 * 48) + (size_t)w * 48;
                sA += pA[o];
                sB += pB[o];
            }
        }
        if (i >= 156) {
            nkA[i - 156] = fmaxf(sqrtf(sA), 1e-12f);
            nkB[i - 156] = fmaxf(sqrtf(sB), 1e-12f);
        } else if (i >= 144) {
            nqA[i - 144] = fmaxf(sqrtf(sA), 1e-12f);
            nqB[i - 144] = fmaxf(sqrtf(sB), 1e-12f);
        }
    }
    __syncthreads();
    if (i < 144) {
        int c = i / CHEAD, d = i % CHEAD;
        float tp = temp[h];
        GA[i] =  sA / (nqA[c] * nkA[d]) * tp;
        GB[i] = -sB / (nqB[c] * nkB[d]) * tp;
    }
    __syncthreads();
    if (i < 24) {
        float* G = (i < CHEAD) ? GA : GB;
        float* O = (i < CHEAD) ? attnA : attnB;
        int c = i % CHEAD;
        float mx = -1e30f;
        for (int d = 0; d < CHEAD; d++) mx = fmaxf(mx, G[c * CHEAD + d]);
        float e[CHEAD];
        float s = 0.f;
        for (int d = 0; d < CHEAD; d++) {
            e[d] = expf(G[c * CHEAD + d] - mx);
            s += e[d];
        }
        float inv = 1.f / s;
        for (int d = 0; d < CHEAD; d++)
            O[(size_t)bh * 144 + c * CHEAD + d] = e[d] * inv;
    }
}

// ---------------------------------------------------------------------------
// cw_pk[b] = pack_tf32(P @ blockdiag(attn[b])); grid (4, 6). (unchanged)
// ---------------------------------------------------------------------------
__global__ void cw_kernel(const float* __restrict__ P0,
                          const float* __restrict__ P1,
                          const float* __restrict__ atA,
                          const float* __restrict__ atB,
                          uint32_t* __restrict__ cwApk,
                          uint32_t* __restrict__ cwBpk) {
    int b  = blockIdx.x >> 1;
    int br = blockIdx.x & 1;
    const float* P  = br ? P1 : P0;
    const float* at = (br ? atB : atA) + (size_t)b * HEADS * 144;
    uint32_t* out = (br ? cwBpk : cwApk) + (size_t)b * 9216;
    __shared__ float a_s[HEADS * 144];
    for (int i = threadIdx.x; i < HEADS * 144; i += blockDim.x) a_s[i] = at[i];
    __syncthreads();
    int base = blockIdx.y * 1536;
#pragma unroll
    for (int r = 0; r < 6; r++) {
        int o = base + r * 256 + threadIdx.x;
        int m = o / 96, n = o % 96;
        int h = n / CHEAD, d = n % CHEAD;
        float s = 0.f;
#pragma unroll
        for (int c = 0; c < CHEAD; c++)
            s += P[m * 96 + h * CHEAD + c] * a_s[h * 144 + c * CHEAD + d];
        out[a_pack_off(m, n)] = f2tf(s);
    }
}

// ---------------------------------------------------------------------------
// Launch
// ---------------------------------------------------------------------------
extern "C" void kernel_launch(void* const* d_in, const int* in_sizes, int n_in,
                              void* d_out, int out_size) {
    const float* x       = (const float*)d_in[0];
    const float* y       = (const float*)d_in[1];
    const float* ln1_w   = (const float*)d_in[2];
    const float* ln1_b   = (const float*)d_in[3];
    const float* ln2_w   = (const float*)d_in[4];
    const float* ln2_b   = (const float*)d_in[5];
    const float* qkvA_w  = (const float*)d_in[6];
    const float* dwA_w   = (const float*)d_in[7];
    const float* qkvB_w  = (const float*)d_in[8];
    const float* dwB_w   = (const float*)d_in[9];
    const float* projA_w = (const float*)d_in[10];
    const float* projB_w = (const float*)d_in[11];
    const float* concat_w= (const float*)d_in[12];
    const float* temp    = (const float*)d_in[13];
    const float* pin_w   = (const float*)d_in[14];
    const float* dwf_w   = (const float*)d_in[15];
    const float* pout_w  = (const float*)d_in[16];
    float* out = (float*)d_out;

    cudaFuncSetAttribute(gemm96,   cudaFuncAttributeMaxDynamicSharedMemorySize, G96_SMEM_BYTES);
    cudaFuncSetAttribute(gemmPout, cudaFuncAttributeMaxDynamicSharedMemorySize, G96_SMEM_BYTES);
    cudaFuncSetAttribute(gemm4_tc, cudaFuncAttributeMaxDynamicSharedMemorySize, GEMM_SMEM_BYTES);

    __nv_bfloat16 *qkvA, *qkvAd, *qkvB, *qkvBd, *t, *gate;
    float *x1, *stsX, *stsY, *gpA, *gpB, *atA, *atB, *P0, *P1;
    uint32_t *prepQA, *prepQB, *prepPin, *prepPout_p, *prepC0, *prepC1, *cwApk, *cwBpk;
    float *sQA, *tQA, *sQB, *tQB, *sPin, *tPin;
    cudaGetSymbolAddress((void**)&qkvA,   g_qkvA);
    cudaGetSymbolAddress((void**)&qkvAd,  g_qkvAd);
    cudaGetSymbolAddress((void**)&qkvB,   g_qkvB);
    cudaGetSymbolAddress((void**)&qkvBd,  g_qkvBd);
    cudaGetSymbolAddress((void**)&t,      g_t);
    cudaGetSymbolAddress((void**)&gate,   g_gate);
    cudaGetSymbolAddress((void**)&x1,     g_x1);
    cudaGetSymbolAddress((void**)&stsX,   g_stsX);
    cudaGetSymbolAddress((void**)&stsY,   g_stsY);
    cudaGetSymbolAddress((void**)&gpA,    g_gpartA);
    cudaGetSymbolAddress((void**)&gpB,    g_gpartB);
    cudaGetSymbolAddress((void**)&atA,    g_attnA);
    cudaGetSymbolAddress((void**)&atB,    g_attnB);
    cudaGetSymbolAddress((void**)&P0,     g_P0);
    cudaGetSymbolAddress((void**)&P1,     g_P1);
    cudaGetSymbolAddress((void**)&prepQA,   g_prepQA);
    cudaGetSymbolAddress((void**)&prepQB,   g_prepQB);
    cudaGetSymbolAddress((void**)&prepPin,  g_prepPin);
    cudaGetSymbolAddress((void**)&prepPout_p, g_prepPout);
    cudaGetSymbolAddress((void**)&prepC0,   g_prepC0);
    cudaGetSymbolAddress((void**)&prepC1,   g_prepC1);
    cudaGetSymbolAddress((void**)&cwApk,    g_cwApk);
    cudaGetSymbolAddress((void**)&cwBpk,    g_cwBpk);
    cudaGetSymbolAddress((void**)&sQA,    g_sQA);
    cudaGetSymbolAddress((void**)&tQA,    g_tQA);
    cudaGetSymbolAddress((void**)&sQB,    g_sQB);
    cudaGetSymbolAddress((void**)&tQB,    g_tQB);
    cudaGetSymbolAddress((void**)&sPin,   g_sPin);
    cudaGetSymbolAddress((void**)&tPin,   g_tPin);

    const size_t P96   = (size_t)CDIM * HW;
    const size_t P288E = (size_t)3 * CDIM * HW;
    const size_t P510E = (size_t)2 * HIDDEN * HW;
    const size_t PGATE = (size_t)288 * HW;

    megaprep<<<53, 256>>>(qkvA_w, qkvB_w, pin_w, pout_w, concat_w,
                          projA_w, projB_w, ln1_w, ln1_b, ln2_w, ln2_b,
                          prepQA, prepQB, prepPin, prepPout_p, prepC0, prepC1,
                          sQA, tQA, sQB, tQB, sPin, tPin, P0, P1);

    // qkv for both branches; stats self-computed, persisted for gemm4
    {
        G96P p;
        p.Apk[0] = prepQA; p.Apk[1] = prepQB;
        p.sv[0] = sQA; p.sv[1] = sQB;
        p.tv[0] = tQA; p.tv[1] = tQB;
        p.X[0] = x; p.X[1] = y;
        p.stsOut[0] = (float2*)stsX; p.stsOut[1] = (float2*)stsY;
        p.Y[0] = qkvA; p.Y[1] = qkvB;
        dim3 g(3, HW / 128, BATCH * 2);
        gemm96<<<g, 256, G96_SMEM_BYTES>>>(p, 288, 2, P96, P288E);
    }

    // depthwise 3x3, both branches, 2 rows/thread
    {
        dim3 blk(32, 8), g(IMG / 128, IMG / 16, 2 * BATCH * 288);
        dw3_kernel<<<g, blk>>>(qkvA, qkvB, dwA_w, dwB_w, qkvAd, qkvBd);
    }

    // Gram quadrants + fused norms, both branches
    {
        dim3 g(128, HEADS, 2 * BATCH);
        gram1_kernel<<<g, 256>>>(qkvAd, qkvBd, gpA, gpB);
    }

    attn_kernel<<<BATCH * HEADS, 192>>>(gpA, gpB, temp, atA, atB);
    {
        dim3 g(4, 6);
        cw_kernel<<<g, 256>>>(P0, P1, atA, atB, cwApk, cwBpk);
    }

    // fused x1 = x + cwA@vA + cwB@vB + concat0@LN(x) + concat1@LN(y)
    {
        G4 p;
        p.Apk[0] = cwApk;  p.aBatch[0] = 9216;
        p.Apk[1] = cwBpk;  p.aBatch[1] = 9216;
        p.Apk[2] = prepC0; p.aBatch[2] = 0;
        p.Apk[3] = prepC1; p.aBatch[3] = 0;
        p.X[0] = qkvAd + 192 * (size_t)HW; p.xBatch[0] = P288E; p.stats[0] = nullptr; p.isbf16[0] = 1;
        p.X[1] = qkvBd + 192 * (size_t)HW; p.xBatch[1] = P288E; p.stats[1] = nullptr; p.isbf16[1] = 1;
        p.X[2] = x;                        p.xBatch[2] = P96;   p.stats[2] = stsX;    p.isbf16[2] = 0;
        p.X[3] = y;                        p.xBatch[3] = P96;   p.stats[3] = stsY;    p.isbf16[3] = 0;
        dim3 g(1, HW / 128, BATCH);
        gemm4_tc<<<g, 256, GEMM_SMEM_BYTES>>>(p, ln1_w, ln1_b, x, x1);
    }

    // pin = W@LN2(x1): stats self-computed
    {
        G96P p;
        p.Apk[0] = prepPin; p.Apk[1] = prepPin;
        p.sv[0] = sPin; p.sv[1] = sPin;
        p.tv[0] = tPin; p.tv[1] = tPin;
        p.X[0] = x1; p.X[1] = x1;
        p.stsOut[0] = nullptr; p.stsOut[1] = nullptr;
        p.Y[0] = t; p.Y[1] = t;
        dim3 g(6, HW / 128, BATCH);
        gemm96<<<g, 256, G96_SMEM_BYTES>>>(p, 510, 1, P96, P510E);
    }

    // fused depthwise + gelu gate, 2 rows/thread
    {
        dim3 blk(32, 8), g(IMG / 128, IMG / 16, BATCH * HIDDEN);
        dwgate_kernel<<<g, blk>>>(t, dwf_w, gate);
    }

    // pout + residual x1 -> output
    {
        dim3 g(1, HW / 128, BATCH);
        gemmPout<<<g, 256, G96_SMEM_BYTES>>>(prepPout_p, gate, x1, out,
                                             PGATE, P96, P96);
    }
}

// round 12
// speedup vs baseline: 4.9666x; 1.1423x over previous
#include <cuda_runtime.h>
#include <cuda_bf16.h>
#include <math.h>
#include <stdint.h>

#define HW      65536
#define IMG     256
#define BATCH   2
#define CDIM    96
#define HEADS   8
#define CHEAD   12
#define HIDDEN  255

// ---------------------------------------------------------------------------
// Scratch
// ---------------------------------------------------------------------------
__device__ __nv_bfloat16 g_qkvA [BATCH * 3 * CDIM * HW];
__device__ __nv_bfloat16 g_qkvAd[BATCH * 3 * CDIM * HW];
__device__ __nv_bfloat16 g_qkvB [BATCH * 3 * CDIM * HW];
__device__ __nv_bfloat16 g_qkvBd[BATCH * 3 * CDIM * HW];
__device__ __nv_bfloat16 g_t    [BATCH * 2 * HIDDEN * HW];
__device__ __nv_bfloat16 g_gate [BATCH * 288 * HW];   // 288-pitch; rows 255..287 stay zero
__device__ float g_x1   [BATCH * CDIM * HW];
__device__ float g_stsX [BATCH * HW * 2];
__device__ float g_stsY [BATCH * HW * 2];
// Gram partials: [bh][chunk*4+quad][warp][48]
__device__ float g_gpartA[BATCH * HEADS * 128 * 8 * 48];
__device__ float g_gpartB[BATCH * HEADS * 128 * 8 * 48];
__device__ float g_attnA [BATCH * HEADS * 144];
__device__ float g_attnB [BATCH * HEADS * 144];
__device__ float g_P0  [CDIM * CDIM];
__device__ float g_P1  [CDIM * CDIM];
// prepacked tf32 fragment tiles
__device__ uint32_t g_prepQA  [3 * 9216];
__device__ uint32_t g_prepQB  [3 * 9216];
__device__ uint32_t g_prepPin [6 * 9216];
__device__ uint32_t g_prepPout[3 * 9216];
__device__ uint32_t g_prepC0  [9216];
__device__ uint32_t g_prepC1  [9216];
__device__ uint32_t g_cwApk   [BATCH * 9216];
__device__ uint32_t g_cwBpk   [BATCH * 9216];
__device__ float g_sQA[288],  g_tQA[288];
__device__ float g_sQB[288],  g_tQB[288];
__device__ float g_sPin[576], g_tPin[576];

// ---------------------------------------------------------------------------
// tf32 / cp.async helpers
// ---------------------------------------------------------------------------
__device__ __forceinline__ uint32_t f2tf(float f) {
    uint32_t u;
    asm("cvt.rna.tf32.f32 %0, %1;" : "=r"(u) : "f"(f));
    return u;
}

__device__ __forceinline__ void mma_tf32(float* c, const uint32_t* a, const uint32_t* b) {
    asm volatile(
        "mma.sync.aligned.m16n8k8.row.col.f32.tf32.tf32.f32 "
        "{%0,%1,%2,%3}, {%4,%5,%6,%7}, {%8,%9}, {%0,%1,%2,%3};"
        : "+f"(c[0]), "+f"(c[1]), "+f"(c[2]), "+f"(c[3])
        : "r"(a[0]), "r"(a[1]), "r"(a[2]), "r"(a[3]), "r"(b[0]), "r"(b[1]));
}

__device__ __forceinline__ void cp16(void* smem, const void* gmem) {
    uint32_t a = (uint32_t)__cvta_generic_to_shared(smem);
    asm volatile("cp.async.cg.shared.global [%0], [%1], 16;\n" :: "r"(a), "l"(gmem));
}
#define CP_COMMIT()  asm volatile("cp.async.commit_group;\n")
#define CP_WAIT(n)   asm volatile("cp.async.wait_group %0;\n" :: "n"(n))

__device__ __forceinline__ int a_pack_off(int m, int k) {
    return (k >> 3) * 768 + (m >> 4) * 128 + (m & 7) * 16 + (k & 3) * 4
         + ((k >> 2) & 1) * 2 + ((m >> 3) & 1);
}

#define GEMM_SMEM_WORDS (9216 + 96*136 + 128 + 128 + 96 + 96)
#define GEMM_SMEM_BYTES (GEMM_SMEM_WORDS * 4)
// gemm96: full B panel (96x136) + one A tile + stats
#define G96_SMEM_WORDS  (96*136 + 9216 + 256)
#define G96_SMEM_BYTES  (G96_SMEM_WORDS * 4)
// pout keeps double-buffered 32-row B ring
#define POUT_SMEM_WORDS (9216 + 2*32*136)
#define POUT_SMEM_BYTES (POUT_SMEM_WORDS * 4)

// ---------------------------------------------------------------------------
// Mega-prep (unchanged).
// ---------------------------------------------------------------------------
__device__ void prep_tile(const float* __restrict__ W, int M, int tile,
                          const float* __restrict__ wln,
                          const float* __restrict__ bln,
                          uint32_t* __restrict__ Apk,
                          float* __restrict__ svec, float* __restrict__ tvec,
                          float* wls, float* bls) {
    int m0 = tile * 96;
    if (threadIdx.x < 96) { wls[threadIdx.x] = wln[threadIdx.x]; bls[threadIdx.x] = bln[threadIdx.x]; }
    __syncthreads();
#pragma unroll
    for (int i = 0; i < 36; i++) {
        int idx = threadIdx.x + i * 256;
        int m = idx / 96;
        int k = idx - m * 96;
        float v = 0.f;
        if (m0 + m < M) v = W[(size_t)(m0 + m) * 96 + k] * wls[k];
        Apk[tile * 9216 + a_pack_off(m, k)] = f2tf(v);
    }
    if (threadIdx.x < 96) {
        int gm = m0 + threadIdx.x;
        float s = 0.f, tt = 0.f;
        if (gm < M) {
            for (int k = 0; k < 96; k++) {
                float w = W[(size_t)gm * 96 + k];
                s  += w * wls[k];
                tt += w * bls[k];
            }
        }
        svec[tile * 96 + threadIdx.x] = s;
        tvec[tile * 96 + threadIdx.x] = tt;
    }
}

__global__ void megaprep(
        const float* __restrict__ qkvA_w, const float* __restrict__ qkvB_w,
        const float* __restrict__ pin_w,  const float* __restrict__ pout_w,
        const float* __restrict__ concat_w,
        const float* __restrict__ projA_w, const float* __restrict__ projB_w,
        const float* __restrict__ ln1_w, const float* __restrict__ ln1_b,
        const float* __restrict__ ln2_w, const float* __restrict__ ln2_b,
        uint32_t* __restrict__ prepQA, uint32_t* __restrict__ prepQB,
        uint32_t* __restrict__ prepPin, uint32_t* __restrict__ prepPout,
        uint32_t* __restrict__ prepC0, uint32_t* __restrict__ prepC1,
        float* __restrict__ sQA, float* __restrict__ tQA,
        float* __restrict__ sQB, float* __restrict__ tQB,
        float* __restrict__ sPin, float* __restrict__ tPin,
        float* __restrict__ P0, float* __restrict__ P1) {
    __shared__ float sbuf[96 * 96];
    int bid = blockIdx.x;
    if (bid < 3) {
        prep_tile(qkvA_w, 288, bid, ln1_w, ln1_b, prepQA, sQA, tQA, sbuf, sbuf + 96);
    } else if (bid < 6) {
        prep_tile(qkvB_w, 288, bid - 3, ln1_w, ln1_b, prepQB, sQB, tQB, sbuf, sbuf + 96);
    } else if (bid < 12) {
        prep_tile(pin_w, 510, bid - 6, ln2_w, ln2_b, prepPin, sPin, tPin, sbuf, sbuf + 96);
    } else if (bid < 15) {
        int s = bid - 12;
#pragma unroll
        for (int i = 0; i < 36; i++) {
            int idx = threadIdx.x + i * 256;
            int m = idx / 96;
            int k = idx - m * 96;
            int kg = s * 96 + k;
            float v = (kg < HIDDEN) ? pout_w[(size_t)m * HIDDEN + kg] : 0.f;
            prepPout[s * 9216 + a_pack_off(m, k)] = f2tf(v);
        }
    } else if (bid < 17) {
        const float* W = concat_w + (bid == 16 ? 96 : 0);
        uint32_t* out = (bid == 16) ? prepC1 : prepC0;
#pragma unroll
        for (int i = 0; i < 36; i++) {
            int idx = threadIdx.x + i * 256;
            int m = idx / 96;
            int k = idx - m * 96;
            out[a_pack_off(m, k)] = f2tf(W[(size_t)m * 192 + k]);
        }
    } else {
        int w = bid - 17;
        int br = w & 1;
        int yt = w >> 1;
        const float* proj = br ? projB_w : projA_w;
        const float* cw   = concat_w + (br ? 96 : 0);
        float* P = br ? P1 : P0;
        for (int i = threadIdx.x; i < 96 * 96; i += 256) sbuf[i] = proj[i];
        __syncthreads();
        int base = yt * 512;
#pragma unroll
        for (int r = 0; r < 2; r++) {
            int o = base + r * 256 + threadIdx.x;
            int m = o / 96, n = o % 96;
            float s = 0.f;
#pragma unroll 8
            for (int c = 0; c < 96; c++) s += cw[m * 192 + c] * sbuf[c * 96 + n];
            P[o] = s;
        }
    }
}

// ---------------------------------------------------------------------------
// 32-k MMA chunk on the 96x128 tile.
// ---------------------------------------------------------------------------
__device__ __forceinline__ void g96_chunk(
        float acc[3][4][4], const uint32_t* __restrict__ As,
        const uint32_t* __restrict__ Bbuf,
        int kc, int g, int t, int wmi, int wn) {
#pragma unroll
    for (int ks2 = 0; ks2 < 4; ks2++) {
        const uint32_t* Ab = As + (kc * 4 + ks2) * 768 + g * 16 + t * 4;
        const uint32_t* Bb = Bbuf + (ks2 * 8 + t) * 136 + wn + g;
        uint4 a4[3];
        uint32_t bf[4][2];
#pragma unroll
        for (int mi = 0; mi < 3; mi++)
            a4[mi] = *reinterpret_cast<const uint4*>(Ab + (wmi + mi) * 128);
#pragma unroll
        for (int ni = 0; ni < 4; ni++) {
            bf[ni][0] = Bb[ni * 8];
            bf[ni][1] = Bb[4 * 136 + ni * 8];
        }
#pragma unroll
        for (int mi = 0; mi < 3; mi++) {
            uint32_t af[4] = {a4[mi].x, a4[mi].y, a4[mi].z, a4[mi].w};
#pragma unroll
            for (int ni = 0; ni < 4; ni++)
                mma_tf32(acc[mi][ni], af, bf[ni]);
        }
    }
}

// ---------------------------------------------------------------------------
// B-resident multi-M gemm96: stage the full 96x128 B panel once, loop over
// m-tiles internally (A tiles via cp.async, next-A overlapped with epilogue).
// Stats computed once per column. grid (1, HW/128, NB*BATCH).
// ---------------------------------------------------------------------------
struct G96P {
    const uint32_t* Apk[2];
    const float*    sv[2];
    const float*    tv[2];
    const float*    X[2];
    float2*         stsOut[2];
    __nv_bfloat16*  Y[2];
};

__global__ void __launch_bounds__(256, 2) gemm96(
        G96P p, int M, int NB, int Mtiles, size_t xBatch, size_t yBatch) {
    extern __shared__ uint32_t sm[];
    uint32_t* Bs = sm;                       // 96*136 = 13056
    uint32_t* As = sm + 13056;               // 9216
    float* mu_s  = (float*)(sm + 13056 + 9216);
    float* inv_s = mu_s + 128;

    int z  = blockIdx.z;
    int br = z % NB;
    int bz = z / NB;
    const float* Xb = p.X[br] + (size_t)bz * xBatch;
    __nv_bfloat16* Yb = p.Y[br] + (size_t)bz * yBatch;
    const float* svec = p.sv[br];
    const float* tvec = p.tv[br];
    const uint32_t* Apk = p.Apk[br];

    int n0 = blockIdx.y * 128;
    int tid  = threadIdx.x;
    int warp = tid >> 5;
    int lane = tid & 31;
    int g = lane >> 2;
    int t = lane & 3;
    int wm  = (warp >> 2) * 48;
    int wmi = (warp >> 2) * 3;
    int wn  = (warp & 3) * 32;

#define LOADA96(mt)                                                          \
    {                                                                        \
        const uint4* Ag = reinterpret_cast<const uint4*>(Apk + (size_t)(mt) * 9216); \
        _Pragma("unroll")                                                    \
        for (int i = 0; i < 9; i++) {                                        \
            int idx = tid + i * 256;                                         \
            cp16(As + idx * 4, Ag + idx);                                    \
        }                                                                    \
    }

    // ---- stage full B panel (96 rows) + A tile 0 ----
#pragma unroll
    for (int j = 0; j < 12; j++) {
        int idx = tid + j * 256;
        int k = idx >> 5, n4 = idx & 31;
        cp16(Bs + k * 136 + n4 * 4, Xb + (size_t)k * HW + n0 + n4 * 4);
    }
    LOADA96(0);
    CP_COMMIT();
    CP_WAIT(0);
    __syncthreads();

    // ---- stats once per column ----
    if (tid < 128) {
        float csum = 0.f, csq = 0.f;
#pragma unroll 8
        for (int k = 0; k < 96; k++) {
            float v = __uint_as_float(Bs[k * 136 + tid]);
            csum += v; csq += v * v;
        }
        float mu  = csum * (1.f / 96.f);
        float var = csq * (1.f / 96.f) - mu * mu;
        float inv = rsqrtf(var + 1e-5f);
        mu_s[tid]  = mu;
        inv_s[tid] = inv;
        if (p.stsOut[br] != nullptr)
            p.stsOut[br][(size_t)bz * HW + n0 + tid] = make_float2(mu, inv);
    }
    __syncthreads();

    for (int mt = 0; mt < Mtiles; mt++) {
        int m0 = mt * 96;
        float acc[3][4][4];
#pragma unroll
        for (int mi = 0; mi < 3; mi++)
#pragma unroll
            for (int ni = 0; ni < 4; ni++)
#pragma unroll
                for (int r = 0; r < 4; r++) acc[mi][ni][r] = 0.f;

#pragma unroll
        for (int kc = 0; kc < 3; kc++)
            g96_chunk(acc, As, Bs + kc * 4352, kc, g, t, wmi, wn);

        __syncthreads();                     // all warps done with As
        if (mt + 1 < Mtiles) {
            LOADA96(mt + 1);
            CP_COMMIT();
        }

        // ---- factored-LN epilogue for tile mt (overlaps A load) ----
#pragma unroll
        for (int mi = 0; mi < 3; mi++) {
            int r0 = m0 + wm + mi * 16 + g;
            int r1 = r0 + 8;
            float s0 = 0.f, t0 = 0.f, s1 = 0.f, t1 = 0.f;
            if (r0 < M) { s0 = svec[r0]; t0 = tvec[r0]; }
            if (r1 < M) { s1 = svec[r1]; t1 = tvec[r1]; }
#pragma unroll
            for (int ni = 0; ni < 4; ni++) {
                int ln = wn + ni * 8 + 2 * t;
                int col = n0 + ln;
                float i0 = inv_s[ln],     m0v = mu_s[ln]     * i0;
                float i1 = inv_s[ln + 1], m1v = mu_s[ln + 1] * i1;
                if (r0 < M) {
                    float vx = acc[mi][ni][0] * i0 - m0v * s0 + t0;
                    float vy = acc[mi][ni][1] * i1 - m1v * s0 + t0;
                    *reinterpret_cast<__nv_bfloat162*>(Yb + (size_t)r0 * HW + col) =
                        __floats2bfloat162_rn(vx, vy);
                }
                if (r1 < M) {
                    float vx = acc[mi][ni][2] * i0 - m0v * s1 + t1;
                    float vy = acc[mi][ni][3] * i1 - m1v * s1 + t1;
                    *reinterpret_cast<__nv_bfloat162*>(Yb + (size_t)r1 * HW + col) =
                        __floats2bfloat162_rn(vx, vy);
                }
            }
        }

        if (mt + 1 < Mtiles) {
            CP_WAIT(0);
            __syncthreads();
        }
    }
#undef LOADA96
}

// ---------------------------------------------------------------------------
// pout (unchanged from R11).
// ---------------------------------------------------------------------------
__global__ void __launch_bounds__(256, 3) gemmPout(
        const uint32_t* __restrict__ Apk,
        const __nv_bfloat16* __restrict__ X,
        const float* __restrict__ Rsrc,
        float* __restrict__ Y,
        size_t xBatch, size_t yBatch, size_t rBatch) {
    extern __shared__ uint32_t sm[];
    uint32_t* As = sm;
    uint32_t* Bs = sm + 9216;

    int bz = blockIdx.z;
    const __nv_bfloat16* Xb = X + (size_t)bz * xBatch;
    float*       Yb = Y    + (size_t)bz * yBatch;
    const float* Rb = Rsrc + (size_t)bz * rBatch;

    int n0 = blockIdx.y * 128;
    int tid  = threadIdx.x;
    int warp = tid >> 5;
    int lane = tid & 31;
    int g = lane >> 2;
    int t = lane & 3;
    int wm  = (warp >> 2) * 48;
    int wmi = (warp >> 2) * 3;
    int wn  = (warp & 3) * 32;

    int kk = tid >> 3;
    int nb = (tid & 7) * 16;

    uint4 rA, rB;
#define LDGB(c)                                                             \
    {                                                                       \
        const uint4* src = reinterpret_cast<const uint4*>(                  \
            Xb + (size_t)((c) * 32 + kk) * HW + n0 + nb);                   \
        rA = src[0]; rB = src[1];                                           \
    }
#define STSB(c)                                                             \
    {                                                                       \
        uint32_t* dst = Bs + ((c) & 1) * 4352 + kk * 136 + nb;              \
        uint32_t u;                                                         \
        u = rA.x; dst[0]  = u << 16; dst[1]  = u & 0xFFFF0000u;             \
        u = rA.y; dst[2]  = u << 16; dst[3]  = u & 0xFFFF0000u;             \
        u = rA.z; dst[4]  = u << 16; dst[5]  = u & 0xFFFF0000u;             \
        u = rA.w; dst[6]  = u << 16; dst[7]  = u & 0xFFFF0000u;             \
        u = rB.x; dst[8]  = u << 16; dst[9]  = u & 0xFFFF0000u;             \
        u = rB.y; dst[10] = u << 16; dst[11] = u & 0xFFFF0000u;             \
        u = rB.z; dst[12] = u << 16; dst[13] = u & 0xFFFF0000u;             \
        u = rB.w; dst[14] = u << 16; dst[15] = u & 0xFFFF0000u;             \
    }
#define LOADA(s)                                                            \
    {                                                                       \
        const uint4* Ag = reinterpret_cast<const uint4*>(Apk + (s) * 9216); \
        _Pragma("unroll")                                                   \
        for (int i = 0; i < 9; i++) {                                       \
            int idx = tid + i * 256;                                        \
            cp16(As + idx * 4, Ag + idx);                                   \
        }                                                                   \
        CP_COMMIT();                                                        \
    }

    LOADA(0);
    LDGB(0);
    STSB(0);
    LDGB(1);
    CP_WAIT(0);
    __syncthreads();

    float acc[3][4][4];
#pragma unroll
    for (int mi = 0; mi < 3; mi++)
#pragma unroll
        for (int ni = 0; ni < 4; ni++)
#pragma unroll
            for (int r = 0; r < 4; r++) acc[mi][ni][r] = 0.f;

#pragma unroll
    for (int c = 0; c < 9; c++) {
        g96_chunk(acc, As, Bs + (c & 1) * 4352, c % 3, g, t, wmi, wn);
        if (c < 8) {
            __syncthreads();
            bool newA = (c % 3 == 2);
            if (newA) LOADA(c / 3 + 1);
            STSB(c + 1);
            if (c + 2 <= 8) LDGB(c + 2);
            if (newA) CP_WAIT(0);
            __syncthreads();
        }
    }
#undef LOADA
#undef LDGB
#undef STSB

#pragma unroll
    for (int mi = 0; mi < 3; mi++) {
        int r0 = wm + mi * 16 + g;
        int r1 = r0 + 8;
#pragma unroll
        for (int ni = 0; ni < 4; ni++) {
            int col = n0 + wn + ni * 8 + 2 * t;
            float2 ra = *reinterpret_cast<const float2*>(Rb + (size_t)r0 * HW + col);
            float2 rb = *reinterpret_cast<const float2*>(Rb + (size_t)r1 * HW + col);
            float2 v01 = make_float2(acc[mi][ni][0] + ra.x, acc[mi][ni][1] + ra.y);
            float2 v23 = make_float2(acc[mi][ni][2] + rb.x, acc[mi][ni][3] + rb.y);
            *reinterpret_cast<float2*>(Yb + (size_t)r0 * HW + col) = v01;
            *reinterpret_cast<float2*>(Yb + (size_t)r1 * HW + col) = v23;
        }
    }
}

// ---------------------------------------------------------------------------
// 4-source fused GEMM for x1 (unchanged).
// ---------------------------------------------------------------------------
struct G4 {
    const uint32_t* Apk[4];
    size_t          aBatch[4];
    const void*     X[4];
    size_t          xBatch[4];
    const float*    stats[4];
    int             isbf16[4];
};

__global__ void __launch_bounds__(256, 2) gemm4_tc(
        G4 p,
        const float* __restrict__ lnw,
        const float* __restrict__ lnb,
        const float* __restrict__ Rsrc,
        float* __restrict__ Y) {
    extern __shared__ uint32_t smem_u[];
    uint32_t* As  = smem_u;
    uint32_t* Bs  = As + 9216;
    float* mu_s   = (float*)(Bs + 96 * 136);
    float* inv_s  = mu_s + 128;
    float* wln_s  = inv_s + 128;
    float* bln_s  = wln_s + 96;

    int bz = blockIdx.z;
    int n0 = blockIdx.y * 128;
    float*       Yb = Y    + (size_t)bz * CDIM * HW;
    const float* Rb = Rsrc + (size_t)bz * CDIM * HW;

    int tid  = threadIdx.x;
    int warp = tid >> 5;
    int lane = tid & 31;
    int g = lane >> 2;
    int t = lane & 3;
    int wm  = (warp >> 2) * 48;
    int wmi = (warp >> 2) * 3;
    int wn  = (warp & 3) * 32;

    if (tid < 96) { wln_s[tid] = lnw[tid]; bln_s[tid] = lnb[tid]; }

    float acc[3][4][4];
#pragma unroll
    for (int mi = 0; mi < 3; mi++)
#pragma unroll
        for (int ni = 0; ni < 4; ni++)
#pragma unroll
            for (int r = 0; r < 4; r++) acc[mi][ni][r] = 0.f;

    for (int s = 0; s < 4; s++) {
        __syncthreads();
        {
            const uint4* Ag = reinterpret_cast<const uint4*>(p.Apk[s] + (size_t)bz * p.aBatch[s]);
#pragma unroll
            for (int i = 0; i < 9; i++) {
                int idx = tid + i * 256;
                cp16(As + idx * 4, Ag + idx);
            }
            CP_COMMIT();
        }
        if (p.isbf16[s]) {
            const __nv_bfloat16* Xh = (const __nv_bfloat16*)p.X[s] + (size_t)bz * p.xBatch[s];
#pragma unroll
            for (int i = 0; i < 6; i++) {
                int idx = tid + i * 256;
                int k = idx >> 4, n8 = idx & 15;
                const uint32_t* src =
                    reinterpret_cast<const uint32_t*>(Xh + (size_t)k * HW + n0 + n8 * 8);
                uint32_t* dst = Bs + k * 136 + n8 * 8;
#pragma unroll
                for (int j = 0; j < 4; j++) {
                    uint32_t u = src[j];
                    dst[2 * j]     = u << 16;
                    dst[2 * j + 1] = u & 0xFFFF0000u;
                }
            }
        } else {
            const float* Xb = (const float*)p.X[s] + (size_t)bz * p.xBatch[s];
            bool ln = (p.stats[s] != nullptr);
            if (ln && tid < 128) {
                float2 sv = reinterpret_cast<const float2*>(p.stats[s])[(size_t)bz * HW + n0 + tid];
                mu_s[tid]  = sv.x;
                inv_s[tid] = sv.y;
            }
            if (ln) __syncthreads();
#pragma unroll
            for (int i = 0; i < 12; i++) {
                int idx = tid + i * 256;
                int k  = idx >> 5;
                int n4 = idx & 31;
                float4 v = reinterpret_cast<const float4*>(Xb + (size_t)k * HW + n0)[n4];
                if (ln) {
                    int nbq = n4 * 4;
                    float wk = wln_s[k], bk = bln_s[k];
                    v.x = (v.x - mu_s[nbq + 0]) * inv_s[nbq + 0] * wk + bk;
                    v.y = (v.y - mu_s[nbq + 1]) * inv_s[nbq + 1] * wk + bk;
                    v.z = (v.z - mu_s[nbq + 2]) * inv_s[nbq + 2] * wk + bk;
                    v.w = (v.w - mu_s[nbq + 3]) * inv_s[nbq + 3] * wk + bk;
                }
                uint4 u = make_uint4(__float_as_uint(v.x), __float_as_uint(v.y),
                                     __float_as_uint(v.z), __float_as_uint(v.w));
                *reinterpret_cast<uint4*>(Bs + k * 136 + n4 * 4) = u;
            }
        }
        CP_WAIT(0);
        __syncthreads();
#pragma unroll
        for (int ks = 0; ks < 12; ks++) {
            const uint32_t* Ab = As + ks * 768 + g * 16 + t * 4;
            const uint32_t* Bb = Bs + (ks * 8 + t) * 136 + wn + g;
            uint4 a4[3];
            uint32_t bf[4][2];
#pragma unroll
            for (int mi = 0; mi < 3; mi++)
                a4[mi] = *reinterpret_cast<const uint4*>(Ab + (wmi + mi) * 128);
#pragma unroll
            for (int ni = 0; ni < 4; ni++) {
                bf[ni][0] = Bb[ni * 8];
                bf[ni][1] = Bb[4 * 136 + ni * 8];
            }
#pragma unroll
            for (int mi = 0; mi < 3; mi++) {
                uint32_t af[4] = {a4[mi].x, a4[mi].y, a4[mi].z, a4[mi].w};
#pragma unroll
                for (int ni = 0; ni < 4; ni++)
                    mma_tf32(acc[mi][ni], af, bf[ni]);
            }
        }
    }

#pragma unroll
    for (int mi = 0; mi < 3; mi++) {
        int r0 = wm + mi * 16 + g;
        int r1 = r0 + 8;
#pragma unroll
        for (int ni = 0; ni < 4; ni++) {
            int col = n0 + wn + ni * 8 + 2 * t;
            float2 ra = *reinterpret_cast<const float2*>(Rb + (size_t)r0 * HW + col);
            float2 rb = *reinterpret_cast<const float2*>(Rb + (size_t)r1 * HW + col);
            float2 v01 = make_float2(acc[mi][ni][0] + ra.x, acc[mi][ni][1] + ra.y);
            float2 v23 = make_float2(acc[mi][ni][2] + rb.x, acc[mi][ni][3] + rb.y);
            *reinterpret_cast<float2*>(Yb + (size_t)r0 * HW + col) = v01;
            *reinterpret_cast<float2*>(Yb + (size_t)r1 * HW + col) = v23;
        }
    }
}

// ---------------------------------------------------------------------------
// Depthwise 3x3, 2 output rows per thread (unchanged).
// ---------------------------------------------------------------------------
__global__ void dw3_kernel(const __nv_bfloat16* __restrict__ qA,
                           const __nv_bfloat16* __restrict__ qB,
                           const float* __restrict__ wA,
                           const float* __restrict__ wB,
                           __nv_bfloat16* __restrict__ oA,
                           __nv_bfloat16* __restrict__ oB) {
    int pl = blockIdx.z;
    int br = pl >= BATCH * 288;
    int rem = pl - br * BATCH * 288;
    int c = rem % 288;
    const __nv_bfloat16* ip = (br ? qB : qA) + (size_t)rem * HW;
    const float* wp = (br ? wB : wA) + c * 9;
    __nv_bfloat16* op = (br ? oB : oA) + (size_t)rem * HW;

    int x0 = (blockIdx.x * 32 + threadIdx.x) * 4;
    int y0 = (blockIdx.y * 8 + threadIdx.y) * 2;

    float w[9];
#pragma unroll
    for (int i = 0; i < 9; i++) w[i] = wp[i];

    float a0[4] = {0.f, 0.f, 0.f, 0.f};
    float a1[4] = {0.f, 0.f, 0.f, 0.f};
#pragma unroll
    for (int dy = -1; dy <= 2; dy++) {
        int yy = y0 + dy;
        if (yy < 0 || yy >= IMG) continue;
        const __nv_bfloat16* row = ip + yy * IMG;
        float v[6];
        v[0] = (x0 > 0) ? __bfloat162float(row[x0 - 1]) : 0.f;
        {
            const __nv_bfloat162* r2 = reinterpret_cast<const __nv_bfloat162*>(row + x0);
            float2 a = __bfloat1622float2(r2[0]);
            float2 b = __bfloat1622float2(r2[1]);
            v[1] = a.x; v[2] = a.y; v[3] = b.x; v[4] = b.y;
        }
        v[5] = (x0 + 4 < IMG) ? __bfloat162float(row[x0 + 4]) : 0.f;
        if (dy <= 1) {
            const float* wr = w + (dy + 1) * 3;
#pragma unroll
            for (int j = 0; j < 4; j++)
                a0[j] += wr[0] * v[j] + wr[1] * v[j + 1] + wr[2] * v[j + 2];
        }
        if (dy >= 0) {
            const float* wr = w + dy * 3;
#pragma unroll
            for (int j = 0; j < 4; j++)
                a1[j] += wr[0] * v[j] + wr[1] * v[j + 1] + wr[2] * v[j + 2];
        }
    }

    *reinterpret_cast<__nv_bfloat162*>(op + y0 * IMG + x0)     = __floats2bfloat162_rn(a0[0], a0[1]);
    *reinterpret_cast<__nv_bfloat162*>(op + y0 * IMG + x0 + 2) = __floats2bfloat162_rn(a0[2], a0[3]);
    *reinterpret_cast<__nv_bfloat162*>(op + (y0 + 1) * IMG + x0)     = __floats2bfloat162_rn(a1[0], a1[1]);
    *reinterpret_cast<__nv_bfloat162*>(op + (y0 + 1) * IMG + x0 + 2) = __floats2bfloat162_rn(a1[2], a1[3]);
}

// ---------------------------------------------------------------------------
// Fused FFN tail (unchanged).
// ---------------------------------------------------------------------------
__global__ void dwgate_kernel(const __nv_bfloat16* __restrict__ t,
                              const float* __restrict__ dwf,
                              __nv_bfloat16* __restrict__ gate) {
    int pl = blockIdx.z;
    int b = pl / HIDDEN, k = pl % HIDDEN;
    int x0 = (blockIdx.x * 32 + threadIdx.x) * 4;
    int y0 = (blockIdx.y * 8 + threadIdx.y) * 2;
    const __nv_bfloat16* i1 = t + ((size_t)b * 2 * HIDDEN + k) * HW;
    const __nv_bfloat16* i2 = t + ((size_t)b * 2 * HIDDEN + HIDDEN + k) * HW;
    const float* w1 = dwf + k * 9;
    const float* w2 = dwf + (HIDDEN + k) * 9;

    float wa[9], wb[9];
#pragma unroll
    for (int i = 0; i < 9; i++) { wa[i] = w1[i]; wb[i] = w2[i]; }

    float s1r0[4] = {0.f, 0.f, 0.f, 0.f}, s2r0[4] = {0.f, 0.f, 0.f, 0.f};
    float s1r1[4] = {0.f, 0.f, 0.f, 0.f}, s2r1[4] = {0.f, 0.f, 0.f, 0.f};
#pragma unroll
    for (int dy = -1; dy <= 2; dy++) {
        int yy = y0 + dy;
        if (yy < 0 || yy >= IMG) continue;
        const __nv_bfloat16* r1 = i1 + yy * IMG;
        const __nv_bfloat16* r2 = i2 + yy * IMG;
        float v1[6], v2[6];
        v1[0] = (x0 > 0) ? __bfloat162float(r1[x0 - 1]) : 0.f;
        v2[0] = (x0 > 0) ? __bfloat162float(r2[x0 - 1]) : 0.f;
        {
            const __nv_bfloat162* p1 = reinterpret_cast<const __nv_bfloat162*>(r1 + x0);
            const __nv_bfloat162* p2 = reinterpret_cast<const __nv_bfloat162*>(r2 + x0);
            float2 a1 = __bfloat1622float2(p1[0]), b1 = __bfloat1622float2(p1[1]);
            float2 a2 = __bfloat1622float2(p2[0]), b2 = __bfloat1622float2(p2[1]);
            v1[1] = a1.x; v1[2] = a1.y; v1[3] = b1.x; v1[4] = b1.y;
            v2[1] = a2.x; v2[2] = a2.y; v2[3] = b2.x; v2[4] = b2.y;
        }
        v1[5] = (x0 + 4 < IMG) ? __bfloat162float(r1[x0 + 4]) : 0.f;
        v2[5] = (x0 + 4 < IMG) ? __bfloat162float(r2[x0 + 4]) : 0.f;
        if (dy <= 1) {
            const float* wra = wa + (dy + 1) * 3;
            const float* wrb = wb + (dy + 1) * 3;
#pragma unroll
            for (int j = 0; j < 4; j++) {
                s1r0[j] += wra[0] * v1[j] + wra[1] * v1[j + 1] + wra[2] * v1[j + 2];
                s2r0[j] += wrb[0] * v2[j] + wrb[1] * v2[j + 1] + wrb[2] * v2[j + 2];
            }
        }
        if (dy >= 0) {
            const float* wra = wa + dy * 3;
            const float* wrb = wb + dy * 3;
#pragma unroll
            for (int j = 0; j < 4; j++) {
                s1r1[j] += wra[0] * v1[j] + wra[1] * v1[j + 1] + wra[2] * v1[j + 2];
                s2r1[j] += wrb[0] * v2[j] + wrb[1] * v2[j + 1] + wrb[2] * v2[j + 2];
            }
        }
    }

    float o0[4], o1[4];
#pragma unroll
    for (int j = 0; j < 4; j++) {
        float gl0 = 0.5f * s1r0[j] * (1.f + erff(s1r0[j] * 0.7071067811865475f));
        o0[j] = gl0 * s2r0[j];
        float gl1 = 0.5f * s1r1[j] * (1.f + erff(s1r1[j] * 0.7071067811865475f));
        o1[j] = gl1 * s2r1[j];
    }
    __nv_bfloat16* gp0 = gate + ((size_t)b * 288 + k) * HW + y0 * IMG + x0;
    __nv_bfloat16* gp1 = gp0 + IMG;
    *reinterpret_cast<__nv_bfloat162*>(gp0)     = __floats2bfloat162_rn(o0[0], o0[1]);
    *reinterpret_cast<__nv_bfloat162*>(gp0 + 2) = __floats2bfloat162_rn(o0[2], o0[3]);
    *reinterpret_cast<__nv_bfloat162*>(gp1)     = __floats2bfloat162_rn(o1[0], o1[1]);
    *reinterpret_cast<__nv_bfloat162*>(gp1 + 2) = __floats2bfloat162_rn(o1[2], o1[3]);
}

// ---------------------------------------------------------------------------
// Gram stage 1, quadrant split, uint2 loads (unchanged from R11).
// ---------------------------------------------------------------------------
__global__ void __launch_bounds__(256, 2) gram1_kernel(
        const __nv_bfloat16* __restrict__ qkvAd,
        const __nv_bfloat16* __restrict__ qkvBd,
        float* __restrict__ gpA, float* __restrict__ gpB) {
    int bx = blockIdx.x;
    int chunk = bx >> 2;
    int quad  = bx & 3;
    int qh = quad >> 1;
    int kh = quad & 1;
    int h = blockIdx.y;
    int b  = blockIdx.z >> 1;
    int br = blockIdx.z & 1;
    const __nv_bfloat16* qb = (br ? qkvAd : qkvBd) + ((size_t)b * 288 + h * CHEAD + qh * 6) * HW;
    const __nv_bfloat16* kb = (br ? qkvBd : qkvAd) + ((size_t)b * 288 + 96 + h * CHEAD + kh * 6) * HW;
    float* part = br ? gpB : gpA;

    float acc[36];
#pragma unroll
    for (int i = 0; i < 36; i++) acc[i] = 0.f;
    float qsq[6] = {0.f, 0.f, 0.f, 0.f, 0.f, 0.f};
    float ksq[6] = {0.f, 0.f, 0.f, 0.f, 0.f, 0.f};

    int p0 = chunk * 2048 + threadIdx.x * 4;
#pragma unroll
    for (int it = 0; it < 2; it++) {
        int p = p0 + it * 1024;
        float2 qv[6][2], kv[6][2];
#pragma unroll
        for (int c = 0; c < 6; c++) {
            uint2 u = *reinterpret_cast<const uint2*>(qb + (size_t)c * HW + p);
            qv[c][0] = __bfloat1622float2(*reinterpret_cast<__nv_bfloat162*>(&u.x));
            qv[c][1] = __bfloat1622float2(*reinterpret_cast<__nv_bfloat162*>(&u.y));
        }
#pragma unroll
        for (int d = 0; d < 6; d++) {
            uint2 u = *reinterpret_cast<const uint2*>(kb + (size_t)d * HW + p);
            kv[d][0] = __bfloat1622float2(*reinterpret_cast<__nv_bfloat162*>(&u.x));
            kv[d][1] = __bfloat1622float2(*reinterpret_cast<__nv_bfloat162*>(&u.y));
        }
#pragma unroll
        for (int c = 0; c < 6; c++)
#pragma unroll
            for (int d = 0; d < 6; d++)
                acc[c * 6 + d] += qv[c][0].x * kv[d][0].x + qv[c][0].y * kv[d][0].y
                                + qv[c][1].x * kv[d][1].x + qv[c][1].y * kv[d][1].y;
#pragma unroll
        for (int c = 0; c < 6; c++)
            qsq[c] += qv[c][0].x * qv[c][0].x + qv[c][0].y * qv[c][0].y
                    + qv[c][1].x * qv[c][1].x + qv[c][1].y * qv[c][1].y;
#pragma unroll
        for (int d = 0; d < 6; d++)
            ksq[d] += kv[d][0].x * kv[d][0].x + kv[d][0].y * kv[d][0].y
                    + kv[d][1].x * kv[d][1].x + kv[d][1].y * kv[d][1].y;
    }

    int warp = threadIdx.x >> 5;
    int lane = threadIdx.x & 31;
    float* outp = part + ((((size_t)(b * HEADS + h)) * 128 + bx) * 8 + warp) * 48;
#pragma unroll
    for (int i = 0; i < 48; i++) {
        float v = (i < 36) ? acc[i] : (i < 42 ? qsq[i - 36] : ksq[i - 42]);
#pragma unroll
        for (int off = 16; off > 0; off >>= 1)
            v += __shfl_down_sync(0xffffffffu, v, off);
        if (lane == 0) outp[i] = v;
    }
}

// ---------------------------------------------------------------------------
// Gram stage 2 with quadrant-layout partials + norms + temp + softmax.
// ---------------------------------------------------------------------------
__global__ void attn_kernel(const float* __restrict__ partA,
                            const float* __restrict__ partB,
                            const float* __restrict__ temp,
                            float* __restrict__ attnA,
                            float* __restrict__ attnB) {
    int bh = blockIdx.x;
    int h = bh % HEADS;
    __shared__ float GA[144], GB[144];
    __shared__ float nqA[12], nkA[12], nqB[12], nkB[12];
    int i = threadIdx.x;
    float sA = 0.f, sB = 0.f;
    if (i < 168) {
        int quad, off;
        if (i < 144) {
            int c = i / CHEAD, d = i % CHEAD;
            quad = (c / 6) * 2 + (d / 6);
            off  = (c % 6) * 6 + (d % 6);
        } else if (i < 156) {
            int c = i - 144;
            quad = (c / 6) * 2;
            off  = 36 + (c % 6);
        } else {
            int d = i - 156;
            quad = (d / 6);
            off  = 42 + (d % 6);
        }
        const float* pA = partA + (((size_t)bh * 128 + quad) * 8) * 48 + off;
        const float* pB = partB + (((size_t)bh * 128 + quad) * 8) * 48 + off;
        for (int ch = 0; ch < 32; ch++) {
#pragma unroll
            for (int w = 0; w < 8; w++) {
                size_t o = (size_t)ch * (4 * 8 * 48) + (size_t)w * 48;
                sA += pA[o];
                sB += pB[o];
            }
        }
        if (i >= 156) {
            nkA[i - 156] = fmaxf(sqrtf(sA), 1e-12f);
            nkB[i - 156] = fmaxf(sqrtf(sB), 1e-12f);
        } else if (i >= 144) {
            nqA[i - 144] = fmaxf(sqrtf(sA), 1e-12f);
            nqB[i - 144] = fmaxf(sqrtf(sB), 1e-12f);
        }
    }
    __syncthreads();
    if (i < 144) {
        int c = i / CHEAD, d = i % CHEAD;
        float tp = temp[h];
        GA[i] =  sA / (nqA[c] * nkA[d]) * tp;
        GB[i] = -sB / (nqB[c] * nkB[d]) * tp;
    }
    __syncthreads();
    if (i < 24) {
        float* G = (i < CHEAD) ? GA : GB;
        float* O = (i < CHEAD) ? attnA : attnB;
        int c = i % CHEAD;
        float mx = -1e30f;
        for (int d = 0; d < CHEAD; d++) mx = fmaxf(mx, G[c * CHEAD + d]);
        float e[CHEAD];
        float s = 0.f;
        for (int d = 0; d < CHEAD; d++) {
            e[d] = expf(G[c * CHEAD + d] - mx);
            s += e[d];
        }
        float inv = 1.f / s;
        for (int d = 0; d < CHEAD; d++)
            O[(size_t)bh * 144 + c * CHEAD + d] = e[d] * inv;
    }
}

// ---------------------------------------------------------------------------
// cw_pk (unchanged).
// ---------------------------------------------------------------------------
__global__ void cw_kernel(const float* __restrict__ P0,
                          const float* __restrict__ P1,
                          const float* __restrict__ atA,
                          const float* __restrict__ atB,
                          uint32_t* __restrict__ cwApk,
                          uint32_t* __restrict__ cwBpk) {
    int b  = blockIdx.x >> 1;
    int br = blockIdx.x & 1;
    const float* P  = br ? P1 : P0;
    const float* at = (br ? atB : atA) + (size_t)b * HEADS * 144;
    uint32_t* out = (br ? cwBpk : cwApk) + (size_t)b * 9216;
    __shared__ float a_s[HEADS * 144];
    for (int i = threadIdx.x; i < HEADS * 144; i += blockDim.x) a_s[i] = at[i];
    __syncthreads();
    int base = blockIdx.y * 1536;
#pragma unroll
    for (int r = 0; r < 6; r++) {
        int o = base + r * 256 + threadIdx.x;
        int m = o / 96, n = o % 96;
        int h = n / CHEAD, d = n % CHEAD;
        float s = 0.f;
#pragma unroll
        for (int c = 0; c < CHEAD; c++)
            s += P[m * 96 + h * CHEAD + c] * a_s[h * 144 + c * CHEAD + d];
        out[a_pack_off(m, n)] = f2tf(s);
    }
}

// ---------------------------------------------------------------------------
// Launch
// ---------------------------------------------------------------------------
extern "C" void kernel_launch(void* const* d_in, const int* in_sizes, int n_in,
                              void* d_out, int out_size) {
    const float* x       = (const float*)d_in[0];
    const float* y       = (const float*)d_in[1];
    const float* ln1_w   = (const float*)d_in[2];
    const float* ln1_b   = (const float*)d_in[3];
    const float* ln2_w   = (const float*)d_in[4];
    const float* ln2_b   = (const float*)d_in[5];
    const float* qkvA_w  = (const float*)d_in[6];
    const float* dwA_w   = (const float*)d_in[7];
    const float* qkvB_w  = (const float*)d_in[8];
    const float* dwB_w   = (const float*)d_in[9];
    const float* projA_w = (const float*)d_in[10];
    const float* projB_w = (const float*)d_in[11];
    const float* concat_w= (const float*)d_in[12];
    const float* temp    = (const float*)d_in[13];
    const float* pin_w   = (const float*)d_in[14];
    const float* dwf_w   = (const float*)d_in[15];
    const float* pout_w  = (const float*)d_in[16];
    float* out = (float*)d_out;

    cudaFuncSetAttribute(gemm96,   cudaFuncAttributeMaxDynamicSharedMemorySize, G96_SMEM_BYTES);
    cudaFuncSetAttribute(gemmPout, cudaFuncAttributeMaxDynamicSharedMemorySize, POUT_SMEM_BYTES);
    cudaFuncSetAttribute(gemm4_tc, cudaFuncAttributeMaxDynamicSharedMemorySize, GEMM_SMEM_BYTES);

    __nv_bfloat16 *qkvA, *qkvAd, *qkvB, *qkvBd, *t, *gate;
    float *x1, *stsX, *stsY, *gpA, *gpB, *atA, *atB, *P0, *P1;
    uint32_t *prepQA, *prepQB, *prepPin, *prepPout_p, *prepC0, *prepC1, *cwApk, *cwBpk;
    float *sQA, *tQA, *sQB, *tQB, *sPin, *tPin;
    cudaGetSymbolAddress((void**)&qkvA,   g_qkvA);
    cudaGetSymbolAddress((void**)&qkvAd,  g_qkvAd);
    cudaGetSymbolAddress((void**)&qkvB,   g_qkvB);
    cudaGetSymbolAddress((void**)&qkvBd,  g_qkvBd);
    cudaGetSymbolAddress((void**)&t,      g_t);
    cudaGetSymbolAddress((void**)&gate,   g_gate);
    cudaGetSymbolAddress((void**)&x1,     g_x1);
    cudaGetSymbolAddress((void**)&stsX,   g_stsX);
    cudaGetSymbolAddress((void**)&stsY,   g_stsY);
    cudaGetSymbolAddress((void**)&gpA,    g_gpartA);
    cudaGetSymbolAddress((void**)&gpB,    g_gpartB);
    cudaGetSymbolAddress((void**)&atA,    g_attnA);
    cudaGetSymbolAddress((void**)&atB,    g_attnB);
    cudaGetSymbolAddress((void**)&P0,     g_P0);
    cudaGetSymbolAddress((void**)&P1,     g_P1);
    cudaGetSymbolAddress((void**)&prepQA,   g_prepQA);
    cudaGetSymbolAddress((void**)&prepQB,   g_prepQB);
    cudaGetSymbolAddress((void**)&prepPin,  g_prepPin);
    cudaGetSymbolAddress((void**)&prepPout_p, g_prepPout);
    cudaGetSymbolAddress((void**)&prepC0,   g_prepC0);
    cudaGetSymbolAddress((void**)&prepC1,   g_prepC1);
    cudaGetSymbolAddress((void**)&cwApk,    g_cwApk);
    cudaGetSymbolAddress((void**)&cwBpk,    g_cwBpk);
    cudaGetSymbolAddress((void**)&sQA,    g_sQA);
    cudaGetSymbolAddress((void**)&tQA,    g_tQA);
    cudaGetSymbolAddress((void**)&sQB,    g_sQB);
    cudaGetSymbolAddress((void**)&tQB,    g_tQB);
    cudaGetSymbolAddress((void**)&sPin,   g_sPin);
    cudaGetSymbolAddress((void**)&tPin,   g_tPin);

    const size_t P96   = (size_t)CDIM * HW;
    const size_t P288E = (size_t)3 * CDIM * HW;
    const size_t P510E = (size_t)2 * HIDDEN * HW;
    const size_t PGATE = (size_t)288 * HW;

    megaprep<<<53, 256>>>(qkvA_w, qkvB_w, pin_w, pout_w, concat_w,
                          projA_w, projB_w, ln1_w, ln1_b, ln2_w, ln2_b,
                          prepQA, prepQB, prepPin, prepPout_p, prepC0, prepC1,
                          sQA, tQA, sQB, tQB, sPin, tPin, P0, P1);

    // qkv for both branches (B-resident, 3 m-tiles in-block)
    {
        G96P p;
        p.Apk[0] = prepQA; p.Apk[1] = prepQB;
        p.sv[0] = sQA; p.sv[1] = sQB;
        p.tv[0] = tQA; p.tv[1] = tQB;
        p.X[0] = x; p.X[1] = y;
        p.stsOut[0] = (float2*)stsX; p.stsOut[1] = (float2*)stsY;
        p.Y[0] = qkvA; p.Y[1] = qkvB;
        dim3 g(1, HW / 128, BATCH * 2);
        gemm96<<<g, 256, G96_SMEM_BYTES>>>(p, 288, 2, 3, P96, P288E);
    }

    // depthwise 3x3, both branches, 2 rows/thread
    {
        dim3 blk(32, 8), g(IMG / 128, IMG / 16, 2 * BATCH * 288);
        dw3_kernel<<<g, blk>>>(qkvA, qkvB, dwA_w, dwB_w, qkvAd, qkvBd);
    }

    // Gram quadrants + fused norms, both branches
    {
        dim3 g(128, HEADS, 2 * BATCH);
        gram1_kernel<<<g, 256>>>(qkvAd, qkvBd, gpA, gpB);
    }

    attn_kernel<<<BATCH * HEADS, 192>>>(gpA, gpB, temp, atA, atB);
    {
        dim3 g(4, 6);
        cw_kernel<<<g, 256>>>(P0, P1, atA, atB, cwApk, cwBpk);
    }

    // fused x1 = x + cwA@vA + cwB@vB + concat0@LN(x) + concat1@LN(y)
    {
        G4 p;
        p.Apk[0] = cwApk;  p.aBatch[0] = 9216;
        p.Apk[1] = cwBpk;  p.aBatch[1] = 9216;
        p.Apk[2] = prepC0; p.aBatch[2] = 0;
        p.Apk[3] = prepC1; p.aBatch[3] = 0;
        p.X[0] = qkvAd + 192 * (size_t)HW; p.xBatch[0] = P288E; p.stats[0] = nullptr; p.isbf16[0] = 1;
        p.X[1] = qkvBd + 192 * (size_t)HW; p.xBatch[1] = P288E; p.stats[1] = nullptr; p.isbf16[1] = 1;
        p.X[2] = x;                        p.xBatch[2] = P96;   p.stats[2] = stsX;    p.isbf16[2] = 0;
        p.X[3] = y;                        p.xBatch[3] = P96;   p.stats[3] = stsY;    p.isbf16[3] = 0;
        dim3 g(1, HW / 128, BATCH);
        gemm4_tc<<<g, 256, GEMM_SMEM_BYTES>>>(p, ln1_w, ln1_b, x, x1);
    }

    // pin = W@LN2(x1), B-resident with 6 m-tiles in-block
    {
        G96P p;
        p.Apk[0] = prepPin; p.Apk[1] = prepPin;
        p.sv[0] = sPin; p.sv[1] = sPin;
        p.tv[0] = tPin; p.tv[1] = tPin;
        p.X[0] = x1; p.X[1] = x1;
        p.stsOut[0] = nullptr; p.stsOut[1] = nullptr;
        p.Y[0] = t; p.Y[1] = t;
        dim3 g(1, HW / 128, BATCH);
        gemm96<<<g, 256, G96_SMEM_BYTES>>>(p, 510, 1, 6, P96, P510E);
    }

    // fused depthwise + gelu gate, 2 rows/thread
    {
        dim3 blk(32, 8), g(IMG / 128, IMG / 16, BATCH * HIDDEN);
        dwgate_kernel<<<g, blk>>>(t, dwf_w, gate);
    }

    // pout + residual x1 -> output
    {
        dim3 g(1, HW / 128, BATCH);
        gemmPout<<<g, 256, POUT_SMEM_BYTES>>>(prepPout_p, gate, x1, out,
                                              PGATE, P96, P96);
    }
}